// round 1
// baseline (speedup 1.0000x reference)
#include <cuda_runtime.h>
#include <math.h>
#include <stdint.h>

// Model dims
#define SEQ    2048
#define DIM    1024
#define NHEAD  16
#define DH     64
#define NLAYER 2
#define NEXP   8
#define FFI    512
#define SFI    1024
#define VOCAB  32000

// ---------------- static scratch (no allocations allowed) ----------------
__device__ float g_h[SEQ * DIM];
__device__ float g_x[SEQ * DIM];
__device__ float g_q[SEQ * DIM];
__device__ float g_k[SEQ * DIM];
__device__ float g_v[SEQ * DIM];
__device__ float g_o[SEQ * DIM];
__device__ float g_big[(size_t)NHEAD * SEQ * SEQ];   // scores [16][2048][2048]; reused as logits [2048][32000]
__device__ float g_g[SEQ * FFI];
__device__ float g_u[SEQ * FFI];
__device__ float g_gs[SEQ * SFI];
__device__ float g_us[SEQ * SFI];
__device__ float g_comb[SEQ * NEXP];

// ---------------- generic tiled SGEMM ----------------
// C[M,N] = alpha * A[M,K] * op(B) (+ C if ACC)
// TRANSB: B is [N,K] row-major (op(B)=B^T). else B is [K,N] row-major.
// CAUSAL: skip blocks entirely above diagonal (for QK^T scores, M==N==SEQ).
// CAUSALK: limit K loop to m0+128 (for A*V where A is causal-masked).
template<bool TRANSB, bool ACC, bool CAUSAL, bool CAUSALK>
__global__ void __launch_bounds__(256) sgemm_kernel(
    const float* __restrict__ A, const float* __restrict__ B, float* __restrict__ C,
    int M, int N, int K, int lda, int ldb, int ldc, float alpha)
{
    const int m0 = blockIdx.y * 128;
    const int n0 = blockIdx.x * 128;
    if (CAUSAL && n0 > m0) return;

    __shared__ float As[8][128];
    __shared__ float Bs[8][128];

    const int tid = threadIdx.x;
    const int tx = tid & 15;
    const int ty = tid >> 4;

    const int arow = tid >> 1;
    const int acol = (tid & 1) << 2;

    float acc[8][8];
#pragma unroll
    for (int i = 0; i < 8; i++)
#pragma unroll
        for (int j = 0; j < 8; j++) acc[i][j] = 0.f;

    int kend = K;
    if (CAUSALK) { int ke = m0 + 128; kend = ke < K ? ke : K; }

    const float* Ap = A + (size_t)(m0 + arow) * lda + acol;

    const float* Bp;
    int brow, bcol;
    if (TRANSB) {
        brow = tid >> 1; bcol = (tid & 1) << 2;
        Bp = B + (size_t)(n0 + brow) * ldb + bcol;
    } else {
        brow = tid >> 5; bcol = (tid & 31) << 2;
        Bp = B + (size_t)brow * ldb + n0 + bcol;
    }

    for (int k0 = 0; k0 < kend; k0 += 8) {
        float4 av = *(const float4*)(Ap + k0);
        As[acol + 0][arow] = av.x;
        As[acol + 1][arow] = av.y;
        As[acol + 2][arow] = av.z;
        As[acol + 3][arow] = av.w;

        if (TRANSB) {
            float4 bv = make_float4(0.f, 0.f, 0.f, 0.f);
            if (n0 + brow < N) bv = *(const float4*)(Bp + k0);
            Bs[bcol + 0][brow] = bv.x;
            Bs[bcol + 1][brow] = bv.y;
            Bs[bcol + 2][brow] = bv.z;
            Bs[bcol + 3][brow] = bv.w;
        } else {
            float4 bv = make_float4(0.f, 0.f, 0.f, 0.f);
            if (n0 + bcol < N) bv = *(const float4*)(Bp + (size_t)k0 * ldb);
            *(float4*)&Bs[brow][bcol] = bv;
        }
        __syncthreads();

#pragma unroll
        for (int kk = 0; kk < 8; kk++) {
            float a[8], b[8];
            *(float4*)&a[0] = *(const float4*)&As[kk][ty * 8];
            *(float4*)&a[4] = *(const float4*)&As[kk][ty * 8 + 4];
            *(float4*)&b[0] = *(const float4*)&Bs[kk][tx * 8];
            *(float4*)&b[4] = *(const float4*)&Bs[kk][tx * 8 + 4];
#pragma unroll
            for (int i = 0; i < 8; i++)
#pragma unroll
                for (int j = 0; j < 8; j++)
                    acc[i][j] += a[i] * b[j];
        }
        __syncthreads();
    }

#pragma unroll
    for (int i = 0; i < 8; i++) {
        int row = m0 + ty * 8 + i;
#pragma unroll
        for (int j = 0; j < 8; j++) {
            int col = n0 + tx * 8 + j;
            if (col < N) {
                size_t idx = (size_t)row * ldc + col;
                float vv = alpha * acc[i][j];
                C[idx] = ACC ? (C[idx] + vv) : vv;
            }
        }
    }
}

// ---------------- small kernels ----------------
__global__ void embed_gather(const int* __restrict__ tok, const float* __restrict__ emb,
                             float* __restrict__ h)
{
    int s = blockIdx.x;
    int t = tok[s];
    const float* e = emb + (size_t)t * DIM;
    for (int d = threadIdx.x; d < DIM; d += blockDim.x)
        h[(size_t)s * DIM + d] = e[d];
}

__global__ void rmsnorm_kernel(const float* __restrict__ x, const float* __restrict__ w,
                               float* __restrict__ o)
{
    int row = blockIdx.x;
    const float* xr = x + (size_t)row * DIM;
    __shared__ float red[256];
    int tid = threadIdx.x;
    float s = 0.f;
    for (int d = tid; d < DIM; d += 256) { float v = xr[d]; s += v * v; }
    red[tid] = s; __syncthreads();
    for (int st = 128; st > 0; st >>= 1) {
        if (tid < st) red[tid] += red[tid + st];
        __syncthreads();
    }
    float rs = rsqrtf(red[0] / (float)DIM + 1e-6f);
    for (int d = tid; d < DIM; d += 256)
        o[(size_t)row * DIM + d] = xr[d] * rs * w[d];
}

__global__ void rope_kernel(float* __restrict__ q, float* __restrict__ k)
{
    int s = blockIdx.x;
    int tid = threadIdx.x;          // 512 = 16 heads * 32 pairs
    int h = tid >> 5, i = tid & 31;
    float freq = powf(10000.f, -(float)(2 * i) / 64.f);
    float ang = (float)s * freq;
    float sn, cs;
    sincosf(ang, &sn, &cs);
    size_t base = (size_t)s * DIM + h * DH + i;
    float q1 = q[base], q2 = q[base + 32];
    q[base]      = q1 * cs - q2 * sn;
    q[base + 32] = q2 * cs + q1 * sn;
    float k1 = k[base], k2 = k[base + 32];
    k[base]      = k1 * cs - k2 * sn;
    k[base + 32] = k2 * cs + k1 * sn;
}

__global__ void softmax_causal(float* __restrict__ sc)
{
    int row = blockIdx.x;
    int head = blockIdx.y;
    float* p = sc + (size_t)head * SEQ * SEQ + (size_t)row * SEQ;
    int n = row + 1;
    __shared__ float red[256];
    int tid = threadIdx.x;

    float m = -1e30f;
    for (int j = tid; j < n; j += 256) m = fmaxf(m, p[j]);
    red[tid] = m; __syncthreads();
    for (int st = 128; st > 0; st >>= 1) {
        if (tid < st) red[tid] = fmaxf(red[tid], red[tid + st]);
        __syncthreads();
    }
    m = red[0]; __syncthreads();

    float s = 0.f;
    for (int j = tid; j < n; j += 256) {
        float e = expf(p[j] - m);
        p[j] = e;
        s += e;
    }
    red[tid] = s; __syncthreads();
    for (int st = 128; st > 0; st >>= 1) {
        if (tid < st) red[tid] += red[tid + st];
        __syncthreads();
    }
    float inv = 1.f / red[0];
    for (int j = tid; j < SEQ; j += 256) {
        if (j < n) p[j] *= inv;
        else       p[j] = 0.f;
    }
}

__global__ void gate_topk(const float* __restrict__ x, const float* __restrict__ gw,
                          float* __restrict__ comb)
{
    int t = blockIdx.x;
    int tid = threadIdx.x;
    int e = tid >> 5, lane = tid & 31;
    const float* xr = x + (size_t)t * DIM;
    const float* wr = gw + (size_t)e * DIM;
    float s = 0.f;
    for (int d = lane; d < DIM; d += 32) s += xr[d] * wr[d];
    for (int o = 16; o; o >>= 1) s += __shfl_down_sync(0xffffffffu, s, o);
    __shared__ float lg[NEXP];
    if (lane == 0) lg[e] = s;
    __syncthreads();
    if (tid == 0) {
        float m = -1e30f;
        for (int i = 0; i < NEXP; i++) m = fmaxf(m, lg[i]);
        float p[NEXP]; float sum = 0.f;
        for (int i = 0; i < NEXP; i++) { p[i] = expf(lg[i] - m); sum += p[i]; }
        float inv = 1.f / sum;
        for (int i = 0; i < NEXP; i++) p[i] *= inv;
        int i0 = 0;
        for (int i = 1; i < NEXP; i++) if (p[i] > p[i0]) i0 = i;
        int i1 = -1;
        for (int i = 0; i < NEXP; i++) {
            if (i == i0) continue;
            if (i1 < 0 || p[i] > p[i1]) i1 = i;
        }
        for (int i = 0; i < NEXP; i++)
            comb[t * NEXP + i] = (i == i0 || i == i1) ? p[i] : 0.f;
    }
}

__global__ void act_routed(float* __restrict__ g, const float* __restrict__ u,
                           const float* __restrict__ comb, int e)
{
    int idx = blockIdx.x * 256 + threadIdx.x;   // < SEQ*FFI
    int t = idx >> 9;                            // /512
    float w = comb[t * NEXP + e];
    float gv = g[idx], uv = u[idx];
    float sig = 1.f / (1.f + expf(-gv));
    g[idx] = gv * sig * uv * w;
}

__global__ void act_silu_mul(float* __restrict__ g, const float* __restrict__ u)
{
    int idx = blockIdx.x * 256 + threadIdx.x;   // < SEQ*SFI
    float gv = g[idx], uv = u[idx];
    float sig = 1.f / (1.f + expf(-gv));
    g[idx] = gv * sig * uv;
}

__global__ void zero_scalar(float* p)
{
    if (threadIdx.x == 0 && blockIdx.x == 0) p[0] = 0.f;
}

__global__ void loss_kernel(const float* __restrict__ logits, const int* __restrict__ tgt,
                            float* __restrict__ out)
{
    int row = blockIdx.x;
    const float* lr = logits + (size_t)row * VOCAB;
    __shared__ float red[256];
    int tid = threadIdx.x;

    float m = -1e30f;
    for (int j = tid; j < VOCAB; j += 256) m = fmaxf(m, lr[j]);
    red[tid] = m; __syncthreads();
    for (int st = 128; st > 0; st >>= 1) {
        if (tid < st) red[tid] = fmaxf(red[tid], red[tid + st]);
        __syncthreads();
    }
    m = red[0]; __syncthreads();

    float s = 0.f;
    for (int j = tid; j < VOCAB; j += 256) s += expf(lr[j] - m);
    red[tid] = s; __syncthreads();
    for (int st = 128; st > 0; st >>= 1) {
        if (tid < st) red[tid] += red[tid + st];
        __syncthreads();
    }
    if (tid == 0) {
        int lab = tgt[row];
        if (lab != -100) {
            float lse = m + logf(red[0]);
            atomicAdd(out, lse - lr[lab]);
        }
    }
}

// ---------------- host-side launchers ----------------
static inline dim3 ggrid(int M, int N) { return dim3((N + 127) / 128, (M + 127) / 128); }

static void gemm_nt(const float* A, const float* B, float* C,
                    int M, int N, int K, int lda, int ldb, int ldc, float alpha)
{
    sgemm_kernel<true, false, false, false><<<ggrid(M, N), 256>>>(A, B, C, M, N, K, lda, ldb, ldc, alpha);
}
static void gemm_nt_acc(const float* A, const float* B, float* C,
                        int M, int N, int K, int lda, int ldb, int ldc, float alpha)
{
    sgemm_kernel<true, true, false, false><<<ggrid(M, N), 256>>>(A, B, C, M, N, K, lda, ldb, ldc, alpha);
}
static void gemm_nt_causal(const float* A, const float* B, float* C,
                           int M, int N, int K, int lda, int ldb, int ldc, float alpha)
{
    sgemm_kernel<true, false, true, false><<<ggrid(M, N), 256>>>(A, B, C, M, N, K, lda, ldb, ldc, alpha);
}
static void gemm_nn_ck(const float* A, const float* B, float* C,
                       int M, int N, int K, int lda, int ldb, int ldc, float alpha)
{
    sgemm_kernel<false, false, false, true><<<ggrid(M, N), 256>>>(A, B, C, M, N, K, lda, ldb, ldc, alpha);
}

extern "C" void kernel_launch(void* const* d_in, const int* in_sizes, int n_in,
                              void* d_out, int out_size)
{
    (void)in_sizes; (void)n_in; (void)out_size;
    const int*   src       = (const int*)d_in[0];
    const int*   tgt       = (const int*)d_in[1];
    const float* embed     = (const float*)d_in[2];
    const float* Wq        = (const float*)d_in[3];
    const float* Wk        = (const float*)d_in[4];
    const float* Wv        = (const float*)d_in[5];
    const float* Wo        = (const float*)d_in[6];
    const float* ln1       = (const float*)d_in[7];
    const float* ln2       = (const float*)d_in[8];
    const float* gate_w    = (const float*)d_in[9];
    const float* gate_proj = (const float*)d_in[10];
    const float* up_proj   = (const float*)d_in[11];
    const float* down_proj = (const float*)d_in[12];
    const float* sg        = (const float*)d_in[13];
    const float* su        = (const float*)d_in[14];
    const float* sd        = (const float*)d_in[15];
    const float* final_ln  = (const float*)d_in[16];
    const float* lm_head   = (const float*)d_in[17];
    float* out = (float*)d_out;

    float *h, *x, *q, *k, *v, *o, *big, *g, *u, *gs, *us, *comb;
    cudaGetSymbolAddress((void**)&h,    g_h);
    cudaGetSymbolAddress((void**)&x,    g_x);
    cudaGetSymbolAddress((void**)&q,    g_q);
    cudaGetSymbolAddress((void**)&k,    g_k);
    cudaGetSymbolAddress((void**)&v,    g_v);
    cudaGetSymbolAddress((void**)&o,    g_o);
    cudaGetSymbolAddress((void**)&big,  g_big);
    cudaGetSymbolAddress((void**)&g,    g_g);
    cudaGetSymbolAddress((void**)&u,    g_u);
    cudaGetSymbolAddress((void**)&gs,   g_gs);
    cudaGetSymbolAddress((void**)&us,   g_us);
    cudaGetSymbolAddress((void**)&comb, g_comb);

    const float attn_scale = 0.125f;   // 1/sqrt(64)

    embed_gather<<<SEQ, 256>>>(src, embed, h);

    for (int l = 0; l < NLAYER; l++) {
        // ---- attention ----
        rmsnorm_kernel<<<SEQ, 256>>>(h, ln1 + (size_t)l * DIM, x);
        gemm_nt(x, Wq + (size_t)l * DIM * DIM, q, SEQ, DIM, DIM, DIM, DIM, DIM, 1.f);
        gemm_nt(x, Wk + (size_t)l * DIM * DIM, k, SEQ, DIM, DIM, DIM, DIM, DIM, 1.f);
        gemm_nt(x, Wv + (size_t)l * DIM * DIM, v, SEQ, DIM, DIM, DIM, DIM, DIM, 1.f);
        rope_kernel<<<SEQ, NHEAD * 32>>>(q, k);

        for (int hh = 0; hh < NHEAD; hh++) {
            gemm_nt_causal(q + hh * DH, k + hh * DH, big + (size_t)hh * SEQ * SEQ,
                           SEQ, SEQ, DH, DIM, DIM, SEQ, attn_scale);
        }
        softmax_causal<<<dim3(SEQ, NHEAD), 256>>>(big);
        for (int hh = 0; hh < NHEAD; hh++) {
            gemm_nn_ck(big + (size_t)hh * SEQ * SEQ, v + hh * DH, o + hh * DH,
                       SEQ, DH, SEQ, SEQ, DIM, DIM, 1.f);
        }
        gemm_nt_acc(o, Wo + (size_t)l * DIM * DIM, h, SEQ, DIM, DIM, DIM, DIM, DIM, 1.f);

        // ---- MoE ----
        rmsnorm_kernel<<<SEQ, 256>>>(h, ln2 + (size_t)l * DIM, x);
        gate_topk<<<SEQ, 256>>>(x, gate_w + (size_t)l * NEXP * DIM, comb);

        for (int e = 0; e < NEXP; e++) {
            const float* gp = gate_proj + ((size_t)l * NEXP + e) * FFI * DIM;
            const float* up = up_proj   + ((size_t)l * NEXP + e) * FFI * DIM;
            const float* dp = down_proj + ((size_t)l * NEXP + e) * DIM * FFI;
            gemm_nt(x, gp, g, SEQ, FFI, DIM, DIM, DIM, FFI, 1.f);
            gemm_nt(x, up, u, SEQ, FFI, DIM, DIM, DIM, FFI, 1.f);
            act_routed<<<(SEQ * FFI) / 256, 256>>>(g, u, comb, e);
            gemm_nt_acc(g, dp, h, SEQ, DIM, FFI, FFI, FFI, DIM, 1.f);
        }

        // shared expert
        gemm_nt(x, sg + (size_t)l * SFI * DIM, gs, SEQ, SFI, DIM, DIM, DIM, SFI, 1.f);
        gemm_nt(x, su + (size_t)l * SFI * DIM, us, SEQ, SFI, DIM, DIM, DIM, SFI, 1.f);
        act_silu_mul<<<(SEQ * SFI) / 256, 256>>>(gs, us);
        gemm_nt_acc(gs, sd + (size_t)l * DIM * SFI, h, SEQ, DIM, SFI, SFI, SFI, DIM, 1.f);
    }

    // ---- head + loss ----
    rmsnorm_kernel<<<SEQ, 256>>>(h, final_ln, x);
    gemm_nt(x, lm_head, big, SEQ, VOCAB, DIM, DIM, DIM, VOCAB, 1.f);
    zero_scalar<<<1, 32>>>(out);
    loss_kernel<<<SEQ, 256>>>(big, tgt, out);
}

// round 2
// speedup vs baseline: 3.1960x; 3.1960x over previous
#include <cuda_runtime.h>
#include <cuda_bf16.h>
#include <math.h>
#include <stdint.h>

// Model dims
#define SEQ    2048
#define DIM    1024
#define NHEAD  16
#define DH     64
#define NLAYER 2
#define NEXP   8
#define FFI    512
#define SFI    1024
#define VOCAB  32000

#define BM 128
#define BN 128
#define BK 32
#define LDS_PAD 8          // smem row stride = BK + 8 = 40 elems (80B, 16B aligned)

// ---------------- static scratch (no allocations allowed) ----------------
__device__ float g_h[SEQ * DIM];
__device__ float g_x[SEQ * DIM];
__device__ float g_q[SEQ * DIM];
__device__ float g_k[SEQ * DIM];
__device__ float g_v[SEQ * DIM];
__device__ float g_o[SEQ * DIM];
__device__ float g_big[(size_t)NHEAD * SEQ * SEQ];   // scores; reused as logits [2048][32000]
__device__ float g_g[SEQ * FFI];
__device__ float g_u[SEQ * FFI];
__device__ float g_gs[SEQ * SFI];
__device__ float g_us[SEQ * SFI];
__device__ float g_comb[SEQ * NEXP];

// ---------------- helpers ----------------
__device__ __forceinline__ uint32_t cvt_bf16x2(float lo, float hi) {
    uint32_t r;
    asm("cvt.rn.bf16x2.f32 %0, %1, %2;" : "=r"(r) : "f"(hi), "f"(lo));
    return r;
}

__device__ __forceinline__ void ldsm4(uint32_t &r0, uint32_t &r1, uint32_t &r2, uint32_t &r3,
                                      uint32_t addr) {
    asm volatile("ldmatrix.sync.aligned.m8n8.x4.shared.b16 {%0,%1,%2,%3}, [%4];"
                 : "=r"(r0), "=r"(r1), "=r"(r2), "=r"(r3) : "r"(addr));
}

__device__ __forceinline__ void mma16816(float* c, const uint32_t* a, const uint32_t* b) {
    asm volatile(
        "mma.sync.aligned.m16n8k16.row.col.f32.bf16.bf16.f32 "
        "{%0,%1,%2,%3}, {%4,%5,%6,%7}, {%8,%9}, {%0,%1,%2,%3};"
        : "+f"(c[0]), "+f"(c[1]), "+f"(c[2]), "+f"(c[3])
        : "r"(a[0]), "r"(a[1]), "r"(a[2]), "r"(a[3]), "r"(b[0]), "r"(b[1]));
}

// ---------------- bf16 tensor-core GEMM ----------------
// C[M,N] = alpha * A[M,K](f32) * op(B)(f32)  (+ C if ACC), accumulate f32.
// TRANSB: B is [N,K] row-major. else B is [K,N] row-major.
// CAUSAL:  skip blocks entirely above the diagonal (M==N==SEQ score GEMM).
// CAUSALK: limit K loop to m0+BM (A*V where A is causal-masked).
// Requires: M % 128 == 0, K % 32 == 0, N % 4 == 0.
template<bool TRANSB, bool ACC, bool CAUSAL, bool CAUSALK>
__global__ void __launch_bounds__(256) mma_gemm_kernel(
    const float* __restrict__ A, const float* __restrict__ B, float* __restrict__ C,
    int M, int N, int K, int lda, int ldb, int ldc, float alpha)
{
    const int m0 = blockIdx.y * BM;
    const int n0 = blockIdx.x * BN;
    if (CAUSAL && n0 > m0) return;

    __shared__ __align__(16) __nv_bfloat16 As[BM][BK + LDS_PAD];
    __shared__ __align__(16) __nv_bfloat16 Bs[BN][BK + LDS_PAD];

    const int tid = threadIdx.x;
    const int lane = tid & 31;
    const int wid = tid >> 5;
    const int warp_m = wid & 3;    // 4 warps along M, 32 rows each
    const int warp_n = wid >> 2;   // 2 warps along N, 64 cols each
    const int g  = lane >> 3;
    const int lr = lane & 7;

    const uint32_t As_base = (uint32_t)__cvta_generic_to_shared(&As[0][0]);
    const uint32_t Bs_base = (uint32_t)__cvta_generic_to_shared(&Bs[0][0]);

    float acc[2][8][4];
#pragma unroll
    for (int mt = 0; mt < 2; mt++)
#pragma unroll
        for (int nt = 0; nt < 8; nt++)
#pragma unroll
            for (int i = 0; i < 4; i++) acc[mt][nt][i] = 0.f;

    int kend = K;
    if (CAUSALK) { int ke = m0 + BM; kend = ke < K ? ke : K; }

    for (int k0 = 0; k0 < kend; k0 += BK) {
        // ---- load A tile: 128x32 f32 -> bf16 smem ----
#pragma unroll
        for (int i = 0; i < 4; i++) {
            int id = i * 256 + tid;          // 0..1023
            int r = id >> 3;                 // 0..127
            int c = (id & 7) << 2;           // 0,4,..,28
            float4 v = *(const float4*)(A + (size_t)(m0 + r) * lda + k0 + c);
            uint2 pk;
            pk.x = cvt_bf16x2(v.x, v.y);
            pk.y = cvt_bf16x2(v.z, v.w);
            *(uint2*)&As[r][c] = pk;
        }
        // ---- load B tile into Bs[n][k] ----
        if (TRANSB) {
#pragma unroll
            for (int i = 0; i < 4; i++) {
                int id = i * 256 + tid;
                int r = id >> 3;
                int c = (id & 7) << 2;
                float4 v = make_float4(0.f, 0.f, 0.f, 0.f);
                if (n0 + r < N) v = *(const float4*)(B + (size_t)(n0 + r) * ldb + k0 + c);
                uint2 pk;
                pk.x = cvt_bf16x2(v.x, v.y);
                pk.y = cvt_bf16x2(v.z, v.w);
                *(uint2*)&Bs[r][c] = pk;
            }
        } else {
#pragma unroll
            for (int i = 0; i < 4; i++) {
                int id = i * 256 + tid;
                int kr = id >> 5;            // 0..31
                int nc = (id & 31) << 2;     // 0..124
                float4 v = make_float4(0.f, 0.f, 0.f, 0.f);
                if (n0 + nc < N) v = *(const float4*)(B + (size_t)(k0 + kr) * ldb + n0 + nc);
                Bs[nc + 0][kr] = __float2bfloat16(v.x);
                Bs[nc + 1][kr] = __float2bfloat16(v.y);
                Bs[nc + 2][kr] = __float2bfloat16(v.z);
                Bs[nc + 3][kr] = __float2bfloat16(v.w);
            }
        }
        __syncthreads();

        // ---- compute: 2 k16 steps ----
#pragma unroll
        for (int ks = 0; ks < 2; ks++) {
            uint32_t a[2][4];
#pragma unroll
            for (int mt = 0; mt < 2; mt++) {
                int row = warp_m * 32 + mt * 16 + (g & 1) * 8 + lr;
                int col = ks * 16 + (g >> 1) * 8;
                ldsm4(a[mt][0], a[mt][1], a[mt][2], a[mt][3],
                      As_base + (uint32_t)(row * (BK + LDS_PAD) + col) * 2);
            }
            uint32_t b[8][2];
#pragma unroll
            for (int np = 0; np < 4; np++) {
                int row = warp_n * 64 + np * 16 + (g >> 1) * 8 + lr;
                int col = ks * 16 + (g & 1) * 8;
                uint32_t r0, r1, r2, r3;
                ldsm4(r0, r1, r2, r3,
                      Bs_base + (uint32_t)(row * (BK + LDS_PAD) + col) * 2);
                b[2 * np][0] = r0; b[2 * np][1] = r1;
                b[2 * np + 1][0] = r2; b[2 * np + 1][1] = r3;
            }
#pragma unroll
            for (int mt = 0; mt < 2; mt++)
#pragma unroll
                for (int nt = 0; nt < 8; nt++)
                    mma16816(acc[mt][nt], a[mt], b[nt]);
        }
        __syncthreads();
    }

    // ---- epilogue ----
    const int r0c = lane >> 2;
    const int cc  = (lane & 3) * 2;
#pragma unroll
    for (int mt = 0; mt < 2; mt++) {
        int rbase = m0 + warp_m * 32 + mt * 16 + r0c;
#pragma unroll
        for (int nt = 0; nt < 8; nt++) {
            int col = n0 + warp_n * 64 + nt * 8 + cc;
            if (col < N) {
                size_t i00 = (size_t)rbase * ldc + col;
                size_t i10 = (size_t)(rbase + 8) * ldc + col;
                float v0 = alpha * acc[mt][nt][0];
                float v1 = alpha * acc[mt][nt][1];
                float v2 = alpha * acc[mt][nt][2];
                float v3 = alpha * acc[mt][nt][3];
                if (ACC) {
                    C[i00]     += v0; C[i00 + 1] += v1;
                    C[i10]     += v2; C[i10 + 1] += v3;
                } else {
                    C[i00]     = v0; C[i00 + 1] = v1;
                    C[i10]     = v2; C[i10 + 1] = v3;
                }
            }
        }
    }
}

// ---------------- small kernels ----------------
__global__ void embed_gather(const int* __restrict__ tok, const float* __restrict__ emb,
                             float* __restrict__ h)
{
    int s = blockIdx.x;
    int t = tok[s];
    const float* e = emb + (size_t)t * DIM;
    for (int d = threadIdx.x; d < DIM; d += blockDim.x)
        h[(size_t)s * DIM + d] = e[d];
}

__global__ void rmsnorm_kernel(const float* __restrict__ x, const float* __restrict__ w,
                               float* __restrict__ o)
{
    int row = blockIdx.x;
    const float* xr = x + (size_t)row * DIM;
    __shared__ float red[256];
    int tid = threadIdx.x;
    float s = 0.f;
    for (int d = tid; d < DIM; d += 256) { float v = xr[d]; s += v * v; }
    red[tid] = s; __syncthreads();
    for (int st = 128; st > 0; st >>= 1) {
        if (tid < st) red[tid] += red[tid + st];
        __syncthreads();
    }
    float rs = rsqrtf(red[0] / (float)DIM + 1e-6f);
    for (int d = tid; d < DIM; d += 256)
        o[(size_t)row * DIM + d] = xr[d] * rs * w[d];
}

__global__ void rope_kernel(float* __restrict__ q, float* __restrict__ k)
{
    int s = blockIdx.x;
    int tid = threadIdx.x;          // 512 = 16 heads * 32 pairs
    int h = tid >> 5, i = tid & 31;
    float freq = powf(10000.f, -(float)(2 * i) / 64.f);
    float ang = (float)s * freq;
    float sn, cs;
    sincosf(ang, &sn, &cs);
    size_t base = (size_t)s * DIM + h * DH + i;
    float q1 = q[base], q2 = q[base + 32];
    q[base]      = q1 * cs - q2 * sn;
    q[base + 32] = q2 * cs + q1 * sn;
    float k1 = k[base], k2 = k[base + 32];
    k[base]      = k1 * cs - k2 * sn;
    k[base + 32] = k2 * cs + k1 * sn;
}

__global__ void softmax_causal(float* __restrict__ sc)
{
    int row = blockIdx.x;
    int head = blockIdx.y;
    float* p = sc + (size_t)head * SEQ * SEQ + (size_t)row * SEQ;
    int n = row + 1;
    __shared__ float red[256];
    int tid = threadIdx.x;

    float m = -1e30f;
    for (int j = tid; j < n; j += 256) m = fmaxf(m, p[j]);
    red[tid] = m; __syncthreads();
    for (int st = 128; st > 0; st >>= 1) {
        if (tid < st) red[tid] = fmaxf(red[tid], red[tid + st]);
        __syncthreads();
    }
    m = red[0]; __syncthreads();

    float s = 0.f;
    for (int j = tid; j < n; j += 256) {
        float e = expf(p[j] - m);
        p[j] = e;
        s += e;
    }
    red[tid] = s; __syncthreads();
    for (int st = 128; st > 0; st >>= 1) {
        if (tid < st) red[tid] += red[tid + st];
        __syncthreads();
    }
    float inv = 1.f / red[0];
    for (int j = tid; j < SEQ; j += 256) {
        if (j < n) p[j] *= inv;
        else       p[j] = 0.f;
    }
}

__global__ void gate_topk(const float* __restrict__ x, const float* __restrict__ gw,
                          float* __restrict__ comb)
{
    int t = blockIdx.x;
    int tid = threadIdx.x;
    int e = tid >> 5, lane = tid & 31;
    const float* xr = x + (size_t)t * DIM;
    const float* wr = gw + (size_t)e * DIM;
    float s = 0.f;
    for (int d = lane; d < DIM; d += 32) s += xr[d] * wr[d];
    for (int o = 16; o; o >>= 1) s += __shfl_down_sync(0xffffffffu, s, o);
    __shared__ float lg[NEXP];
    if (lane == 0) lg[e] = s;
    __syncthreads();
    if (tid == 0) {
        float m = -1e30f;
        for (int i = 0; i < NEXP; i++) m = fmaxf(m, lg[i]);
        float p[NEXP]; float sum = 0.f;
        for (int i = 0; i < NEXP; i++) { p[i] = expf(lg[i] - m); sum += p[i]; }
        float inv = 1.f / sum;
        for (int i = 0; i < NEXP; i++) p[i] *= inv;
        int i0 = 0;
        for (int i = 1; i < NEXP; i++) if (p[i] > p[i0]) i0 = i;
        int i1 = -1;
        for (int i = 0; i < NEXP; i++) {
            if (i == i0) continue;
            if (i1 < 0 || p[i] > p[i1]) i1 = i;
        }
        for (int i = 0; i < NEXP; i++)
            comb[t * NEXP + i] = (i == i0 || i == i1) ? p[i] : 0.f;
    }
}

__global__ void act_routed(float* __restrict__ g, const float* __restrict__ u,
                           const float* __restrict__ comb, int e)
{
    int idx = blockIdx.x * 256 + threadIdx.x;   // < SEQ*FFI
    int t = idx >> 9;                            // /512
    float w = comb[t * NEXP + e];
    float gv = g[idx], uv = u[idx];
    float sig = 1.f / (1.f + expf(-gv));
    g[idx] = gv * sig * uv * w;
}

__global__ void act_silu_mul(float* __restrict__ g, const float* __restrict__ u)
{
    int idx = blockIdx.x * 256 + threadIdx.x;   // < SEQ*SFI
    float gv = g[idx], uv = u[idx];
    float sig = 1.f / (1.f + expf(-gv));
    g[idx] = gv * sig * uv;
}

__global__ void zero_scalar(float* p)
{
    if (threadIdx.x == 0 && blockIdx.x == 0) p[0] = 0.f;
}

__global__ void loss_kernel(const float* __restrict__ logits, const int* __restrict__ tgt,
                            float* __restrict__ out)
{
    int row = blockIdx.x;
    const float* lr = logits + (size_t)row * VOCAB;
    __shared__ float red[256];
    int tid = threadIdx.x;

    float m = -1e30f;
    for (int j = tid; j < VOCAB; j += 256) m = fmaxf(m, lr[j]);
    red[tid] = m; __syncthreads();
    for (int st = 128; st > 0; st >>= 1) {
        if (tid < st) red[tid] = fmaxf(red[tid], red[tid + st]);
        __syncthreads();
    }
    m = red[0]; __syncthreads();

    float s = 0.f;
    for (int j = tid; j < VOCAB; j += 256) s += expf(lr[j] - m);
    red[tid] = s; __syncthreads();
    for (int st = 128; st > 0; st >>= 1) {
        if (tid < st) red[tid] += red[tid + st];
        __syncthreads();
    }
    if (tid == 0) {
        int lab = tgt[row];
        if (lab != -100) {
            float lse = m + logf(red[0]);
            atomicAdd(out, lse - lr[lab]);
        }
    }
}

// ---------------- host-side launchers ----------------
static inline dim3 ggrid(int M, int N) { return dim3((N + BN - 1) / BN, (M + BM - 1) / BM); }

static void gemm_nt(const float* A, const float* B, float* C,
                    int M, int N, int K, int lda, int ldb, int ldc, float alpha)
{
    mma_gemm_kernel<true, false, false, false><<<ggrid(M, N), 256>>>(A, B, C, M, N, K, lda, ldb, ldc, alpha);
}
static void gemm_nt_acc(const float* A, const float* B, float* C,
                        int M, int N, int K, int lda, int ldb, int ldc, float alpha)
{
    mma_gemm_kernel<true, true, false, false><<<ggrid(M, N), 256>>>(A, B, C, M, N, K, lda, ldb, ldc, alpha);
}
static void gemm_nt_causal(const float* A, const float* B, float* C,
                           int M, int N, int K, int lda, int ldb, int ldc, float alpha)
{
    mma_gemm_kernel<true, false, true, false><<<ggrid(M, N), 256>>>(A, B, C, M, N, K, lda, ldb, ldc, alpha);
}
static void gemm_nn_ck(const float* A, const float* B, float* C,
                       int M, int N, int K, int lda, int ldb, int ldc, float alpha)
{
    mma_gemm_kernel<false, false, false, true><<<ggrid(M, N), 256>>>(A, B, C, M, N, K, lda, ldb, ldc, alpha);
}

extern "C" void kernel_launch(void* const* d_in, const int* in_sizes, int n_in,
                              void* d_out, int out_size)
{
    (void)in_sizes; (void)n_in; (void)out_size;
    const int*   src       = (const int*)d_in[0];
    const int*   tgt       = (const int*)d_in[1];
    const float* embed     = (const float*)d_in[2];
    const float* Wq        = (const float*)d_in[3];
    const float* Wk        = (const float*)d_in[4];
    const float* Wv        = (const float*)d_in[5];
    const float* Wo        = (const float*)d_in[6];
    const float* ln1       = (const float*)d_in[7];
    const float* ln2       = (const float*)d_in[8];
    const float* gate_w    = (const float*)d_in[9];
    const float* gate_proj = (const float*)d_in[10];
    const float* up_proj   = (const float*)d_in[11];
    const float* down_proj = (const float*)d_in[12];
    const float* sg        = (const float*)d_in[13];
    const float* su        = (const float*)d_in[14];
    const float* sd        = (const float*)d_in[15];
    const float* final_ln  = (const float*)d_in[16];
    const float* lm_head   = (const float*)d_in[17];
    float* out = (float*)d_out;

    float *h, *x, *q, *k, *v, *o, *big, *g, *u, *gs, *us, *comb;
    cudaGetSymbolAddress((void**)&h,    g_h);
    cudaGetSymbolAddress((void**)&x,    g_x);
    cudaGetSymbolAddress((void**)&q,    g_q);
    cudaGetSymbolAddress((void**)&k,    g_k);
    cudaGetSymbolAddress((void**)&v,    g_v);
    cudaGetSymbolAddress((void**)&o,    g_o);
    cudaGetSymbolAddress((void**)&big,  g_big);
    cudaGetSymbolAddress((void**)&g,    g_g);
    cudaGetSymbolAddress((void**)&u,    g_u);
    cudaGetSymbolAddress((void**)&gs,   g_gs);
    cudaGetSymbolAddress((void**)&us,   g_us);
    cudaGetSymbolAddress((void**)&comb, g_comb);

    const float attn_scale = 0.125f;   // 1/sqrt(64)

    embed_gather<<<SEQ, 256>>>(src, embed, h);

    for (int l = 0; l < NLAYER; l++) {
        // ---- attention ----
        rmsnorm_kernel<<<SEQ, 256>>>(h, ln1 + (size_t)l * DIM, x);
        gemm_nt(x, Wq + (size_t)l * DIM * DIM, q, SEQ, DIM, DIM, DIM, DIM, DIM, 1.f);
        gemm_nt(x, Wk + (size_t)l * DIM * DIM, k, SEQ, DIM, DIM, DIM, DIM, DIM, 1.f);
        gemm_nt(x, Wv + (size_t)l * DIM * DIM, v, SEQ, DIM, DIM, DIM, DIM, DIM, 1.f);
        rope_kernel<<<SEQ, NHEAD * 32>>>(q, k);

        for (int hh = 0; hh < NHEAD; hh++) {
            gemm_nt_causal(q + hh * DH, k + hh * DH, big + (size_t)hh * SEQ * SEQ,
                           SEQ, SEQ, DH, DIM, DIM, SEQ, attn_scale);
        }
        softmax_causal<<<dim3(SEQ, NHEAD), 256>>>(big);
        for (int hh = 0; hh < NHEAD; hh++) {
            gemm_nn_ck(big + (size_t)hh * SEQ * SEQ, v + hh * DH, o + hh * DH,
                       SEQ, DH, SEQ, SEQ, DIM, DIM, 1.f);
        }
        gemm_nt_acc(o, Wo + (size_t)l * DIM * DIM, h, SEQ, DIM, DIM, DIM, DIM, DIM, 1.f);

        // ---- MoE ----
        rmsnorm_kernel<<<SEQ, 256>>>(h, ln2 + (size_t)l * DIM, x);
        gate_topk<<<SEQ, 256>>>(x, gate_w + (size_t)l * NEXP * DIM, comb);

        for (int e = 0; e < NEXP; e++) {
            const float* gp = gate_proj + ((size_t)l * NEXP + e) * FFI * DIM;
            const float* up = up_proj   + ((size_t)l * NEXP + e) * FFI * DIM;
            const float* dp = down_proj + ((size_t)l * NEXP + e) * DIM * FFI;
            gemm_nt(x, gp, g, SEQ, FFI, DIM, DIM, DIM, FFI, 1.f);
            gemm_nt(x, up, u, SEQ, FFI, DIM, DIM, DIM, FFI, 1.f);
            act_routed<<<(SEQ * FFI) / 256, 256>>>(g, u, comb, e);
            gemm_nt_acc(g, dp, h, SEQ, DIM, FFI, FFI, FFI, DIM, 1.f);
        }

        // shared expert
        gemm_nt(x, sg + (size_t)l * SFI * DIM, gs, SEQ, SFI, DIM, DIM, DIM, SFI, 1.f);
        gemm_nt(x, su + (size_t)l * SFI * DIM, us, SEQ, SFI, DIM, DIM, DIM, SFI, 1.f);
        act_silu_mul<<<(SEQ * SFI) / 256, 256>>>(gs, us);
        gemm_nt_acc(gs, sd + (size_t)l * DIM * SFI, h, SEQ, DIM, SFI, SFI, SFI, DIM, 1.f);
    }

    // ---- head + loss ----
    rmsnorm_kernel<<<SEQ, 256>>>(h, final_ln, x);
    gemm_nt(x, lm_head, big, SEQ, VOCAB, DIM, DIM, DIM, VOCAB, 1.f);
    zero_scalar<<<1, 32>>>(out);
    loss_kernel<<<SEQ, 256>>>(big, tgt, out);
}

// round 3
// speedup vs baseline: 3.7273x; 1.1663x over previous
#include <cuda_runtime.h>
#include <cuda_bf16.h>
#include <math.h>
#include <stdint.h>

// Model dims
#define SEQ    2048
#define DIM    1024
#define NHEAD  16
#define DH     64
#define NLAYER 2
#define NEXP   8
#define FFI    512
#define SFI    1024
#define VOCAB  32000

#define BM 128
#define BN 128
#define BK 32
#define LDS_PAD 8          // smem row stride = 40 bf16 = 80B

// ---------------- static scratch (no allocations allowed) ----------------
__device__ float g_h[SEQ * DIM];
__device__ float g_x[SEQ * DIM];
__device__ float g_q[SEQ * DIM];
__device__ float g_k[SEQ * DIM];
__device__ float g_v[SEQ * DIM];
__device__ float g_o[SEQ * DIM];
__device__ float g_big[(size_t)NHEAD * SEQ * SEQ];   // scores; reused as logits [2048][32000]
__device__ float g_g[SEQ * FFI];
__device__ float g_u[SEQ * FFI];
__device__ float g_gs[SEQ * SFI];
__device__ float g_us[SEQ * SFI];
__device__ float g_comb[SEQ * NEXP];

// ---------------- helpers ----------------
__device__ __forceinline__ uint32_t cvt_bf16x2(float lo, float hi) {
    uint32_t r;
    asm("cvt.rn.bf16x2.f32 %0, %1, %2;" : "=r"(r) : "f"(hi), "f"(lo));
    return r;
}

__device__ __forceinline__ void ldsm4(uint32_t &r0, uint32_t &r1, uint32_t &r2, uint32_t &r3,
                                      uint32_t addr) {
    asm volatile("ldmatrix.sync.aligned.m8n8.x4.shared.b16 {%0,%1,%2,%3}, [%4];"
                 : "=r"(r0), "=r"(r1), "=r"(r2), "=r"(r3) : "r"(addr));
}

__device__ __forceinline__ void mma16816(float* c, const uint32_t* a, const uint32_t* b) {
    asm volatile(
        "mma.sync.aligned.m16n8k16.row.col.f32.bf16.bf16.f32 "
        "{%0,%1,%2,%3}, {%4,%5,%6,%7}, {%8,%9}, {%0,%1,%2,%3};"
        : "+f"(c[0]), "+f"(c[1]), "+f"(c[2]), "+f"(c[3])
        : "r"(a[0]), "r"(a[1]), "r"(a[2]), "r"(a[3]), "r"(b[0]), "r"(b[1]));
}

// ---------------- bf16 tensor-core GEMM, 2-stage register-staged pipeline ----
// C[M,N] = alpha * A[M,K](f32) * op(B)(f32)  (+ C if ACC), accumulate f32.
// TRANSB: B is [N,K] row-major. else B is [K,N] row-major.
// CAUSAL:  skip blocks entirely above the diagonal (M==N==SEQ score GEMM).
// CAUSALK: limit K loop to m0+BM (A*V where A is causal-masked).
// Requires: M % 128 == 0, K % 32 == 0, N % 4 == 0.
template<bool TRANSB, bool ACC, bool CAUSAL, bool CAUSALK>
__global__ void __launch_bounds__(256, 1) mma_gemm_kernel(
    const float* __restrict__ A, const float* __restrict__ B, float* __restrict__ C,
    int M, int N, int K, int lda, int ldb, int ldc, float alpha)
{
    const int m0 = blockIdx.y * BM;
    const int n0 = blockIdx.x * BN;
    if (CAUSAL && n0 > m0) return;

    __shared__ __align__(16) __nv_bfloat16 As[2][BM][BK + LDS_PAD];
    __shared__ __align__(16) __nv_bfloat16 Bs[2][BN][BK + LDS_PAD];
    constexpr uint32_t ASZ = BM * (BK + LDS_PAD) * 2;
    constexpr uint32_t BSZ = BN * (BK + LDS_PAD) * 2;

    const int tid = threadIdx.x;
    const int lane = tid & 31;
    const int wid = tid >> 5;
    const int warp_m = wid & 3;    // 4 warps along M, 32 rows each
    const int warp_n = wid >> 2;   // 2 warps along N, 64 cols each
    const int g  = lane >> 3;
    const int lr = lane & 7;

    const uint32_t As_base = (uint32_t)__cvta_generic_to_shared(&As[0][0][0]);
    const uint32_t Bs_base = (uint32_t)__cvta_generic_to_shared(&Bs[0][0][0]);

    // per-thread load coordinates
    const int ar = tid >> 1;                 // row pair base
    // A tile: id = i*256+tid -> r=id>>3, c=(id&7)<<2
    float acc[2][8][4];
#pragma unroll
    for (int mt = 0; mt < 2; mt++)
#pragma unroll
        for (int nt = 0; nt < 8; nt++)
#pragma unroll
            for (int i = 0; i < 4; i++) acc[mt][nt][i] = 0.f;

    int kend = K;
    if (CAUSALK) { int ke = m0 + BM; kend = ke < K ? ke : K; }
    (void)ar;

    float4 ra[4], rb[4];

    // ---- loaders (global -> regs) ----
    auto load_a = [&](int k0) {
#pragma unroll
        for (int i = 0; i < 4; i++) {
            int id = i * 256 + tid;
            int r = id >> 3;
            int c = (id & 7) << 2;
            ra[i] = *(const float4*)(A + (size_t)(m0 + r) * lda + k0 + c);
        }
    };
    auto load_b = [&](int k0) {
        if (TRANSB) {
#pragma unroll
            for (int i = 0; i < 4; i++) {
                int id = i * 256 + tid;
                int r = id >> 3;
                int c = (id & 7) << 2;
                rb[i] = make_float4(0.f, 0.f, 0.f, 0.f);
                if (n0 + r < N) rb[i] = *(const float4*)(B + (size_t)(n0 + r) * ldb + k0 + c);
            }
        } else {
#pragma unroll
            for (int i = 0; i < 4; i++) {
                int id = i * 256 + tid;
                int kr = id >> 5;
                int nc = (id & 31) << 2;
                rb[i] = make_float4(0.f, 0.f, 0.f, 0.f);
                if (n0 + nc < N) rb[i] = *(const float4*)(B + (size_t)(k0 + kr) * ldb + n0 + nc);
            }
        }
    };
    // ---- converters (regs -> smem, bf16) ----
    auto store_a = [&](int s) {
#pragma unroll
        for (int i = 0; i < 4; i++) {
            int id = i * 256 + tid;
            int r = id >> 3;
            int c = (id & 7) << 2;
            uint2 pk;
            pk.x = cvt_bf16x2(ra[i].x, ra[i].y);
            pk.y = cvt_bf16x2(ra[i].z, ra[i].w);
            *(uint2*)&As[s][r][c] = pk;
        }
    };
    auto store_b = [&](int s) {
        if (TRANSB) {
#pragma unroll
            for (int i = 0; i < 4; i++) {
                int id = i * 256 + tid;
                int r = id >> 3;
                int c = (id & 7) << 2;
                uint2 pk;
                pk.x = cvt_bf16x2(rb[i].x, rb[i].y);
                pk.y = cvt_bf16x2(rb[i].z, rb[i].w);
                *(uint2*)&Bs[s][r][c] = pk;
            }
        } else {
#pragma unroll
            for (int i = 0; i < 4; i++) {
                int id = i * 256 + tid;
                int kr = id >> 5;
                int nc = (id & 31) << 2;
                Bs[s][nc + 0][kr] = __float2bfloat16(rb[i].x);
                Bs[s][nc + 1][kr] = __float2bfloat16(rb[i].y);
                Bs[s][nc + 2][kr] = __float2bfloat16(rb[i].z);
                Bs[s][nc + 3][kr] = __float2bfloat16(rb[i].w);
            }
        }
    };

    // ---- prologue: stage 0 ----
    load_a(0); load_b(0);
    store_a(0); store_b(0);
    __syncthreads();

    int s = 0;
    for (int k0 = 0; k0 < kend; k0 += BK) {
        const bool more = (k0 + BK) < kend;
        if (more) { load_a(k0 + BK); load_b(k0 + BK); }   // overlap with compute

        const uint32_t a_base = As_base + (s ? ASZ : 0);
        const uint32_t b_base = Bs_base + (s ? BSZ : 0);

#pragma unroll
        for (int ks = 0; ks < 2; ks++) {
            uint32_t a[2][4];
#pragma unroll
            for (int mt = 0; mt < 2; mt++) {
                int row = warp_m * 32 + mt * 16 + (g & 1) * 8 + lr;
                int col = ks * 16 + (g >> 1) * 8;
                ldsm4(a[mt][0], a[mt][1], a[mt][2], a[mt][3],
                      a_base + (uint32_t)(row * (BK + LDS_PAD) + col) * 2);
            }
            uint32_t b[8][2];
#pragma unroll
            for (int np = 0; np < 4; np++) {
                int row = warp_n * 64 + np * 16 + (g >> 1) * 8 + lr;
                int col = ks * 16 + (g & 1) * 8;
                uint32_t r0, r1, r2, r3;
                ldsm4(r0, r1, r2, r3,
                      b_base + (uint32_t)(row * (BK + LDS_PAD) + col) * 2);
                b[2 * np][0] = r0; b[2 * np][1] = r1;
                b[2 * np + 1][0] = r2; b[2 * np + 1][1] = r3;
            }
#pragma unroll
            for (int mt = 0; mt < 2; mt++)
#pragma unroll
                for (int nt = 0; nt < 8; nt++)
                    mma16816(acc[mt][nt], a[mt], b[nt]);
        }

        if (more) { store_a(s ^ 1); store_b(s ^ 1); }
        __syncthreads();
        s ^= 1;
    }

    // ---- epilogue ----
    const int r0c = lane >> 2;
    const int cc  = (lane & 3) * 2;
#pragma unroll
    for (int mt = 0; mt < 2; mt++) {
        int rbase = m0 + warp_m * 32 + mt * 16 + r0c;
#pragma unroll
        for (int nt = 0; nt < 8; nt++) {
            int col = n0 + warp_n * 64 + nt * 8 + cc;
            if (col < N) {
                size_t i00 = (size_t)rbase * ldc + col;
                size_t i10 = (size_t)(rbase + 8) * ldc + col;
                float v0 = alpha * acc[mt][nt][0];
                float v1 = alpha * acc[mt][nt][1];
                float v2 = alpha * acc[mt][nt][2];
                float v3 = alpha * acc[mt][nt][3];
                if (ACC) {
                    C[i00]     += v0; C[i00 + 1] += v1;
                    C[i10]     += v2; C[i10 + 1] += v3;
                } else {
                    C[i00]     = v0; C[i00 + 1] = v1;
                    C[i10]     = v2; C[i10 + 1] = v3;
                }
            }
        }
    }
}

// ---------------- small kernels ----------------
__global__ void embed_gather(const int* __restrict__ tok, const float* __restrict__ emb,
                             float* __restrict__ h)
{
    int s = blockIdx.x;
    int t = tok[s];
    const float* e = emb + (size_t)t * DIM;
    for (int d = threadIdx.x; d < DIM; d += blockDim.x)
        h[(size_t)s * DIM + d] = e[d];
}

__global__ void rmsnorm_kernel(const float* __restrict__ x, const float* __restrict__ w,
                               float* __restrict__ o)
{
    int row = blockIdx.x;
    const float* xr = x + (size_t)row * DIM;
    __shared__ float red[256];
    int tid = threadIdx.x;
    float s = 0.f;
    for (int d = tid; d < DIM; d += 256) { float v = xr[d]; s += v * v; }
    red[tid] = s; __syncthreads();
    for (int st = 128; st > 0; st >>= 1) {
        if (tid < st) red[tid] += red[tid + st];
        __syncthreads();
    }
    float rs = rsqrtf(red[0] / (float)DIM + 1e-6f);
    for (int d = tid; d < DIM; d += 256)
        o[(size_t)row * DIM + d] = xr[d] * rs * w[d];
}

__global__ void rope_kernel(float* __restrict__ q, float* __restrict__ k)
{
    int s = blockIdx.x;
    int tid = threadIdx.x;          // 512 = 16 heads * 32 pairs
    int h = tid >> 5, i = tid & 31;
    float freq = powf(10000.f, -(float)(2 * i) / 64.f);
    float ang = (float)s * freq;
    float sn, cs;
    sincosf(ang, &sn, &cs);
    size_t base = (size_t)s * DIM + h * DH + i;
    float q1 = q[base], q2 = q[base + 32];
    q[base]      = q1 * cs - q2 * sn;
    q[base + 32] = q2 * cs + q1 * sn;
    float k1 = k[base], k2 = k[base + 32];
    k[base]      = k1 * cs - k2 * sn;
    k[base + 32] = k2 * cs + k1 * sn;
}

__global__ void softmax_causal(float* __restrict__ sc)
{
    int row = blockIdx.x;
    int head = blockIdx.y;
    float* p = sc + (size_t)head * SEQ * SEQ + (size_t)row * SEQ;
    int n = row + 1;
    __shared__ float red[256];
    int tid = threadIdx.x;

    float m = -1e30f;
    for (int j = tid; j < n; j += 256) m = fmaxf(m, p[j]);
    red[tid] = m; __syncthreads();
    for (int st = 128; st > 0; st >>= 1) {
        if (tid < st) red[tid] = fmaxf(red[tid], red[tid + st]);
        __syncthreads();
    }
    m = red[0]; __syncthreads();

    float s = 0.f;
    for (int j = tid; j < n; j += 256) {
        float e = expf(p[j] - m);
        p[j] = e;
        s += e;
    }
    red[tid] = s; __syncthreads();
    for (int st = 128; st > 0; st >>= 1) {
        if (tid < st) red[tid] += red[tid + st];
        __syncthreads();
    }
    float inv = 1.f / red[0];
    for (int j = tid; j < SEQ; j += 256) {
        if (j < n) p[j] *= inv;
        else       p[j] = 0.f;
    }
}

__global__ void gate_topk(const float* __restrict__ x, const float* __restrict__ gw,
                          float* __restrict__ comb)
{
    int t = blockIdx.x;
    int tid = threadIdx.x;
    int e = tid >> 5, lane = tid & 31;
    const float* xr = x + (size_t)t * DIM;
    const float* wr = gw + (size_t)e * DIM;
    float s = 0.f;
    for (int d = lane; d < DIM; d += 32) s += xr[d] * wr[d];
    for (int o = 16; o; o >>= 1) s += __shfl_down_sync(0xffffffffu, s, o);
    __shared__ float lg[NEXP];
    if (lane == 0) lg[e] = s;
    __syncthreads();
    if (tid == 0) {
        float m = -1e30f;
        for (int i = 0; i < NEXP; i++) m = fmaxf(m, lg[i]);
        float p[NEXP]; float sum = 0.f;
        for (int i = 0; i < NEXP; i++) { p[i] = expf(lg[i] - m); sum += p[i]; }
        float inv = 1.f / sum;
        for (int i = 0; i < NEXP; i++) p[i] *= inv;
        int i0 = 0;
        for (int i = 1; i < NEXP; i++) if (p[i] > p[i0]) i0 = i;
        int i1 = -1;
        for (int i = 0; i < NEXP; i++) {
            if (i == i0) continue;
            if (i1 < 0 || p[i] > p[i1]) i1 = i;
        }
        for (int i = 0; i < NEXP; i++)
            comb[t * NEXP + i] = (i == i0 || i == i1) ? p[i] : 0.f;
    }
}

__global__ void act_routed(float* __restrict__ g, const float* __restrict__ u,
                           const float* __restrict__ comb, int e)
{
    int idx = blockIdx.x * 256 + threadIdx.x;   // < SEQ*FFI
    int t = idx >> 9;                            // /512
    float w = comb[t * NEXP + e];
    float gv = g[idx], uv = u[idx];
    float sig = 1.f / (1.f + expf(-gv));
    g[idx] = gv * sig * uv * w;
}

__global__ void act_silu_mul(float* __restrict__ g, const float* __restrict__ u)
{
    int idx = blockIdx.x * 256 + threadIdx.x;   // < SEQ*SFI
    float gv = g[idx], uv = u[idx];
    float sig = 1.f / (1.f + expf(-gv));
    g[idx] = gv * sig * uv;
}

__global__ void zero_scalar(float* p)
{
    if (threadIdx.x == 0 && blockIdx.x == 0) p[0] = 0.f;
}

__global__ void loss_kernel(const float* __restrict__ logits, const int* __restrict__ tgt,
                            float* __restrict__ out)
{
    int row = blockIdx.x;
    const float* lr = logits + (size_t)row * VOCAB;
    __shared__ float red[256];
    int tid = threadIdx.x;

    float m = -1e30f;
    for (int j = tid; j < VOCAB; j += 256) m = fmaxf(m, lr[j]);
    red[tid] = m; __syncthreads();
    for (int st = 128; st > 0; st >>= 1) {
        if (tid < st) red[tid] = fmaxf(red[tid], red[tid + st]);
        __syncthreads();
    }
    m = red[0]; __syncthreads();

    float s = 0.f;
    for (int j = tid; j < VOCAB; j += 256) s += expf(lr[j] - m);
    red[tid] = s; __syncthreads();
    for (int st = 128; st > 0; st >>= 1) {
        if (tid < st) red[tid] += red[tid + st];
        __syncthreads();
    }
    if (tid == 0) {
        int lab = tgt[row];
        if (lab != -100) {
            float lse = m + logf(red[0]);
            atomicAdd(out, lse - lr[lab]);
        }
    }
}

// ---------------- host-side launchers ----------------
static inline dim3 ggrid(int M, int N) { return dim3((N + BN - 1) / BN, (M + BM - 1) / BM); }

static void gemm_nt(const float* A, const float* B, float* C,
                    int M, int N, int K, int lda, int ldb, int ldc, float alpha)
{
    mma_gemm_kernel<true, false, false, false><<<ggrid(M, N), 256>>>(A, B, C, M, N, K, lda, ldb, ldc, alpha);
}
static void gemm_nt_acc(const float* A, const float* B, float* C,
                        int M, int N, int K, int lda, int ldb, int ldc, float alpha)
{
    mma_gemm_kernel<true, true, false, false><<<ggrid(M, N), 256>>>(A, B, C, M, N, K, lda, ldb, ldc, alpha);
}
static void gemm_nt_causal(const float* A, const float* B, float* C,
                           int M, int N, int K, int lda, int ldb, int ldc, float alpha)
{
    mma_gemm_kernel<true, false, true, false><<<ggrid(M, N), 256>>>(A, B, C, M, N, K, lda, ldb, ldc, alpha);
}
static void gemm_nn_ck(const float* A, const float* B, float* C,
                       int M, int N, int K, int lda, int ldb, int ldc, float alpha)
{
    mma_gemm_kernel<false, false, false, true><<<ggrid(M, N), 256>>>(A, B, C, M, N, K, lda, ldb, ldc, alpha);
}

extern "C" void kernel_launch(void* const* d_in, const int* in_sizes, int n_in,
                              void* d_out, int out_size)
{
    (void)in_sizes; (void)n_in; (void)out_size;
    const int*   src       = (const int*)d_in[0];
    const int*   tgt       = (const int*)d_in[1];
    const float* embed     = (const float*)d_in[2];
    const float* Wq        = (const float*)d_in[3];
    const float* Wk        = (const float*)d_in[4];
    const float* Wv        = (const float*)d_in[5];
    const float* Wo        = (const float*)d_in[6];
    const float* ln1       = (const float*)d_in[7];
    const float* ln2       = (const float*)d_in[8];
    const float* gate_w    = (const float*)d_in[9];
    const float* gate_proj = (const float*)d_in[10];
    const float* up_proj   = (const float*)d_in[11];
    const float* down_proj = (const float*)d_in[12];
    const float* sg        = (const float*)d_in[13];
    const float* su        = (const float*)d_in[14];
    const float* sd        = (const float*)d_in[15];
    const float* final_ln  = (const float*)d_in[16];
    const float* lm_head   = (const float*)d_in[17];
    float* out = (float*)d_out;

    float *h, *x, *q, *k, *v, *o, *big, *g, *u, *gs, *us, *comb;
    cudaGetSymbolAddress((void**)&h,    g_h);
    cudaGetSymbolAddress((void**)&x,    g_x);
    cudaGetSymbolAddress((void**)&q,    g_q);
    cudaGetSymbolAddress((void**)&k,    g_k);
    cudaGetSymbolAddress((void**)&v,    g_v);
    cudaGetSymbolAddress((void**)&o,    g_o);
    cudaGetSymbolAddress((void**)&big,  g_big);
    cudaGetSymbolAddress((void**)&g,    g_g);
    cudaGetSymbolAddress((void**)&u,    g_u);
    cudaGetSymbolAddress((void**)&gs,   g_gs);
    cudaGetSymbolAddress((void**)&us,   g_us);
    cudaGetSymbolAddress((void**)&comb, g_comb);

    const float attn_scale = 0.125f;   // 1/sqrt(64)

    embed_gather<<<SEQ, 256>>>(src, embed, h);

    for (int l = 0; l < NLAYER; l++) {
        // ---- attention ----
        rmsnorm_kernel<<<SEQ, 256>>>(h, ln1 + (size_t)l * DIM, x);
        gemm_nt(x, Wq + (size_t)l * DIM * DIM, q, SEQ, DIM, DIM, DIM, DIM, DIM, 1.f);
        gemm_nt(x, Wk + (size_t)l * DIM * DIM, k, SEQ, DIM, DIM, DIM, DIM, DIM, 1.f);
        gemm_nt(x, Wv + (size_t)l * DIM * DIM, v, SEQ, DIM, DIM, DIM, DIM, DIM, 1.f);
        rope_kernel<<<SEQ, NHEAD * 32>>>(q, k);

        for (int hh = 0; hh < NHEAD; hh++) {
            gemm_nt_causal(q + hh * DH, k + hh * DH, big + (size_t)hh * SEQ * SEQ,
                           SEQ, SEQ, DH, DIM, DIM, SEQ, attn_scale);
        }
        softmax_causal<<<dim3(SEQ, NHEAD), 256>>>(big);
        for (int hh = 0; hh < NHEAD; hh++) {
            gemm_nn_ck(big + (size_t)hh * SEQ * SEQ, v + hh * DH, o + hh * DH,
                       SEQ, DH, SEQ, SEQ, DIM, DIM, 1.f);
        }
        gemm_nt_acc(o, Wo + (size_t)l * DIM * DIM, h, SEQ, DIM, DIM, DIM, DIM, DIM, 1.f);

        // ---- MoE ----
        rmsnorm_kernel<<<SEQ, 256>>>(h, ln2 + (size_t)l * DIM, x);
        gate_topk<<<SEQ, 256>>>(x, gate_w + (size_t)l * NEXP * DIM, comb);

        for (int e = 0; e < NEXP; e++) {
            const float* gp = gate_proj + ((size_t)l * NEXP + e) * FFI * DIM;
            const float* up = up_proj   + ((size_t)l * NEXP + e) * FFI * DIM;
            const float* dp = down_proj + ((size_t)l * NEXP + e) * DIM * FFI;
            gemm_nt(x, gp, g, SEQ, FFI, DIM, DIM, DIM, FFI, 1.f);
            gemm_nt(x, up, u, SEQ, FFI, DIM, DIM, DIM, FFI, 1.f);
            act_routed<<<(SEQ * FFI) / 256, 256>>>(g, u, comb, e);
            gemm_nt_acc(g, dp, h, SEQ, DIM, FFI, FFI, FFI, DIM, 1.f);
        }

        // shared expert
        gemm_nt(x, sg + (size_t)l * SFI * DIM, gs, SEQ, SFI, DIM, DIM, DIM, SFI, 1.f);
        gemm_nt(x, su + (size_t)l * SFI * DIM, us, SEQ, SFI, DIM, DIM, DIM, SFI, 1.f);
        act_silu_mul<<<(SEQ * SFI) / 256, 256>>>(gs, us);
        gemm_nt_acc(gs, sd + (size_t)l * DIM * SFI, h, SEQ, DIM, SFI, SFI, SFI, DIM, 1.f);
    }

    // ---- head + loss ----
    rmsnorm_kernel<<<SEQ, 256>>>(h, final_ln, x);
    gemm_nt(x, lm_head, big, SEQ, VOCAB, DIM, DIM, DIM, VOCAB, 1.f);
    zero_scalar<<<1, 32>>>(out);
    loss_kernel<<<SEQ, 256>>>(big, tgt, out);
}

// round 4
// speedup vs baseline: 8.4877x; 2.2772x over previous
#include <cuda_runtime.h>
#include <cuda_bf16.h>
#include <math.h>
#include <stdint.h>

// Model dims
#define SEQ    2048
#define DIM    1024
#define NHEAD  16
#define DH     64
#define NLAYER 2
#define NEXP   8
#define FFI    512
#define SFI    1024
#define VOCAB  32000

#define BM 128
#define BN 128
#define BK 32
#define LDS_PAD 8          // smem row stride = 40 bf16 = 80B

#define QSCALE 0.1803368801111137f   // 0.125 * log2(e)

// ---------------- static scratch (no allocations allowed) ----------------
__device__ float g_h[SEQ * DIM];
__device__ float g_x[SEQ * DIM];
__device__ float g_q[SEQ * DIM];
__device__ float g_k[SEQ * DIM];
__device__ float g_v[SEQ * DIM];
__device__ float g_o[SEQ * DIM];
__device__ float g_big[(size_t)SEQ * VOCAB];         // logits [2048][32000]
__device__ float g_g[SEQ * FFI];
__device__ float g_u[SEQ * FFI];
__device__ float g_gs[SEQ * SFI];
__device__ float g_us[SEQ * SFI];
__device__ float g_comb[SEQ * NEXP];

// ---------------- helpers ----------------
__device__ __forceinline__ uint32_t cvt_bf16x2(float lo, float hi) {
    uint32_t r;
    asm("cvt.rn.bf16x2.f32 %0, %1, %2;" : "=r"(r) : "f"(hi), "f"(lo));
    return r;
}

__device__ __forceinline__ void ldsm4(uint32_t &r0, uint32_t &r1, uint32_t &r2, uint32_t &r3,
                                      uint32_t addr) {
    asm volatile("ldmatrix.sync.aligned.m8n8.x4.shared.b16 {%0,%1,%2,%3}, [%4];"
                 : "=r"(r0), "=r"(r1), "=r"(r2), "=r"(r3) : "r"(addr));
}

__device__ __forceinline__ void mma16816(float* c, const uint32_t* a, const uint32_t* b) {
    asm volatile(
        "mma.sync.aligned.m16n8k16.row.col.f32.bf16.bf16.f32 "
        "{%0,%1,%2,%3}, {%4,%5,%6,%7}, {%8,%9}, {%0,%1,%2,%3};"
        : "+f"(c[0]), "+f"(c[1]), "+f"(c[2]), "+f"(c[3])
        : "r"(a[0]), "r"(a[1]), "r"(a[2]), "r"(a[3]), "r"(b[0]), "r"(b[1]));
}

// ---------------- bf16 tensor-core GEMM, 2-stage register-staged pipeline ----
template<bool TRANSB, bool ACC>
__global__ void __launch_bounds__(256, 1) mma_gemm_kernel(
    const float* __restrict__ A, const float* __restrict__ B, float* __restrict__ C,
    int M, int N, int K, int lda, int ldb, int ldc, float alpha)
{
    const int m0 = blockIdx.y * BM;
    const int n0 = blockIdx.x * BN;

    __shared__ __align__(16) __nv_bfloat16 As[2][BM][BK + LDS_PAD];
    __shared__ __align__(16) __nv_bfloat16 Bs[2][BN][BK + LDS_PAD];
    constexpr uint32_t ASZ = BM * (BK + LDS_PAD) * 2;
    constexpr uint32_t BSZ = BN * (BK + LDS_PAD) * 2;

    const int tid = threadIdx.x;
    const int lane = tid & 31;
    const int wid = tid >> 5;
    const int warp_m = wid & 3;
    const int warp_n = wid >> 2;
    const int g  = lane >> 3;
    const int lr = lane & 7;

    const uint32_t As_base = (uint32_t)__cvta_generic_to_shared(&As[0][0][0]);
    const uint32_t Bs_base = (uint32_t)__cvta_generic_to_shared(&Bs[0][0][0]);

    float acc[2][8][4];
#pragma unroll
    for (int mt = 0; mt < 2; mt++)
#pragma unroll
        for (int nt = 0; nt < 8; nt++)
#pragma unroll
            for (int i = 0; i < 4; i++) acc[mt][nt][i] = 0.f;

    float4 ra[4], rb[4];

    auto load_a = [&](int k0) {
#pragma unroll
        for (int i = 0; i < 4; i++) {
            int id = i * 256 + tid;
            int r = id >> 3;
            int c = (id & 7) << 2;
            ra[i] = *(const float4*)(A + (size_t)(m0 + r) * lda + k0 + c);
        }
    };
    auto load_b = [&](int k0) {
        if (TRANSB) {
#pragma unroll
            for (int i = 0; i < 4; i++) {
                int id = i * 256 + tid;
                int r = id >> 3;
                int c = (id & 7) << 2;
                rb[i] = make_float4(0.f, 0.f, 0.f, 0.f);
                if (n0 + r < N) rb[i] = *(const float4*)(B + (size_t)(n0 + r) * ldb + k0 + c);
            }
        } else {
#pragma unroll
            for (int i = 0; i < 4; i++) {
                int id = i * 256 + tid;
                int kr = id >> 5;
                int nc = (id & 31) << 2;
                rb[i] = make_float4(0.f, 0.f, 0.f, 0.f);
                if (n0 + nc < N) rb[i] = *(const float4*)(B + (size_t)(k0 + kr) * ldb + n0 + nc);
            }
        }
    };
    auto store_a = [&](int s) {
#pragma unroll
        for (int i = 0; i < 4; i++) {
            int id = i * 256 + tid;
            int r = id >> 3;
            int c = (id & 7) << 2;
            uint2 pk;
            pk.x = cvt_bf16x2(ra[i].x, ra[i].y);
            pk.y = cvt_bf16x2(ra[i].z, ra[i].w);
            *(uint2*)&As[s][r][c] = pk;
        }
    };
    auto store_b = [&](int s) {
        if (TRANSB) {
#pragma unroll
            for (int i = 0; i < 4; i++) {
                int id = i * 256 + tid;
                int r = id >> 3;
                int c = (id & 7) << 2;
                uint2 pk;
                pk.x = cvt_bf16x2(rb[i].x, rb[i].y);
                pk.y = cvt_bf16x2(rb[i].z, rb[i].w);
                *(uint2*)&Bs[s][r][c] = pk;
            }
        } else {
#pragma unroll
            for (int i = 0; i < 4; i++) {
                int id = i * 256 + tid;
                int kr = id >> 5;
                int nc = (id & 31) << 2;
                Bs[s][nc + 0][kr] = __float2bfloat16(rb[i].x);
                Bs[s][nc + 1][kr] = __float2bfloat16(rb[i].y);
                Bs[s][nc + 2][kr] = __float2bfloat16(rb[i].z);
                Bs[s][nc + 3][kr] = __float2bfloat16(rb[i].w);
            }
        }
    };

    load_a(0); load_b(0);
    store_a(0); store_b(0);
    __syncthreads();

    int s = 0;
    for (int k0 = 0; k0 < K; k0 += BK) {
        const bool more = (k0 + BK) < K;
        if (more) { load_a(k0 + BK); load_b(k0 + BK); }

        const uint32_t a_base = As_base + (s ? ASZ : 0);
        const uint32_t b_base = Bs_base + (s ? BSZ : 0);

#pragma unroll
        for (int ks = 0; ks < 2; ks++) {
            uint32_t a[2][4];
#pragma unroll
            for (int mt = 0; mt < 2; mt++) {
                int row = warp_m * 32 + mt * 16 + (g & 1) * 8 + lr;
                int col = ks * 16 + (g >> 1) * 8;
                ldsm4(a[mt][0], a[mt][1], a[mt][2], a[mt][3],
                      a_base + (uint32_t)(row * (BK + LDS_PAD) + col) * 2);
            }
            uint32_t b[8][2];
#pragma unroll
            for (int np = 0; np < 4; np++) {
                int row = warp_n * 64 + np * 16 + (g >> 1) * 8 + lr;
                int col = ks * 16 + (g & 1) * 8;
                uint32_t r0, r1, r2, r3;
                ldsm4(r0, r1, r2, r3,
                      b_base + (uint32_t)(row * (BK + LDS_PAD) + col) * 2);
                b[2 * np][0] = r0; b[2 * np][1] = r1;
                b[2 * np + 1][0] = r2; b[2 * np + 1][1] = r3;
            }
#pragma unroll
            for (int mt = 0; mt < 2; mt++)
#pragma unroll
                for (int nt = 0; nt < 8; nt++)
                    mma16816(acc[mt][nt], a[mt], b[nt]);
        }

        if (more) { store_a(s ^ 1); store_b(s ^ 1); }
        __syncthreads();
        s ^= 1;
    }

    const int r0c = lane >> 2;
    const int cc  = (lane & 3) * 2;
#pragma unroll
    for (int mt = 0; mt < 2; mt++) {
        int rbase = m0 + warp_m * 32 + mt * 16 + r0c;
#pragma unroll
        for (int nt = 0; nt < 8; nt++) {
            int col = n0 + warp_n * 64 + nt * 8 + cc;
            if (col < N) {
                size_t i00 = (size_t)rbase * ldc + col;
                size_t i10 = (size_t)(rbase + 8) * ldc + col;
                float v0 = alpha * acc[mt][nt][0];
                float v1 = alpha * acc[mt][nt][1];
                float v2 = alpha * acc[mt][nt][2];
                float v3 = alpha * acc[mt][nt][3];
                if (ACC) {
                    C[i00]     += v0; C[i00 + 1] += v1;
                    C[i10]     += v2; C[i10 + 1] += v3;
                } else {
                    C[i00]     = v0; C[i00 + 1] = v1;
                    C[i10]     = v2; C[i10 + 1] = v3;
                }
            }
        }
    }
}

// ---------------- fused flash attention ----------------
// grid = (SEQ/128, NHEAD), 256 threads (8 warps x 16 q-rows).
// q/k/v/o are [SEQ][DIM] fp32, head slice via head*DH.
// Q is pre-scaled by 0.125*log2(e); softmax runs in base-2 domain.
__global__ void __launch_bounds__(256, 1) flash_attn_kernel(
    const float* __restrict__ q, const float* __restrict__ k,
    const float* __restrict__ v, float* __restrict__ o)
{
    const int qb = blockIdx.x;
    const int head = blockIdx.y;
    const int q0 = qb * 128;
    const int hoff = head * DH;

    __shared__ __align__(16) __nv_bfloat16 bufA[128 * 72];   // Q [128][72]; reused as V^T [64][136]
    __shared__ __align__(16) __nv_bfloat16 Ks[128 * 72];

    const int tid = threadIdx.x;
    const int lane = tid & 31;
    const int wid = tid >> 5;
    const int g = lane >> 3, lr = lane & 7;
    const int r0 = wid * 16;

    const uint32_t bufA_base = (uint32_t)__cvta_generic_to_shared(bufA);
    const uint32_t Ks_base = (uint32_t)__cvta_generic_to_shared(Ks);

    // ---- load Q tile (scaled), then lift fragments to registers ----
#pragma unroll
    for (int i = 0; i < 8; i++) {
        int id = i * 256 + tid;
        int r = id >> 4;
        int c = (id & 15) << 2;
        float4 val = *(const float4*)(q + (size_t)(q0 + r) * DIM + hoff + c);
        uint2 pk;
        pk.x = cvt_bf16x2(val.x * QSCALE, val.y * QSCALE);
        pk.y = cvt_bf16x2(val.z * QSCALE, val.w * QSCALE);
        *(uint2*)&bufA[r * 72 + c] = pk;
    }
    __syncthreads();

    uint32_t qa[4][4];
#pragma unroll
    for (int kt = 0; kt < 4; kt++) {
        int row = r0 + (g & 1) * 8 + lr;
        int col = kt * 16 + (g >> 1) * 8;
        ldsm4(qa[kt][0], qa[kt][1], qa[kt][2], qa[kt][3],
              bufA_base + (uint32_t)(row * 72 + col) * 2);
    }
    __syncthreads();   // bufA free for V^T

    float acc_o[8][4];
#pragma unroll
    for (int nt = 0; nt < 8; nt++)
#pragma unroll
        for (int i = 0; i < 4; i++) acc_o[nt][i] = 0.f;

    float mA = -1e30f, mB = -1e30f, lA = 0.f, lB = 0.f;
    const int rA = q0 + r0 + (lane >> 2);
    const int rB = rA + 8;

    for (int kb = 0; kb <= qb; kb++) {
        const int kk0 = kb * 128;
        // ---- load K tile ----
#pragma unroll
        for (int i = 0; i < 8; i++) {
            int id = i * 256 + tid;
            int r = id >> 4;
            int c = (id & 15) << 2;
            float4 val = *(const float4*)(k + (size_t)(kk0 + r) * DIM + hoff + c);
            uint2 pk;
            pk.x = cvt_bf16x2(val.x, val.y);
            pk.y = cvt_bf16x2(val.z, val.w);
            *(uint2*)&Ks[r * 72 + c] = pk;
        }
        // ---- load V tile transposed: bufA[n][kk], stride 136 ----
#pragma unroll
        for (int i = 0; i < 8; i++) {
            int id = i * 256 + tid;
            int r = id >> 4;
            int c = (id & 15) << 2;
            float4 val = *(const float4*)(v + (size_t)(kk0 + r) * DIM + hoff + c);
            bufA[(c + 0) * 136 + r] = __float2bfloat16(val.x);
            bufA[(c + 1) * 136 + r] = __float2bfloat16(val.y);
            bufA[(c + 2) * 136 + r] = __float2bfloat16(val.z);
            bufA[(c + 3) * 136 + r] = __float2bfloat16(val.w);
        }
        __syncthreads();

        // ---- S = Q K^T (16x128 per warp) ----
        float sacc[16][4];
#pragma unroll
        for (int nt = 0; nt < 16; nt++)
#pragma unroll
            for (int i = 0; i < 4; i++) sacc[nt][i] = 0.f;

#pragma unroll
        for (int kt = 0; kt < 4; kt++) {
#pragma unroll
            for (int np = 0; np < 8; np++) {
                int row = np * 16 + (g >> 1) * 8 + lr;
                int col = kt * 16 + (g & 1) * 8;
                uint32_t b0, b1, b2, b3;
                ldsm4(b0, b1, b2, b3, Ks_base + (uint32_t)(row * 72 + col) * 2);
                uint32_t bb0[2] = {b0, b1}, bb1[2] = {b2, b3};
                mma16816(sacc[2 * np],     qa[kt], bb0);
                mma16816(sacc[2 * np + 1], qa[kt], bb1);
            }
        }

        // ---- causal mask (diag block only) ----
        if (kb == qb) {
#pragma unroll
            for (int nt = 0; nt < 16; nt++) {
                int cb = kk0 + nt * 8 + 2 * (lane & 3);
                if (cb     > rA) sacc[nt][0] = -1e30f;
                if (cb + 1 > rA) sacc[nt][1] = -1e30f;
                if (cb     > rB) sacc[nt][2] = -1e30f;
                if (cb + 1 > rB) sacc[nt][3] = -1e30f;
            }
        }

        // ---- online softmax (base-2) ----
        float cmA = -1e30f, cmB = -1e30f;
#pragma unroll
        for (int nt = 0; nt < 16; nt++) {
            cmA = fmaxf(cmA, fmaxf(sacc[nt][0], sacc[nt][1]));
            cmB = fmaxf(cmB, fmaxf(sacc[nt][2], sacc[nt][3]));
        }
        cmA = fmaxf(cmA, __shfl_xor_sync(0xffffffffu, cmA, 1));
        cmA = fmaxf(cmA, __shfl_xor_sync(0xffffffffu, cmA, 2));
        cmB = fmaxf(cmB, __shfl_xor_sync(0xffffffffu, cmB, 1));
        cmB = fmaxf(cmB, __shfl_xor_sync(0xffffffffu, cmB, 2));

        float nmA = fmaxf(mA, cmA), nmB = fmaxf(mB, cmB);
        float scA = exp2f(mA - nmA), scB = exp2f(mB - nmB);
        mA = nmA; mB = nmB;

        uint32_t pA[16], pB[16];
        float sA = 0.f, sB = 0.f;
#pragma unroll
        for (int nt = 0; nt < 16; nt++) {
            float p0 = exp2f(sacc[nt][0] - mA);
            float p1 = exp2f(sacc[nt][1] - mA);
            float p2 = exp2f(sacc[nt][2] - mB);
            float p3 = exp2f(sacc[nt][3] - mB);
            sA += p0 + p1; sB += p2 + p3;
            pA[nt] = cvt_bf16x2(p0, p1);
            pB[nt] = cvt_bf16x2(p2, p3);
        }
        lA = lA * scA + sA;
        lB = lB * scB + sB;
#pragma unroll
        for (int nt = 0; nt < 8; nt++) {
            acc_o[nt][0] *= scA; acc_o[nt][1] *= scA;
            acc_o[nt][2] *= scB; acc_o[nt][3] *= scB;
        }

        // ---- O += P V ----
#pragma unroll
        for (int kt2 = 0; kt2 < 8; kt2++) {
            uint32_t a[4] = { pA[2 * kt2], pB[2 * kt2], pA[2 * kt2 + 1], pB[2 * kt2 + 1] };
#pragma unroll
            for (int np2 = 0; np2 < 4; np2++) {
                int row = np2 * 16 + (g >> 1) * 8 + lr;
                int col = kt2 * 16 + (g & 1) * 8;
                uint32_t b0, b1, b2, b3;
                ldsm4(b0, b1, b2, b3, bufA_base + (uint32_t)(row * 136 + col) * 2);
                uint32_t bb0[2] = {b0, b1}, bb1[2] = {b2, b3};
                mma16816(acc_o[2 * np2],     a, bb0);
                mma16816(acc_o[2 * np2 + 1], a, bb1);
            }
        }
        __syncthreads();
    }

    lA += __shfl_xor_sync(0xffffffffu, lA, 1);
    lA += __shfl_xor_sync(0xffffffffu, lA, 2);
    lB += __shfl_xor_sync(0xffffffffu, lB, 1);
    lB += __shfl_xor_sync(0xffffffffu, lB, 2);
    float iA = 1.f / lA, iB = 1.f / lB;

#pragma unroll
    for (int nt = 0; nt < 8; nt++) {
        int col = hoff + nt * 8 + 2 * (lane & 3);
        float2 v0 = make_float2(acc_o[nt][0] * iA, acc_o[nt][1] * iA);
        float2 v1 = make_float2(acc_o[nt][2] * iB, acc_o[nt][3] * iB);
        *(float2*)(o + (size_t)rA * DIM + col) = v0;
        *(float2*)(o + (size_t)rB * DIM + col) = v1;
    }
}

// ---------------- small kernels ----------------
__global__ void embed_gather(const int* __restrict__ tok, const float* __restrict__ emb,
                             float* __restrict__ h)
{
    int s = blockIdx.x;
    int t = tok[s];
    const float* e = emb + (size_t)t * DIM;
    for (int d = threadIdx.x; d < DIM; d += blockDim.x)
        h[(size_t)s * DIM + d] = e[d];
}

__global__ void rmsnorm_kernel(const float* __restrict__ x, const float* __restrict__ w,
                               float* __restrict__ o)
{
    int row = blockIdx.x;
    const float* xr = x + (size_t)row * DIM;
    __shared__ float red[256];
    int tid = threadIdx.x;
    float s = 0.f;
    for (int d = tid; d < DIM; d += 256) { float v = xr[d]; s += v * v; }
    red[tid] = s; __syncthreads();
    for (int st = 128; st > 0; st >>= 1) {
        if (tid < st) red[tid] += red[tid + st];
        __syncthreads();
    }
    float rs = rsqrtf(red[0] / (float)DIM + 1e-6f);
    for (int d = tid; d < DIM; d += 256)
        o[(size_t)row * DIM + d] = xr[d] * rs * w[d];
}

__global__ void rope_kernel(float* __restrict__ q, float* __restrict__ k)
{
    int s = blockIdx.x;
    int tid = threadIdx.x;
    int h = tid >> 5, i = tid & 31;
    float freq = powf(10000.f, -(float)(2 * i) / 64.f);
    float ang = (float)s * freq;
    float sn, cs;
    sincosf(ang, &sn, &cs);
    size_t base = (size_t)s * DIM + h * DH + i;
    float q1 = q[base], q2 = q[base + 32];
    q[base]      = q1 * cs - q2 * sn;
    q[base + 32] = q2 * cs + q1 * sn;
    float k1 = k[base], k2 = k[base + 32];
    k[base]      = k1 * cs - k2 * sn;
    k[base + 32] = k2 * cs + k1 * sn;
}

__global__ void gate_topk(const float* __restrict__ x, const float* __restrict__ gw,
                          float* __restrict__ comb)
{
    int t = blockIdx.x;
    int tid = threadIdx.x;
    int e = tid >> 5, lane = tid & 31;
    const float* xr = x + (size_t)t * DIM;
    const float* wr = gw + (size_t)e * DIM;
    float s = 0.f;
    for (int d = lane; d < DIM; d += 32) s += xr[d] * wr[d];
    for (int o = 16; o; o >>= 1) s += __shfl_down_sync(0xffffffffu, s, o);
    __shared__ float lg[NEXP];
    if (lane == 0) lg[e] = s;
    __syncthreads();
    if (tid == 0) {
        float m = -1e30f;
        for (int i = 0; i < NEXP; i++) m = fmaxf(m, lg[i]);
        float p[NEXP]; float sum = 0.f;
        for (int i = 0; i < NEXP; i++) { p[i] = expf(lg[i] - m); sum += p[i]; }
        float inv = 1.f / sum;
        for (int i = 0; i < NEXP; i++) p[i] *= inv;
        int i0 = 0;
        for (int i = 1; i < NEXP; i++) if (p[i] > p[i0]) i0 = i;
        int i1 = -1;
        for (int i = 0; i < NEXP; i++) {
            if (i == i0) continue;
            if (i1 < 0 || p[i] > p[i1]) i1 = i;
        }
        for (int i = 0; i < NEXP; i++)
            comb[t * NEXP + i] = (i == i0 || i == i1) ? p[i] : 0.f;
    }
}

__global__ void act_routed(float* __restrict__ g, const float* __restrict__ u,
                           const float* __restrict__ comb, int e)
{
    int idx = blockIdx.x * 256 + threadIdx.x;
    int t = idx >> 9;
    float w = comb[t * NEXP + e];
    float gv = g[idx], uv = u[idx];
    float sig = 1.f / (1.f + expf(-gv));
    g[idx] = gv * sig * uv * w;
}

__global__ void act_silu_mul(float* __restrict__ g, const float* __restrict__ u)
{
    int idx = blockIdx.x * 256 + threadIdx.x;
    float gv = g[idx], uv = u[idx];
    float sig = 1.f / (1.f + expf(-gv));
    g[idx] = gv * sig * uv;
}

__global__ void zero_scalar(float* p)
{
    if (threadIdx.x == 0 && blockIdx.x == 0) p[0] = 0.f;
}

__global__ void loss_kernel(const float* __restrict__ logits, const int* __restrict__ tgt,
                            float* __restrict__ out)
{
    int row = blockIdx.x;
    const float* lr = logits + (size_t)row * VOCAB;
    __shared__ float red[256];
    int tid = threadIdx.x;

    float m = -1e30f;
    for (int j = tid; j < VOCAB; j += 256) m = fmaxf(m, lr[j]);
    red[tid] = m; __syncthreads();
    for (int st = 128; st > 0; st >>= 1) {
        if (tid < st) red[tid] = fmaxf(red[tid], red[tid + st]);
        __syncthreads();
    }
    m = red[0]; __syncthreads();

    float s = 0.f;
    for (int j = tid; j < VOCAB; j += 256) s += expf(lr[j] - m);
    red[tid] = s; __syncthreads();
    for (int st = 128; st > 0; st >>= 1) {
        if (tid < st) red[tid] += red[tid + st];
        __syncthreads();
    }
    if (tid == 0) {
        int lab = tgt[row];
        if (lab != -100) {
            float lse = m + logf(red[0]);
            atomicAdd(out, lse - lr[lab]);
        }
    }
}

// ---------------- host-side launchers ----------------
static inline dim3 ggrid(int M, int N) { return dim3((N + BN - 1) / BN, (M + BM - 1) / BM); }

static void gemm_nt(const float* A, const float* B, float* C,
                    int M, int N, int K, int lda, int ldb, int ldc, float alpha)
{
    mma_gemm_kernel<true, false><<<ggrid(M, N), 256>>>(A, B, C, M, N, K, lda, ldb, ldc, alpha);
}
static void gemm_nt_acc(const float* A, const float* B, float* C,
                        int M, int N, int K, int lda, int ldb, int ldc, float alpha)
{
    mma_gemm_kernel<true, true><<<ggrid(M, N), 256>>>(A, B, C, M, N, K, lda, ldb, ldc, alpha);
}

extern "C" void kernel_launch(void* const* d_in, const int* in_sizes, int n_in,
                              void* d_out, int out_size)
{
    (void)in_sizes; (void)n_in; (void)out_size;
    const int*   src       = (const int*)d_in[0];
    const int*   tgt       = (const int*)d_in[1];
    const float* embed     = (const float*)d_in[2];
    const float* Wq        = (const float*)d_in[3];
    const float* Wk        = (const float*)d_in[4];
    const float* Wv        = (const float*)d_in[5];
    const float* Wo        = (const float*)d_in[6];
    const float* ln1       = (const float*)d_in[7];
    const float* ln2       = (const float*)d_in[8];
    const float* gate_w    = (const float*)d_in[9];
    const float* gate_proj = (const float*)d_in[10];
    const float* up_proj   = (const float*)d_in[11];
    const float* down_proj = (const float*)d_in[12];
    const float* sg        = (const float*)d_in[13];
    const float* su        = (const float*)d_in[14];
    const float* sd        = (const float*)d_in[15];
    const float* final_ln  = (const float*)d_in[16];
    const float* lm_head   = (const float*)d_in[17];
    float* out = (float*)d_out;

    float *h, *x, *q, *k, *v, *o, *big, *g, *u, *gs, *us, *comb;
    cudaGetSymbolAddress((void**)&h,    g_h);
    cudaGetSymbolAddress((void**)&x,    g_x);
    cudaGetSymbolAddress((void**)&q,    g_q);
    cudaGetSymbolAddress((void**)&k,    g_k);
    cudaGetSymbolAddress((void**)&v,    g_v);
    cudaGetSymbolAddress((void**)&o,    g_o);
    cudaGetSymbolAddress((void**)&big,  g_big);
    cudaGetSymbolAddress((void**)&g,    g_g);
    cudaGetSymbolAddress((void**)&u,    g_u);
    cudaGetSymbolAddress((void**)&gs,   g_gs);
    cudaGetSymbolAddress((void**)&us,   g_us);
    cudaGetSymbolAddress((void**)&comb, g_comb);

    embed_gather<<<SEQ, 256>>>(src, embed, h);

    for (int l = 0; l < NLAYER; l++) {
        // ---- attention ----
        rmsnorm_kernel<<<SEQ, 256>>>(h, ln1 + (size_t)l * DIM, x);
        gemm_nt(x, Wq + (size_t)l * DIM * DIM, q, SEQ, DIM, DIM, DIM, DIM, DIM, 1.f);
        gemm_nt(x, Wk + (size_t)l * DIM * DIM, k, SEQ, DIM, DIM, DIM, DIM, DIM, 1.f);
        gemm_nt(x, Wv + (size_t)l * DIM * DIM, v, SEQ, DIM, DIM, DIM, DIM, DIM, 1.f);
        rope_kernel<<<SEQ, NHEAD * 32>>>(q, k);

        flash_attn_kernel<<<dim3(SEQ / 128, NHEAD), 256>>>(q, k, v, o);

        gemm_nt_acc(o, Wo + (size_t)l * DIM * DIM, h, SEQ, DIM, DIM, DIM, DIM, DIM, 1.f);

        // ---- MoE ----
        rmsnorm_kernel<<<SEQ, 256>>>(h, ln2 + (size_t)l * DIM, x);
        gate_topk<<<SEQ, 256>>>(x, gate_w + (size_t)l * NEXP * DIM, comb);

        for (int e = 0; e < NEXP; e++) {
            const float* gp = gate_proj + ((size_t)l * NEXP + e) * FFI * DIM;
            const float* up = up_proj   + ((size_t)l * NEXP + e) * FFI * DIM;
            const float* dp = down_proj + ((size_t)l * NEXP + e) * DIM * FFI;
            gemm_nt(x, gp, g, SEQ, FFI, DIM, DIM, DIM, FFI, 1.f);
            gemm_nt(x, up, u, SEQ, FFI, DIM, DIM, DIM, FFI, 1.f);
            act_routed<<<(SEQ * FFI) / 256, 256>>>(g, u, comb, e);
            gemm_nt_acc(g, dp, h, SEQ, DIM, FFI, FFI, FFI, DIM, 1.f);
        }

        // shared expert
        gemm_nt(x, sg + (size_t)l * SFI * DIM, gs, SEQ, SFI, DIM, DIM, DIM, SFI, 1.f);
        gemm_nt(x, su + (size_t)l * SFI * DIM, us, SEQ, SFI, DIM, DIM, DIM, SFI, 1.f);
        act_silu_mul<<<(SEQ * SFI) / 256, 256>>>(gs, us);
        gemm_nt_acc(gs, sd + (size_t)l * DIM * SFI, h, SEQ, DIM, SFI, SFI, SFI, DIM, 1.f);
    }

    // ---- head + loss ----
    rmsnorm_kernel<<<SEQ, 256>>>(h, final_ln, x);
    gemm_nt(x, lm_head, big, SEQ, VOCAB, DIM, DIM, DIM, VOCAB, 1.f);
    zero_scalar<<<1, 32>>>(out);
    loss_kernel<<<SEQ, 256>>>(big, tgt, out);
}

// round 5
// speedup vs baseline: 14.4823x; 1.7063x over previous
#include <cuda_runtime.h>
#include <cuda_bf16.h>
#include <math.h>
#include <stdint.h>

// Model dims
#define SEQ    2048
#define DIM    1024
#define NHEAD  16
#define DH     64
#define NLAYER 2
#define NEXP   8
#define FFI    512
#define SFI    1024
#define VOCAB  32000

#define BK 32
#define NSTAGE 4
#define BSTRIDE 40                 // smem row stride in bf16 elems (80B)
#define STAGE_BYTES (128 * BSTRIDE * 2)   // 10240 per matrix per stage
#define GEMM_SMEM (2 * NSTAGE * STAGE_BYTES)   // 81920

#define QSCALE 0.1803368801111137f   // 0.125 * log2(e)

// ---------------- static scratch (no allocations allowed) ----------------
__device__ float g_h[SEQ * DIM];
__device__ __nv_bfloat16 g_xb[SEQ * DIM];
__device__ float g_q[SEQ * DIM];
__device__ float g_k[SEQ * DIM];
__device__ float g_v[SEQ * DIM];
__device__ __nv_bfloat16 g_ob[SEQ * DIM];
__device__ float g_big[(size_t)SEQ * VOCAB];     // logits
__device__ float g_gg[SEQ * FFI * NEXP];         // MoE gate acts [2048][4096]
__device__ float g_gu[SEQ * FFI * NEXP];
__device__ __nv_bfloat16 g_gbb[SEQ * FFI * NEXP];
__device__ float g_gs[SEQ * SFI];
__device__ float g_us[SEQ * SFI];
__device__ __nv_bfloat16 g_gsb[SEQ * SFI];
__device__ float g_comb[SEQ * NEXP];
__device__ __nv_bfloat16 g_wb[(size_t)VOCAB * DIM];   // bf16 weight scratch (max = lm_head)

// ---------------- helpers ----------------
__device__ __forceinline__ uint32_t cvt_bf16x2(float lo, float hi) {
    uint32_t r;
    asm("cvt.rn.bf16x2.f32 %0, %1, %2;" : "=r"(r) : "f"(hi), "f"(lo));
    return r;
}

__device__ __forceinline__ void ldsm4(uint32_t &r0, uint32_t &r1, uint32_t &r2, uint32_t &r3,
                                      uint32_t addr) {
    asm volatile("ldmatrix.sync.aligned.m8n8.x4.shared.b16 {%0,%1,%2,%3}, [%4];"
                 : "=r"(r0), "=r"(r1), "=r"(r2), "=r"(r3) : "r"(addr));
}

__device__ __forceinline__ void mma16816(float* c, const uint32_t* a, const uint32_t* b) {
    asm volatile(
        "mma.sync.aligned.m16n8k16.row.col.f32.bf16.bf16.f32 "
        "{%0,%1,%2,%3}, {%4,%5,%6,%7}, {%8,%9}, {%0,%1,%2,%3};"
        : "+f"(c[0]), "+f"(c[1]), "+f"(c[2]), "+f"(c[3])
        : "r"(a[0]), "r"(a[1]), "r"(a[2]), "r"(a[3]), "r"(b[0]), "r"(b[1]));
}

__device__ __forceinline__ void cp_async16(uint32_t dst, const void* src) {
    asm volatile("cp.async.cg.shared.global [%0], [%1], 16;" :: "r"(dst), "l"(src));
}
__device__ __forceinline__ void cp_commit() {
    asm volatile("cp.async.commit_group;");
}
template<int W> __device__ __forceinline__ void cp_wait() {
    asm volatile("cp.async.wait_group %0;" :: "n"(W));
}

// ---------------- bf16 GEMM, 4-stage cp.async pipeline ----------------
// C[M,N](f32) = alpha * A[M,K](bf16) @ B[N,K](bf16)^T  (+C if ACC)
// Requires M%128==0, N%128==0, K%32==0.
template<bool ACC>
__global__ void __launch_bounds__(256, 1) bf16_gemm_kernel(
    const __nv_bfloat16* __restrict__ A, const __nv_bfloat16* __restrict__ B,
    float* __restrict__ C, int M, int N, int K, int lda, int ldb, int ldc, float alpha)
{
    extern __shared__ __align__(16) __nv_bfloat16 smem[];
    const int m0 = blockIdx.y * 128;
    const int n0 = blockIdx.x * 128;

    const int tid = threadIdx.x;
    const int lane = tid & 31;
    const int wid = tid >> 5;
    const int warp_m = wid & 3;      // 4 warps x 32 rows
    const int warp_n = wid >> 2;     // 2 warps x 64 cols
    const int g = lane >> 3, lr = lane & 7;

    const uint32_t As_base = (uint32_t)__cvta_generic_to_shared(smem);
    const uint32_t Bs_base = As_base + NSTAGE * STAGE_BYTES;

    const int ntiles = K >> 5;

    auto issue = [&](int t, int s) {
        const __nv_bfloat16* Ag = A + (size_t)m0 * lda + t * BK;
        const __nv_bfloat16* Bg = B + (size_t)n0 * ldb + t * BK;
        const uint32_t a_s = As_base + s * STAGE_BYTES;
        const uint32_t b_s = Bs_base + s * STAGE_BYTES;
#pragma unroll
        for (int i = 0; i < 2; i++) {
            int id = i * 256 + tid;
            int r = id >> 2;
            int c = (id & 3) * 8;
            cp_async16(a_s + (r * BSTRIDE + c) * 2, Ag + (size_t)r * lda + c);
            cp_async16(b_s + (r * BSTRIDE + c) * 2, Bg + (size_t)r * ldb + c);
        }
    };

    // prologue: stages 0..2
#pragma unroll
    for (int s = 0; s < NSTAGE - 1; s++) {
        if (s < ntiles) issue(s, s);
        cp_commit();
    }

    float acc[2][8][4];
#pragma unroll
    for (int mt = 0; mt < 2; mt++)
#pragma unroll
        for (int nt = 0; nt < 8; nt++)
#pragma unroll
            for (int i = 0; i < 4; i++) acc[mt][nt][i] = 0.f;

    for (int t = 0; t < ntiles; t++) {
        cp_wait<NSTAGE - 2>();
        __syncthreads();

        const int s = t & (NSTAGE - 1);
        const uint32_t a_base = As_base + s * STAGE_BYTES;
        const uint32_t b_base = Bs_base + s * STAGE_BYTES;

#pragma unroll
        for (int ks = 0; ks < 2; ks++) {
            uint32_t a[2][4];
#pragma unroll
            for (int mt = 0; mt < 2; mt++) {
                int row = warp_m * 32 + mt * 16 + (g & 1) * 8 + lr;
                int col = ks * 16 + (g >> 1) * 8;
                ldsm4(a[mt][0], a[mt][1], a[mt][2], a[mt][3],
                      a_base + (uint32_t)(row * BSTRIDE + col) * 2);
            }
            uint32_t b[8][2];
#pragma unroll
            for (int np = 0; np < 4; np++) {
                int row = warp_n * 64 + np * 16 + (g >> 1) * 8 + lr;
                int col = ks * 16 + (g & 1) * 8;
                uint32_t r0, r1, r2, r3;
                ldsm4(r0, r1, r2, r3, b_base + (uint32_t)(row * BSTRIDE + col) * 2);
                b[2 * np][0] = r0; b[2 * np][1] = r1;
                b[2 * np + 1][0] = r2; b[2 * np + 1][1] = r3;
            }
#pragma unroll
            for (int mt = 0; mt < 2; mt++)
#pragma unroll
                for (int nt = 0; nt < 8; nt++)
                    mma16816(acc[mt][nt], a[mt], b[nt]);
        }

        int nt2 = t + NSTAGE - 1;
        if (nt2 < ntiles) issue(nt2, nt2 & (NSTAGE - 1));
        cp_commit();
    }

    // epilogue
    const int r0c = lane >> 2;
    const int cc  = (lane & 3) * 2;
#pragma unroll
    for (int mt = 0; mt < 2; mt++) {
        int rbase = m0 + warp_m * 32 + mt * 16 + r0c;
#pragma unroll
        for (int nt = 0; nt < 8; nt++) {
            int col = n0 + warp_n * 64 + nt * 8 + cc;
            size_t i00 = (size_t)rbase * ldc + col;
            size_t i10 = (size_t)(rbase + 8) * ldc + col;
            float v0 = alpha * acc[mt][nt][0];
            float v1 = alpha * acc[mt][nt][1];
            float v2 = alpha * acc[mt][nt][2];
            float v3 = alpha * acc[mt][nt][3];
            if (ACC) {
                C[i00]     += v0; C[i00 + 1] += v1;
                C[i10]     += v2; C[i10 + 1] += v3;
            } else {
                C[i00]     = v0; C[i00 + 1] = v1;
                C[i10]     = v2; C[i10 + 1] = v3;
            }
        }
    }
}

// ---------------- weight conversion ----------------
__global__ void convert_w(const float* __restrict__ w, __nv_bfloat16* __restrict__ wb)
{
    int idx = blockIdx.x * 256 + threadIdx.x;     // one float4 per thread
    float4 v = *(const float4*)(w + (size_t)idx * 4);
    uint2 pk;
    pk.x = cvt_bf16x2(v.x, v.y);
    pk.y = cvt_bf16x2(v.z, v.w);
    *(uint2*)(wb + (size_t)idx * 4) = pk;
}

// down_projs[l] : [E, D, I] fp32  ->  wb : [D, E*I] bf16
__global__ void convert_down(const float* __restrict__ dp, __nv_bfloat16* __restrict__ wb)
{
    int idx = blockIdx.x * 256 + threadIdx.x;     // over DIM * (NEXP*FFI/4)
    int n = idx >> 10;                            // 4096/4 = 1024 groups/row
    int c4 = idx & 1023;
    int col = c4 * 4;
    int e = col >> 9, i = col & 511;
    float4 v = *(const float4*)(dp + ((size_t)e * DIM + n) * FFI + i);
    uint2 pk;
    pk.x = cvt_bf16x2(v.x, v.y);
    pk.y = cvt_bf16x2(v.z, v.w);
    *(uint2*)(wb + (size_t)n * (NEXP * FFI) + col) = pk;
}

// ---------------- fused flash attention (bf16 output) ----------------
__global__ void __launch_bounds__(256, 1) flash_attn_kernel(
    const float* __restrict__ q, const float* __restrict__ k,
    const float* __restrict__ v, __nv_bfloat16* __restrict__ ob)
{
    const int qb = blockIdx.x;
    const int head = blockIdx.y;
    const int q0 = qb * 128;
    const int hoff = head * DH;

    __shared__ __align__(16) __nv_bfloat16 bufA[128 * 72];   // Q; reused as V^T [64][136]
    __shared__ __align__(16) __nv_bfloat16 Ks[128 * 72];

    const int tid = threadIdx.x;
    const int lane = tid & 31;
    const int wid = tid >> 5;
    const int g = lane >> 3, lr = lane & 7;
    const int r0 = wid * 16;

    const uint32_t bufA_base = (uint32_t)__cvta_generic_to_shared(bufA);
    const uint32_t Ks_base = (uint32_t)__cvta_generic_to_shared(Ks);

#pragma unroll
    for (int i = 0; i < 8; i++) {
        int id = i * 256 + tid;
        int r = id >> 4;
        int c = (id & 15) << 2;
        float4 val = *(const float4*)(q + (size_t)(q0 + r) * DIM + hoff + c);
        uint2 pk;
        pk.x = cvt_bf16x2(val.x * QSCALE, val.y * QSCALE);
        pk.y = cvt_bf16x2(val.z * QSCALE, val.w * QSCALE);
        *(uint2*)&bufA[r * 72 + c] = pk;
    }
    __syncthreads();

    uint32_t qa[4][4];
#pragma unroll
    for (int kt = 0; kt < 4; kt++) {
        int row = r0 + (g & 1) * 8 + lr;
        int col = kt * 16 + (g >> 1) * 8;
        ldsm4(qa[kt][0], qa[kt][1], qa[kt][2], qa[kt][3],
              bufA_base + (uint32_t)(row * 72 + col) * 2);
    }
    __syncthreads();

    float acc_o[8][4];
#pragma unroll
    for (int nt = 0; nt < 8; nt++)
#pragma unroll
        for (int i = 0; i < 4; i++) acc_o[nt][i] = 0.f;

    float mA = -1e30f, mB = -1e30f, lA = 0.f, lB = 0.f;
    const int rA = q0 + r0 + (lane >> 2);
    const int rB = rA + 8;

    for (int kb = 0; kb <= qb; kb++) {
        const int kk0 = kb * 128;
#pragma unroll
        for (int i = 0; i < 8; i++) {
            int id = i * 256 + tid;
            int r = id >> 4;
            int c = (id & 15) << 2;
            float4 val = *(const float4*)(k + (size_t)(kk0 + r) * DIM + hoff + c);
            uint2 pk;
            pk.x = cvt_bf16x2(val.x, val.y);
            pk.y = cvt_bf16x2(val.z, val.w);
            *(uint2*)&Ks[r * 72 + c] = pk;
        }
#pragma unroll
        for (int i = 0; i < 8; i++) {
            int id = i * 256 + tid;
            int r = id >> 4;
            int c = (id & 15) << 2;
            float4 val = *(const float4*)(v + (size_t)(kk0 + r) * DIM + hoff + c);
            bufA[(c + 0) * 136 + r] = __float2bfloat16(val.x);
            bufA[(c + 1) * 136 + r] = __float2bfloat16(val.y);
            bufA[(c + 2) * 136 + r] = __float2bfloat16(val.z);
            bufA[(c + 3) * 136 + r] = __float2bfloat16(val.w);
        }
        __syncthreads();

        float sacc[16][4];
#pragma unroll
        for (int nt = 0; nt < 16; nt++)
#pragma unroll
            for (int i = 0; i < 4; i++) sacc[nt][i] = 0.f;

#pragma unroll
        for (int kt = 0; kt < 4; kt++) {
#pragma unroll
            for (int np = 0; np < 8; np++) {
                int row = np * 16 + (g >> 1) * 8 + lr;
                int col = kt * 16 + (g & 1) * 8;
                uint32_t b0, b1, b2, b3;
                ldsm4(b0, b1, b2, b3, Ks_base + (uint32_t)(row * 72 + col) * 2);
                uint32_t bb0[2] = {b0, b1}, bb1[2] = {b2, b3};
                mma16816(sacc[2 * np],     qa[kt], bb0);
                mma16816(sacc[2 * np + 1], qa[kt], bb1);
            }
        }

        if (kb == qb) {
#pragma unroll
            for (int nt = 0; nt < 16; nt++) {
                int cb = kk0 + nt * 8 + 2 * (lane & 3);
                if (cb     > rA) sacc[nt][0] = -1e30f;
                if (cb + 1 > rA) sacc[nt][1] = -1e30f;
                if (cb     > rB) sacc[nt][2] = -1e30f;
                if (cb + 1 > rB) sacc[nt][3] = -1e30f;
            }
        }

        float cmA = -1e30f, cmB = -1e30f;
#pragma unroll
        for (int nt = 0; nt < 16; nt++) {
            cmA = fmaxf(cmA, fmaxf(sacc[nt][0], sacc[nt][1]));
            cmB = fmaxf(cmB, fmaxf(sacc[nt][2], sacc[nt][3]));
        }
        cmA = fmaxf(cmA, __shfl_xor_sync(0xffffffffu, cmA, 1));
        cmA = fmaxf(cmA, __shfl_xor_sync(0xffffffffu, cmA, 2));
        cmB = fmaxf(cmB, __shfl_xor_sync(0xffffffffu, cmB, 1));
        cmB = fmaxf(cmB, __shfl_xor_sync(0xffffffffu, cmB, 2));

        float nmA = fmaxf(mA, cmA), nmB = fmaxf(mB, cmB);
        float scA = exp2f(mA - nmA), scB = exp2f(mB - nmB);
        mA = nmA; mB = nmB;

        uint32_t pA[16], pB[16];
        float sA = 0.f, sB = 0.f;
#pragma unroll
        for (int nt = 0; nt < 16; nt++) {
            float p0 = exp2f(sacc[nt][0] - mA);
            float p1 = exp2f(sacc[nt][1] - mA);
            float p2 = exp2f(sacc[nt][2] - mB);
            float p3 = exp2f(sacc[nt][3] - mB);
            sA += p0 + p1; sB += p2 + p3;
            pA[nt] = cvt_bf16x2(p0, p1);
            pB[nt] = cvt_bf16x2(p2, p3);
        }
        lA = lA * scA + sA;
        lB = lB * scB + sB;
#pragma unroll
        for (int nt = 0; nt < 8; nt++) {
            acc_o[nt][0] *= scA; acc_o[nt][1] *= scA;
            acc_o[nt][2] *= scB; acc_o[nt][3] *= scB;
        }

#pragma unroll
        for (int kt2 = 0; kt2 < 8; kt2++) {
            uint32_t a[4] = { pA[2 * kt2], pB[2 * kt2], pA[2 * kt2 + 1], pB[2 * kt2 + 1] };
#pragma unroll
            for (int np2 = 0; np2 < 4; np2++) {
                int row = np2 * 16 + (g >> 1) * 8 + lr;
                int col = kt2 * 16 + (g & 1) * 8;
                uint32_t b0, b1, b2, b3;
                ldsm4(b0, b1, b2, b3, bufA_base + (uint32_t)(row * 136 + col) * 2);
                uint32_t bb0[2] = {b0, b1}, bb1[2] = {b2, b3};
                mma16816(acc_o[2 * np2],     a, bb0);
                mma16816(acc_o[2 * np2 + 1], a, bb1);
            }
        }
        __syncthreads();
    }

    lA += __shfl_xor_sync(0xffffffffu, lA, 1);
    lA += __shfl_xor_sync(0xffffffffu, lA, 2);
    lB += __shfl_xor_sync(0xffffffffu, lB, 1);
    lB += __shfl_xor_sync(0xffffffffu, lB, 2);
    float iA = 1.f / lA, iB = 1.f / lB;

#pragma unroll
    for (int nt = 0; nt < 8; nt++) {
        int col = hoff + nt * 8 + 2 * (lane & 3);
        uint32_t p0 = cvt_bf16x2(acc_o[nt][0] * iA, acc_o[nt][1] * iA);
        uint32_t p1 = cvt_bf16x2(acc_o[nt][2] * iB, acc_o[nt][3] * iB);
        *(uint32_t*)(ob + (size_t)rA * DIM + col) = p0;
        *(uint32_t*)(ob + (size_t)rB * DIM + col) = p1;
    }
}

// ---------------- small kernels ----------------
__global__ void embed_gather(const int* __restrict__ tok, const float* __restrict__ emb,
                             float* __restrict__ h)
{
    int s = blockIdx.x;
    int t = tok[s];
    const float* e = emb + (size_t)t * DIM;
    for (int d = threadIdx.x; d < DIM; d += blockDim.x)
        h[(size_t)s * DIM + d] = e[d];
}

// RMSNorm: fp32 in, bf16 out
__global__ void rmsnorm_kernel(const float* __restrict__ x, const float* __restrict__ w,
                               __nv_bfloat16* __restrict__ o)
{
    int row = blockIdx.x;
    const float* xr = x + (size_t)row * DIM;
    __shared__ float red[256];
    int tid = threadIdx.x;
    float s = 0.f;
    for (int d = tid; d < DIM; d += 256) { float v = xr[d]; s += v * v; }
    red[tid] = s; __syncthreads();
    for (int st = 128; st > 0; st >>= 1) {
        if (tid < st) red[tid] += red[tid + st];
        __syncthreads();
    }
    float rs = rsqrtf(red[0] / (float)DIM + 1e-6f);
    for (int d = tid; d < DIM; d += 256)
        o[(size_t)row * DIM + d] = __float2bfloat16(xr[d] * rs * w[d]);
}

__global__ void rope_kernel(float* __restrict__ q, float* __restrict__ k)
{
    int s = blockIdx.x;
    int tid = threadIdx.x;
    int h = tid >> 5, i = tid & 31;
    float freq = powf(10000.f, -(float)(2 * i) / 64.f);
    float ang = (float)s * freq;
    float sn, cs;
    sincosf(ang, &sn, &cs);
    size_t base = (size_t)s * DIM + h * DH + i;
    float q1 = q[base], q2 = q[base + 32];
    q[base]      = q1 * cs - q2 * sn;
    q[base + 32] = q2 * cs + q1 * sn;
    float k1 = k[base], k2 = k[base + 32];
    k[base]      = k1 * cs - k2 * sn;
    k[base + 32] = k2 * cs + k1 * sn;
}

__global__ void gate_topk(const __nv_bfloat16* __restrict__ x, const float* __restrict__ gw,
                          float* __restrict__ comb)
{
    int t = blockIdx.x;
    int tid = threadIdx.x;
    int e = tid >> 5, lane = tid & 31;
    const __nv_bfloat16* xr = x + (size_t)t * DIM;
    const float* wr = gw + (size_t)e * DIM;
    float s = 0.f;
    for (int d = lane; d < DIM; d += 32) s += __bfloat162float(xr[d]) * wr[d];
    for (int o = 16; o; o >>= 1) s += __shfl_down_sync(0xffffffffu, s, o);
    __shared__ float lg[NEXP];
    if (lane == 0) lg[e] = s;
    __syncthreads();
    if (tid == 0) {
        float m = -1e30f;
        for (int i = 0; i < NEXP; i++) m = fmaxf(m, lg[i]);
        float p[NEXP]; float sum = 0.f;
        for (int i = 0; i < NEXP; i++) { p[i] = expf(lg[i] - m); sum += p[i]; }
        float inv = 1.f / sum;
        for (int i = 0; i < NEXP; i++) p[i] *= inv;
        int i0 = 0;
        for (int i = 1; i < NEXP; i++) if (p[i] > p[i0]) i0 = i;
        int i1 = -1;
        for (int i = 0; i < NEXP; i++) {
            if (i == i0) continue;
            if (i1 < 0 || p[i] > p[i1]) i1 = i;
        }
        for (int i = 0; i < NEXP; i++)
            comb[t * NEXP + i] = (i == i0 || i == i1) ? p[i] : 0.f;
    }
}

// batched MoE activation: [2048][4096] -> bf16, weighted by comb
__global__ void act_routed(const float* __restrict__ g, const float* __restrict__ u,
                           const float* __restrict__ comb, __nv_bfloat16* __restrict__ out)
{
    int idx = blockIdx.x * 256 + threadIdx.x;    // < SEQ * NEXP * FFI
    int t = idx >> 12;
    int e = (idx >> 9) & 7;
    float w = comb[t * NEXP + e];
    float gv = g[idx], uv = u[idx];
    float sig = 1.f / (1.f + expf(-gv));
    out[idx] = __float2bfloat16(gv * sig * uv * w);
}

__global__ void act_silu_mul(const float* __restrict__ g, const float* __restrict__ u,
                             __nv_bfloat16* __restrict__ out)
{
    int idx = blockIdx.x * 256 + threadIdx.x;    // < SEQ*SFI
    float gv = g[idx], uv = u[idx];
    float sig = 1.f / (1.f + expf(-gv));
    out[idx] = __float2bfloat16(gv * sig * uv);
}

__global__ void zero_scalar(float* p)
{
    if (threadIdx.x == 0 && blockIdx.x == 0) p[0] = 0.f;
}

__global__ void loss_kernel(const float* __restrict__ logits, const int* __restrict__ tgt,
                            float* __restrict__ out)
{
    int row = blockIdx.x;
    const float* lr = logits + (size_t)row * VOCAB;
    __shared__ float red[256];
    int tid = threadIdx.x;

    float m = -1e30f;
    for (int j = tid; j < VOCAB; j += 256) m = fmaxf(m, lr[j]);
    red[tid] = m; __syncthreads();
    for (int st = 128; st > 0; st >>= 1) {
        if (tid < st) red[tid] = fmaxf(red[tid], red[tid + st]);
        __syncthreads();
    }
    m = red[0]; __syncthreads();

    float s = 0.f;
    for (int j = tid; j < VOCAB; j += 256) s += expf(lr[j] - m);
    red[tid] = s; __syncthreads();
    for (int st = 128; st > 0; st >>= 1) {
        if (tid < st) red[tid] += red[tid + st];
        __syncthreads();
    }
    if (tid == 0) {
        int lab = tgt[row];
        if (lab != -100) {
            float lse = m + logf(red[0]);
            atomicAdd(out, lse - lr[lab]);
        }
    }
}

// ---------------- host-side launchers ----------------
static inline dim3 ggrid(int M, int N) { return dim3(N / 128, M / 128); }

static void gemm(const __nv_bfloat16* A, const __nv_bfloat16* B, float* C,
                 int M, int N, int K, int lda, int ldb, int ldc)
{
    bf16_gemm_kernel<false><<<ggrid(M, N), 256, GEMM_SMEM>>>(A, B, C, M, N, K, lda, ldb, ldc, 1.f);
}
static void gemm_acc(const __nv_bfloat16* A, const __nv_bfloat16* B, float* C,
                     int M, int N, int K, int lda, int ldb, int ldc)
{
    bf16_gemm_kernel<true><<<ggrid(M, N), 256, GEMM_SMEM>>>(A, B, C, M, N, K, lda, ldb, ldc, 1.f);
}
static void conv_w(const float* w, __nv_bfloat16* wb, size_t nelem)
{
    convert_w<<<(int)(nelem / 4 / 256), 256>>>(w, wb);
}

extern "C" void kernel_launch(void* const* d_in, const int* in_sizes, int n_in,
                              void* d_out, int out_size)
{
    (void)in_sizes; (void)n_in; (void)out_size;
    const int*   src       = (const int*)d_in[0];
    const int*   tgt       = (const int*)d_in[1];
    const float* embed     = (const float*)d_in[2];
    const float* Wq        = (const float*)d_in[3];
    const float* Wk        = (const float*)d_in[4];
    const float* Wv        = (const float*)d_in[5];
    const float* Wo        = (const float*)d_in[6];
    const float* ln1       = (const float*)d_in[7];
    const float* ln2       = (const float*)d_in[8];
    const float* gate_w    = (const float*)d_in[9];
    const float* gate_proj = (const float*)d_in[10];
    const float* up_proj   = (const float*)d_in[11];
    const float* down_proj = (const float*)d_in[12];
    const float* sg        = (const float*)d_in[13];
    const float* su        = (const float*)d_in[14];
    const float* sd        = (const float*)d_in[15];
    const float* final_ln  = (const float*)d_in[16];
    const float* lm_head   = (const float*)d_in[17];
    float* out = (float*)d_out;

    cudaFuncSetAttribute(bf16_gemm_kernel<false>, cudaFuncAttributeMaxDynamicSharedMemorySize, GEMM_SMEM);
    cudaFuncSetAttribute(bf16_gemm_kernel<true>,  cudaFuncAttributeMaxDynamicSharedMemorySize, GEMM_SMEM);

    float *h, *q, *k, *v, *big, *gg, *gu, *gs, *us, *comb;
    __nv_bfloat16 *xb, *ob, *gbb, *gsb, *wb;
    cudaGetSymbolAddress((void**)&h,    g_h);
    cudaGetSymbolAddress((void**)&xb,   g_xb);
    cudaGetSymbolAddress((void**)&q,    g_q);
    cudaGetSymbolAddress((void**)&k,    g_k);
    cudaGetSymbolAddress((void**)&v,    g_v);
    cudaGetSymbolAddress((void**)&ob,   g_ob);
    cudaGetSymbolAddress((void**)&big,  g_big);
    cudaGetSymbolAddress((void**)&gg,   g_gg);
    cudaGetSymbolAddress((void**)&gu,   g_gu);
    cudaGetSymbolAddress((void**)&gbb,  g_gbb);
    cudaGetSymbolAddress((void**)&gs,   g_gs);
    cudaGetSymbolAddress((void**)&us,   g_us);
    cudaGetSymbolAddress((void**)&gsb,  g_gsb);
    cudaGetSymbolAddress((void**)&comb, g_comb);
    cudaGetSymbolAddress((void**)&wb,   g_wb);

    embed_gather<<<SEQ, 256>>>(src, embed, h);

    for (int l = 0; l < NLAYER; l++) {
        const size_t DD = (size_t)DIM * DIM;
        // ---- attention ----
        rmsnorm_kernel<<<SEQ, 256>>>(h, ln1 + (size_t)l * DIM, xb);
        conv_w(Wq + l * DD, wb, DD);
        gemm(xb, wb, q, SEQ, DIM, DIM, DIM, DIM, DIM);
        conv_w(Wk + l * DD, wb, DD);
        gemm(xb, wb, k, SEQ, DIM, DIM, DIM, DIM, DIM);
        conv_w(Wv + l * DD, wb, DD);
        gemm(xb, wb, v, SEQ, DIM, DIM, DIM, DIM, DIM);
        rope_kernel<<<SEQ, NHEAD * 32>>>(q, k);

        flash_attn_kernel<<<dim3(SEQ / 128, NHEAD), 256>>>(q, k, v, ob);

        conv_w(Wo + l * DD, wb, DD);
        gemm_acc(ob, wb, h, SEQ, DIM, DIM, DIM, DIM, DIM);

        // ---- MoE (batched dense) ----
        rmsnorm_kernel<<<SEQ, 256>>>(h, ln2 + (size_t)l * DIM, xb);
        gate_topk<<<SEQ, 256>>>(xb, gate_w + (size_t)l * NEXP * DIM, comb);

        const size_t EID = (size_t)NEXP * FFI * DIM;   // 4M elems
        conv_w(gate_proj + l * EID, wb, EID);
        gemm(xb, wb, gg, SEQ, NEXP * FFI, DIM, DIM, DIM, NEXP * FFI);
        conv_w(up_proj + l * EID, wb, EID);
        gemm(xb, wb, gu, SEQ, NEXP * FFI, DIM, DIM, DIM, NEXP * FFI);
        act_routed<<<(SEQ * NEXP * FFI) / 256, 256>>>(gg, gu, comb, gbb);
        convert_down<<<(DIM * NEXP * FFI / 4) / 256, 256>>>(down_proj + l * EID, wb);
        gemm_acc(gbb, wb, h, SEQ, DIM, NEXP * FFI, NEXP * FFI, NEXP * FFI, DIM);

        // shared expert
        const size_t SD = (size_t)SFI * DIM;
        conv_w(sg + l * SD, wb, SD);
        gemm(xb, wb, gs, SEQ, SFI, DIM, DIM, DIM, SFI);
        conv_w(su + l * SD, wb, SD);
        gemm(xb, wb, us, SEQ, SFI, DIM, DIM, DIM, SFI);
        act_silu_mul<<<(SEQ * SFI) / 256, 256>>>(gs, us, gsb);
        conv_w(sd + l * SD, wb, SD);
        gemm_acc(gsb, wb, h, SEQ, DIM, SFI, SFI, SFI, DIM);
    }

    // ---- head + loss ----
    rmsnorm_kernel<<<SEQ, 256>>>(h, final_ln, xb);
    conv_w(lm_head, wb, (size_t)VOCAB * DIM);
    gemm(xb, wb, big, SEQ, VOCAB, DIM, DIM, DIM, VOCAB);
    zero_scalar<<<1, 32>>>(out);
    loss_kernel<<<SEQ, 256>>>(big, tgt, out);
}

// round 6
// speedup vs baseline: 20.1111x; 1.3887x over previous
#include <cuda_runtime.h>
#include <cuda_bf16.h>
#include <math.h>
#include <stdint.h>

// Model dims
#define SEQ    2048
#define DIM    1024
#define NHEAD  16
#define DH     64
#define NLAYER 2
#define NEXP   8
#define FFI    512
#define SFI    1024
#define VOCAB  32000

#define BK 32
#define NSTAGE 4
#define BSTRIDE 40
#define STAGE_BYTES (128 * BSTRIDE * 2)
#define GEMM_SMEM (2 * NSTAGE * STAGE_BYTES)   // 81920

#define QSCALE 0.1803368801111137f   // 0.125 * log2(e)

// ---------------- static scratch ----------------
__device__ float g_h[SEQ * DIM];
__device__ __nv_bfloat16 g_xb[SEQ * DIM];
__device__ float g_qkv[SEQ * 3 * DIM];                       // fused QKV
__device__ __nv_bfloat16 g_ob[SEQ * DIM];
__device__ float g_big[(size_t)SEQ * VOCAB];                 // logits; reused as yg [8][2048][1024]
__device__ float g_gg[(size_t)NEXP * SEQ * DIM];             // MoE gate|up acts; reused as shared gsus
__device__ __nv_bfloat16 g_actb[(size_t)NEXP * SEQ * FFI];
__device__ __nv_bfloat16 g_xg[(size_t)NEXP * SEQ * DIM];     // gathered tokens per expert
__device__ __nv_bfloat16 g_gsb[SEQ * SFI];
__device__ __nv_bfloat16 g_wb[(size_t)VOCAB * DIM];          // bf16 weight scratch
__device__ int   g_cnt[NEXP];
__device__ int2  g_topi[SEQ];
__device__ int2  g_pos[SEQ];
__device__ float2 g_topw[SEQ];

// ---------------- helpers ----------------
__device__ __forceinline__ uint32_t cvt_bf16x2(float lo, float hi) {
    uint32_t r;
    asm("cvt.rn.bf16x2.f32 %0, %1, %2;" : "=r"(r) : "f"(hi), "f"(lo));
    return r;
}
__device__ __forceinline__ void ldsm4(uint32_t &r0, uint32_t &r1, uint32_t &r2, uint32_t &r3,
                                      uint32_t addr) {
    asm volatile("ldmatrix.sync.aligned.m8n8.x4.shared.b16 {%0,%1,%2,%3}, [%4];"
                 : "=r"(r0), "=r"(r1), "=r"(r2), "=r"(r3) : "r"(addr));
}
__device__ __forceinline__ void mma16816(float* c, const uint32_t* a, const uint32_t* b) {
    asm volatile(
        "mma.sync.aligned.m16n8k16.row.col.f32.bf16.bf16.f32 "
        "{%0,%1,%2,%3}, {%4,%5,%6,%7}, {%8,%9}, {%0,%1,%2,%3};"
        : "+f"(c[0]), "+f"(c[1]), "+f"(c[2]), "+f"(c[3])
        : "r"(a[0]), "r"(a[1]), "r"(a[2]), "r"(a[3]), "r"(b[0]), "r"(b[1]));
}
__device__ __forceinline__ void cp_async16(uint32_t dst, const void* src) {
    asm volatile("cp.async.cg.shared.global [%0], [%1], 16;" :: "r"(dst), "l"(src));
}
__device__ __forceinline__ void cp_commit() { asm volatile("cp.async.commit_group;"); }
template<int W> __device__ __forceinline__ void cp_wait() {
    asm volatile("cp.async.wait_group %0;" :: "n"(W));
}

// ---------------- shared 128x128 GEMM tile body ----------------
// A,B,C pre-offset to tile origin. A[128,K](bf16,lda), B[128,K](bf16,ldb), C[128,128](f32,ldc).
template<bool ACC>
__device__ __forceinline__ void gemm128_body(
    const __nv_bfloat16* __restrict__ A, const __nv_bfloat16* __restrict__ B,
    float* __restrict__ C, int K, int lda, int ldb, int ldc)
{
    extern __shared__ __align__(16) __nv_bfloat16 smem[];
    const int tid = threadIdx.x;
    const int lane = tid & 31;
    const int wid = tid >> 5;
    const int warp_m = wid & 3;
    const int warp_n = wid >> 2;
    const int g = lane >> 3, lr = lane & 7;

    const uint32_t As_base = (uint32_t)__cvta_generic_to_shared(smem);
    const uint32_t Bs_base = As_base + NSTAGE * STAGE_BYTES;
    const int ntiles = K >> 5;

    auto issue = [&](int t, int s) {
        const __nv_bfloat16* Ag = A + t * BK;
        const __nv_bfloat16* Bg = B + t * BK;
        const uint32_t a_s = As_base + s * STAGE_BYTES;
        const uint32_t b_s = Bs_base + s * STAGE_BYTES;
#pragma unroll
        for (int i = 0; i < 2; i++) {
            int id = i * 256 + tid;
            int r = id >> 2;
            int c = (id & 3) * 8;
            cp_async16(a_s + (r * BSTRIDE + c) * 2, Ag + (size_t)r * lda + c);
            cp_async16(b_s + (r * BSTRIDE + c) * 2, Bg + (size_t)r * ldb + c);
        }
    };

#pragma unroll
    for (int s = 0; s < NSTAGE - 1; s++) {
        if (s < ntiles) issue(s, s);
        cp_commit();
    }

    float acc[2][8][4];
#pragma unroll
    for (int mt = 0; mt < 2; mt++)
#pragma unroll
        for (int nt = 0; nt < 8; nt++)
#pragma unroll
            for (int i = 0; i < 4; i++) acc[mt][nt][i] = 0.f;

    for (int t = 0; t < ntiles; t++) {
        cp_wait<NSTAGE - 2>();
        __syncthreads();

        const int s = t & (NSTAGE - 1);
        const uint32_t a_base = As_base + s * STAGE_BYTES;
        const uint32_t b_base = Bs_base + s * STAGE_BYTES;

#pragma unroll
        for (int ks = 0; ks < 2; ks++) {
            uint32_t a[2][4];
#pragma unroll
            for (int mt = 0; mt < 2; mt++) {
                int row = warp_m * 32 + mt * 16 + (g & 1) * 8 + lr;
                int col = ks * 16 + (g >> 1) * 8;
                ldsm4(a[mt][0], a[mt][1], a[mt][2], a[mt][3],
                      a_base + (uint32_t)(row * BSTRIDE + col) * 2);
            }
            uint32_t b[8][2];
#pragma unroll
            for (int np = 0; np < 4; np++) {
                int row = warp_n * 64 + np * 16 + (g >> 1) * 8 + lr;
                int col = ks * 16 + (g & 1) * 8;
                uint32_t r0, r1, r2, r3;
                ldsm4(r0, r1, r2, r3, b_base + (uint32_t)(row * BSTRIDE + col) * 2);
                b[2 * np][0] = r0; b[2 * np][1] = r1;
                b[2 * np + 1][0] = r2; b[2 * np + 1][1] = r3;
            }
#pragma unroll
            for (int mt = 0; mt < 2; mt++)
#pragma unroll
                for (int nt = 0; nt < 8; nt++)
                    mma16816(acc[mt][nt], a[mt], b[nt]);
        }

        int nt2 = t + NSTAGE - 1;
        if (nt2 < ntiles) issue(nt2, nt2 & (NSTAGE - 1));
        cp_commit();
    }

    const int r0c = lane >> 2;
    const int cc  = (lane & 3) * 2;
#pragma unroll
    for (int mt = 0; mt < 2; mt++) {
        int rbase = warp_m * 32 + mt * 16 + r0c;
#pragma unroll
        for (int nt = 0; nt < 8; nt++) {
            int col = warp_n * 64 + nt * 8 + cc;
            size_t i00 = (size_t)rbase * ldc + col;
            size_t i10 = (size_t)(rbase + 8) * ldc + col;
            if (ACC) {
                C[i00]     += acc[mt][nt][0]; C[i00 + 1] += acc[mt][nt][1];
                C[i10]     += acc[mt][nt][2]; C[i10 + 1] += acc[mt][nt][3];
            } else {
                C[i00]     = acc[mt][nt][0]; C[i00 + 1] = acc[mt][nt][1];
                C[i10]     = acc[mt][nt][2]; C[i10 + 1] = acc[mt][nt][3];
            }
        }
    }
}

template<bool ACC>
__global__ void __launch_bounds__(256, 2) bf16_gemm_kernel(
    const __nv_bfloat16* __restrict__ A, const __nv_bfloat16* __restrict__ B,
    float* __restrict__ C, int K, int lda, int ldb, int ldc)
{
    A += (size_t)blockIdx.y * 128 * lda;
    B += (size_t)blockIdx.x * 128 * ldb;
    C += (size_t)blockIdx.y * 128 * ldc + blockIdx.x * 128;
    gemm128_body<ACC>(A, B, C, K, lda, ldb, ldc);
}

// grouped MoE GEMM: blockIdx.y = e*16 + row_block; early-exit on per-expert count.
__global__ void __launch_bounds__(256, 2) moe_gemm_kernel(
    const __nv_bfloat16* __restrict__ A, const __nv_bfloat16* __restrict__ B,
    float* __restrict__ C, const int* __restrict__ cnt, int K, int N)
{
    const int e = blockIdx.y >> 4;
    const int rb = blockIdx.y & 15;
    if (rb * 128 >= cnt[e]) return;
    A += ((size_t)e * SEQ + rb * 128) * K;
    B += (size_t)e * N * K + (size_t)blockIdx.x * 128 * K;
    C += ((size_t)e * SEQ + rb * 128) * N + blockIdx.x * 128;
    gemm128_body<false>(A, B, C, K, K, K, N);
}

// ---------------- weight conversion ----------------
__global__ void convert_w(const float* __restrict__ w, __nv_bfloat16* __restrict__ wb)
{
    int idx = blockIdx.x * 256 + threadIdx.x;
    float4 v = *(const float4*)(w + (size_t)idx * 4);
    uint2 pk;
    pk.x = cvt_bf16x2(v.x, v.y);
    pk.y = cvt_bf16x2(v.z, v.w);
    *(uint2*)(wb + (size_t)idx * 4) = pk;
}

// gate_projs[E][I][D] + up_projs[E][I][D] -> wb[E][2I][D]  (rows 0..511 gate, 512..1023 up)
__global__ void convert_gateup(const float* __restrict__ gp, const float* __restrict__ up,
                               __nv_bfloat16* __restrict__ wb)
{
    int idx = blockIdx.x * 256 + threadIdx.x;     // over 8*1024*1024/4
    int k4 = idx & 255;
    int n  = (idx >> 8) & 1023;
    int e  = idx >> 18;
    const float* src = (n < FFI)
        ? gp + ((size_t)e * FFI + n) * DIM + k4 * 4
        : up + ((size_t)e * FFI + (n - FFI)) * DIM + k4 * 4;
    float4 v = *(const float4*)src;
    uint2 pk;
    pk.x = cvt_bf16x2(v.x, v.y);
    pk.y = cvt_bf16x2(v.z, v.w);
    *(uint2*)(wb + (((size_t)e * 2 * FFI + n) * DIM) + k4 * 4) = pk;
}

// ---------------- fused flash attention ----------------
__global__ void __launch_bounds__(256, 1) flash_attn_kernel(
    const float* __restrict__ q, const float* __restrict__ k,
    const float* __restrict__ v, __nv_bfloat16* __restrict__ ob, int ldq)
{
    const int qb = blockIdx.x;
    const int head = blockIdx.y;
    const int q0 = qb * 128;
    const int hoff = head * DH;

    __shared__ __align__(16) __nv_bfloat16 bufA[128 * 72];
    __shared__ __align__(16) __nv_bfloat16 Ks[128 * 72];

    const int tid = threadIdx.x;
    const int lane = tid & 31;
    const int wid = tid >> 5;
    const int g = lane >> 3, lr = lane & 7;
    const int r0 = wid * 16;

    const uint32_t bufA_base = (uint32_t)__cvta_generic_to_shared(bufA);
    const uint32_t Ks_base = (uint32_t)__cvta_generic_to_shared(Ks);

#pragma unroll
    for (int i = 0; i < 8; i++) {
        int id = i * 256 + tid;
        int r = id >> 4;
        int c = (id & 15) << 2;
        float4 val = *(const float4*)(q + (size_t)(q0 + r) * ldq + hoff + c);
        uint2 pk;
        pk.x = cvt_bf16x2(val.x * QSCALE, val.y * QSCALE);
        pk.y = cvt_bf16x2(val.z * QSCALE, val.w * QSCALE);
        *(uint2*)&bufA[r * 72 + c] = pk;
    }
    __syncthreads();

    uint32_t qa[4][4];
#pragma unroll
    for (int kt = 0; kt < 4; kt++) {
        int row = r0 + (g & 1) * 8 + lr;
        int col = kt * 16 + (g >> 1) * 8;
        ldsm4(qa[kt][0], qa[kt][1], qa[kt][2], qa[kt][3],
              bufA_base + (uint32_t)(row * 72 + col) * 2);
    }
    __syncthreads();

    float acc_o[8][4];
#pragma unroll
    for (int nt = 0; nt < 8; nt++)
#pragma unroll
        for (int i = 0; i < 4; i++) acc_o[nt][i] = 0.f;

    float mA = -1e30f, mB = -1e30f, lA = 0.f, lB = 0.f;
    const int rA = q0 + r0 + (lane >> 2);
    const int rB = rA + 8;

    for (int kb = 0; kb <= qb; kb++) {
        const int kk0 = kb * 128;
#pragma unroll
        for (int i = 0; i < 8; i++) {
            int id = i * 256 + tid;
            int r = id >> 4;
            int c = (id & 15) << 2;
            float4 val = *(const float4*)(k + (size_t)(kk0 + r) * ldq + hoff + c);
            uint2 pk;
            pk.x = cvt_bf16x2(val.x, val.y);
            pk.y = cvt_bf16x2(val.z, val.w);
            *(uint2*)&Ks[r * 72 + c] = pk;
        }
#pragma unroll
        for (int i = 0; i < 8; i++) {
            int id = i * 256 + tid;
            int r = id >> 4;
            int c = (id & 15) << 2;
            float4 val = *(const float4*)(v + (size_t)(kk0 + r) * ldq + hoff + c);
            bufA[(c + 0) * 136 + r] = __float2bfloat16(val.x);
            bufA[(c + 1) * 136 + r] = __float2bfloat16(val.y);
            bufA[(c + 2) * 136 + r] = __float2bfloat16(val.z);
            bufA[(c + 3) * 136 + r] = __float2bfloat16(val.w);
        }
        __syncthreads();

        float sacc[16][4];
#pragma unroll
        for (int nt = 0; nt < 16; nt++)
#pragma unroll
            for (int i = 0; i < 4; i++) sacc[nt][i] = 0.f;

#pragma unroll
        for (int kt = 0; kt < 4; kt++) {
#pragma unroll
            for (int np = 0; np < 8; np++) {
                int row = np * 16 + (g >> 1) * 8 + lr;
                int col = kt * 16 + (g & 1) * 8;
                uint32_t b0, b1, b2, b3;
                ldsm4(b0, b1, b2, b3, Ks_base + (uint32_t)(row * 72 + col) * 2);
                uint32_t bb0[2] = {b0, b1}, bb1[2] = {b2, b3};
                mma16816(sacc[2 * np],     qa[kt], bb0);
                mma16816(sacc[2 * np + 1], qa[kt], bb1);
            }
        }

        if (kb == qb) {
#pragma unroll
            for (int nt = 0; nt < 16; nt++) {
                int cb = kk0 + nt * 8 + 2 * (lane & 3);
                if (cb     > rA) sacc[nt][0] = -1e30f;
                if (cb + 1 > rA) sacc[nt][1] = -1e30f;
                if (cb     > rB) sacc[nt][2] = -1e30f;
                if (cb + 1 > rB) sacc[nt][3] = -1e30f;
            }
        }

        float cmA = -1e30f, cmB = -1e30f;
#pragma unroll
        for (int nt = 0; nt < 16; nt++) {
            cmA = fmaxf(cmA, fmaxf(sacc[nt][0], sacc[nt][1]));
            cmB = fmaxf(cmB, fmaxf(sacc[nt][2], sacc[nt][3]));
        }
        cmA = fmaxf(cmA, __shfl_xor_sync(0xffffffffu, cmA, 1));
        cmA = fmaxf(cmA, __shfl_xor_sync(0xffffffffu, cmA, 2));
        cmB = fmaxf(cmB, __shfl_xor_sync(0xffffffffu, cmB, 1));
        cmB = fmaxf(cmB, __shfl_xor_sync(0xffffffffu, cmB, 2));

        float nmA = fmaxf(mA, cmA), nmB = fmaxf(mB, cmB);
        float scA = exp2f(mA - nmA), scB = exp2f(mB - nmB);
        mA = nmA; mB = nmB;

        uint32_t pA[16], pB[16];
        float sA = 0.f, sB = 0.f;
#pragma unroll
        for (int nt = 0; nt < 16; nt++) {
            float p0 = exp2f(sacc[nt][0] - mA);
            float p1 = exp2f(sacc[nt][1] - mA);
            float p2 = exp2f(sacc[nt][2] - mB);
            float p3 = exp2f(sacc[nt][3] - mB);
            sA += p0 + p1; sB += p2 + p3;
            pA[nt] = cvt_bf16x2(p0, p1);
            pB[nt] = cvt_bf16x2(p2, p3);
        }
        lA = lA * scA + sA;
        lB = lB * scB + sB;
#pragma unroll
        for (int nt = 0; nt < 8; nt++) {
            acc_o[nt][0] *= scA; acc_o[nt][1] *= scA;
            acc_o[nt][2] *= scB; acc_o[nt][3] *= scB;
        }

#pragma unroll
        for (int kt2 = 0; kt2 < 8; kt2++) {
            uint32_t a[4] = { pA[2 * kt2], pB[2 * kt2], pA[2 * kt2 + 1], pB[2 * kt2 + 1] };
#pragma unroll
            for (int np2 = 0; np2 < 4; np2++) {
                int row = np2 * 16 + (g >> 1) * 8 + lr;
                int col = kt2 * 16 + (g & 1) * 8;
                uint32_t b0, b1, b2, b3;
                ldsm4(b0, b1, b2, b3, bufA_base + (uint32_t)(row * 136 + col) * 2);
                uint32_t bb0[2] = {b0, b1}, bb1[2] = {b2, b3};
                mma16816(acc_o[2 * np2],     a, bb0);
                mma16816(acc_o[2 * np2 + 1], a, bb1);
            }
        }
        __syncthreads();
    }

    lA += __shfl_xor_sync(0xffffffffu, lA, 1);
    lA += __shfl_xor_sync(0xffffffffu, lA, 2);
    lB += __shfl_xor_sync(0xffffffffu, lB, 1);
    lB += __shfl_xor_sync(0xffffffffu, lB, 2);
    float iA = 1.f / lA, iB = 1.f / lB;

#pragma unroll
    for (int nt = 0; nt < 8; nt++) {
        int col = hoff + nt * 8 + 2 * (lane & 3);
        uint32_t p0 = cvt_bf16x2(acc_o[nt][0] * iA, acc_o[nt][1] * iA);
        uint32_t p1 = cvt_bf16x2(acc_o[nt][2] * iB, acc_o[nt][3] * iB);
        *(uint32_t*)(ob + (size_t)rA * DIM + col) = p0;
        *(uint32_t*)(ob + (size_t)rB * DIM + col) = p1;
    }
}

// ---------------- small kernels ----------------
__global__ void embed_gather(const int* __restrict__ tok, const float* __restrict__ emb,
                             float* __restrict__ h)
{
    int s = blockIdx.x;
    int t = tok[s];
    const float* e = emb + (size_t)t * DIM;
    for (int d = threadIdx.x; d < DIM; d += blockDim.x)
        h[(size_t)s * DIM + d] = e[d];
}

__global__ void rmsnorm_kernel(const float* __restrict__ x, const float* __restrict__ w,
                               __nv_bfloat16* __restrict__ o)
{
    int row = blockIdx.x;
    const float* xr = x + (size_t)row * DIM;
    __shared__ float red[256];
    int tid = threadIdx.x;
    float s = 0.f;
    for (int d = tid; d < DIM; d += 256) { float v = xr[d]; s += v * v; }
    red[tid] = s; __syncthreads();
    for (int st = 128; st > 0; st >>= 1) {
        if (tid < st) red[tid] += red[tid + st];
        __syncthreads();
    }
    float rs = rsqrtf(red[0] / (float)DIM + 1e-6f);
    for (int d = tid; d < DIM; d += 256)
        o[(size_t)row * DIM + d] = __float2bfloat16(xr[d] * rs * w[d]);
}

// rope on fused qkv: q at col 0, k at col DIM (row stride 3*DIM)
__global__ void rope_kernel(float* __restrict__ qkv)
{
    int s = blockIdx.x;
    int tid = threadIdx.x;
    int h = tid >> 5, i = tid & 31;
    float freq = powf(10000.f, -(float)(2 * i) / 64.f);
    float ang = (float)s * freq;
    float sn, cs;
    sincosf(ang, &sn, &cs);
    size_t base = (size_t)s * (3 * DIM) + h * DH + i;
    float q1 = qkv[base], q2 = qkv[base + 32];
    qkv[base]      = q1 * cs - q2 * sn;
    qkv[base + 32] = q2 * cs + q1 * sn;
    size_t kb = base + DIM;
    float k1 = qkv[kb], k2 = qkv[kb + 32];
    qkv[kb]      = k1 * cs - k2 * sn;
    qkv[kb + 32] = k2 * cs + k1 * sn;
}

__global__ void gate_topk(const __nv_bfloat16* __restrict__ x, const float* __restrict__ gw,
                          int2* __restrict__ topi, float2* __restrict__ topw)
{
    int t = blockIdx.x;
    int tid = threadIdx.x;
    int e = tid >> 5, lane = tid & 31;
    const __nv_bfloat16* xr = x + (size_t)t * DIM;
    const float* wr = gw + (size_t)e * DIM;
    float s = 0.f;
    for (int d = lane; d < DIM; d += 32) s += __bfloat162float(xr[d]) * wr[d];
    for (int o = 16; o; o >>= 1) s += __shfl_down_sync(0xffffffffu, s, o);
    __shared__ float lg[NEXP];
    if (lane == 0) lg[e] = s;
    __syncthreads();
    if (tid == 0) {
        float m = -1e30f;
        for (int i = 0; i < NEXP; i++) m = fmaxf(m, lg[i]);
        float p[NEXP]; float sum = 0.f;
        for (int i = 0; i < NEXP; i++) { p[i] = expf(lg[i] - m); sum += p[i]; }
        float inv = 1.f / sum;
        for (int i = 0; i < NEXP; i++) p[i] *= inv;
        int i0 = 0;
        for (int i = 1; i < NEXP; i++) if (p[i] > p[i0]) i0 = i;
        int i1 = -1;
        for (int i = 0; i < NEXP; i++) {
            if (i == i0) continue;
            if (i1 < 0 || p[i] > p[i1]) i1 = i;
        }
        topi[t] = make_int2(i0, i1);
        topw[t] = make_float2(p[i0], p[i1]);
    }
}

__global__ void zero_counts(int* cnt)
{
    if (threadIdx.x < NEXP) cnt[threadIdx.x] = 0;
}

// gather token rows into per-expert buffers; record slots
__global__ void gather_rows(const __nv_bfloat16* __restrict__ xb, __nv_bfloat16* __restrict__ xg,
                            const int2* __restrict__ topi, int2* __restrict__ pos,
                            int* __restrict__ cnt)
{
    int t = blockIdx.x;
    __shared__ int sp[2];
    int2 ti = topi[t];
    if (threadIdx.x == 0) {
        sp[0] = atomicAdd(&cnt[ti.x], 1);
        sp[1] = atomicAdd(&cnt[ti.y], 1);
    }
    __syncthreads();
    const uint32_t* src = (const uint32_t*)(xb + (size_t)t * DIM);
    uint32_t* d0 = (uint32_t*)(xg + ((size_t)ti.x * SEQ + sp[0]) * DIM);
    uint32_t* d1 = (uint32_t*)(xg + ((size_t)ti.y * SEQ + sp[1]) * DIM);
    for (int i = threadIdx.x; i < DIM / 2; i += 256) {
        uint32_t v = src[i];
        d0[i] = v; d1[i] = v;
    }
    if (threadIdx.x == 0) pos[t] = make_int2(sp[0], sp[1]);
}

// MoE act: silu(g)*u from concat row [gate(512)|up(512)] -> bf16
__global__ void act_moe(const float* __restrict__ gg, __nv_bfloat16* __restrict__ actb,
                        const int* __restrict__ cnt)
{
    int e = blockIdx.y;
    int m = blockIdx.x;
    if (m >= cnt[e]) return;
    const float* row = gg + ((size_t)e * SEQ + m) * (2 * FFI);
    __nv_bfloat16* orow = actb + ((size_t)e * SEQ + m) * FFI;
    for (int i = threadIdx.x; i < FFI; i += 256) {
        float gv = row[i], uv = row[i + FFI];
        float sig = 1.f / (1.f + expf(-gv));
        orow[i] = __float2bfloat16(gv * sig * uv);
    }
}

// scatter: h[t] += w0*yg[e0][p0] + w1*yg[e1][p1]
__global__ void scatter_add(float* __restrict__ h, const float* __restrict__ yg,
                            const int2* __restrict__ topi, const int2* __restrict__ pos,
                            const float2* __restrict__ topw)
{
    int t = blockIdx.x;
    int2 ti = topi[t];
    int2 ps = pos[t];
    float2 w = topw[t];
    const float* y0 = yg + ((size_t)ti.x * SEQ + ps.x) * DIM;
    const float* y1 = yg + ((size_t)ti.y * SEQ + ps.y) * DIM;
    float* hr = h + (size_t)t * DIM;
    for (int d = threadIdx.x; d < DIM; d += 256)
        hr[d] += w.x * y0[d] + w.y * y1[d];
}

// shared expert act: row [gate(1024)|up(1024)]
__global__ void act_shared(const float* __restrict__ gsus, __nv_bfloat16* __restrict__ out)
{
    int t = blockIdx.x;
    const float* row = gsus + (size_t)t * (2 * SFI);
    __nv_bfloat16* orow = out + (size_t)t * SFI;
    for (int i = threadIdx.x; i < SFI; i += 256) {
        float gv = row[i], uv = row[i + SFI];
        float sig = 1.f / (1.f + expf(-gv));
        orow[i] = __float2bfloat16(gv * sig * uv);
    }
}

__global__ void zero_scalar(float* p)
{
    if (threadIdx.x == 0 && blockIdx.x == 0) p[0] = 0.f;
}

__global__ void loss_kernel(const float* __restrict__ logits, const int* __restrict__ tgt,
                            float* __restrict__ out)
{
    int row = blockIdx.x;
    const float* lr = logits + (size_t)row * VOCAB;
    __shared__ float red[256];
    int tid = threadIdx.x;

    float m = -1e30f;
    for (int j = tid; j < VOCAB; j += 256) m = fmaxf(m, lr[j]);
    red[tid] = m; __syncthreads();
    for (int st = 128; st > 0; st >>= 1) {
        if (tid < st) red[tid] = fmaxf(red[tid], red[tid + st]);
        __syncthreads();
    }
    m = red[0]; __syncthreads();

    float s = 0.f;
    for (int j = tid; j < VOCAB; j += 256) s += expf(lr[j] - m);
    red[tid] = s; __syncthreads();
    for (int st = 128; st > 0; st >>= 1) {
        if (tid < st) red[tid] += red[tid + st];
        __syncthreads();
    }
    if (tid == 0) {
        int lab = tgt[row];
        if (lab != -100) {
            float lse = m + logf(red[0]);
            atomicAdd(out, lse - lr[lab]);
        }
    }
}

// ---------------- host ----------------
static void gemm(const __nv_bfloat16* A, const __nv_bfloat16* B, float* C,
                 int M, int N, int K, int lda, int ldb, int ldc)
{
    bf16_gemm_kernel<false><<<dim3(N / 128, M / 128), 256, GEMM_SMEM>>>(A, B, C, K, lda, ldb, ldc);
}
static void gemm_acc(const __nv_bfloat16* A, const __nv_bfloat16* B, float* C,
                     int M, int N, int K, int lda, int ldb, int ldc)
{
    bf16_gemm_kernel<true><<<dim3(N / 128, M / 128), 256, GEMM_SMEM>>>(A, B, C, K, lda, ldb, ldc);
}
static void conv_w(const float* w, __nv_bfloat16* wb, size_t nelem)
{
    convert_w<<<(int)(nelem / 4 / 256), 256>>>(w, wb);
}

extern "C" void kernel_launch(void* const* d_in, const int* in_sizes, int n_in,
                              void* d_out, int out_size)
{
    (void)in_sizes; (void)n_in; (void)out_size;
    const int*   src       = (const int*)d_in[0];
    const int*   tgt       = (const int*)d_in[1];
    const float* embed     = (const float*)d_in[2];
    const float* Wq        = (const float*)d_in[3];
    const float* Wk        = (const float*)d_in[4];
    const float* Wv        = (const float*)d_in[5];
    const float* Wo        = (const float*)d_in[6];
    const float* ln1       = (const float*)d_in[7];
    const float* ln2       = (const float*)d_in[8];
    const float* gate_w    = (const float*)d_in[9];
    const float* gate_proj = (const float*)d_in[10];
    const float* up_proj   = (const float*)d_in[11];
    const float* down_proj = (const float*)d_in[12];
    const float* sg        = (const float*)d_in[13];
    const float* su        = (const float*)d_in[14];
    const float* sd        = (const float*)d_in[15];
    const float* final_ln  = (const float*)d_in[16];
    const float* lm_head   = (const float*)d_in[17];
    float* out = (float*)d_out;

    cudaFuncSetAttribute(bf16_gemm_kernel<false>, cudaFuncAttributeMaxDynamicSharedMemorySize, GEMM_SMEM);
    cudaFuncSetAttribute(bf16_gemm_kernel<true>,  cudaFuncAttributeMaxDynamicSharedMemorySize, GEMM_SMEM);
    cudaFuncSetAttribute(moe_gemm_kernel,         cudaFuncAttributeMaxDynamicSharedMemorySize, GEMM_SMEM);

    float *h, *qkv, *big, *gg;
    __nv_bfloat16 *xb, *ob, *actb, *xg, *gsb, *wb;
    int *cnt; int2 *topi, *pos; float2 *topw;
    cudaGetSymbolAddress((void**)&h,    g_h);
    cudaGetSymbolAddress((void**)&xb,   g_xb);
    cudaGetSymbolAddress((void**)&qkv,  g_qkv);
    cudaGetSymbolAddress((void**)&ob,   g_ob);
    cudaGetSymbolAddress((void**)&big,  g_big);
    cudaGetSymbolAddress((void**)&gg,   g_gg);
    cudaGetSymbolAddress((void**)&actb, g_actb);
    cudaGetSymbolAddress((void**)&xg,   g_xg);
    cudaGetSymbolAddress((void**)&gsb,  g_gsb);
    cudaGetSymbolAddress((void**)&wb,   g_wb);
    cudaGetSymbolAddress((void**)&cnt,  g_cnt);
    cudaGetSymbolAddress((void**)&topi, g_topi);
    cudaGetSymbolAddress((void**)&pos,  g_pos);
    cudaGetSymbolAddress((void**)&topw, g_topw);

    float* yg = big;   // reuse logits buffer as MoE down output

    embed_gather<<<SEQ, 256>>>(src, embed, h);

    const size_t DD = (size_t)DIM * DIM;
    for (int l = 0; l < NLAYER; l++) {
        // ---- attention ----
        rmsnorm_kernel<<<SEQ, 256>>>(h, ln1 + (size_t)l * DIM, xb);
        conv_w(Wq + l * DD, wb,          DD);
        conv_w(Wk + l * DD, wb + DD,     DD);
        conv_w(Wv + l * DD, wb + 2 * DD, DD);
        gemm(xb, wb, qkv, SEQ, 3 * DIM, DIM, DIM, DIM, 3 * DIM);
        rope_kernel<<<SEQ, NHEAD * 32>>>(qkv);

        flash_attn_kernel<<<dim3(SEQ / 128, NHEAD), 256>>>(qkv, qkv + DIM, qkv + 2 * DIM, ob, 3 * DIM);

        conv_w(Wo + l * DD, wb, DD);
        gemm_acc(ob, wb, h, SEQ, DIM, DIM, DIM, DIM, DIM);

        // ---- MoE (sparse top-2) ----
        rmsnorm_kernel<<<SEQ, 256>>>(h, ln2 + (size_t)l * DIM, xb);
        gate_topk<<<SEQ, 256>>>(xb, gate_w + (size_t)l * NEXP * DIM, topi, topw);
        zero_counts<<<1, 32>>>(cnt);
        gather_rows<<<SEQ, 256>>>(xb, xg, topi, pos, cnt);

        const size_t EID = (size_t)NEXP * FFI * DIM;
        convert_gateup<<<(NEXP * 2 * FFI * DIM / 4) / 256, 256>>>(
            gate_proj + l * EID, up_proj + l * EID, wb);
        moe_gemm_kernel<<<dim3((2 * FFI) / 128, NEXP * 16), 256, GEMM_SMEM>>>(
            xg, wb, gg, cnt, DIM, 2 * FFI);
        act_moe<<<dim3(SEQ, NEXP), 256>>>(gg, actb, cnt);
        conv_w(down_proj + l * EID, wb, EID);
        moe_gemm_kernel<<<dim3(DIM / 128, NEXP * 16), 256, GEMM_SMEM>>>(
            actb, wb, yg, cnt, FFI, DIM);
        scatter_add<<<SEQ, 256>>>(h, yg, topi, pos, topw);

        // ---- shared expert ----
        const size_t SD = (size_t)SFI * DIM;
        conv_w(sg + l * SD, wb,      SD);
        conv_w(su + l * SD, wb + SD, SD);
        gemm(xb, wb, gg, SEQ, 2 * SFI, DIM, DIM, DIM, 2 * SFI);
        act_shared<<<SEQ, 256>>>(gg, gsb);
        conv_w(sd + l * SD, wb, SD);
        gemm_acc(gsb, wb, h, SEQ, DIM, SFI, SFI, SFI, DIM);
    }

    // ---- head + loss ----
    rmsnorm_kernel<<<SEQ, 256>>>(h, final_ln, xb);
    conv_w(lm_head, wb, (size_t)VOCAB * DIM);
    gemm(xb, wb, big, SEQ, VOCAB, DIM, DIM, DIM, VOCAB);
    zero_scalar<<<1, 32>>>(out);
    loss_kernel<<<SEQ, 256>>>(big, tgt, out);
}

// round 8
// speedup vs baseline: 20.8107x; 1.0348x over previous
#include <cuda_runtime.h>
#include <cuda_bf16.h>
#include <math.h>
#include <stdint.h>

// Model dims
#define SEQ    2048
#define DIM    1024
#define NHEAD  16
#define DH     64
#define NLAYER 2
#define NEXP   8
#define FFI    512
#define SFI    1024
#define VOCAB  32000

#define BK 32
#define NSTAGE 4
#define BSTRIDE 40
#define STAGE_BYTES (128 * BSTRIDE * 2)
#define GEMM_SMEM (2 * NSTAGE * STAGE_BYTES)   // 81920

#define QSCALE 0.1803368801111137f   // 0.125 * log2(e)

// ---------------- static scratch ----------------
__device__ float g_h[SEQ * DIM];
__device__ __nv_bfloat16 g_xb[SEQ * DIM];
__device__ float g_qkv[SEQ * 3 * DIM];                       // fused QKV
__device__ __nv_bfloat16 g_ob[SEQ * DIM];
__device__ float g_big[(size_t)SEQ * VOCAB];                 // logits; reused as yg [8][2048][1024]
__device__ float g_gg[(size_t)NEXP * SEQ * DIM];             // MoE gate|up acts; reused as shared gsus
__device__ __nv_bfloat16 g_actb[(size_t)NEXP * SEQ * FFI];
__device__ __nv_bfloat16 g_xg[(size_t)NEXP * SEQ * DIM];     // gathered tokens per expert
__device__ __nv_bfloat16 g_gsb[SEQ * SFI];
__device__ __nv_bfloat16 g_wb[(size_t)VOCAB * DIM];          // bf16 weight scratch
__device__ int   g_cnt[NEXP];
__device__ int2  g_topi[SEQ];
__device__ int2  g_pos[SEQ];
__device__ float2 g_topw[SEQ];

// ---------------- helpers ----------------
__device__ __forceinline__ uint32_t cvt_bf16x2(float lo, float hi) {
    uint32_t r;
    asm("cvt.rn.bf16x2.f32 %0, %1, %2;" : "=r"(r) : "f"(hi), "f"(lo));
    return r;
}
__device__ __forceinline__ void ldsm4(uint32_t &r0, uint32_t &r1, uint32_t &r2, uint32_t &r3,
                                      uint32_t addr) {
    asm volatile("ldmatrix.sync.aligned.m8n8.x4.shared.b16 {%0,%1,%2,%3}, [%4];"
                 : "=r"(r0), "=r"(r1), "=r"(r2), "=r"(r3) : "r"(addr));
}
__device__ __forceinline__ void mma16816(float* c, const uint32_t* a, const uint32_t* b) {
    asm volatile(
        "mma.sync.aligned.m16n8k16.row.col.f32.bf16.bf16.f32 "
        "{%0,%1,%2,%3}, {%4,%5,%6,%7}, {%8,%9}, {%0,%1,%2,%3};"
        : "+f"(c[0]), "+f"(c[1]), "+f"(c[2]), "+f"(c[3])
        : "r"(a[0]), "r"(a[1]), "r"(a[2]), "r"(a[3]), "r"(b[0]), "r"(b[1]));
}
__device__ __forceinline__ void cp_async16(uint32_t dst, const void* src) {
    asm volatile("cp.async.cg.shared.global [%0], [%1], 16;" :: "r"(dst), "l"(src));
}
__device__ __forceinline__ void cp_commit() { asm volatile("cp.async.commit_group;"); }
template<int W> __device__ __forceinline__ void cp_wait() {
    asm volatile("cp.async.wait_group %0;" :: "n"(W));
}

// ---------------- shared 128x128 GEMM tile body ----------------
template<bool ACC>
__device__ __forceinline__ void gemm128_body(
    const __nv_bfloat16* __restrict__ A, const __nv_bfloat16* __restrict__ B,
    float* __restrict__ C, int K, int lda, int ldb, int ldc)
{
    extern __shared__ __align__(16) __nv_bfloat16 smem[];
    const int tid = threadIdx.x;
    const int lane = tid & 31;
    const int wid = tid >> 5;
    const int warp_m = wid & 3;
    const int warp_n = wid >> 2;
    const int g = lane >> 3, lr = lane & 7;

    const uint32_t As_base = (uint32_t)__cvta_generic_to_shared(smem);
    const uint32_t Bs_base = As_base + NSTAGE * STAGE_BYTES;
    const int ntiles = K >> 5;

    auto issue = [&](int t, int s) {
        const __nv_bfloat16* Ag = A + t * BK;
        const __nv_bfloat16* Bg = B + t * BK;
        const uint32_t a_s = As_base + s * STAGE_BYTES;
        const uint32_t b_s = Bs_base + s * STAGE_BYTES;
#pragma unroll
        for (int i = 0; i < 2; i++) {
            int id = i * 256 + tid;
            int r = id >> 2;
            int c = (id & 3) * 8;
            cp_async16(a_s + (r * BSTRIDE + c) * 2, Ag + (size_t)r * lda + c);
            cp_async16(b_s + (r * BSTRIDE + c) * 2, Bg + (size_t)r * ldb + c);
        }
    };

#pragma unroll
    for (int s = 0; s < NSTAGE - 1; s++) {
        if (s < ntiles) issue(s, s);
        cp_commit();
    }

    float acc[2][8][4];
#pragma unroll
    for (int mt = 0; mt < 2; mt++)
#pragma unroll
        for (int nt = 0; nt < 8; nt++)
#pragma unroll
            for (int i = 0; i < 4; i++) acc[mt][nt][i] = 0.f;

    for (int t = 0; t < ntiles; t++) {
        cp_wait<NSTAGE - 2>();
        __syncthreads();

        const int s = t & (NSTAGE - 1);
        const uint32_t a_base = As_base + s * STAGE_BYTES;
        const uint32_t b_base = Bs_base + s * STAGE_BYTES;

#pragma unroll
        for (int ks = 0; ks < 2; ks++) {
            uint32_t a[2][4];
#pragma unroll
            for (int mt = 0; mt < 2; mt++) {
                int row = warp_m * 32 + mt * 16 + (g & 1) * 8 + lr;
                int col = ks * 16 + (g >> 1) * 8;
                ldsm4(a[mt][0], a[mt][1], a[mt][2], a[mt][3],
                      a_base + (uint32_t)(row * BSTRIDE + col) * 2);
            }
            uint32_t b[8][2];
#pragma unroll
            for (int np = 0; np < 4; np++) {
                int row = warp_n * 64 + np * 16 + (g >> 1) * 8 + lr;
                int col = ks * 16 + (g & 1) * 8;
                uint32_t r0, r1, r2, r3;
                ldsm4(r0, r1, r2, r3, b_base + (uint32_t)(row * BSTRIDE + col) * 2);
                b[2 * np][0] = r0; b[2 * np][1] = r1;
                b[2 * np + 1][0] = r2; b[2 * np + 1][1] = r3;
            }
#pragma unroll
            for (int mt = 0; mt < 2; mt++)
#pragma unroll
                for (int nt = 0; nt < 8; nt++)
                    mma16816(acc[mt][nt], a[mt], b[nt]);
        }

        int nt2 = t + NSTAGE - 1;
        if (nt2 < ntiles) issue(nt2, nt2 & (NSTAGE - 1));
        cp_commit();
    }

    const int r0c = lane >> 2;
    const int cc  = (lane & 3) * 2;
#pragma unroll
    for (int mt = 0; mt < 2; mt++) {
        int rbase = warp_m * 32 + mt * 16 + r0c;
#pragma unroll
        for (int nt = 0; nt < 8; nt++) {
            int col = warp_n * 64 + nt * 8 + cc;
            size_t i00 = (size_t)rbase * ldc + col;
            size_t i10 = (size_t)(rbase + 8) * ldc + col;
            if (ACC) {
                C[i00]     += acc[mt][nt][0]; C[i00 + 1] += acc[mt][nt][1];
                C[i10]     += acc[mt][nt][2]; C[i10 + 1] += acc[mt][nt][3];
            } else {
                C[i00]     = acc[mt][nt][0]; C[i00 + 1] = acc[mt][nt][1];
                C[i10]     = acc[mt][nt][2]; C[i10 + 1] = acc[mt][nt][3];
            }
        }
    }
}

template<bool ACC>
__global__ void __launch_bounds__(256, 2) bf16_gemm_kernel(
    const __nv_bfloat16* __restrict__ A, const __nv_bfloat16* __restrict__ B,
    float* __restrict__ C, int K, int lda, int ldb, int ldc)
{
    A += (size_t)blockIdx.y * 128 * lda;
    B += (size_t)blockIdx.x * 128 * ldb;
    C += (size_t)blockIdx.y * 128 * ldc + blockIdx.x * 128;
    gemm128_body<ACC>(A, B, C, K, lda, ldb, ldc);
}

__global__ void __launch_bounds__(256, 2) moe_gemm_kernel(
    const __nv_bfloat16* __restrict__ A, const __nv_bfloat16* __restrict__ B,
    float* __restrict__ C, const int* __restrict__ cnt, int K, int N)
{
    const int e = blockIdx.y >> 4;
    const int rb = blockIdx.y & 15;
    if (rb * 128 >= cnt[e]) return;
    A += ((size_t)e * SEQ + rb * 128) * K;
    B += (size_t)e * N * K + (size_t)blockIdx.x * 128 * K;
    C += ((size_t)e * SEQ + rb * 128) * N + blockIdx.x * 128;
    gemm128_body<false>(A, B, C, K, K, K, N);
}

// ---------------- weight conversion (ILP-4, contiguous block span) ----------------
// Each block covers a contiguous 1024-float4 span; each thread 4 independent 16B loads.
// grid = nelem / 4096.
__global__ void convert_w(const float* __restrict__ w, __nv_bfloat16* __restrict__ wb)
{
    const float4* w4 = (const float4*)w;
    uint2* o2 = (uint2*)wb;
    size_t base = (size_t)blockIdx.x * 1024 + threadIdx.x;
    float4 v[4];
#pragma unroll
    for (int k = 0; k < 4; k++) v[k] = w4[base + k * 256];
#pragma unroll
    for (int k = 0; k < 4; k++) {
        uint2 pk;
        pk.x = cvt_bf16x2(v[k].x, v[k].y);
        pk.y = cvt_bf16x2(v[k].z, v[k].w);
        o2[base + k * 256] = pk;
    }
}

// gate_projs[E][I][D] + up_projs[E][I][D] -> wb[E][2I][D], ILP-4
__global__ void convert_gateup(const float* __restrict__ gp, const float* __restrict__ up,
                               __nv_bfloat16* __restrict__ wb)
{
    size_t base = (size_t)blockIdx.x * 1024 + threadIdx.x;   // float4 index
    float4 v[4];
    size_t idxs[4];
#pragma unroll
    for (int k = 0; k < 4; k++) {
        size_t idx = base + k * 256;
        int k4 = (int)(idx & 255);
        int n  = (int)((idx >> 8) & 1023);
        int e  = (int)(idx >> 18);
        const float* src = (n < FFI)
            ? gp + ((size_t)e * FFI + n) * DIM + k4 * 4
            : up + ((size_t)e * FFI + (n - FFI)) * DIM + k4 * 4;
        v[k] = *(const float4*)src;
        idxs[k] = ((size_t)e * 2 * FFI + n) * (DIM / 4) + k4;
    }
#pragma unroll
    for (int k = 0; k < 4; k++) {
        uint2 pk;
        pk.x = cvt_bf16x2(v[k].x, v[k].y);
        pk.y = cvt_bf16x2(v[k].z, v[k].w);
        ((uint2*)wb)[idxs[k]] = pk;
    }
}

// ---------------- fused flash attention ----------------
__global__ void __launch_bounds__(256, 1) flash_attn_kernel(
    const float* __restrict__ q, const float* __restrict__ k,
    const float* __restrict__ v, __nv_bfloat16* __restrict__ ob, int ldq)
{
    const int qb = blockIdx.x;
    const int head = blockIdx.y;
    const int q0 = qb * 128;
    const int hoff = head * DH;

    __shared__ __align__(16) __nv_bfloat16 bufA[128 * 72];
    __shared__ __align__(16) __nv_bfloat16 Ks[128 * 72];

    const int tid = threadIdx.x;
    const int lane = tid & 31;
    const int wid = tid >> 5;
    const int g = lane >> 3, lr = lane & 7;
    const int r0 = wid * 16;

    const uint32_t bufA_base = (uint32_t)__cvta_generic_to_shared(bufA);
    const uint32_t Ks_base = (uint32_t)__cvta_generic_to_shared(Ks);

#pragma unroll
    for (int i = 0; i < 8; i++) {
        int id = i * 256 + tid;
        int r = id >> 4;
        int c = (id & 15) << 2;
        float4 val = *(const float4*)(q + (size_t)(q0 + r) * ldq + hoff + c);
        uint2 pk;
        pk.x = cvt_bf16x2(val.x * QSCALE, val.y * QSCALE);
        pk.y = cvt_bf16x2(val.z * QSCALE, val.w * QSCALE);
        *(uint2*)&bufA[r * 72 + c] = pk;
    }
    __syncthreads();

    uint32_t qa[4][4];
#pragma unroll
    for (int kt = 0; kt < 4; kt++) {
        int row = r0 + (g & 1) * 8 + lr;
        int col = kt * 16 + (g >> 1) * 8;
        ldsm4(qa[kt][0], qa[kt][1], qa[kt][2], qa[kt][3],
              bufA_base + (uint32_t)(row * 72 + col) * 2);
    }
    __syncthreads();

    float acc_o[8][4];
#pragma unroll
    for (int nt = 0; nt < 8; nt++)
#pragma unroll
        for (int i = 0; i < 4; i++) acc_o[nt][i] = 0.f;

    float mA = -1e30f, mB = -1e30f, lA = 0.f, lB = 0.f;
    const int rA = q0 + r0 + (lane >> 2);
    const int rB = rA + 8;

    for (int kb = 0; kb <= qb; kb++) {
        const int kk0 = kb * 128;
#pragma unroll
        for (int i = 0; i < 8; i++) {
            int id = i * 256 + tid;
            int r = id >> 4;
            int c = (id & 15) << 2;
            float4 val = *(const float4*)(k + (size_t)(kk0 + r) * ldq + hoff + c);
            uint2 pk;
            pk.x = cvt_bf16x2(val.x, val.y);
            pk.y = cvt_bf16x2(val.z, val.w);
            *(uint2*)&Ks[r * 72 + c] = pk;
        }
#pragma unroll
        for (int i = 0; i < 8; i++) {
            int id = i * 256 + tid;
            int r = id >> 4;
            int c = (id & 15) << 2;
            float4 val = *(const float4*)(v + (size_t)(kk0 + r) * ldq + hoff + c);
            bufA[(c + 0) * 136 + r] = __float2bfloat16(val.x);
            bufA[(c + 1) * 136 + r] = __float2bfloat16(val.y);
            bufA[(c + 2) * 136 + r] = __float2bfloat16(val.z);
            bufA[(c + 3) * 136 + r] = __float2bfloat16(val.w);
        }
        __syncthreads();

        float sacc[16][4];
#pragma unroll
        for (int nt = 0; nt < 16; nt++)
#pragma unroll
            for (int i = 0; i < 4; i++) sacc[nt][i] = 0.f;

#pragma unroll
        for (int kt = 0; kt < 4; kt++) {
#pragma unroll
            for (int np = 0; np < 8; np++) {
                int row = np * 16 + (g >> 1) * 8 + lr;
                int col = kt * 16 + (g & 1) * 8;
                uint32_t b0, b1, b2, b3;
                ldsm4(b0, b1, b2, b3, Ks_base + (uint32_t)(row * 72 + col) * 2);
                uint32_t bb0[2] = {b0, b1}, bb1[2] = {b2, b3};
                mma16816(sacc[2 * np],     qa[kt], bb0);
                mma16816(sacc[2 * np + 1], qa[kt], bb1);
            }
        }

        if (kb == qb) {
#pragma unroll
            for (int nt = 0; nt < 16; nt++) {
                int cb = kk0 + nt * 8 + 2 * (lane & 3);
                if (cb     > rA) sacc[nt][0] = -1e30f;
                if (cb + 1 > rA) sacc[nt][1] = -1e30f;
                if (cb     > rB) sacc[nt][2] = -1e30f;
                if (cb + 1 > rB) sacc[nt][3] = -1e30f;
            }
        }

        float cmA = -1e30f, cmB = -1e30f;
#pragma unroll
        for (int nt = 0; nt < 16; nt++) {
            cmA = fmaxf(cmA, fmaxf(sacc[nt][0], sacc[nt][1]));
            cmB = fmaxf(cmB, fmaxf(sacc[nt][2], sacc[nt][3]));
        }
        cmA = fmaxf(cmA, __shfl_xor_sync(0xffffffffu, cmA, 1));
        cmA = fmaxf(cmA, __shfl_xor_sync(0xffffffffu, cmA, 2));
        cmB = fmaxf(cmB, __shfl_xor_sync(0xffffffffu, cmB, 1));
        cmB = fmaxf(cmB, __shfl_xor_sync(0xffffffffu, cmB, 2));

        float nmA = fmaxf(mA, cmA), nmB = fmaxf(mB, cmB);
        float scA = exp2f(mA - nmA), scB = exp2f(mB - nmB);
        mA = nmA; mB = nmB;

        uint32_t pA[16], pB[16];
        float sA = 0.f, sB = 0.f;
#pragma unroll
        for (int nt = 0; nt < 16; nt++) {
            float p0 = exp2f(sacc[nt][0] - mA);
            float p1 = exp2f(sacc[nt][1] - mA);
            float p2 = exp2f(sacc[nt][2] - mB);
            float p3 = exp2f(sacc[nt][3] - mB);
            sA += p0 + p1; sB += p2 + p3;
            pA[nt] = cvt_bf16x2(p0, p1);
            pB[nt] = cvt_bf16x2(p2, p3);
        }
        lA = lA * scA + sA;
        lB = lB * scB + sB;
#pragma unroll
        for (int nt = 0; nt < 8; nt++) {
            acc_o[nt][0] *= scA; acc_o[nt][1] *= scA;
            acc_o[nt][2] *= scB; acc_o[nt][3] *= scB;
        }

#pragma unroll
        for (int kt2 = 0; kt2 < 8; kt2++) {
            uint32_t a[4] = { pA[2 * kt2], pB[2 * kt2], pA[2 * kt2 + 1], pB[2 * kt2 + 1] };
#pragma unroll
            for (int np2 = 0; np2 < 4; np2++) {
                int row = np2 * 16 + (g >> 1) * 8 + lr;
                int col = kt2 * 16 + (g & 1) * 8;
                uint32_t b0, b1, b2, b3;
                ldsm4(b0, b1, b2, b3, bufA_base + (uint32_t)(row * 136 + col) * 2);
                uint32_t bb0[2] = {b0, b1}, bb1[2] = {b2, b3};
                mma16816(acc_o[2 * np2],     a, bb0);
                mma16816(acc_o[2 * np2 + 1], a, bb1);
            }
        }
        __syncthreads();
    }

    lA += __shfl_xor_sync(0xffffffffu, lA, 1);
    lA += __shfl_xor_sync(0xffffffffu, lA, 2);
    lB += __shfl_xor_sync(0xffffffffu, lB, 1);
    lB += __shfl_xor_sync(0xffffffffu, lB, 2);
    float iA = 1.f / lA, iB = 1.f / lB;

#pragma unroll
    for (int nt = 0; nt < 8; nt++) {
        int col = hoff + nt * 8 + 2 * (lane & 3);
        uint32_t p0 = cvt_bf16x2(acc_o[nt][0] * iA, acc_o[nt][1] * iA);
        uint32_t p1 = cvt_bf16x2(acc_o[nt][2] * iB, acc_o[nt][3] * iB);
        *(uint32_t*)(ob + (size_t)rA * DIM + col) = p0;
        *(uint32_t*)(ob + (size_t)rB * DIM + col) = p1;
    }
}

// ---------------- small kernels ----------------
__global__ void embed_gather(const int* __restrict__ tok, const float* __restrict__ emb,
                             float* __restrict__ h)
{
    int s = blockIdx.x;
    int t = tok[s];
    const float* e = emb + (size_t)t * DIM;
    for (int d = threadIdx.x; d < DIM; d += blockDim.x)
        h[(size_t)s * DIM + d] = e[d];
}

__global__ void rmsnorm_kernel(const float* __restrict__ x, const float* __restrict__ w,
                               __nv_bfloat16* __restrict__ o)
{
    int row = blockIdx.x;
    const float* xr = x + (size_t)row * DIM;
    __shared__ float red[256];
    int tid = threadIdx.x;
    float s = 0.f;
    for (int d = tid; d < DIM; d += 256) { float v = xr[d]; s += v * v; }
    red[tid] = s; __syncthreads();
    for (int st = 128; st > 0; st >>= 1) {
        if (tid < st) red[tid] += red[tid + st];
        __syncthreads();
    }
    float rs = rsqrtf(red[0] / (float)DIM + 1e-6f);
    for (int d = tid; d < DIM; d += 256)
        o[(size_t)row * DIM + d] = __float2bfloat16(xr[d] * rs * w[d]);
}

__global__ void rope_kernel(float* __restrict__ qkv)
{
    int s = blockIdx.x;
    int tid = threadIdx.x;
    int h = tid >> 5, i = tid & 31;
    float freq = powf(10000.f, -(float)(2 * i) / 64.f);
    float ang = (float)s * freq;
    float sn, cs;
    sincosf(ang, &sn, &cs);
    size_t base = (size_t)s * (3 * DIM) + h * DH + i;
    float q1 = qkv[base], q2 = qkv[base + 32];
    qkv[base]      = q1 * cs - q2 * sn;
    qkv[base + 32] = q2 * cs + q1 * sn;
    size_t kb = base + DIM;
    float k1 = qkv[kb], k2 = qkv[kb + 32];
    qkv[kb]      = k1 * cs - k2 * sn;
    qkv[kb + 32] = k2 * cs + k1 * sn;
}

__global__ void gate_topk(const __nv_bfloat16* __restrict__ x, const float* __restrict__ gw,
                          int2* __restrict__ topi, float2* __restrict__ topw)
{
    int t = blockIdx.x;
    int tid = threadIdx.x;
    int e = tid >> 5, lane = tid & 31;
    const __nv_bfloat16* xr = x + (size_t)t * DIM;
    const float* wr = gw + (size_t)e * DIM;
    float s = 0.f;
    for (int d = lane; d < DIM; d += 32) s += __bfloat162float(xr[d]) * wr[d];
    for (int o = 16; o; o >>= 1) s += __shfl_down_sync(0xffffffffu, s, o);
    __shared__ float lg[NEXP];
    if (lane == 0) lg[e] = s;
    __syncthreads();
    if (tid == 0) {
        float m = -1e30f;
        for (int i = 0; i < NEXP; i++) m = fmaxf(m, lg[i]);
        float p[NEXP]; float sum = 0.f;
        for (int i = 0; i < NEXP; i++) { p[i] = expf(lg[i] - m); sum += p[i]; }
        float inv = 1.f / sum;
        for (int i = 0; i < NEXP; i++) p[i] *= inv;
        int i0 = 0;
        for (int i = 1; i < NEXP; i++) if (p[i] > p[i0]) i0 = i;
        int i1 = -1;
        for (int i = 0; i < NEXP; i++) {
            if (i == i0) continue;
            if (i1 < 0 || p[i] > p[i1]) i1 = i;
        }
        topi[t] = make_int2(i0, i1);
        topw[t] = make_float2(p[i0], p[i1]);
    }
}

__global__ void zero_counts(int* cnt)
{
    if (threadIdx.x < NEXP) cnt[threadIdx.x] = 0;
}

__global__ void gather_rows(const __nv_bfloat16* __restrict__ xb, __nv_bfloat16* __restrict__ xg,
                            const int2* __restrict__ topi, int2* __restrict__ pos,
                            int* __restrict__ cnt)
{
    int t = blockIdx.x;
    __shared__ int sp[2];
    int2 ti = topi[t];
    if (threadIdx.x == 0) {
        sp[0] = atomicAdd(&cnt[ti.x], 1);
        sp[1] = atomicAdd(&cnt[ti.y], 1);
    }
    __syncthreads();
    const uint32_t* src = (const uint32_t*)(xb + (size_t)t * DIM);
    uint32_t* d0 = (uint32_t*)(xg + ((size_t)ti.x * SEQ + sp[0]) * DIM);
    uint32_t* d1 = (uint32_t*)(xg + ((size_t)ti.y * SEQ + sp[1]) * DIM);
    for (int i = threadIdx.x; i < DIM / 2; i += 256) {
        uint32_t v = src[i];
        d0[i] = v; d1[i] = v;
    }
    if (threadIdx.x == 0) pos[t] = make_int2(sp[0], sp[1]);
}

__global__ void act_moe(const float* __restrict__ gg, __nv_bfloat16* __restrict__ actb,
                        const int* __restrict__ cnt)
{
    int e = blockIdx.y;
    int m = blockIdx.x;
    if (m >= cnt[e]) return;
    const float* row = gg + ((size_t)e * SEQ + m) * (2 * FFI);
    __nv_bfloat16* orow = actb + ((size_t)e * SEQ + m) * FFI;
    for (int i = threadIdx.x; i < FFI; i += 256) {
        float gv = row[i], uv = row[i + FFI];
        float sig = 1.f / (1.f + expf(-gv));
        orow[i] = __float2bfloat16(gv * sig * uv);
    }
}

__global__ void scatter_add(float* __restrict__ h, const float* __restrict__ yg,
                            const int2* __restrict__ topi, const int2* __restrict__ pos,
                            const float2* __restrict__ topw)
{
    int t = blockIdx.x;
    int2 ti = topi[t];
    int2 ps = pos[t];
    float2 w = topw[t];
    const float* y0 = yg + ((size_t)ti.x * SEQ + ps.x) * DIM;
    const float* y1 = yg + ((size_t)ti.y * SEQ + ps.y) * DIM;
    float* hr = h + (size_t)t * DIM;
    for (int d = threadIdx.x; d < DIM; d += 256)
        hr[d] += w.x * y0[d] + w.y * y1[d];
}

__global__ void act_shared(const float* __restrict__ gsus, __nv_bfloat16* __restrict__ out)
{
    int t = blockIdx.x;
    const float* row = gsus + (size_t)t * (2 * SFI);
    __nv_bfloat16* orow = out + (size_t)t * SFI;
    for (int i = threadIdx.x; i < SFI; i += 256) {
        float gv = row[i], uv = row[i + SFI];
        float sig = 1.f / (1.f + expf(-gv));
        orow[i] = __float2bfloat16(gv * sig * uv);
    }
}

__global__ void zero_scalar(float* p)
{
    if (threadIdx.x == 0 && blockIdx.x == 0) p[0] = 0.f;
}

// single-pass online-softmax loss; float4 loads
__global__ void loss_kernel(const float* __restrict__ logits, const int* __restrict__ tgt,
                            float* __restrict__ out)
{
    int row = blockIdx.x;
    const float4* lr4 = (const float4*)(logits + (size_t)row * VOCAB);
    int tid = threadIdx.x;

    float m = -1e30f, s = 0.f;
    for (int j = tid; j < VOCAB / 4; j += 256) {
        float4 v = lr4[j];
        float mx = fmaxf(fmaxf(v.x, v.y), fmaxf(v.z, v.w));
        if (mx > m) { s *= expf(m - mx); m = mx; }
        s += expf(v.x - m) + expf(v.y - m) + expf(v.z - m) + expf(v.w - m);
    }

    __shared__ float ms[256], ss[256];
    ms[tid] = m; ss[tid] = s;
    __syncthreads();
    for (int st = 128; st > 0; st >>= 1) {
        if (tid < st) {
            float m1 = ms[tid], m2 = ms[tid + st];
            float nm = fmaxf(m1, m2);
            ss[tid] = ss[tid] * expf(m1 - nm) + ss[tid + st] * expf(m2 - nm);
            ms[tid] = nm;
        }
        __syncthreads();
    }
    if (tid == 0) {
        int lab = tgt[row];
        if (lab != -100) {
            float lse = ms[0] + logf(ss[0]);
            atomicAdd(out, lse - logits[(size_t)row * VOCAB + lab]);
        }
    }
}

// ---------------- host ----------------
static void gemm(const __nv_bfloat16* A, const __nv_bfloat16* B, float* C,
                 int M, int N, int K, int lda, int ldb, int ldc)
{
    bf16_gemm_kernel<false><<<dim3(N / 128, M / 128), 256, GEMM_SMEM>>>(A, B, C, K, lda, ldb, ldc);
}
static void gemm_acc(const __nv_bfloat16* A, const __nv_bfloat16* B, float* C,
                     int M, int N, int K, int lda, int ldb, int ldc)
{
    bf16_gemm_kernel<true><<<dim3(N / 128, M / 128), 256, GEMM_SMEM>>>(A, B, C, K, lda, ldb, ldc);
}
static void conv_w(const float* w, __nv_bfloat16* wb, size_t nelem)
{
    convert_w<<<(int)(nelem / 4096), 256>>>(w, wb);   // all sizes divisible by 4096
}

extern "C" void kernel_launch(void* const* d_in, const int* in_sizes, int n_in,
                              void* d_out, int out_size)
{
    (void)in_sizes; (void)n_in; (void)out_size;
    const int*   src       = (const int*)d_in[0];
    const int*   tgt       = (const int*)d_in[1];
    const float* embed     = (const float*)d_in[2];
    const float* Wq        = (const float*)d_in[3];
    const float* Wk        = (const float*)d_in[4];
    const float* Wv        = (const float*)d_in[5];
    const float* Wo        = (const float*)d_in[6];
    const float* ln1       = (const float*)d_in[7];
    const float* ln2       = (const float*)d_in[8];
    const float* gate_w    = (const float*)d_in[9];
    const float* gate_proj = (const float*)d_in[10];
    const float* up_proj   = (const float*)d_in[11];
    const float* down_proj = (const float*)d_in[12];
    const float* sg        = (const float*)d_in[13];
    const float* su        = (const float*)d_in[14];
    const float* sd        = (const float*)d_in[15];
    const float* final_ln  = (const float*)d_in[16];
    const float* lm_head   = (const float*)d_in[17];
    float* out = (float*)d_out;

    cudaFuncSetAttribute(bf16_gemm_kernel<false>, cudaFuncAttributeMaxDynamicSharedMemorySize, GEMM_SMEM);
    cudaFuncSetAttribute(bf16_gemm_kernel<true>,  cudaFuncAttributeMaxDynamicSharedMemorySize, GEMM_SMEM);
    cudaFuncSetAttribute(moe_gemm_kernel,         cudaFuncAttributeMaxDynamicSharedMemorySize, GEMM_SMEM);

    float *h, *qkv, *big, *gg;
    __nv_bfloat16 *xb, *ob, *actb, *xg, *gsb, *wb;
    int *cnt; int2 *topi, *pos; float2 *topw;
    cudaGetSymbolAddress((void**)&h,    g_h);
    cudaGetSymbolAddress((void**)&xb,   g_xb);
    cudaGetSymbolAddress((void**)&qkv,  g_qkv);
    cudaGetSymbolAddress((void**)&ob,   g_ob);
    cudaGetSymbolAddress((void**)&big,  g_big);
    cudaGetSymbolAddress((void**)&gg,   g_gg);
    cudaGetSymbolAddress((void**)&actb, g_actb);
    cudaGetSymbolAddress((void**)&xg,   g_xg);
    cudaGetSymbolAddress((void**)&gsb,  g_gsb);
    cudaGetSymbolAddress((void**)&wb,   g_wb);
    cudaGetSymbolAddress((void**)&cnt,  g_cnt);
    cudaGetSymbolAddress((void**)&topi, g_topi);
    cudaGetSymbolAddress((void**)&pos,  g_pos);
    cudaGetSymbolAddress((void**)&topw, g_topw);

    float* yg = big;

    embed_gather<<<SEQ, 256>>>(src, embed, h);

    const size_t DD = (size_t)DIM * DIM;
    for (int l = 0; l < NLAYER; l++) {
        // ---- attention ----
        rmsnorm_kernel<<<SEQ, 256>>>(h, ln1 + (size_t)l * DIM, xb);
        conv_w(Wq + l * DD, wb,          DD);
        conv_w(Wk + l * DD, wb + DD,     DD);
        conv_w(Wv + l * DD, wb + 2 * DD, DD);
        gemm(xb, wb, qkv, SEQ, 3 * DIM, DIM, DIM, DIM, 3 * DIM);
        rope_kernel<<<SEQ, NHEAD * 32>>>(qkv);

        flash_attn_kernel<<<dim3(SEQ / 128, NHEAD), 256>>>(qkv, qkv + DIM, qkv + 2 * DIM, ob, 3 * DIM);

        conv_w(Wo + l * DD, wb, DD);
        gemm_acc(ob, wb, h, SEQ, DIM, DIM, DIM, DIM, DIM);

        // ---- MoE (sparse top-2) ----
        rmsnorm_kernel<<<SEQ, 256>>>(h, ln2 + (size_t)l * DIM, xb);
        gate_topk<<<SEQ, 256>>>(xb, gate_w + (size_t)l * NEXP * DIM, topi, topw);
        zero_counts<<<1, 32>>>(cnt);
        gather_rows<<<SEQ, 256>>>(xb, xg, topi, pos, cnt);

        const size_t EID = (size_t)NEXP * FFI * DIM;
        convert_gateup<<<(NEXP * 2 * FFI * DIM / 4) / 1024, 256>>>(
            gate_proj + l * EID, up_proj + l * EID, wb);
        moe_gemm_kernel<<<dim3((2 * FFI) / 128, NEXP * 16), 256, GEMM_SMEM>>>(
            xg, wb, gg, cnt, DIM, 2 * FFI);
        act_moe<<<dim3(SEQ, NEXP), 256>>>(gg, actb, cnt);
        conv_w(down_proj + l * EID, wb, EID);
        moe_gemm_kernel<<<dim3(DIM / 128, NEXP * 16), 256, GEMM_SMEM>>>(
            actb, wb, yg, cnt, FFI, DIM);
        scatter_add<<<SEQ, 256>>>(h, yg, topi, pos, topw);

        // ---- shared expert ----
        const size_t SD = (size_t)SFI * DIM;
        conv_w(sg + l * SD, wb,      SD);
        conv_w(su + l * SD, wb + SD, SD);
        gemm(xb, wb, gg, SEQ, 2 * SFI, DIM, DIM, DIM, 2 * SFI);
        act_shared<<<SEQ, 256>>>(gg, gsb);
        conv_w(sd + l * SD, wb, SD);
        gemm_acc(gsb, wb, h, SEQ, DIM, SFI, SFI, SFI, DIM);
    }

    // ---- head + loss ----
    rmsnorm_kernel<<<SEQ, 256>>>(h, final_ln, xb);
    conv_w(lm_head, wb, (size_t)VOCAB * DIM);
    gemm(xb, wb, big, SEQ, VOCAB, DIM, DIM, DIM, VOCAB);
    zero_scalar<<<1, 32>>>(out);
    loss_kernel<<<SEQ, 256>>>(big, tgt, out);
}

// round 9
// speedup vs baseline: 22.3382x; 1.0734x over previous
#include <cuda_runtime.h>
#include <cuda_bf16.h>
#include <math.h>
#include <stdint.h>

// Model dims
#define SEQ    2048
#define DIM    1024
#define NHEAD  16
#define DH     64
#define NLAYER 2
#define NEXP   8
#define FFI    512
#define SFI    1024
#define VOCAB  32000
#define NCB    (VOCAB / 128)        // 250 column blocks in lm_head

#define BK 32
#define NSTAGE 4
#define BSTRIDE 40
#define STAGE_BYTES (128 * BSTRIDE * 2)
#define GEMM_SMEM (2 * NSTAGE * STAGE_BYTES)   // 81920

#define QSCALE 0.1803368801111137f   // 0.125 * log2(e)

// ---------------- static scratch ----------------
__device__ float g_h[SEQ * DIM];
__device__ __nv_bfloat16 g_xb[SEQ * DIM];
__device__ float g_qkv[SEQ * 3 * DIM];                       // fused QKV
__device__ __nv_bfloat16 g_ob[SEQ * DIM];
__device__ float g_yg[(size_t)NEXP * SEQ * DIM];             // MoE down outputs
__device__ float g_gg[(size_t)NEXP * SEQ * DIM];             // MoE gate|up acts; reused as shared gsus
__device__ __nv_bfloat16 g_actb[(size_t)NEXP * SEQ * FFI];
__device__ __nv_bfloat16 g_xg[(size_t)NEXP * SEQ * DIM];     // gathered tokens per expert
__device__ __nv_bfloat16 g_gsb[SEQ * SFI];
__device__ __nv_bfloat16 g_wb[(size_t)VOCAB * DIM];          // bf16 weight scratch
__device__ float2 g_part[(size_t)SEQ * NCB];                 // lm_head loss partials
__device__ int   g_cnt[NEXP];
__device__ int2  g_topi[SEQ];
__device__ int2  g_pos[SEQ];
__device__ float2 g_topw[SEQ];

// ---------------- helpers ----------------
__device__ __forceinline__ uint32_t cvt_bf16x2(float lo, float hi) {
    uint32_t r;
    asm("cvt.rn.bf16x2.f32 %0, %1, %2;" : "=r"(r) : "f"(hi), "f"(lo));
    return r;
}
__device__ __forceinline__ void ldsm4(uint32_t &r0, uint32_t &r1, uint32_t &r2, uint32_t &r3,
                                      uint32_t addr) {
    asm volatile("ldmatrix.sync.aligned.m8n8.x4.shared.b16 {%0,%1,%2,%3}, [%4];"
                 : "=r"(r0), "=r"(r1), "=r"(r2), "=r"(r3) : "r"(addr));
}
__device__ __forceinline__ void mma16816(float* c, const uint32_t* a, const uint32_t* b) {
    asm volatile(
        "mma.sync.aligned.m16n8k16.row.col.f32.bf16.bf16.f32 "
        "{%0,%1,%2,%3}, {%4,%5,%6,%7}, {%8,%9}, {%0,%1,%2,%3};"
        : "+f"(c[0]), "+f"(c[1]), "+f"(c[2]), "+f"(c[3])
        : "r"(a[0]), "r"(a[1]), "r"(a[2]), "r"(a[3]), "r"(b[0]), "r"(b[1]));
}
__device__ __forceinline__ void cp_async16(uint32_t dst, const void* src) {
    asm volatile("cp.async.cg.shared.global [%0], [%1], 16;" :: "r"(dst), "l"(src));
}
__device__ __forceinline__ void cp_commit() { asm volatile("cp.async.commit_group;"); }
template<int W> __device__ __forceinline__ void cp_wait() {
    asm volatile("cp.async.wait_group %0;" :: "n"(W));
}

// ---------------- 128x128 GEMM mainloop (epilogue supplied by caller) ----------------
__device__ __forceinline__ void gemm128_mainloop(
    const __nv_bfloat16* __restrict__ A, const __nv_bfloat16* __restrict__ B,
    int K, int lda, int ldb, float acc[2][8][4])
{
    extern __shared__ __align__(16) __nv_bfloat16 smem[];
    const int tid = threadIdx.x;
    const int lane = tid & 31;
    const int wid = tid >> 5;
    const int warp_m = wid & 3;
    const int warp_n = wid >> 2;
    const int g = lane >> 3, lr = lane & 7;

    const uint32_t As_base = (uint32_t)__cvta_generic_to_shared(smem);
    const uint32_t Bs_base = As_base + NSTAGE * STAGE_BYTES;
    const int ntiles = K >> 5;

    auto issue = [&](int t, int s) {
        const __nv_bfloat16* Ag = A + t * BK;
        const __nv_bfloat16* Bg = B + t * BK;
        const uint32_t a_s = As_base + s * STAGE_BYTES;
        const uint32_t b_s = Bs_base + s * STAGE_BYTES;
#pragma unroll
        for (int i = 0; i < 2; i++) {
            int id = i * 256 + tid;
            int r = id >> 2;
            int c = (id & 3) * 8;
            cp_async16(a_s + (r * BSTRIDE + c) * 2, Ag + (size_t)r * lda + c);
            cp_async16(b_s + (r * BSTRIDE + c) * 2, Bg + (size_t)r * ldb + c);
        }
    };

#pragma unroll
    for (int s = 0; s < NSTAGE - 1; s++) {
        if (s < ntiles) issue(s, s);
        cp_commit();
    }

#pragma unroll
    for (int mt = 0; mt < 2; mt++)
#pragma unroll
        for (int nt = 0; nt < 8; nt++)
#pragma unroll
            for (int i = 0; i < 4; i++) acc[mt][nt][i] = 0.f;

    for (int t = 0; t < ntiles; t++) {
        cp_wait<NSTAGE - 2>();
        __syncthreads();

        const int s = t & (NSTAGE - 1);
        const uint32_t a_base = As_base + s * STAGE_BYTES;
        const uint32_t b_base = Bs_base + s * STAGE_BYTES;

#pragma unroll
        for (int ks = 0; ks < 2; ks++) {
            uint32_t a[2][4];
#pragma unroll
            for (int mt = 0; mt < 2; mt++) {
                int row = warp_m * 32 + mt * 16 + (g & 1) * 8 + lr;
                int col = ks * 16 + (g >> 1) * 8;
                ldsm4(a[mt][0], a[mt][1], a[mt][2], a[mt][3],
                      a_base + (uint32_t)(row * BSTRIDE + col) * 2);
            }
            uint32_t b[8][2];
#pragma unroll
            for (int np = 0; np < 4; np++) {
                int row = warp_n * 64 + np * 16 + (g >> 1) * 8 + lr;
                int col = ks * 16 + (g & 1) * 8;
                uint32_t r0, r1, r2, r3;
                ldsm4(r0, r1, r2, r3, b_base + (uint32_t)(row * BSTRIDE + col) * 2);
                b[2 * np][0] = r0; b[2 * np][1] = r1;
                b[2 * np + 1][0] = r2; b[2 * np + 1][1] = r3;
            }
#pragma unroll
            for (int mt = 0; mt < 2; mt++)
#pragma unroll
                for (int nt = 0; nt < 8; nt++)
                    mma16816(acc[mt][nt], a[mt], b[nt]);
        }

        int nt2 = t + NSTAGE - 1;
        if (nt2 < ntiles) issue(nt2, nt2 & (NSTAGE - 1));
        cp_commit();
    }
}

template<bool ACC>
__device__ __forceinline__ void epilogue_store(float* __restrict__ C, int ldc,
                                               float acc[2][8][4])
{
    const int tid = threadIdx.x;
    const int lane = tid & 31;
    const int wid = tid >> 5;
    const int warp_m = wid & 3;
    const int warp_n = wid >> 2;
    const int r0c = lane >> 2;
    const int cc  = (lane & 3) * 2;
#pragma unroll
    for (int mt = 0; mt < 2; mt++) {
        int rbase = warp_m * 32 + mt * 16 + r0c;
#pragma unroll
        for (int nt = 0; nt < 8; nt++) {
            int col = warp_n * 64 + nt * 8 + cc;
            size_t i00 = (size_t)rbase * ldc + col;
            size_t i10 = (size_t)(rbase + 8) * ldc + col;
            if (ACC) {
                C[i00]     += acc[mt][nt][0]; C[i00 + 1] += acc[mt][nt][1];
                C[i10]     += acc[mt][nt][2]; C[i10 + 1] += acc[mt][nt][3];
            } else {
                C[i00]     = acc[mt][nt][0]; C[i00 + 1] = acc[mt][nt][1];
                C[i10]     = acc[mt][nt][2]; C[i10 + 1] = acc[mt][nt][3];
            }
        }
    }
}

template<bool ACC>
__global__ void __launch_bounds__(256, 2) bf16_gemm_kernel(
    const __nv_bfloat16* __restrict__ A, const __nv_bfloat16* __restrict__ B,
    float* __restrict__ C, int K, int lda, int ldb, int ldc)
{
    A += (size_t)blockIdx.y * 128 * lda;
    B += (size_t)blockIdx.x * 128 * ldb;
    C += (size_t)blockIdx.y * 128 * ldc + blockIdx.x * 128;
    float acc[2][8][4];
    gemm128_mainloop(A, B, K, lda, ldb, acc);
    epilogue_store<ACC>(C, ldc, acc);
}

__global__ void __launch_bounds__(256, 2) moe_gemm_kernel(
    const __nv_bfloat16* __restrict__ A, const __nv_bfloat16* __restrict__ B,
    float* __restrict__ C, const int* __restrict__ cnt, int K, int N)
{
    const int e = blockIdx.y >> 4;
    const int rb = blockIdx.y & 15;
    if (rb * 128 >= cnt[e]) return;
    A += ((size_t)e * SEQ + rb * 128) * K;
    B += (size_t)e * N * K + (size_t)blockIdx.x * 128 * K;
    C += ((size_t)e * SEQ + rb * 128) * N + blockIdx.x * 128;
    float acc[2][8][4];
    gemm128_mainloop(A, B, K, K, K, acc);
    epilogue_store<false>(C, N, acc);
}

// lm_head GEMM with fused loss epilogue: writes per-(row, colblock) online-softmax
// partials (max, sumexp) instead of logits. grid = (NCB, SEQ/128).
__global__ void __launch_bounds__(256, 2) lmhead_gemm_loss(
    const __nv_bfloat16* __restrict__ A, const __nv_bfloat16* __restrict__ B,
    float2* __restrict__ part, int K)
{
    const int bx = blockIdx.x;
    A += (size_t)blockIdx.y * 128 * K;
    B += (size_t)bx * 128 * K;
    float acc[2][8][4];
    gemm128_mainloop(A, B, K, K, K, acc);

    const int tid = threadIdx.x;
    const int lane = tid & 31;
    const int wid = tid >> 5;
    const int warp_m = wid & 3;
    const int warp_n = wid >> 2;

    __shared__ float sm_m[2][128], sm_s[2][128];

#pragma unroll
    for (int mt = 0; mt < 2; mt++) {
#pragma unroll
        for (int half = 0; half < 2; half++) {
            float m = -1e30f;
#pragma unroll
            for (int nt = 0; nt < 8; nt++)
                m = fmaxf(m, fmaxf(acc[mt][nt][2 * half], acc[mt][nt][2 * half + 1]));
            // quad max (lanes 4k..4k+3 hold same row, different cols)
            m = fmaxf(m, __shfl_xor_sync(0xffffffffu, m, 1));
            m = fmaxf(m, __shfl_xor_sync(0xffffffffu, m, 2));
            float s = 0.f;
#pragma unroll
            for (int nt = 0; nt < 8; nt++)
                s += expf(acc[mt][nt][2 * half] - m) + expf(acc[mt][nt][2 * half + 1] - m);
            s += __shfl_xor_sync(0xffffffffu, s, 1);
            s += __shfl_xor_sync(0xffffffffu, s, 2);
            if ((lane & 3) == 0) {
                int row_local = warp_m * 32 + mt * 16 + half * 8 + (lane >> 2);
                sm_m[warp_n][row_local] = m;
                sm_s[warp_n][row_local] = s;
            }
        }
    }
    __syncthreads();

    if (tid < 128) {
        float m1 = sm_m[0][tid], s1 = sm_s[0][tid];
        float m2 = sm_m[1][tid], s2 = sm_s[1][tid];
        float nm = fmaxf(m1, m2);
        float ns = s1 * expf(m1 - nm) + s2 * expf(m2 - nm);
        int row = blockIdx.y * 128 + tid;
        part[(size_t)row * NCB + bx] = make_float2(nm, ns);
    }
}

// merge partials per row + recompute label logit (bf16 dot) + accumulate NLL
__global__ void loss_reduce(const float2* __restrict__ part,
                            const __nv_bfloat16* __restrict__ xb,
                            const __nv_bfloat16* __restrict__ wb,
                            const int* __restrict__ tgt, float* __restrict__ out)
{
    int row = blockIdx.x;
    int tid = threadIdx.x;

    float m = -1e30f, s = 0.f;
    for (int j = tid; j < NCB; j += 256) {
        float2 p = part[(size_t)row * NCB + j];
        float nm = fmaxf(m, p.x);
        s = s * expf(m - nm) + p.y * expf(p.x - nm);
        m = nm;
    }

    __shared__ float ms[256], ss[256], ds[256];
    ms[tid] = m; ss[tid] = s;
    __syncthreads();
    for (int st = 128; st > 0; st >>= 1) {
        if (tid < st) {
            float m1 = ms[tid], m2 = ms[tid + st];
            float nm = fmaxf(m1, m2);
            ss[tid] = ss[tid] * expf(m1 - nm) + ss[tid + st] * expf(m2 - nm);
            ms[tid] = nm;
        }
        __syncthreads();
    }

    int lab = tgt[row];
    int slab = (lab == -100) ? 0 : lab;
    const __nv_bfloat16* xr = xb + (size_t)row * DIM;
    const __nv_bfloat16* wr = wb + (size_t)slab * DIM;
    float d = 0.f;
    for (int i = tid; i < DIM; i += 256)
        d += __bfloat162float(xr[i]) * __bfloat162float(wr[i]);
    ds[tid] = d;
    __syncthreads();
    for (int st = 128; st > 0; st >>= 1) {
        if (tid < st) ds[tid] += ds[tid + st];
        __syncthreads();
    }

    if (tid == 0 && lab != -100) {
        float lse = ms[0] + logf(ss[0]);
        atomicAdd(out, lse - ds[0]);
    }
}

// ---------------- weight conversion (ILP-4, contiguous block span) ----------------
__global__ void convert_w(const float* __restrict__ w, __nv_bfloat16* __restrict__ wb)
{
    const float4* w4 = (const float4*)w;
    uint2* o2 = (uint2*)wb;
    size_t base = (size_t)blockIdx.x * 1024 + threadIdx.x;
    float4 v[4];
#pragma unroll
    for (int k = 0; k < 4; k++) v[k] = w4[base + k * 256];
#pragma unroll
    for (int k = 0; k < 4; k++) {
        uint2 pk;
        pk.x = cvt_bf16x2(v[k].x, v[k].y);
        pk.y = cvt_bf16x2(v[k].z, v[k].w);
        o2[base + k * 256] = pk;
    }
}

__global__ void convert_gateup(const float* __restrict__ gp, const float* __restrict__ up,
                               __nv_bfloat16* __restrict__ wb)
{
    size_t base = (size_t)blockIdx.x * 1024 + threadIdx.x;   // float4 index
    float4 v[4];
    size_t idxs[4];
#pragma unroll
    for (int k = 0; k < 4; k++) {
        size_t idx = base + k * 256;
        int k4 = (int)(idx & 255);
        int n  = (int)((idx >> 8) & 1023);
        int e  = (int)(idx >> 18);
        const float* src = (n < FFI)
            ? gp + ((size_t)e * FFI + n) * DIM + k4 * 4
            : up + ((size_t)e * FFI + (n - FFI)) * DIM + k4 * 4;
        v[k] = *(const float4*)src;
        idxs[k] = ((size_t)e * 2 * FFI + n) * (DIM / 4) + k4;
    }
#pragma unroll
    for (int k = 0; k < 4; k++) {
        uint2 pk;
        pk.x = cvt_bf16x2(v[k].x, v[k].y);
        pk.y = cvt_bf16x2(v[k].z, v[k].w);
        ((uint2*)wb)[idxs[k]] = pk;
    }
}

// ---------------- fused flash attention ----------------
__global__ void __launch_bounds__(256, 1) flash_attn_kernel(
    const float* __restrict__ q, const float* __restrict__ k,
    const float* __restrict__ v, __nv_bfloat16* __restrict__ ob, int ldq)
{
    const int qb = blockIdx.x;
    const int head = blockIdx.y;
    const int q0 = qb * 128;
    const int hoff = head * DH;

    __shared__ __align__(16) __nv_bfloat16 bufA[128 * 72];
    __shared__ __align__(16) __nv_bfloat16 Ks[128 * 72];

    const int tid = threadIdx.x;
    const int lane = tid & 31;
    const int wid = tid >> 5;
    const int g = lane >> 3, lr = lane & 7;
    const int r0 = wid * 16;

    const uint32_t bufA_base = (uint32_t)__cvta_generic_to_shared(bufA);
    const uint32_t Ks_base = (uint32_t)__cvta_generic_to_shared(Ks);

#pragma unroll
    for (int i = 0; i < 8; i++) {
        int id = i * 256 + tid;
        int r = id >> 4;
        int c = (id & 15) << 2;
        float4 val = *(const float4*)(q + (size_t)(q0 + r) * ldq + hoff + c);
        uint2 pk;
        pk.x = cvt_bf16x2(val.x * QSCALE, val.y * QSCALE);
        pk.y = cvt_bf16x2(val.z * QSCALE, val.w * QSCALE);
        *(uint2*)&bufA[r * 72 + c] = pk;
    }
    __syncthreads();

    uint32_t qa[4][4];
#pragma unroll
    for (int kt = 0; kt < 4; kt++) {
        int row = r0 + (g & 1) * 8 + lr;
        int col = kt * 16 + (g >> 1) * 8;
        ldsm4(qa[kt][0], qa[kt][1], qa[kt][2], qa[kt][3],
              bufA_base + (uint32_t)(row * 72 + col) * 2);
    }
    __syncthreads();

    float acc_o[8][4];
#pragma unroll
    for (int nt = 0; nt < 8; nt++)
#pragma unroll
        for (int i = 0; i < 4; i++) acc_o[nt][i] = 0.f;

    float mA = -1e30f, mB = -1e30f, lA = 0.f, lB = 0.f;
    const int rA = q0 + r0 + (lane >> 2);
    const int rB = rA + 8;

    for (int kb = 0; kb <= qb; kb++) {
        const int kk0 = kb * 128;
#pragma unroll
        for (int i = 0; i < 8; i++) {
            int id = i * 256 + tid;
            int r = id >> 4;
            int c = (id & 15) << 2;
            float4 val = *(const float4*)(k + (size_t)(kk0 + r) * ldq + hoff + c);
            uint2 pk;
            pk.x = cvt_bf16x2(val.x, val.y);
            pk.y = cvt_bf16x2(val.z, val.w);
            *(uint2*)&Ks[r * 72 + c] = pk;
        }
#pragma unroll
        for (int i = 0; i < 8; i++) {
            int id = i * 256 + tid;
            int r = id >> 4;
            int c = (id & 15) << 2;
            float4 val = *(const float4*)(v + (size_t)(kk0 + r) * ldq + hoff + c);
            bufA[(c + 0) * 136 + r] = __float2bfloat16(val.x);
            bufA[(c + 1) * 136 + r] = __float2bfloat16(val.y);
            bufA[(c + 2) * 136 + r] = __float2bfloat16(val.z);
            bufA[(c + 3) * 136 + r] = __float2bfloat16(val.w);
        }
        __syncthreads();

        float sacc[16][4];
#pragma unroll
        for (int nt = 0; nt < 16; nt++)
#pragma unroll
            for (int i = 0; i < 4; i++) sacc[nt][i] = 0.f;

#pragma unroll
        for (int kt = 0; kt < 4; kt++) {
#pragma unroll
            for (int np = 0; np < 8; np++) {
                int row = np * 16 + (g >> 1) * 8 + lr;
                int col = kt * 16 + (g & 1) * 8;
                uint32_t b0, b1, b2, b3;
                ldsm4(b0, b1, b2, b3, Ks_base + (uint32_t)(row * 72 + col) * 2);
                uint32_t bb0[2] = {b0, b1}, bb1[2] = {b2, b3};
                mma16816(sacc[2 * np],     qa[kt], bb0);
                mma16816(sacc[2 * np + 1], qa[kt], bb1);
            }
        }

        if (kb == qb) {
#pragma unroll
            for (int nt = 0; nt < 16; nt++) {
                int cb = kk0 + nt * 8 + 2 * (lane & 3);
                if (cb     > rA) sacc[nt][0] = -1e30f;
                if (cb + 1 > rA) sacc[nt][1] = -1e30f;
                if (cb     > rB) sacc[nt][2] = -1e30f;
                if (cb + 1 > rB) sacc[nt][3] = -1e30f;
            }
        }

        float cmA = -1e30f, cmB = -1e30f;
#pragma unroll
        for (int nt = 0; nt < 16; nt++) {
            cmA = fmaxf(cmA, fmaxf(sacc[nt][0], sacc[nt][1]));
            cmB = fmaxf(cmB, fmaxf(sacc[nt][2], sacc[nt][3]));
        }
        cmA = fmaxf(cmA, __shfl_xor_sync(0xffffffffu, cmA, 1));
        cmA = fmaxf(cmA, __shfl_xor_sync(0xffffffffu, cmA, 2));
        cmB = fmaxf(cmB, __shfl_xor_sync(0xffffffffu, cmB, 1));
        cmB = fmaxf(cmB, __shfl_xor_sync(0xffffffffu, cmB, 2));

        float nmA = fmaxf(mA, cmA), nmB = fmaxf(mB, cmB);
        float scA = exp2f(mA - nmA), scB = exp2f(mB - nmB);
        mA = nmA; mB = nmB;

        uint32_t pA[16], pB[16];
        float sA = 0.f, sB = 0.f;
#pragma unroll
        for (int nt = 0; nt < 16; nt++) {
            float p0 = exp2f(sacc[nt][0] - mA);
            float p1 = exp2f(sacc[nt][1] - mA);
            float p2 = exp2f(sacc[nt][2] - mB);
            float p3 = exp2f(sacc[nt][3] - mB);
            sA += p0 + p1; sB += p2 + p3;
            pA[nt] = cvt_bf16x2(p0, p1);
            pB[nt] = cvt_bf16x2(p2, p3);
        }
        lA = lA * scA + sA;
        lB = lB * scB + sB;
#pragma unroll
        for (int nt = 0; nt < 8; nt++) {
            acc_o[nt][0] *= scA; acc_o[nt][1] *= scA;
            acc_o[nt][2] *= scB; acc_o[nt][3] *= scB;
        }

#pragma unroll
        for (int kt2 = 0; kt2 < 8; kt2++) {
            uint32_t a[4] = { pA[2 * kt2], pB[2 * kt2], pA[2 * kt2 + 1], pB[2 * kt2 + 1] };
#pragma unroll
            for (int np2 = 0; np2 < 4; np2++) {
                int row = np2 * 16 + (g >> 1) * 8 + lr;
                int col = kt2 * 16 + (g & 1) * 8;
                uint32_t b0, b1, b2, b3;
                ldsm4(b0, b1, b2, b3, bufA_base + (uint32_t)(row * 136 + col) * 2);
                uint32_t bb0[2] = {b0, b1}, bb1[2] = {b2, b3};
                mma16816(acc_o[2 * np2],     a, bb0);
                mma16816(acc_o[2 * np2 + 1], a, bb1);
            }
        }
        __syncthreads();
    }

    lA += __shfl_xor_sync(0xffffffffu, lA, 1);
    lA += __shfl_xor_sync(0xffffffffu, lA, 2);
    lB += __shfl_xor_sync(0xffffffffu, lB, 1);
    lB += __shfl_xor_sync(0xffffffffu, lB, 2);
    float iA = 1.f / lA, iB = 1.f / lB;

#pragma unroll
    for (int nt = 0; nt < 8; nt++) {
        int col = hoff + nt * 8 + 2 * (lane & 3);
        uint32_t p0 = cvt_bf16x2(acc_o[nt][0] * iA, acc_o[nt][1] * iA);
        uint32_t p1 = cvt_bf16x2(acc_o[nt][2] * iB, acc_o[nt][3] * iB);
        *(uint32_t*)(ob + (size_t)rA * DIM + col) = p0;
        *(uint32_t*)(ob + (size_t)rB * DIM + col) = p1;
    }
}

// ---------------- small kernels ----------------
__global__ void embed_gather(const int* __restrict__ tok, const float* __restrict__ emb,
                             float* __restrict__ h)
{
    int s = blockIdx.x;
    int t = tok[s];
    const float* e = emb + (size_t)t * DIM;
    for (int d = threadIdx.x; d < DIM; d += blockDim.x)
        h[(size_t)s * DIM + d] = e[d];
}

__global__ void rmsnorm_kernel(const float* __restrict__ x, const float* __restrict__ w,
                               __nv_bfloat16* __restrict__ o)
{
    int row = blockIdx.x;
    const float* xr = x + (size_t)row * DIM;
    __shared__ float red[256];
    int tid = threadIdx.x;
    float s = 0.f;
    for (int d = tid; d < DIM; d += 256) { float v = xr[d]; s += v * v; }
    red[tid] = s; __syncthreads();
    for (int st = 128; st > 0; st >>= 1) {
        if (tid < st) red[tid] += red[tid + st];
        __syncthreads();
    }
    float rs = rsqrtf(red[0] / (float)DIM + 1e-6f);
    for (int d = tid; d < DIM; d += 256)
        o[(size_t)row * DIM + d] = __float2bfloat16(xr[d] * rs * w[d]);
}

__global__ void rope_kernel(float* __restrict__ qkv)
{
    int s = blockIdx.x;
    int tid = threadIdx.x;
    int h = tid >> 5, i = tid & 31;
    float freq = powf(10000.f, -(float)(2 * i) / 64.f);
    float ang = (float)s * freq;
    float sn, cs;
    sincosf(ang, &sn, &cs);
    size_t base = (size_t)s * (3 * DIM) + h * DH + i;
    float q1 = qkv[base], q2 = qkv[base + 32];
    qkv[base]      = q1 * cs - q2 * sn;
    qkv[base + 32] = q2 * cs + q1 * sn;
    size_t kb = base + DIM;
    float k1 = qkv[kb], k2 = qkv[kb + 32];
    qkv[kb]      = k1 * cs - k2 * sn;
    qkv[kb + 32] = k2 * cs + k1 * sn;
}

__global__ void gate_topk(const __nv_bfloat16* __restrict__ x, const float* __restrict__ gw,
                          int2* __restrict__ topi, float2* __restrict__ topw)
{
    int t = blockIdx.x;
    int tid = threadIdx.x;
    int e = tid >> 5, lane = tid & 31;
    const __nv_bfloat16* xr = x + (size_t)t * DIM;
    const float* wr = gw + (size_t)e * DIM;
    float s = 0.f;
    for (int d = lane; d < DIM; d += 32) s += __bfloat162float(xr[d]) * wr[d];
    for (int o = 16; o; o >>= 1) s += __shfl_down_sync(0xffffffffu, s, o);
    __shared__ float lg[NEXP];
    if (lane == 0) lg[e] = s;
    __syncthreads();
    if (tid == 0) {
        float m = -1e30f;
        for (int i = 0; i < NEXP; i++) m = fmaxf(m, lg[i]);
        float p[NEXP]; float sum = 0.f;
        for (int i = 0; i < NEXP; i++) { p[i] = expf(lg[i] - m); sum += p[i]; }
        float inv = 1.f / sum;
        for (int i = 0; i < NEXP; i++) p[i] *= inv;
        int i0 = 0;
        for (int i = 1; i < NEXP; i++) if (p[i] > p[i0]) i0 = i;
        int i1 = -1;
        for (int i = 0; i < NEXP; i++) {
            if (i == i0) continue;
            if (i1 < 0 || p[i] > p[i1]) i1 = i;
        }
        topi[t] = make_int2(i0, i1);
        topw[t] = make_float2(p[i0], p[i1]);
    }
}

__global__ void zero_counts(int* cnt)
{
    if (threadIdx.x < NEXP) cnt[threadIdx.x] = 0;
}

__global__ void gather_rows(const __nv_bfloat16* __restrict__ xb, __nv_bfloat16* __restrict__ xg,
                            const int2* __restrict__ topi, int2* __restrict__ pos,
                            int* __restrict__ cnt)
{
    int t = blockIdx.x;
    __shared__ int sp[2];
    int2 ti = topi[t];
    if (threadIdx.x == 0) {
        sp[0] = atomicAdd(&cnt[ti.x], 1);
        sp[1] = atomicAdd(&cnt[ti.y], 1);
    }
    __syncthreads();
    const uint32_t* src = (const uint32_t*)(xb + (size_t)t * DIM);
    uint32_t* d0 = (uint32_t*)(xg + ((size_t)ti.x * SEQ + sp[0]) * DIM);
    uint32_t* d1 = (uint32_t*)(xg + ((size_t)ti.y * SEQ + sp[1]) * DIM);
    for (int i = threadIdx.x; i < DIM / 2; i += 256) {
        uint32_t v = src[i];
        d0[i] = v; d1[i] = v;
    }
    if (threadIdx.x == 0) pos[t] = make_int2(sp[0], sp[1]);
}

__global__ void act_moe(const float* __restrict__ gg, __nv_bfloat16* __restrict__ actb,
                        const int* __restrict__ cnt)
{
    int e = blockIdx.y;
    int m = blockIdx.x;
    if (m >= cnt[e]) return;
    const float* row = gg + ((size_t)e * SEQ + m) * (2 * FFI);
    __nv_bfloat16* orow = actb + ((size_t)e * SEQ + m) * FFI;
    for (int i = threadIdx.x; i < FFI; i += 256) {
        float gv = row[i], uv = row[i + FFI];
        float sig = 1.f / (1.f + expf(-gv));
        orow[i] = __float2bfloat16(gv * sig * uv);
    }
}

__global__ void scatter_add(float* __restrict__ h, const float* __restrict__ yg,
                            const int2* __restrict__ topi, const int2* __restrict__ pos,
                            const float2* __restrict__ topw)
{
    int t = blockIdx.x;
    int2 ti = topi[t];
    int2 ps = pos[t];
    float2 w = topw[t];
    const float* y0 = yg + ((size_t)ti.x * SEQ + ps.x) * DIM;
    const float* y1 = yg + ((size_t)ti.y * SEQ + ps.y) * DIM;
    float* hr = h + (size_t)t * DIM;
    for (int d = threadIdx.x; d < DIM; d += 256)
        hr[d] += w.x * y0[d] + w.y * y1[d];
}

__global__ void act_shared(const float* __restrict__ gsus, __nv_bfloat16* __restrict__ out)
{
    int t = blockIdx.x;
    const float* row = gsus + (size_t)t * (2 * SFI);
    __nv_bfloat16* orow = out + (size_t)t * SFI;
    for (int i = threadIdx.x; i < SFI; i += 256) {
        float gv = row[i], uv = row[i + SFI];
        float sig = 1.f / (1.f + expf(-gv));
        orow[i] = __float2bfloat16(gv * sig * uv);
    }
}

__global__ void zero_scalar(float* p)
{
    if (threadIdx.x == 0 && blockIdx.x == 0) p[0] = 0.f;
}

// ---------------- host ----------------
static void gemm(const __nv_bfloat16* A, const __nv_bfloat16* B, float* C,
                 int M, int N, int K, int lda, int ldb, int ldc)
{
    bf16_gemm_kernel<false><<<dim3(N / 128, M / 128), 256, GEMM_SMEM>>>(A, B, C, K, lda, ldb, ldc);
}
static void gemm_acc(const __nv_bfloat16* A, const __nv_bfloat16* B, float* C,
                     int M, int N, int K, int lda, int ldb, int ldc)
{
    bf16_gemm_kernel<true><<<dim3(N / 128, M / 128), 256, GEMM_SMEM>>>(A, B, C, K, lda, ldb, ldc);
}
static void conv_w(const float* w, __nv_bfloat16* wb, size_t nelem)
{
    convert_w<<<(int)(nelem / 4096), 256>>>(w, wb);
}

extern "C" void kernel_launch(void* const* d_in, const int* in_sizes, int n_in,
                              void* d_out, int out_size)
{
    (void)in_sizes; (void)n_in; (void)out_size;
    const int*   src       = (const int*)d_in[0];
    const int*   tgt       = (const int*)d_in[1];
    const float* embed     = (const float*)d_in[2];
    const float* Wq        = (const float*)d_in[3];
    const float* Wk        = (const float*)d_in[4];
    const float* Wv        = (const float*)d_in[5];
    const float* Wo        = (const float*)d_in[6];
    const float* ln1       = (const float*)d_in[7];
    const float* ln2       = (const float*)d_in[8];
    const float* gate_w    = (const float*)d_in[9];
    const float* gate_proj = (const float*)d_in[10];
    const float* up_proj   = (const float*)d_in[11];
    const float* down_proj = (const float*)d_in[12];
    const float* sg        = (const float*)d_in[13];
    const float* su        = (const float*)d_in[14];
    const float* sd        = (const float*)d_in[15];
    const float* final_ln  = (const float*)d_in[16];
    const float* lm_head   = (const float*)d_in[17];
    float* out = (float*)d_out;

    cudaFuncSetAttribute(bf16_gemm_kernel<false>, cudaFuncAttributeMaxDynamicSharedMemorySize, GEMM_SMEM);
    cudaFuncSetAttribute(bf16_gemm_kernel<true>,  cudaFuncAttributeMaxDynamicSharedMemorySize, GEMM_SMEM);
    cudaFuncSetAttribute(moe_gemm_kernel,         cudaFuncAttributeMaxDynamicSharedMemorySize, GEMM_SMEM);
    cudaFuncSetAttribute(lmhead_gemm_loss,        cudaFuncAttributeMaxDynamicSharedMemorySize, GEMM_SMEM);

    float *h, *qkv, *yg, *gg;
    __nv_bfloat16 *xb, *ob, *actb, *xg, *gsb, *wb;
    float2 *partb;
    int *cnt; int2 *topi, *pos; float2 *topw;
    cudaGetSymbolAddress((void**)&h,    g_h);
    cudaGetSymbolAddress((void**)&xb,   g_xb);
    cudaGetSymbolAddress((void**)&qkv,  g_qkv);
    cudaGetSymbolAddress((void**)&ob,   g_ob);
    cudaGetSymbolAddress((void**)&yg,   g_yg);
    cudaGetSymbolAddress((void**)&gg,   g_gg);
    cudaGetSymbolAddress((void**)&actb, g_actb);
    cudaGetSymbolAddress((void**)&xg,   g_xg);
    cudaGetSymbolAddress((void**)&gsb,  g_gsb);
    cudaGetSymbolAddress((void**)&wb,   g_wb);
    cudaGetSymbolAddress((void**)&partb, g_part);
    cudaGetSymbolAddress((void**)&cnt,  g_cnt);
    cudaGetSymbolAddress((void**)&topi, g_topi);
    cudaGetSymbolAddress((void**)&pos,  g_pos);
    cudaGetSymbolAddress((void**)&topw, g_topw);

    embed_gather<<<SEQ, 256>>>(src, embed, h);

    const size_t DD = (size_t)DIM * DIM;
    for (int l = 0; l < NLAYER; l++) {
        // ---- attention ----
        rmsnorm_kernel<<<SEQ, 256>>>(h, ln1 + (size_t)l * DIM, xb);
        conv_w(Wq + l * DD, wb,          DD);
        conv_w(Wk + l * DD, wb + DD,     DD);
        conv_w(Wv + l * DD, wb + 2 * DD, DD);
        gemm(xb, wb, qkv, SEQ, 3 * DIM, DIM, DIM, DIM, 3 * DIM);
        rope_kernel<<<SEQ, NHEAD * 32>>>(qkv);

        flash_attn_kernel<<<dim3(SEQ / 128, NHEAD), 256>>>(qkv, qkv + DIM, qkv + 2 * DIM, ob, 3 * DIM);

        conv_w(Wo + l * DD, wb, DD);
        gemm_acc(ob, wb, h, SEQ, DIM, DIM, DIM, DIM, DIM);

        // ---- MoE (sparse top-2) ----
        rmsnorm_kernel<<<SEQ, 256>>>(h, ln2 + (size_t)l * DIM, xb);
        gate_topk<<<SEQ, 256>>>(xb, gate_w + (size_t)l * NEXP * DIM, topi, topw);
        zero_counts<<<1, 32>>>(cnt);
        gather_rows<<<SEQ, 256>>>(xb, xg, topi, pos, cnt);

        const size_t EID = (size_t)NEXP * FFI * DIM;
        convert_gateup<<<(NEXP * 2 * FFI * DIM / 4) / 1024, 256>>>(
            gate_proj + l * EID, up_proj + l * EID, wb);
        moe_gemm_kernel<<<dim3((2 * FFI) / 128, NEXP * 16), 256, GEMM_SMEM>>>(
            xg, wb, gg, cnt, DIM, 2 * FFI);
        act_moe<<<dim3(SEQ, NEXP), 256>>>(gg, actb, cnt);
        conv_w(down_proj + l * EID, wb, EID);
        moe_gemm_kernel<<<dim3(DIM / 128, NEXP * 16), 256, GEMM_SMEM>>>(
            actb, wb, yg, cnt, FFI, DIM);
        scatter_add<<<SEQ, 256>>>(h, yg, topi, pos, topw);

        // ---- shared expert ----
        const size_t SD = (size_t)SFI * DIM;
        conv_w(sg + l * SD, wb,      SD);
        conv_w(su + l * SD, wb + SD, SD);
        gemm(xb, wb, gg, SEQ, 2 * SFI, DIM, DIM, DIM, 2 * SFI);
        act_shared<<<SEQ, 256>>>(gg, gsb);
        conv_w(sd + l * SD, wb, SD);
        gemm_acc(gsb, wb, h, SEQ, DIM, SFI, SFI, SFI, DIM);
    }

    // ---- head + fused loss ----
    rmsnorm_kernel<<<SEQ, 256>>>(h, final_ln, xb);
    conv_w(lm_head, wb, (size_t)VOCAB * DIM);
    lmhead_gemm_loss<<<dim3(NCB, SEQ / 128), 256, GEMM_SMEM>>>(xb, wb, partb, DIM);
    zero_scalar<<<1, 32>>>(out);
    loss_reduce<<<SEQ, 256>>>(partb, xb, wb, tgt, out);
}

// round 10
// speedup vs baseline: 23.0205x; 1.0305x over previous
#include <cuda_runtime.h>
#include <cuda_bf16.h>
#include <math.h>
#include <stdint.h>

// Model dims
#define SEQ    2048
#define DIM    1024
#define NHEAD  16
#define DH     64
#define NLAYER 2
#define NEXP   8
#define FFI    512
#define SFI    1024
#define VOCAB  32000
#define NCB    (VOCAB / 128)        // 250 column blocks in lm_head

#define BK 32
#define NSTAGE 4
#define BSTRIDE 40
#define STAGE_BYTES (128 * BSTRIDE * 2)
#define GEMM_SMEM (2 * NSTAGE * STAGE_BYTES)   // 81920

#define CONV_GRID 1184              // 8 CTAs/SM * 148 SMs

#define QSCALE 0.1803368801111137f  // 0.125 * log2(e)

// ---------------- static scratch ----------------
__device__ float g_h[SEQ * DIM];
__device__ __nv_bfloat16 g_xb[SEQ * DIM];
__device__ float g_qkv[SEQ * 3 * DIM];
__device__ __nv_bfloat16 g_ob[SEQ * DIM];
__device__ float g_yg[(size_t)NEXP * SEQ * DIM];             // MoE down outputs
__device__ __nv_bfloat16 g_actb[(size_t)NEXP * SEQ * FFI];
__device__ __nv_bfloat16 g_xg[(size_t)NEXP * SEQ * DIM];
__device__ __nv_bfloat16 g_gsb[SEQ * SFI];
__device__ __nv_bfloat16 g_wb[(size_t)VOCAB * DIM];          // bf16 weight scratch
__device__ float2 g_part[(size_t)SEQ * NCB];
__device__ int   g_cnt[NEXP];
__device__ int2  g_topi[SEQ];
__device__ int2  g_pos[SEQ];
__device__ float2 g_topw[SEQ];

// ---------------- helpers ----------------
__device__ __forceinline__ uint32_t cvt_bf16x2(float lo, float hi) {
    uint32_t r;
    asm("cvt.rn.bf16x2.f32 %0, %1, %2;" : "=r"(r) : "f"(hi), "f"(lo));
    return r;
}
__device__ __forceinline__ void ldsm4(uint32_t &r0, uint32_t &r1, uint32_t &r2, uint32_t &r3,
                                      uint32_t addr) {
    asm volatile("ldmatrix.sync.aligned.m8n8.x4.shared.b16 {%0,%1,%2,%3}, [%4];"
                 : "=r"(r0), "=r"(r1), "=r"(r2), "=r"(r3) : "r"(addr));
}
__device__ __forceinline__ void mma16816(float* c, const uint32_t* a, const uint32_t* b) {
    asm volatile(
        "mma.sync.aligned.m16n8k16.row.col.f32.bf16.bf16.f32 "
        "{%0,%1,%2,%3}, {%4,%5,%6,%7}, {%8,%9}, {%0,%1,%2,%3};"
        : "+f"(c[0]), "+f"(c[1]), "+f"(c[2]), "+f"(c[3])
        : "r"(a[0]), "r"(a[1]), "r"(a[2]), "r"(a[3]), "r"(b[0]), "r"(b[1]));
}
__device__ __forceinline__ void cp_async16(uint32_t dst, const void* src) {
    asm volatile("cp.async.cg.shared.global [%0], [%1], 16;" :: "r"(dst), "l"(src));
}
__device__ __forceinline__ void cp_commit() { asm volatile("cp.async.commit_group;"); }
template<int W> __device__ __forceinline__ void cp_wait() {
    asm volatile("cp.async.wait_group %0;" :: "n"(W));
}

// ---------------- 128x128 GEMM mainloop ----------------
__device__ __forceinline__ void gemm128_mainloop(
    const __nv_bfloat16* __restrict__ A, const __nv_bfloat16* __restrict__ B,
    int K, int lda, int ldb, float acc[2][8][4])
{
    extern __shared__ __align__(16) __nv_bfloat16 smem[];
    const int tid = threadIdx.x;
    const int lane = tid & 31;
    const int wid = tid >> 5;
    const int warp_m = wid & 3;
    const int warp_n = wid >> 2;
    const int g = lane >> 3, lr = lane & 7;

    const uint32_t As_base = (uint32_t)__cvta_generic_to_shared(smem);
    const uint32_t Bs_base = As_base + NSTAGE * STAGE_BYTES;
    const int ntiles = K >> 5;

    auto issue = [&](int t, int s) {
        const __nv_bfloat16* Ag = A + t * BK;
        const __nv_bfloat16* Bg = B + t * BK;
        const uint32_t a_s = As_base + s * STAGE_BYTES;
        const uint32_t b_s = Bs_base + s * STAGE_BYTES;
#pragma unroll
        for (int i = 0; i < 2; i++) {
            int id = i * 256 + tid;
            int r = id >> 2;
            int c = (id & 3) * 8;
            cp_async16(a_s + (r * BSTRIDE + c) * 2, Ag + (size_t)r * lda + c);
            cp_async16(b_s + (r * BSTRIDE + c) * 2, Bg + (size_t)r * ldb + c);
        }
    };

#pragma unroll
    for (int s = 0; s < NSTAGE - 1; s++) {
        if (s < ntiles) issue(s, s);
        cp_commit();
    }

#pragma unroll
    for (int mt = 0; mt < 2; mt++)
#pragma unroll
        for (int nt = 0; nt < 8; nt++)
#pragma unroll
            for (int i = 0; i < 4; i++) acc[mt][nt][i] = 0.f;

    for (int t = 0; t < ntiles; t++) {
        cp_wait<NSTAGE - 2>();
        __syncthreads();

        const int s = t & (NSTAGE - 1);
        const uint32_t a_base = As_base + s * STAGE_BYTES;
        const uint32_t b_base = Bs_base + s * STAGE_BYTES;

#pragma unroll
        for (int ks = 0; ks < 2; ks++) {
            uint32_t a[2][4];
#pragma unroll
            for (int mt = 0; mt < 2; mt++) {
                int row = warp_m * 32 + mt * 16 + (g & 1) * 8 + lr;
                int col = ks * 16 + (g >> 1) * 8;
                ldsm4(a[mt][0], a[mt][1], a[mt][2], a[mt][3],
                      a_base + (uint32_t)(row * BSTRIDE + col) * 2);
            }
            uint32_t b[8][2];
#pragma unroll
            for (int np = 0; np < 4; np++) {
                int row = warp_n * 64 + np * 16 + (g >> 1) * 8 + lr;
                int col = ks * 16 + (g & 1) * 8;
                uint32_t r0, r1, r2, r3;
                ldsm4(r0, r1, r2, r3, b_base + (uint32_t)(row * BSTRIDE + col) * 2);
                b[2 * np][0] = r0; b[2 * np][1] = r1;
                b[2 * np + 1][0] = r2; b[2 * np + 1][1] = r3;
            }
#pragma unroll
            for (int mt = 0; mt < 2; mt++)
#pragma unroll
                for (int nt = 0; nt < 8; nt++)
                    mma16816(acc[mt][nt], a[mt], b[nt]);
        }

        int nt2 = t + NSTAGE - 1;
        if (nt2 < ntiles) issue(nt2, nt2 & (NSTAGE - 1));
        cp_commit();
    }
}

template<bool ACC>
__device__ __forceinline__ void epilogue_store(float* __restrict__ C, int ldc,
                                               float acc[2][8][4])
{
    const int tid = threadIdx.x;
    const int lane = tid & 31;
    const int wid = tid >> 5;
    const int warp_m = wid & 3;
    const int warp_n = wid >> 2;
    const int r0c = lane >> 2;
    const int cc  = (lane & 3) * 2;
#pragma unroll
    for (int mt = 0; mt < 2; mt++) {
        int rbase = warp_m * 32 + mt * 16 + r0c;
#pragma unroll
        for (int nt = 0; nt < 8; nt++) {
            int col = warp_n * 64 + nt * 8 + cc;
            size_t i00 = (size_t)rbase * ldc + col;
            size_t i10 = (size_t)(rbase + 8) * ldc + col;
            if (ACC) {
                C[i00]     += acc[mt][nt][0]; C[i00 + 1] += acc[mt][nt][1];
                C[i10]     += acc[mt][nt][2]; C[i10 + 1] += acc[mt][nt][3];
            } else {
                C[i00]     = acc[mt][nt][0]; C[i00 + 1] = acc[mt][nt][1];
                C[i10]     = acc[mt][nt][2]; C[i10 + 1] = acc[mt][nt][3];
            }
        }
    }
}

// SiLU(gate)*up epilogue over interleaved (gate,up) column pairs.
// O pre-offset to tile origin; ldo in bf16 elems; writes one bf16 per col pair.
__device__ __forceinline__ void epilogue_act(__nv_bfloat16* __restrict__ O, int ldo,
                                             float acc[2][8][4])
{
    const int tid = threadIdx.x;
    const int lane = tid & 31;
    const int wid = tid >> 5;
    const int warp_m = wid & 3;
    const int warp_n = wid >> 2;
    const int r0c = lane >> 2;
    const int cp0 = lane & 3;
#pragma unroll
    for (int mt = 0; mt < 2; mt++) {
        int rbase = warp_m * 32 + mt * 16 + r0c;
#pragma unroll
        for (int nt = 0; nt < 8; nt++) {
            int cp = warp_n * 32 + nt * 4 + cp0;
            float g0 = acc[mt][nt][0], u0 = acc[mt][nt][1];
            float g1 = acc[mt][nt][2], u1 = acc[mt][nt][3];
            float s0 = 1.f / (1.f + expf(-g0));
            float s1 = 1.f / (1.f + expf(-g1));
            O[(size_t)rbase * ldo + cp]       = __float2bfloat16(g0 * s0 * u0);
            O[(size_t)(rbase + 8) * ldo + cp] = __float2bfloat16(g1 * s1 * u1);
        }
    }
}

template<bool ACC>
__global__ void __launch_bounds__(256, 2) bf16_gemm_kernel(
    const __nv_bfloat16* __restrict__ A, const __nv_bfloat16* __restrict__ B,
    float* __restrict__ C, int K, int lda, int ldb, int ldc)
{
    A += (size_t)blockIdx.y * 128 * lda;
    B += (size_t)blockIdx.x * 128 * ldb;
    C += (size_t)blockIdx.y * 128 * ldc + blockIdx.x * 128;
    float acc[2][8][4];
    gemm128_mainloop(A, B, K, lda, ldb, acc);
    epilogue_store<ACC>(C, ldc, acc);
}

// shared-expert gate|up GEMM with fused SiLU*up epilogue (interleaved weights)
__global__ void __launch_bounds__(256, 2) gemm_act_kernel(
    const __nv_bfloat16* __restrict__ A, const __nv_bfloat16* __restrict__ B,
    __nv_bfloat16* __restrict__ O, int K)
{
    A += (size_t)blockIdx.y * 128 * K;
    B += (size_t)blockIdx.x * 128 * K;
    O += (size_t)blockIdx.y * 128 * SFI + blockIdx.x * 64;
    float acc[2][8][4];
    gemm128_mainloop(A, B, K, K, K, acc);
    epilogue_act(O, SFI, acc);
}

// MoE gate|up GEMM with fused SiLU*up epilogue
__global__ void __launch_bounds__(256, 2) moe_gemm_act_kernel(
    const __nv_bfloat16* __restrict__ A, const __nv_bfloat16* __restrict__ B,
    __nv_bfloat16* __restrict__ O, const int* __restrict__ cnt)
{
    const int e = blockIdx.y >> 4;
    const int rb = blockIdx.y & 15;
    if (rb * 128 >= cnt[e]) return;
    A += ((size_t)e * SEQ + rb * 128) * DIM;
    B += (size_t)e * (2 * FFI) * DIM + (size_t)blockIdx.x * 128 * DIM;
    O += ((size_t)e * SEQ + rb * 128) * FFI + blockIdx.x * 64;
    float acc[2][8][4];
    gemm128_mainloop(A, B, DIM, DIM, DIM, acc);
    epilogue_act(O, FFI, acc);
}

// MoE down GEMM
__global__ void __launch_bounds__(256, 2) moe_gemm_kernel(
    const __nv_bfloat16* __restrict__ A, const __nv_bfloat16* __restrict__ B,
    float* __restrict__ C, const int* __restrict__ cnt, int K, int N)
{
    const int e = blockIdx.y >> 4;
    const int rb = blockIdx.y & 15;
    if (rb * 128 >= cnt[e]) return;
    A += ((size_t)e * SEQ + rb * 128) * K;
    B += (size_t)e * N * K + (size_t)blockIdx.x * 128 * K;
    C += ((size_t)e * SEQ + rb * 128) * N + blockIdx.x * 128;
    float acc[2][8][4];
    gemm128_mainloop(A, B, K, K, K, acc);
    epilogue_store<false>(C, N, acc);
}

// lm_head GEMM with fused loss epilogue
__global__ void __launch_bounds__(256, 2) lmhead_gemm_loss(
    const __nv_bfloat16* __restrict__ A, const __nv_bfloat16* __restrict__ B,
    float2* __restrict__ part, int K)
{
    const int bx = blockIdx.x;
    A += (size_t)blockIdx.y * 128 * K;
    B += (size_t)bx * 128 * K;
    float acc[2][8][4];
    gemm128_mainloop(A, B, K, K, K, acc);

    const int tid = threadIdx.x;
    const int lane = tid & 31;
    const int wid = tid >> 5;
    const int warp_m = wid & 3;
    const int warp_n = wid >> 2;

    __shared__ float sm_m[2][128], sm_s[2][128];

#pragma unroll
    for (int mt = 0; mt < 2; mt++) {
#pragma unroll
        for (int half = 0; half < 2; half++) {
            float m = -1e30f;
#pragma unroll
            for (int nt = 0; nt < 8; nt++)
                m = fmaxf(m, fmaxf(acc[mt][nt][2 * half], acc[mt][nt][2 * half + 1]));
            m = fmaxf(m, __shfl_xor_sync(0xffffffffu, m, 1));
            m = fmaxf(m, __shfl_xor_sync(0xffffffffu, m, 2));
            float s = 0.f;
#pragma unroll
            for (int nt = 0; nt < 8; nt++)
                s += expf(acc[mt][nt][2 * half] - m) + expf(acc[mt][nt][2 * half + 1] - m);
            s += __shfl_xor_sync(0xffffffffu, s, 1);
            s += __shfl_xor_sync(0xffffffffu, s, 2);
            if ((lane & 3) == 0) {
                int row_local = warp_m * 32 + mt * 16 + half * 8 + (lane >> 2);
                sm_m[warp_n][row_local] = m;
                sm_s[warp_n][row_local] = s;
            }
        }
    }
    __syncthreads();

    if (tid < 128) {
        float m1 = sm_m[0][tid], s1 = sm_s[0][tid];
        float m2 = sm_m[1][tid], s2 = sm_s[1][tid];
        float nm = fmaxf(m1, m2);
        float ns = s1 * expf(m1 - nm) + s2 * expf(m2 - nm);
        int row = blockIdx.y * 128 + tid;
        part[(size_t)row * NCB + bx] = make_float2(nm, ns);
    }
}

__global__ void loss_reduce(const float2* __restrict__ part,
                            const __nv_bfloat16* __restrict__ xb,
                            const __nv_bfloat16* __restrict__ wb,
                            const int* __restrict__ tgt, float* __restrict__ out)
{
    int row = blockIdx.x;
    int tid = threadIdx.x;

    float m = -1e30f, s = 0.f;
    for (int j = tid; j < NCB; j += 256) {
        float2 p = part[(size_t)row * NCB + j];
        float nm = fmaxf(m, p.x);
        s = s * expf(m - nm) + p.y * expf(p.x - nm);
        m = nm;
    }

    __shared__ float ms[256], ss[256], ds[256];
    ms[tid] = m; ss[tid] = s;
    __syncthreads();
    for (int st = 128; st > 0; st >>= 1) {
        if (tid < st) {
            float m1 = ms[tid], m2 = ms[tid + st];
            float nm = fmaxf(m1, m2);
            ss[tid] = ss[tid] * expf(m1 - nm) + ss[tid + st] * expf(m2 - nm);
            ms[tid] = nm;
        }
        __syncthreads();
    }

    int lab = tgt[row];
    int slab = (lab == -100) ? 0 : lab;
    const __nv_bfloat16* xr = xb + (size_t)row * DIM;
    const __nv_bfloat16* wr = wb + (size_t)slab * DIM;
    float d = 0.f;
    for (int i = tid; i < DIM; i += 256)
        d += __bfloat162float(xr[i]) * __bfloat162float(wr[i]);
    ds[tid] = d;
    __syncthreads();
    for (int st = 128; st > 0; st >>= 1) {
        if (tid < st) ds[tid] += ds[tid + st];
        __syncthreads();
    }

    if (tid == 0 && lab != -100) {
        float lse = ms[0] + logf(ss[0]);
        atomicAdd(out, lse - ds[0]);
    }
}

// ---------------- weight conversion (grid-stride, full occupancy) ----------------
__global__ void convert_w(const float* __restrict__ w, __nv_bfloat16* __restrict__ wb,
                          size_t n4)
{
    const float4* w4 = (const float4*)w;
    uint2* o2 = (uint2*)wb;
    size_t stride = (size_t)gridDim.x * 256;
    for (size_t i = (size_t)blockIdx.x * 256 + threadIdx.x; i < n4; i += stride * 4) {
        float4 v[4];
        bool ok[4];
#pragma unroll
        for (int k = 0; k < 4; k++) {
            size_t j = i + (size_t)k * stride;
            ok[k] = j < n4;
            if (ok[k]) v[k] = w4[j];
        }
#pragma unroll
        for (int k = 0; k < 4; k++) if (ok[k]) {
            uint2 pk;
            pk.x = cvt_bf16x2(v[k].x, v[k].y);
            pk.y = cvt_bf16x2(v[k].z, v[k].w);
            o2[i + (size_t)k * stride] = pk;
        }
    }
}

// a,b: [E][R][DIM] fp32; wb: [E][2R][DIM] bf16, row 2i=a_i, 2i+1=b_i.
// log2r2 = log2(2*R). n4 = total float4s of output.
__global__ void convert_pair(const float* __restrict__ a, const float* __restrict__ b,
                             __nv_bfloat16* __restrict__ wb, size_t n4, int log2r2)
{
    uint2* o2 = (uint2*)wb;
    size_t stride = (size_t)gridDim.x * 256;
    for (size_t i = (size_t)blockIdx.x * 256 + threadIdx.x; i < n4; i += stride * 4) {
        float4 v[4];
        bool ok[4];
#pragma unroll
        for (int k = 0; k < 4; k++) {
            size_t j = i + (size_t)k * stride;
            ok[k] = j < n4;
            if (ok[k]) {
                int k4 = (int)(j & 255);
                size_t n = j >> 8;
                size_t e = n >> log2r2;
                int r = (int)(n & ((1u << log2r2) - 1));
                const float* src = ((r & 1) ? b : a)
                    + ((e << (log2r2 - 1)) + (r >> 1)) * (size_t)DIM + k4 * 4;
                v[k] = *(const float4*)src;
            }
        }
#pragma unroll
        for (int k = 0; k < 4; k++) if (ok[k]) {
            uint2 pk;
            pk.x = cvt_bf16x2(v[k].x, v[k].y);
            pk.y = cvt_bf16x2(v[k].z, v[k].w);
            o2[i + (size_t)k * stride] = pk;
        }
    }
}

// ---------------- fused flash attention ----------------
__global__ void __launch_bounds__(256, 1) flash_attn_kernel(
    const float* __restrict__ q, const float* __restrict__ k,
    const float* __restrict__ v, __nv_bfloat16* __restrict__ ob, int ldq)
{
    const int qb = blockIdx.x;
    const int head = blockIdx.y;
    const int q0 = qb * 128;
    const int hoff = head * DH;

    __shared__ __align__(16) __nv_bfloat16 bufA[128 * 72];
    __shared__ __align__(16) __nv_bfloat16 Ks[128 * 72];

    const int tid = threadIdx.x;
    const int lane = tid & 31;
    const int wid = tid >> 5;
    const int g = lane >> 3, lr = lane & 7;
    const int r0 = wid * 16;

    const uint32_t bufA_base = (uint32_t)__cvta_generic_to_shared(bufA);
    const uint32_t Ks_base = (uint32_t)__cvta_generic_to_shared(Ks);

#pragma unroll
    for (int i = 0; i < 8; i++) {
        int id = i * 256 + tid;
        int r = id >> 4;
        int c = (id & 15) << 2;
        float4 val = *(const float4*)(q + (size_t)(q0 + r) * ldq + hoff + c);
        uint2 pk;
        pk.x = cvt_bf16x2(val.x * QSCALE, val.y * QSCALE);
        pk.y = cvt_bf16x2(val.z * QSCALE, val.w * QSCALE);
        *(uint2*)&bufA[r * 72 + c] = pk;
    }
    __syncthreads();

    uint32_t qa[4][4];
#pragma unroll
    for (int kt = 0; kt < 4; kt++) {
        int row = r0 + (g & 1) * 8 + lr;
        int col = kt * 16 + (g >> 1) * 8;
        ldsm4(qa[kt][0], qa[kt][1], qa[kt][2], qa[kt][3],
              bufA_base + (uint32_t)(row * 72 + col) * 2);
    }
    __syncthreads();

    float acc_o[8][4];
#pragma unroll
    for (int nt = 0; nt < 8; nt++)
#pragma unroll
        for (int i = 0; i < 4; i++) acc_o[nt][i] = 0.f;

    float mA = -1e30f, mB = -1e30f, lA = 0.f, lB = 0.f;
    const int rA = q0 + r0 + (lane >> 2);
    const int rB = rA + 8;

    for (int kb = 0; kb <= qb; kb++) {
        const int kk0 = kb * 128;
#pragma unroll
        for (int i = 0; i < 8; i++) {
            int id = i * 256 + tid;
            int r = id >> 4;
            int c = (id & 15) << 2;
            float4 val = *(const float4*)(k + (size_t)(kk0 + r) * ldq + hoff + c);
            uint2 pk;
            pk.x = cvt_bf16x2(val.x, val.y);
            pk.y = cvt_bf16x2(val.z, val.w);
            *(uint2*)&Ks[r * 72 + c] = pk;
        }
#pragma unroll
        for (int i = 0; i < 8; i++) {
            int id = i * 256 + tid;
            int r = id >> 4;
            int c = (id & 15) << 2;
            float4 val = *(const float4*)(v + (size_t)(kk0 + r) * ldq + hoff + c);
            bufA[(c + 0) * 136 + r] = __float2bfloat16(val.x);
            bufA[(c + 1) * 136 + r] = __float2bfloat16(val.y);
            bufA[(c + 2) * 136 + r] = __float2bfloat16(val.z);
            bufA[(c + 3) * 136 + r] = __float2bfloat16(val.w);
        }
        __syncthreads();

        float sacc[16][4];
#pragma unroll
        for (int nt = 0; nt < 16; nt++)
#pragma unroll
            for (int i = 0; i < 4; i++) sacc[nt][i] = 0.f;

#pragma unroll
        for (int kt = 0; kt < 4; kt++) {
#pragma unroll
            for (int np = 0; np < 8; np++) {
                int row = np * 16 + (g >> 1) * 8 + lr;
                int col = kt * 16 + (g & 1) * 8;
                uint32_t b0, b1, b2, b3;
                ldsm4(b0, b1, b2, b3, Ks_base + (uint32_t)(row * 72 + col) * 2);
                uint32_t bb0[2] = {b0, b1}, bb1[2] = {b2, b3};
                mma16816(sacc[2 * np],     qa[kt], bb0);
                mma16816(sacc[2 * np + 1], qa[kt], bb1);
            }
        }

        if (kb == qb) {
#pragma unroll
            for (int nt = 0; nt < 16; nt++) {
                int cb = kk0 + nt * 8 + 2 * (lane & 3);
                if (cb     > rA) sacc[nt][0] = -1e30f;
                if (cb + 1 > rA) sacc[nt][1] = -1e30f;
                if (cb     > rB) sacc[nt][2] = -1e30f;
                if (cb + 1 > rB) sacc[nt][3] = -1e30f;
            }
        }

        float cmA = -1e30f, cmB = -1e30f;
#pragma unroll
        for (int nt = 0; nt < 16; nt++) {
            cmA = fmaxf(cmA, fmaxf(sacc[nt][0], sacc[nt][1]));
            cmB = fmaxf(cmB, fmaxf(sacc[nt][2], sacc[nt][3]));
        }
        cmA = fmaxf(cmA, __shfl_xor_sync(0xffffffffu, cmA, 1));
        cmA = fmaxf(cmA, __shfl_xor_sync(0xffffffffu, cmA, 2));
        cmB = fmaxf(cmB, __shfl_xor_sync(0xffffffffu, cmB, 1));
        cmB = fmaxf(cmB, __shfl_xor_sync(0xffffffffu, cmB, 2));

        float nmA = fmaxf(mA, cmA), nmB = fmaxf(mB, cmB);
        float scA = exp2f(mA - nmA), scB = exp2f(mB - nmB);
        mA = nmA; mB = nmB;

        uint32_t pA[16], pB[16];
        float sA = 0.f, sB = 0.f;
#pragma unroll
        for (int nt = 0; nt < 16; nt++) {
            float p0 = exp2f(sacc[nt][0] - mA);
            float p1 = exp2f(sacc[nt][1] - mA);
            float p2 = exp2f(sacc[nt][2] - mB);
            float p3 = exp2f(sacc[nt][3] - mB);
            sA += p0 + p1; sB += p2 + p3;
            pA[nt] = cvt_bf16x2(p0, p1);
            pB[nt] = cvt_bf16x2(p2, p3);
        }
        lA = lA * scA + sA;
        lB = lB * scB + sB;
#pragma unroll
        for (int nt = 0; nt < 8; nt++) {
            acc_o[nt][0] *= scA; acc_o[nt][1] *= scA;
            acc_o[nt][2] *= scB; acc_o[nt][3] *= scB;
        }

#pragma unroll
        for (int kt2 = 0; kt2 < 8; kt2++) {
            uint32_t a[4] = { pA[2 * kt2], pB[2 * kt2], pA[2 * kt2 + 1], pB[2 * kt2 + 1] };
#pragma unroll
            for (int np2 = 0; np2 < 4; np2++) {
                int row = np2 * 16 + (g >> 1) * 8 + lr;
                int col = kt2 * 16 + (g & 1) * 8;
                uint32_t b0, b1, b2, b3;
                ldsm4(b0, b1, b2, b3, bufA_base + (uint32_t)(row * 136 + col) * 2);
                uint32_t bb0[2] = {b0, b1}, bb1[2] = {b2, b3};
                mma16816(acc_o[2 * np2],     a, bb0);
                mma16816(acc_o[2 * np2 + 1], a, bb1);
            }
        }
        __syncthreads();
    }

    lA += __shfl_xor_sync(0xffffffffu, lA, 1);
    lA += __shfl_xor_sync(0xffffffffu, lA, 2);
    lB += __shfl_xor_sync(0xffffffffu, lB, 1);
    lB += __shfl_xor_sync(0xffffffffu, lB, 2);
    float iA = 1.f / lA, iB = 1.f / lB;

#pragma unroll
    for (int nt = 0; nt < 8; nt++) {
        int col = hoff + nt * 8 + 2 * (lane & 3);
        uint32_t p0 = cvt_bf16x2(acc_o[nt][0] * iA, acc_o[nt][1] * iA);
        uint32_t p1 = cvt_bf16x2(acc_o[nt][2] * iB, acc_o[nt][3] * iB);
        *(uint32_t*)(ob + (size_t)rA * DIM + col) = p0;
        *(uint32_t*)(ob + (size_t)rB * DIM + col) = p1;
    }
}

// ---------------- small kernels ----------------
__global__ void embed_gather(const int* __restrict__ tok, const float* __restrict__ emb,
                             float* __restrict__ h)
{
    int s = blockIdx.x;
    int t = tok[s];
    const float* e = emb + (size_t)t * DIM;
    for (int d = threadIdx.x; d < DIM; d += blockDim.x)
        h[(size_t)s * DIM + d] = e[d];
}

__global__ void rmsnorm_kernel(const float* __restrict__ x, const float* __restrict__ w,
                               __nv_bfloat16* __restrict__ o)
{
    int row = blockIdx.x;
    const float* xr = x + (size_t)row * DIM;
    __shared__ float red[256];
    int tid = threadIdx.x;
    float s = 0.f;
    for (int d = tid; d < DIM; d += 256) { float v = xr[d]; s += v * v; }
    red[tid] = s; __syncthreads();
    for (int st = 128; st > 0; st >>= 1) {
        if (tid < st) red[tid] += red[tid + st];
        __syncthreads();
    }
    float rs = rsqrtf(red[0] / (float)DIM + 1e-6f);
    for (int d = tid; d < DIM; d += 256)
        o[(size_t)row * DIM + d] = __float2bfloat16(xr[d] * rs * w[d]);
}

__global__ void rope_kernel(float* __restrict__ qkv)
{
    int s = blockIdx.x;
    int tid = threadIdx.x;
    int h = tid >> 5, i = tid & 31;
    float freq = powf(10000.f, -(float)(2 * i) / 64.f);
    float ang = (float)s * freq;
    float sn, cs;
    sincosf(ang, &sn, &cs);
    size_t base = (size_t)s * (3 * DIM) + h * DH + i;
    float q1 = qkv[base], q2 = qkv[base + 32];
    qkv[base]      = q1 * cs - q2 * sn;
    qkv[base + 32] = q2 * cs + q1 * sn;
    size_t kb = base + DIM;
    float k1 = qkv[kb], k2 = qkv[kb + 32];
    qkv[kb]      = k1 * cs - k2 * sn;
    qkv[kb + 32] = k2 * cs + k1 * sn;
}

__global__ void gate_topk(const __nv_bfloat16* __restrict__ x, const float* __restrict__ gw,
                          int2* __restrict__ topi, float2* __restrict__ topw)
{
    int t = blockIdx.x;
    int tid = threadIdx.x;
    int e = tid >> 5, lane = tid & 31;
    const __nv_bfloat16* xr = x + (size_t)t * DIM;
    const float* wr = gw + (size_t)e * DIM;
    float s = 0.f;
    for (int d = lane; d < DIM; d += 32) s += __bfloat162float(xr[d]) * wr[d];
    for (int o = 16; o; o >>= 1) s += __shfl_down_sync(0xffffffffu, s, o);
    __shared__ float lg[NEXP];
    if (lane == 0) lg[e] = s;
    __syncthreads();
    if (tid == 0) {
        float m = -1e30f;
        for (int i = 0; i < NEXP; i++) m = fmaxf(m, lg[i]);
        float p[NEXP]; float sum = 0.f;
        for (int i = 0; i < NEXP; i++) { p[i] = expf(lg[i] - m); sum += p[i]; }
        float inv = 1.f / sum;
        for (int i = 0; i < NEXP; i++) p[i] *= inv;
        int i0 = 0;
        for (int i = 1; i < NEXP; i++) if (p[i] > p[i0]) i0 = i;
        int i1 = -1;
        for (int i = 0; i < NEXP; i++) {
            if (i == i0) continue;
            if (i1 < 0 || p[i] > p[i1]) i1 = i;
        }
        topi[t] = make_int2(i0, i1);
        topw[t] = make_float2(p[i0], p[i1]);
    }
}

__global__ void zero_counts(int* cnt)
{
    if (threadIdx.x < NEXP) cnt[threadIdx.x] = 0;
}

__global__ void gather_rows(const __nv_bfloat16* __restrict__ xb, __nv_bfloat16* __restrict__ xg,
                            const int2* __restrict__ topi, int2* __restrict__ pos,
                            int* __restrict__ cnt)
{
    int t = blockIdx.x;
    __shared__ int sp[2];
    int2 ti = topi[t];
    if (threadIdx.x == 0) {
        sp[0] = atomicAdd(&cnt[ti.x], 1);
        sp[1] = atomicAdd(&cnt[ti.y], 1);
    }
    __syncthreads();
    const uint32_t* src = (const uint32_t*)(xb + (size_t)t * DIM);
    uint32_t* d0 = (uint32_t*)(xg + ((size_t)ti.x * SEQ + sp[0]) * DIM);
    uint32_t* d1 = (uint32_t*)(xg + ((size_t)ti.y * SEQ + sp[1]) * DIM);
    for (int i = threadIdx.x; i < DIM / 2; i += 256) {
        uint32_t v = src[i];
        d0[i] = v; d1[i] = v;
    }
    if (threadIdx.x == 0) pos[t] = make_int2(sp[0], sp[1]);
}

__global__ void scatter_add(float* __restrict__ h, const float* __restrict__ yg,
                            const int2* __restrict__ topi, const int2* __restrict__ pos,
                            const float2* __restrict__ topw)
{
    int t = blockIdx.x;
    int2 ti = topi[t];
    int2 ps = pos[t];
    float2 w = topw[t];
    const float* y0 = yg + ((size_t)ti.x * SEQ + ps.x) * DIM;
    const float* y1 = yg + ((size_t)ti.y * SEQ + ps.y) * DIM;
    float* hr = h + (size_t)t * DIM;
    for (int d = threadIdx.x; d < DIM; d += 256)
        hr[d] += w.x * y0[d] + w.y * y1[d];
}

__global__ void zero_scalar(float* p)
{
    if (threadIdx.x == 0 && blockIdx.x == 0) p[0] = 0.f;
}

// ---------------- host ----------------
static void gemm(const __nv_bfloat16* A, const __nv_bfloat16* B, float* C,
                 int M, int N, int K, int lda, int ldb, int ldc)
{
    bf16_gemm_kernel<false><<<dim3(N / 128, M / 128), 256, GEMM_SMEM>>>(A, B, C, K, lda, ldb, ldc);
}
static void gemm_acc(const __nv_bfloat16* A, const __nv_bfloat16* B, float* C,
                     int M, int N, int K, int lda, int ldb, int ldc)
{
    bf16_gemm_kernel<true><<<dim3(N / 128, M / 128), 256, GEMM_SMEM>>>(A, B, C, K, lda, ldb, ldc);
}
static void conv_w(const float* w, __nv_bfloat16* wb, size_t nelem)
{
    convert_w<<<CONV_GRID, 256>>>(w, wb, nelem / 4);
}

extern "C" void kernel_launch(void* const* d_in, const int* in_sizes, int n_in,
                              void* d_out, int out_size)
{
    (void)in_sizes; (void)n_in; (void)out_size;
    const int*   src       = (const int*)d_in[0];
    const int*   tgt       = (const int*)d_in[1];
    const float* embed     = (const float*)d_in[2];
    const float* Wq        = (const float*)d_in[3];
    const float* Wk        = (const float*)d_in[4];
    const float* Wv        = (const float*)d_in[5];
    const float* Wo        = (const float*)d_in[6];
    const float* ln1       = (const float*)d_in[7];
    const float* ln2       = (const float*)d_in[8];
    const float* gate_w    = (const float*)d_in[9];
    const float* gate_proj = (const float*)d_in[10];
    const float* up_proj   = (const float*)d_in[11];
    const float* down_proj = (const float*)d_in[12];
    const float* sg        = (const float*)d_in[13];
    const float* su        = (const float*)d_in[14];
    const float* sd        = (const float*)d_in[15];
    const float* final_ln  = (const float*)d_in[16];
    const float* lm_head   = (const float*)d_in[17];
    float* out = (float*)d_out;

    cudaFuncSetAttribute(bf16_gemm_kernel<false>, cudaFuncAttributeMaxDynamicSharedMemorySize, GEMM_SMEM);
    cudaFuncSetAttribute(bf16_gemm_kernel<true>,  cudaFuncAttributeMaxDynamicSharedMemorySize, GEMM_SMEM);
    cudaFuncSetAttribute(moe_gemm_kernel,         cudaFuncAttributeMaxDynamicSharedMemorySize, GEMM_SMEM);
    cudaFuncSetAttribute(moe_gemm_act_kernel,     cudaFuncAttributeMaxDynamicSharedMemorySize, GEMM_SMEM);
    cudaFuncSetAttribute(gemm_act_kernel,         cudaFuncAttributeMaxDynamicSharedMemorySize, GEMM_SMEM);
    cudaFuncSetAttribute(lmhead_gemm_loss,        cudaFuncAttributeMaxDynamicSharedMemorySize, GEMM_SMEM);

    float *h, *qkv, *yg;
    __nv_bfloat16 *xb, *ob, *actb, *xg, *gsb, *wb;
    float2 *partb;
    int *cnt; int2 *topi, *pos; float2 *topw;
    cudaGetSymbolAddress((void**)&h,    g_h);
    cudaGetSymbolAddress((void**)&xb,   g_xb);
    cudaGetSymbolAddress((void**)&qkv,  g_qkv);
    cudaGetSymbolAddress((void**)&ob,   g_ob);
    cudaGetSymbolAddress((void**)&yg,   g_yg);
    cudaGetSymbolAddress((void**)&actb, g_actb);
    cudaGetSymbolAddress((void**)&xg,   g_xg);
    cudaGetSymbolAddress((void**)&gsb,  g_gsb);
    cudaGetSymbolAddress((void**)&wb,   g_wb);
    cudaGetSymbolAddress((void**)&partb, g_part);
    cudaGetSymbolAddress((void**)&cnt,  g_cnt);
    cudaGetSymbolAddress((void**)&topi, g_topi);
    cudaGetSymbolAddress((void**)&pos,  g_pos);
    cudaGetSymbolAddress((void**)&topw, g_topw);

    embed_gather<<<SEQ, 256>>>(src, embed, h);

    const size_t DD = (size_t)DIM * DIM;
    for (int l = 0; l < NLAYER; l++) {
        // ---- attention ----
        rmsnorm_kernel<<<SEQ, 256>>>(h, ln1 + (size_t)l * DIM, xb);
        conv_w(Wq + l * DD, wb,          DD);
        conv_w(Wk + l * DD, wb + DD,     DD);
        conv_w(Wv + l * DD, wb + 2 * DD, DD);
        gemm(xb, wb, qkv, SEQ, 3 * DIM, DIM, DIM, DIM, 3 * DIM);
        rope_kernel<<<SEQ, NHEAD * 32>>>(qkv);

        flash_attn_kernel<<<dim3(SEQ / 128, NHEAD), 256>>>(qkv, qkv + DIM, qkv + 2 * DIM, ob, 3 * DIM);

        conv_w(Wo + l * DD, wb, DD);
        gemm_acc(ob, wb, h, SEQ, DIM, DIM, DIM, DIM, DIM);

        // ---- MoE (sparse top-2, fused act) ----
        rmsnorm_kernel<<<SEQ, 256>>>(h, ln2 + (size_t)l * DIM, xb);
        gate_topk<<<SEQ, 256>>>(xb, gate_w + (size_t)l * NEXP * DIM, topi, topw);
        zero_counts<<<1, 32>>>(cnt);
        gather_rows<<<SEQ, 256>>>(xb, xg, topi, pos, cnt);

        const size_t EID = (size_t)NEXP * FFI * DIM;
        convert_pair<<<CONV_GRID, 256>>>(gate_proj + l * EID, up_proj + l * EID, wb,
                                         2 * EID / 4, 10);     // R=FFI=512
        moe_gemm_act_kernel<<<dim3((2 * FFI) / 128, NEXP * 16), 256, GEMM_SMEM>>>(
            xg, wb, actb, cnt);
        conv_w(down_proj + l * EID, wb, EID);
        moe_gemm_kernel<<<dim3(DIM / 128, NEXP * 16), 256, GEMM_SMEM>>>(
            actb, wb, yg, cnt, FFI, DIM);
        scatter_add<<<SEQ, 256>>>(h, yg, topi, pos, topw);

        // ---- shared expert (fused act) ----
        const size_t SD = (size_t)SFI * DIM;
        convert_pair<<<CONV_GRID, 256>>>(sg + l * SD, su + l * SD, wb,
                                         2 * SD / 4, 11);      // R=SFI=1024
        gemm_act_kernel<<<dim3((2 * SFI) / 128, SEQ / 128), 256, GEMM_SMEM>>>(xb, wb, gsb, DIM);
        conv_w(sd + l * SD, wb, SD);
        gemm_acc(gsb, wb, h, SEQ, DIM, SFI, SFI, SFI, DIM);
    }

    // ---- head + fused loss ----
    rmsnorm_kernel<<<SEQ, 256>>>(h, final_ln, xb);
    conv_w(lm_head, wb, (size_t)VOCAB * DIM);
    lmhead_gemm_loss<<<dim3(NCB, SEQ / 128), 256, GEMM_SMEM>>>(xb, wb, partb, DIM);
    zero_scalar<<<1, 32>>>(out);
    loss_reduce<<<SEQ, 256>>>(partb, xb, wb, tgt, out);
}

// round 12
// speedup vs baseline: 23.9515x; 1.0404x over previous
#include <cuda_runtime.h>
#include <cuda_bf16.h>
#include <math.h>
#include <stdint.h>

// Model dims
#define SEQ    2048
#define DIM    1024
#define NHEAD  16
#define DH     64
#define NLAYER 2
#define NEXP   8
#define FFI    512
#define SFI    1024
#define VOCAB  32000
#define NCB    (VOCAB / 128)        // 250 column blocks in lm_head

#define BK 32
#define NSTAGE 4
#define BSTRIDE 40
#define STAGE_BYTES (128 * BSTRIDE * 2)
#define GEMM_SMEM (2 * NSTAGE * STAGE_BYTES)   // 81920

#define CONV_GRID 1184              // 8 CTAs/SM * 148 SMs

#define QSCALE 0.1803368801111137f  // 0.125 * log2(e)

// layer weight scratch layout (bf16 elems); DD = 1M elems
#define WDD   ((size_t)DIM * DIM)
#define O_QKV 0
#define O_WO  (3 * WDD)
#define O_GU  (4 * WDD)                         // NEXP*2*FFI*DIM = 8M
#define O_DN  (O_GU + (size_t)NEXP * 2 * FFI * DIM)
#define O_SH  (O_DN + (size_t)NEXP * FFI * DIM)  // +4M
#define O_SD  (O_SH + (size_t)2 * SFI * DIM)     // +2M
#define WL_TOTAL (O_SD + (size_t)SFI * DIM)      // 19M elems

// ---------------- static scratch ----------------
__device__ float g_h[SEQ * DIM];
__device__ __nv_bfloat16 g_xb[SEQ * DIM];
__device__ float g_qkv[SEQ * 3 * DIM];
__device__ __nv_bfloat16 g_ob[SEQ * DIM];
__device__ float g_yg[(size_t)NEXP * SEQ * DIM];
__device__ __nv_bfloat16 g_actb[(size_t)NEXP * SEQ * FFI];
__device__ __nv_bfloat16 g_xg[(size_t)NEXP * SEQ * DIM];
__device__ __nv_bfloat16 g_gsb[SEQ * SFI];
__device__ __nv_bfloat16 g_wl0[WL_TOTAL];              // layer 0 weights (bf16)
__device__ __nv_bfloat16 g_wl1[WL_TOTAL];              // layer 1 weights (bf16)
__device__ __nv_bfloat16 g_wbL[(size_t)VOCAB * DIM];   // lm_head (bf16)
__device__ float2 g_part[(size_t)SEQ * NCB];
__device__ int   g_cnt[NEXP];
__device__ int2  g_topi[SEQ];
__device__ int2  g_pos[SEQ];
__device__ float2 g_topw[SEQ];

// ---------------- helpers ----------------
__device__ __forceinline__ uint32_t cvt_bf16x2(float lo, float hi) {
    uint32_t r;
    asm("cvt.rn.bf16x2.f32 %0, %1, %2;" : "=r"(r) : "f"(hi), "f"(lo));
    return r;
}
__device__ __forceinline__ void ldsm4(uint32_t &r0, uint32_t &r1, uint32_t &r2, uint32_t &r3,
                                      uint32_t addr) {
    asm volatile("ldmatrix.sync.aligned.m8n8.x4.shared.b16 {%0,%1,%2,%3}, [%4];"
                 : "=r"(r0), "=r"(r1), "=r"(r2), "=r"(r3) : "r"(addr));
}
__device__ __forceinline__ void mma16816(float* c, const uint32_t* a, const uint32_t* b) {
    asm volatile(
        "mma.sync.aligned.m16n8k16.row.col.f32.bf16.bf16.f32 "
        "{%0,%1,%2,%3}, {%4,%5,%6,%7}, {%8,%9}, {%0,%1,%2,%3};"
        : "+f"(c[0]), "+f"(c[1]), "+f"(c[2]), "+f"(c[3])
        : "r"(a[0]), "r"(a[1]), "r"(a[2]), "r"(a[3]), "r"(b[0]), "r"(b[1]));
}
__device__ __forceinline__ void cp_async16(uint32_t dst, const void* src) {
    asm volatile("cp.async.cg.shared.global [%0], [%1], 16;" :: "r"(dst), "l"(src));
}
__device__ __forceinline__ void cp_commit() { asm volatile("cp.async.commit_group;"); }
template<int W> __device__ __forceinline__ void cp_wait() {
    asm volatile("cp.async.wait_group %0;" :: "n"(W));
}

// ---------------- 128x128 GEMM mainloop ----------------
__device__ __forceinline__ void gemm128_mainloop(
    const __nv_bfloat16* __restrict__ A, const __nv_bfloat16* __restrict__ B,
    int K, int lda, int ldb, float acc[2][8][4])
{
    extern __shared__ __align__(16) __nv_bfloat16 smem[];
    const int tid = threadIdx.x;
    const int lane = tid & 31;
    const int wid = tid >> 5;
    const int warp_m = wid & 3;
    const int warp_n = wid >> 2;
    const int g = lane >> 3, lr = lane & 7;

    const uint32_t As_base = (uint32_t)__cvta_generic_to_shared(smem);
    const uint32_t Bs_base = As_base + NSTAGE * STAGE_BYTES;
    const int ntiles = K >> 5;

    auto issue = [&](int t, int s) {
        const __nv_bfloat16* Ag = A + t * BK;
        const __nv_bfloat16* Bg = B + t * BK;
        const uint32_t a_s = As_base + s * STAGE_BYTES;
        const uint32_t b_s = Bs_base + s * STAGE_BYTES;
#pragma unroll
        for (int i = 0; i < 2; i++) {
            int id = i * 256 + tid;
            int r = id >> 2;
            int c = (id & 3) * 8;
            cp_async16(a_s + (r * BSTRIDE + c) * 2, Ag + (size_t)r * lda + c);
            cp_async16(b_s + (r * BSTRIDE + c) * 2, Bg + (size_t)r * ldb + c);
        }
    };

#pragma unroll
    for (int s = 0; s < NSTAGE - 1; s++) {
        if (s < ntiles) issue(s, s);
        cp_commit();
    }

#pragma unroll
    for (int mt = 0; mt < 2; mt++)
#pragma unroll
        for (int nt = 0; nt < 8; nt++)
#pragma unroll
            for (int i = 0; i < 4; i++) acc[mt][nt][i] = 0.f;

    for (int t = 0; t < ntiles; t++) {
        cp_wait<NSTAGE - 2>();
        __syncthreads();

        const int s = t & (NSTAGE - 1);
        const uint32_t a_base = As_base + s * STAGE_BYTES;
        const uint32_t b_base = Bs_base + s * STAGE_BYTES;

#pragma unroll
        for (int ks = 0; ks < 2; ks++) {
            uint32_t a[2][4];
#pragma unroll
            for (int mt = 0; mt < 2; mt++) {
                int row = warp_m * 32 + mt * 16 + (g & 1) * 8 + lr;
                int col = ks * 16 + (g >> 1) * 8;
                ldsm4(a[mt][0], a[mt][1], a[mt][2], a[mt][3],
                      a_base + (uint32_t)(row * BSTRIDE + col) * 2);
            }
            uint32_t b[8][2];
#pragma unroll
            for (int np = 0; np < 4; np++) {
                int row = warp_n * 64 + np * 16 + (g >> 1) * 8 + lr;
                int col = ks * 16 + (g & 1) * 8;
                uint32_t r0, r1, r2, r3;
                ldsm4(r0, r1, r2, r3, b_base + (uint32_t)(row * BSTRIDE + col) * 2);
                b[2 * np][0] = r0; b[2 * np][1] = r1;
                b[2 * np + 1][0] = r2; b[2 * np + 1][1] = r3;
            }
#pragma unroll
            for (int mt = 0; mt < 2; mt++)
#pragma unroll
                for (int nt = 0; nt < 8; nt++)
                    mma16816(acc[mt][nt], a[mt], b[nt]);
        }

        int nt2 = t + NSTAGE - 1;
        if (nt2 < ntiles) issue(nt2, nt2 & (NSTAGE - 1));
        cp_commit();
    }
}

template<bool ACC>
__device__ __forceinline__ void epilogue_store(float* __restrict__ C, int ldc,
                                               float acc[2][8][4])
{
    const int tid = threadIdx.x;
    const int lane = tid & 31;
    const int wid = tid >> 5;
    const int warp_m = wid & 3;
    const int warp_n = wid >> 2;
    const int r0c = lane >> 2;
    const int cc  = (lane & 3) * 2;
#pragma unroll
    for (int mt = 0; mt < 2; mt++) {
        int rbase = warp_m * 32 + mt * 16 + r0c;
#pragma unroll
        for (int nt = 0; nt < 8; nt++) {
            int col = warp_n * 64 + nt * 8 + cc;
            size_t i00 = (size_t)rbase * ldc + col;
            size_t i10 = (size_t)(rbase + 8) * ldc + col;
            if (ACC) {
                C[i00]     += acc[mt][nt][0]; C[i00 + 1] += acc[mt][nt][1];
                C[i10]     += acc[mt][nt][2]; C[i10 + 1] += acc[mt][nt][3];
            } else {
                C[i00]     = acc[mt][nt][0]; C[i00 + 1] = acc[mt][nt][1];
                C[i10]     = acc[mt][nt][2]; C[i10 + 1] = acc[mt][nt][3];
            }
        }
    }
}

__device__ __forceinline__ void epilogue_act(__nv_bfloat16* __restrict__ O, int ldo,
                                             float acc[2][8][4])
{
    const int tid = threadIdx.x;
    const int lane = tid & 31;
    const int wid = tid >> 5;
    const int warp_m = wid & 3;
    const int warp_n = wid >> 2;
    const int r0c = lane >> 2;
    const int cp0 = lane & 3;
#pragma unroll
    for (int mt = 0; mt < 2; mt++) {
        int rbase = warp_m * 32 + mt * 16 + r0c;
#pragma unroll
        for (int nt = 0; nt < 8; nt++) {
            int cp = warp_n * 32 + nt * 4 + cp0;
            float g0 = acc[mt][nt][0], u0 = acc[mt][nt][1];
            float g1 = acc[mt][nt][2], u1 = acc[mt][nt][3];
            float s0 = 1.f / (1.f + expf(-g0));
            float s1 = 1.f / (1.f + expf(-g1));
            O[(size_t)rbase * ldo + cp]       = __float2bfloat16(g0 * s0 * u0);
            O[(size_t)(rbase + 8) * ldo + cp] = __float2bfloat16(g1 * s1 * u1);
        }
    }
}

template<bool ACC>
__global__ void __launch_bounds__(256, 2) bf16_gemm_kernel(
    const __nv_bfloat16* __restrict__ A, const __nv_bfloat16* __restrict__ B,
    float* __restrict__ C, int K, int lda, int ldb, int ldc)
{
    A += (size_t)blockIdx.y * 128 * lda;
    B += (size_t)blockIdx.x * 128 * ldb;
    C += (size_t)blockIdx.y * 128 * ldc + blockIdx.x * 128;
    float acc[2][8][4];
    gemm128_mainloop(A, B, K, lda, ldb, acc);
    epilogue_store<ACC>(C, ldc, acc);
}

__global__ void __launch_bounds__(256, 2) gemm_act_kernel(
    const __nv_bfloat16* __restrict__ A, const __nv_bfloat16* __restrict__ B,
    __nv_bfloat16* __restrict__ O, int K)
{
    A += (size_t)blockIdx.y * 128 * K;
    B += (size_t)blockIdx.x * 128 * K;
    O += (size_t)blockIdx.y * 128 * SFI + blockIdx.x * 64;
    float acc[2][8][4];
    gemm128_mainloop(A, B, K, K, K, acc);
    epilogue_act(O, SFI, acc);
}

__global__ void __launch_bounds__(256, 2) moe_gemm_act_kernel(
    const __nv_bfloat16* __restrict__ A, const __nv_bfloat16* __restrict__ B,
    __nv_bfloat16* __restrict__ O, const int* __restrict__ cnt)
{
    const int e = blockIdx.y >> 4;
    const int rb = blockIdx.y & 15;
    if (rb * 128 >= cnt[e]) return;
    A += ((size_t)e * SEQ + rb * 128) * DIM;
    B += (size_t)e * (2 * FFI) * DIM + (size_t)blockIdx.x * 128 * DIM;
    O += ((size_t)e * SEQ + rb * 128) * FFI + blockIdx.x * 64;
    float acc[2][8][4];
    gemm128_mainloop(A, B, DIM, DIM, DIM, acc);
    epilogue_act(O, FFI, acc);
}

__global__ void __launch_bounds__(256, 2) moe_gemm_kernel(
    const __nv_bfloat16* __restrict__ A, const __nv_bfloat16* __restrict__ B,
    float* __restrict__ C, const int* __restrict__ cnt, int K, int N)
{
    const int e = blockIdx.y >> 4;
    const int rb = blockIdx.y & 15;
    if (rb * 128 >= cnt[e]) return;
    A += ((size_t)e * SEQ + rb * 128) * K;
    B += (size_t)e * N * K + (size_t)blockIdx.x * 128 * K;
    C += ((size_t)e * SEQ + rb * 128) * N + blockIdx.x * 128;
    float acc[2][8][4];
    gemm128_mainloop(A, B, K, K, K, acc);
    epilogue_store<false>(C, N, acc);
}

// lm_head GEMM with fused loss epilogue (mma.sync; tcgen05 unavailable on this toolchain)
__global__ void __launch_bounds__(256, 2) lmhead_gemm_loss(
    const __nv_bfloat16* __restrict__ A, const __nv_bfloat16* __restrict__ B,
    float2* __restrict__ part, int K)
{
    const int bx = blockIdx.x;
    A += (size_t)blockIdx.y * 128 * K;
    B += (size_t)bx * 128 * K;
    float acc[2][8][4];
    gemm128_mainloop(A, B, K, K, K, acc);

    const int tid = threadIdx.x;
    const int lane = tid & 31;
    const int wid = tid >> 5;
    const int warp_m = wid & 3;
    const int warp_n = wid >> 2;

    __shared__ float sm_m[2][128], sm_s[2][128];

#pragma unroll
    for (int mt = 0; mt < 2; mt++) {
#pragma unroll
        for (int half = 0; half < 2; half++) {
            float m = -1e30f;
#pragma unroll
            for (int nt = 0; nt < 8; nt++)
                m = fmaxf(m, fmaxf(acc[mt][nt][2 * half], acc[mt][nt][2 * half + 1]));
            m = fmaxf(m, __shfl_xor_sync(0xffffffffu, m, 1));
            m = fmaxf(m, __shfl_xor_sync(0xffffffffu, m, 2));
            float s = 0.f;
#pragma unroll
            for (int nt = 0; nt < 8; nt++)
                s += expf(acc[mt][nt][2 * half] - m) + expf(acc[mt][nt][2 * half + 1] - m);
            s += __shfl_xor_sync(0xffffffffu, s, 1);
            s += __shfl_xor_sync(0xffffffffu, s, 2);
            if ((lane & 3) == 0) {
                int row_local = warp_m * 32 + mt * 16 + half * 8 + (lane >> 2);
                sm_m[warp_n][row_local] = m;
                sm_s[warp_n][row_local] = s;
            }
        }
    }
    __syncthreads();

    if (tid < 128) {
        float m1 = sm_m[0][tid], s1 = sm_s[0][tid];
        float m2 = sm_m[1][tid], s2 = sm_s[1][tid];
        float nm = fmaxf(m1, m2);
        float ns = s1 * expf(m1 - nm) + s2 * expf(m2 - nm);
        int row = blockIdx.y * 128 + tid;
        part[(size_t)row * NCB + bx] = make_float2(nm, ns);
    }
}

__global__ void loss_reduce(const float2* __restrict__ part,
                            const __nv_bfloat16* __restrict__ xb,
                            const __nv_bfloat16* __restrict__ wb,
                            const int* __restrict__ tgt, float* __restrict__ out)
{
    int row = blockIdx.x;
    int tid = threadIdx.x;

    float m = -1e30f, s = 0.f;
    for (int j = tid; j < NCB; j += 256) {
        float2 p = part[(size_t)row * NCB + j];
        float nm = fmaxf(m, p.x);
        s = s * expf(m - nm) + p.y * expf(p.x - nm);
        m = nm;
    }

    __shared__ float ms[256], ss[256], ds[256];
    ms[tid] = m; ss[tid] = s;
    __syncthreads();
    for (int st = 128; st > 0; st >>= 1) {
        if (tid < st) {
            float m1 = ms[tid], m2 = ms[tid + st];
            float nm = fmaxf(m1, m2);
            ss[tid] = ss[tid] * expf(m1 - nm) + ss[tid + st] * expf(m2 - nm);
            ms[tid] = nm;
        }
        __syncthreads();
    }

    int lab = tgt[row];
    int slab = (lab == -100) ? 0 : lab;
    const __nv_bfloat16* xr = xb + (size_t)row * DIM;
    const __nv_bfloat16* wr = wb + (size_t)slab * DIM;
    float d = 0.f;
    for (int i = tid; i < DIM; i += 256)
        d += __bfloat162float(xr[i]) * __bfloat162float(wr[i]);
    ds[tid] = d;
    __syncthreads();
    for (int st = 128; st > 0; st >>= 1) {
        if (tid < st) ds[tid] += ds[tid + st];
        __syncthreads();
    }

    if (tid == 0 && lab != -100) {
        float lse = ms[0] + logf(ss[0]);
        atomicAdd(out, lse - ds[0]);
    }
}

// ---------------- weight conversion (grid-stride) ----------------
__global__ void convert_w(const float* __restrict__ w, __nv_bfloat16* __restrict__ wb,
                          size_t n4)
{
    const float4* w4 = (const float4*)w;
    uint2* o2 = (uint2*)wb;
    size_t stride = (size_t)gridDim.x * 256;
    for (size_t i = (size_t)blockIdx.x * 256 + threadIdx.x; i < n4; i += stride * 4) {
        float4 v[4];
        bool ok[4];
#pragma unroll
        for (int k = 0; k < 4; k++) {
            size_t j = i + (size_t)k * stride;
            ok[k] = j < n4;
            if (ok[k]) v[k] = w4[j];
        }
#pragma unroll
        for (int k = 0; k < 4; k++) if (ok[k]) {
            uint2 pk;
            pk.x = cvt_bf16x2(v[k].x, v[k].y);
            pk.y = cvt_bf16x2(v[k].z, v[k].w);
            o2[i + (size_t)k * stride] = pk;
        }
    }
}

__global__ void convert_pair(const float* __restrict__ a, const float* __restrict__ b,
                             __nv_bfloat16* __restrict__ wb, size_t n4, int log2r2)
{
    uint2* o2 = (uint2*)wb;
    size_t stride = (size_t)gridDim.x * 256;
    for (size_t i = (size_t)blockIdx.x * 256 + threadIdx.x; i < n4; i += stride * 4) {
        float4 v[4];
        bool ok[4];
#pragma unroll
        for (int k = 0; k < 4; k++) {
            size_t j = i + (size_t)k * stride;
            ok[k] = j < n4;
            if (ok[k]) {
                int k4 = (int)(j & 255);
                size_t n = j >> 8;
                size_t e = n >> log2r2;
                int r = (int)(n & ((1u << log2r2) - 1));
                const float* src = ((r & 1) ? b : a)
                    + ((e << (log2r2 - 1)) + (r >> 1)) * (size_t)DIM + k4 * 4;
                v[k] = *(const float4*)src;
            }
        }
#pragma unroll
        for (int k = 0; k < 4; k++) if (ok[k]) {
            uint2 pk;
            pk.x = cvt_bf16x2(v[k].x, v[k].y);
            pk.y = cvt_bf16x2(v[k].z, v[k].w);
            o2[i + (size_t)k * stride] = pk;
        }
    }
}

// ---------------- fused flash attention ----------------
__global__ void __launch_bounds__(256, 1) flash_attn_kernel(
    const float* __restrict__ q, const float* __restrict__ k,
    const float* __restrict__ v, __nv_bfloat16* __restrict__ ob, int ldq)
{
    const int qb = blockIdx.x;
    const int head = blockIdx.y;
    const int q0 = qb * 128;
    const int hoff = head * DH;

    __shared__ __align__(16) __nv_bfloat16 bufA[128 * 72];
    __shared__ __align__(16) __nv_bfloat16 Ks[128 * 72];

    const int tid = threadIdx.x;
    const int lane = tid & 31;
    const int wid = tid >> 5;
    const int g = lane >> 3, lr = lane & 7;
    const int r0 = wid * 16;

    const uint32_t bufA_base = (uint32_t)__cvta_generic_to_shared(bufA);
    const uint32_t Ks_base = (uint32_t)__cvta_generic_to_shared(Ks);

#pragma unroll
    for (int i = 0; i < 8; i++) {
        int id = i * 256 + tid;
        int r = id >> 4;
        int c = (id & 15) << 2;
        float4 val = *(const float4*)(q + (size_t)(q0 + r) * ldq + hoff + c);
        uint2 pk;
        pk.x = cvt_bf16x2(val.x * QSCALE, val.y * QSCALE);
        pk.y = cvt_bf16x2(val.z * QSCALE, val.w * QSCALE);
        *(uint2*)&bufA[r * 72 + c] = pk;
    }
    __syncthreads();

    uint32_t qa[4][4];
#pragma unroll
    for (int kt = 0; kt < 4; kt++) {
        int row = r0 + (g & 1) * 8 + lr;
        int col = kt * 16 + (g >> 1) * 8;
        ldsm4(qa[kt][0], qa[kt][1], qa[kt][2], qa[kt][3],
              bufA_base + (uint32_t)(row * 72 + col) * 2);
    }
    __syncthreads();

    float acc_o[8][4];
#pragma unroll
    for (int nt = 0; nt < 8; nt++)
#pragma unroll
        for (int i = 0; i < 4; i++) acc_o[nt][i] = 0.f;

    float mA = -1e30f, mB = -1e30f, lA = 0.f, lB = 0.f;
    const int rA = q0 + r0 + (lane >> 2);
    const int rB = rA + 8;

    for (int kb = 0; kb <= qb; kb++) {
        const int kk0 = kb * 128;
#pragma unroll
        for (int i = 0; i < 8; i++) {
            int id = i * 256 + tid;
            int r = id >> 4;
            int c = (id & 15) << 2;
            float4 val = *(const float4*)(k + (size_t)(kk0 + r) * ldq + hoff + c);
            uint2 pk;
            pk.x = cvt_bf16x2(val.x, val.y);
            pk.y = cvt_bf16x2(val.z, val.w);
            *(uint2*)&Ks[r * 72 + c] = pk;
        }
#pragma unroll
        for (int i = 0; i < 8; i++) {
            int id = i * 256 + tid;
            int r = id >> 4;
            int c = (id & 15) << 2;
            float4 val = *(const float4*)(v + (size_t)(kk0 + r) * ldq + hoff + c);
            bufA[(c + 0) * 136 + r] = __float2bfloat16(val.x);
            bufA[(c + 1) * 136 + r] = __float2bfloat16(val.y);
            bufA[(c + 2) * 136 + r] = __float2bfloat16(val.z);
            bufA[(c + 3) * 136 + r] = __float2bfloat16(val.w);
        }
        __syncthreads();

        float sacc[16][4];
#pragma unroll
        for (int nt = 0; nt < 16; nt++)
#pragma unroll
            for (int i = 0; i < 4; i++) sacc[nt][i] = 0.f;

#pragma unroll
        for (int kt = 0; kt < 4; kt++) {
#pragma unroll
            for (int np = 0; np < 8; np++) {
                int row = np * 16 + (g >> 1) * 8 + lr;
                int col = kt * 16 + (g & 1) * 8;
                uint32_t b0, b1, b2, b3;
                ldsm4(b0, b1, b2, b3, Ks_base + (uint32_t)(row * 72 + col) * 2);
                uint32_t bb0[2] = {b0, b1}, bb1[2] = {b2, b3};
                mma16816(sacc[2 * np],     qa[kt], bb0);
                mma16816(sacc[2 * np + 1], qa[kt], bb1);
            }
        }

        if (kb == qb) {
#pragma unroll
            for (int nt = 0; nt < 16; nt++) {
                int cb = kk0 + nt * 8 + 2 * (lane & 3);
                if (cb     > rA) sacc[nt][0] = -1e30f;
                if (cb + 1 > rA) sacc[nt][1] = -1e30f;
                if (cb     > rB) sacc[nt][2] = -1e30f;
                if (cb + 1 > rB) sacc[nt][3] = -1e30f;
            }
        }

        float cmA = -1e30f, cmB = -1e30f;
#pragma unroll
        for (int nt = 0; nt < 16; nt++) {
            cmA = fmaxf(cmA, fmaxf(sacc[nt][0], sacc[nt][1]));
            cmB = fmaxf(cmB, fmaxf(sacc[nt][2], sacc[nt][3]));
        }
        cmA = fmaxf(cmA, __shfl_xor_sync(0xffffffffu, cmA, 1));
        cmA = fmaxf(cmA, __shfl_xor_sync(0xffffffffu, cmA, 2));
        cmB = fmaxf(cmB, __shfl_xor_sync(0xffffffffu, cmB, 1));
        cmB = fmaxf(cmB, __shfl_xor_sync(0xffffffffu, cmB, 2));

        float nmA = fmaxf(mA, cmA), nmB = fmaxf(mB, cmB);
        float scA = exp2f(mA - nmA), scB = exp2f(mB - nmB);
        mA = nmA; mB = nmB;

        uint32_t pA[16], pB[16];
        float sA = 0.f, sB = 0.f;
#pragma unroll
        for (int nt = 0; nt < 16; nt++) {
            float p0 = exp2f(sacc[nt][0] - mA);
            float p1 = exp2f(sacc[nt][1] - mA);
            float p2 = exp2f(sacc[nt][2] - mB);
            float p3 = exp2f(sacc[nt][3] - mB);
            sA += p0 + p1; sB += p2 + p3;
            pA[nt] = cvt_bf16x2(p0, p1);
            pB[nt] = cvt_bf16x2(p2, p3);
        }
        lA = lA * scA + sA;
        lB = lB * scB + sB;
#pragma unroll
        for (int nt = 0; nt < 8; nt++) {
            acc_o[nt][0] *= scA; acc_o[nt][1] *= scA;
            acc_o[nt][2] *= scB; acc_o[nt][3] *= scB;
        }

#pragma unroll
        for (int kt2 = 0; kt2 < 8; kt2++) {
            uint32_t a[4] = { pA[2 * kt2], pB[2 * kt2], pA[2 * kt2 + 1], pB[2 * kt2 + 1] };
#pragma unroll
            for (int np2 = 0; np2 < 4; np2++) {
                int row = np2 * 16 + (g >> 1) * 8 + lr;
                int col = kt2 * 16 + (g & 1) * 8;
                uint32_t b0, b1, b2, b3;
                ldsm4(b0, b1, b2, b3, bufA_base + (uint32_t)(row * 136 + col) * 2);
                uint32_t bb0[2] = {b0, b1}, bb1[2] = {b2, b3};
                mma16816(acc_o[2 * np2],     a, bb0);
                mma16816(acc_o[2 * np2 + 1], a, bb1);
            }
        }
        __syncthreads();
    }

    lA += __shfl_xor_sync(0xffffffffu, lA, 1);
    lA += __shfl_xor_sync(0xffffffffu, lA, 2);
    lB += __shfl_xor_sync(0xffffffffu, lB, 1);
    lB += __shfl_xor_sync(0xffffffffu, lB, 2);
    float iA = 1.f / lA, iB = 1.f / lB;

#pragma unroll
    for (int nt = 0; nt < 8; nt++) {
        int col = hoff + nt * 8 + 2 * (lane & 3);
        uint32_t p0 = cvt_bf16x2(acc_o[nt][0] * iA, acc_o[nt][1] * iA);
        uint32_t p1 = cvt_bf16x2(acc_o[nt][2] * iB, acc_o[nt][3] * iB);
        *(uint32_t*)(ob + (size_t)rA * DIM + col) = p0;
        *(uint32_t*)(ob + (size_t)rB * DIM + col) = p1;
    }
}

// ---------------- small kernels ----------------
__global__ void embed_gather(const int* __restrict__ tok, const float* __restrict__ emb,
                             float* __restrict__ h)
{
    int s = blockIdx.x;
    int t = tok[s];
    const float* e = emb + (size_t)t * DIM;
    for (int d = threadIdx.x; d < DIM; d += blockDim.x)
        h[(size_t)s * DIM + d] = e[d];
}

__global__ void rmsnorm_kernel(const float* __restrict__ x, const float* __restrict__ w,
                               __nv_bfloat16* __restrict__ o)
{
    int row = blockIdx.x;
    const float* xr = x + (size_t)row * DIM;
    __shared__ float red[256];
    int tid = threadIdx.x;
    float s = 0.f;
    for (int d = tid; d < DIM; d += 256) { float v = xr[d]; s += v * v; }
    red[tid] = s; __syncthreads();
    for (int st = 128; st > 0; st >>= 1) {
        if (tid < st) red[tid] += red[tid + st];
        __syncthreads();
    }
    float rs = rsqrtf(red[0] / (float)DIM + 1e-6f);
    for (int d = tid; d < DIM; d += 256)
        o[(size_t)row * DIM + d] = __float2bfloat16(xr[d] * rs * w[d]);
}

__global__ void rope_kernel(float* __restrict__ qkv)
{
    int s = blockIdx.x;
    int tid = threadIdx.x;
    int h = tid >> 5, i = tid & 31;
    float freq = powf(10000.f, -(float)(2 * i) / 64.f);
    float ang = (float)s * freq;
    float sn, cs;
    sincosf(ang, &sn, &cs);
    size_t base = (size_t)s * (3 * DIM) + h * DH + i;
    float q1 = qkv[base], q2 = qkv[base + 32];
    qkv[base]      = q1 * cs - q2 * sn;
    qkv[base + 32] = q2 * cs + q1 * sn;
    size_t kb = base + DIM;
    float k1 = qkv[kb], k2 = qkv[kb + 32];
    qkv[kb]      = k1 * cs - k2 * sn;
    qkv[kb + 32] = k2 * cs + k1 * sn;
}

__global__ void gate_topk(const __nv_bfloat16* __restrict__ x, const float* __restrict__ gw,
                          int2* __restrict__ topi, float2* __restrict__ topw)
{
    int t = blockIdx.x;
    int tid = threadIdx.x;
    int e = tid >> 5, lane = tid & 31;
    const __nv_bfloat16* xr = x + (size_t)t * DIM;
    const float* wr = gw + (size_t)e * DIM;
    float s = 0.f;
    for (int d = lane; d < DIM; d += 32) s += __bfloat162float(xr[d]) * wr[d];
    for (int o = 16; o; o >>= 1) s += __shfl_down_sync(0xffffffffu, s, o);
    __shared__ float lg[NEXP];
    if (lane == 0) lg[e] = s;
    __syncthreads();
    if (tid == 0) {
        float m = -1e30f;
        for (int i = 0; i < NEXP; i++) m = fmaxf(m, lg[i]);
        float p[NEXP]; float sum = 0.f;
        for (int i = 0; i < NEXP; i++) { p[i] = expf(lg[i] - m); sum += p[i]; }
        float inv = 1.f / sum;
        for (int i = 0; i < NEXP; i++) p[i] *= inv;
        int i0 = 0;
        for (int i = 1; i < NEXP; i++) if (p[i] > p[i0]) i0 = i;
        int i1 = -1;
        for (int i = 0; i < NEXP; i++) {
            if (i == i0) continue;
            if (i1 < 0 || p[i] > p[i1]) i1 = i;
        }
        topi[t] = make_int2(i0, i1);
        topw[t] = make_float2(p[i0], p[i1]);
    }
}

__global__ void zero_counts(int* cnt)
{
    if (threadIdx.x < NEXP) cnt[threadIdx.x] = 0;
}

__global__ void gather_rows(const __nv_bfloat16* __restrict__ xb, __nv_bfloat16* __restrict__ xg,
                            const int2* __restrict__ topi, int2* __restrict__ pos,
                            int* __restrict__ cnt)
{
    int t = blockIdx.x;
    __shared__ int sp[2];
    int2 ti = topi[t];
    if (threadIdx.x == 0) {
        sp[0] = atomicAdd(&cnt[ti.x], 1);
        sp[1] = atomicAdd(&cnt[ti.y], 1);
    }
    __syncthreads();
    const uint32_t* src = (const uint32_t*)(xb + (size_t)t * DIM);
    uint32_t* d0 = (uint32_t*)(xg + ((size_t)ti.x * SEQ + sp[0]) * DIM);
    uint32_t* d1 = (uint32_t*)(xg + ((size_t)ti.y * SEQ + sp[1]) * DIM);
    for (int i = threadIdx.x; i < DIM / 2; i += 256) {
        uint32_t v = src[i];
        d0[i] = v; d1[i] = v;
    }
    if (threadIdx.x == 0) pos[t] = make_int2(sp[0], sp[1]);
}

__global__ void scatter_add(float* __restrict__ h, const float* __restrict__ yg,
                            const int2* __restrict__ topi, const int2* __restrict__ pos,
                            const float2* __restrict__ topw)
{
    int t = blockIdx.x;
    int2 ti = topi[t];
    int2 ps = pos[t];
    float2 w = topw[t];
    const float* y0 = yg + ((size_t)ti.x * SEQ + ps.x) * DIM;
    const float* y1 = yg + ((size_t)ti.y * SEQ + ps.y) * DIM;
    float* hr = h + (size_t)t * DIM;
    for (int d = threadIdx.x; d < DIM; d += 256)
        hr[d] += w.x * y0[d] + w.y * y1[d];
}

__global__ void zero_scalar(float* p)
{
    if (threadIdx.x == 0 && blockIdx.x == 0) p[0] = 0.f;
}

// ---------------- host ----------------
static void gemm(const __nv_bfloat16* A, const __nv_bfloat16* B, float* C,
                 int M, int N, int K, int lda, int ldb, int ldc)
{
    bf16_gemm_kernel<false><<<dim3(N / 128, M / 128), 256, GEMM_SMEM>>>(A, B, C, K, lda, ldb, ldc);
}
static void gemm_acc(const __nv_bfloat16* A, const __nv_bfloat16* B, float* C,
                     int M, int N, int K, int lda, int ldb, int ldc)
{
    bf16_gemm_kernel<true><<<dim3(N / 128, M / 128), 256, GEMM_SMEM>>>(A, B, C, K, lda, ldb, ldc);
}
static void conv_w_s(cudaStream_t s, const float* w, __nv_bfloat16* wb, size_t nelem)
{
    convert_w<<<CONV_GRID, 256, 0, s>>>(w, wb, nelem / 4);
}

// convert all weights of layer l into wl (on stream s)
static void convert_layer(cudaStream_t s, int l,
                          const float* Wq, const float* Wk, const float* Wv, const float* Wo,
                          const float* gate_proj, const float* up_proj, const float* down_proj,
                          const float* sg, const float* su, const float* sd,
                          __nv_bfloat16* wl)
{
    const size_t DD = WDD;
    const size_t EID = (size_t)NEXP * FFI * DIM;
    const size_t SD = (size_t)SFI * DIM;
    conv_w_s(s, Wq + l * DD, wl + O_QKV,          DD);
    conv_w_s(s, Wk + l * DD, wl + O_QKV + DD,     DD);
    conv_w_s(s, Wv + l * DD, wl + O_QKV + 2 * DD, DD);
    conv_w_s(s, Wo + l * DD, wl + O_WO, DD);
    convert_pair<<<CONV_GRID, 256, 0, s>>>(gate_proj + l * EID, up_proj + l * EID,
                                           wl + O_GU, 2 * EID / 4, 10);
    conv_w_s(s, down_proj + l * EID, wl + O_DN, EID);
    convert_pair<<<CONV_GRID, 256, 0, s>>>(sg + l * SD, su + l * SD,
                                           wl + O_SH, 2 * SD / 4, 11);
    conv_w_s(s, sd + l * SD, wl + O_SD, SD);
}

extern "C" void kernel_launch(void* const* d_in, const int* in_sizes, int n_in,
                              void* d_out, int out_size)
{
    (void)in_sizes; (void)n_in; (void)out_size;
    const int*   src       = (const int*)d_in[0];
    const int*   tgt       = (const int*)d_in[1];
    const float* embed     = (const float*)d_in[2];
    const float* Wq        = (const float*)d_in[3];
    const float* Wk        = (const float*)d_in[4];
    const float* Wv        = (const float*)d_in[5];
    const float* Wo        = (const float*)d_in[6];
    const float* ln1       = (const float*)d_in[7];
    const float* ln2       = (const float*)d_in[8];
    const float* gate_w    = (const float*)d_in[9];
    const float* gate_proj = (const float*)d_in[10];
    const float* up_proj   = (const float*)d_in[11];
    const float* down_proj = (const float*)d_in[12];
    const float* sg        = (const float*)d_in[13];
    const float* su        = (const float*)d_in[14];
    const float* sd        = (const float*)d_in[15];
    const float* final_ln  = (const float*)d_in[16];
    const float* lm_head   = (const float*)d_in[17];
    float* out = (float*)d_out;

    // one-time resources (created on the uncaptured correctness call)
    static cudaStream_t sC = nullptr;
    static cudaEvent_t evFork = nullptr, evL[NLAYER], evLM = nullptr;
    if (!sC) {
        cudaStreamCreateWithFlags(&sC, cudaStreamNonBlocking);
        cudaEventCreateWithFlags(&evFork, cudaEventDisableTiming);
        for (int l = 0; l < NLAYER; l++)
            cudaEventCreateWithFlags(&evL[l], cudaEventDisableTiming);
        cudaEventCreateWithFlags(&evLM, cudaEventDisableTiming);

        cudaFuncSetAttribute(bf16_gemm_kernel<false>, cudaFuncAttributeMaxDynamicSharedMemorySize, GEMM_SMEM);
        cudaFuncSetAttribute(bf16_gemm_kernel<true>,  cudaFuncAttributeMaxDynamicSharedMemorySize, GEMM_SMEM);
        cudaFuncSetAttribute(moe_gemm_kernel,         cudaFuncAttributeMaxDynamicSharedMemorySize, GEMM_SMEM);
        cudaFuncSetAttribute(moe_gemm_act_kernel,     cudaFuncAttributeMaxDynamicSharedMemorySize, GEMM_SMEM);
        cudaFuncSetAttribute(gemm_act_kernel,         cudaFuncAttributeMaxDynamicSharedMemorySize, GEMM_SMEM);
        cudaFuncSetAttribute(lmhead_gemm_loss,        cudaFuncAttributeMaxDynamicSharedMemorySize, GEMM_SMEM);
    }

    float *h, *qkv, *yg;
    __nv_bfloat16 *xb, *ob, *actb, *xg, *gsb, *wbL;
    __nv_bfloat16 *wl[NLAYER];
    float2 *partb;
    int *cnt; int2 *topi, *pos; float2 *topw;
    cudaGetSymbolAddress((void**)&h,     g_h);
    cudaGetSymbolAddress((void**)&xb,    g_xb);
    cudaGetSymbolAddress((void**)&qkv,   g_qkv);
    cudaGetSymbolAddress((void**)&ob,    g_ob);
    cudaGetSymbolAddress((void**)&yg,    g_yg);
    cudaGetSymbolAddress((void**)&actb,  g_actb);
    cudaGetSymbolAddress((void**)&xg,    g_xg);
    cudaGetSymbolAddress((void**)&gsb,   g_gsb);
    cudaGetSymbolAddress((void**)&wl[0], g_wl0);
    cudaGetSymbolAddress((void**)&wl[1], g_wl1);
    cudaGetSymbolAddress((void**)&wbL,   g_wbL);
    cudaGetSymbolAddress((void**)&partb, g_part);
    cudaGetSymbolAddress((void**)&cnt,   g_cnt);
    cudaGetSymbolAddress((void**)&topi,  g_topi);
    cudaGetSymbolAddress((void**)&pos,   g_pos);
    cudaGetSymbolAddress((void**)&topw,  g_topw);

    // ---- fork: all weight conversions on side stream ----
    cudaEventRecord(evFork, 0);
    cudaStreamWaitEvent(sC, evFork, 0);
    for (int l = 0; l < NLAYER; l++) {
        convert_layer(sC, l, Wq, Wk, Wv, Wo, gate_proj, up_proj, down_proj,
                      sg, su, sd, wl[l]);
        cudaEventRecord(evL[l], sC);
    }
    conv_w_s(sC, lm_head, wbL, (size_t)VOCAB * DIM);
    cudaEventRecord(evLM, sC);

    // ---- main stream compute ----
    embed_gather<<<SEQ, 256>>>(src, embed, h);

    for (int l = 0; l < NLAYER; l++) {
        __nv_bfloat16* w = wl[l];
        rmsnorm_kernel<<<SEQ, 256>>>(h, ln1 + (size_t)l * DIM, xb);
        cudaStreamWaitEvent(0, evL[l], 0);   // layer-l weights ready

        gemm(xb, w + O_QKV, qkv, SEQ, 3 * DIM, DIM, DIM, DIM, 3 * DIM);
        rope_kernel<<<SEQ, NHEAD * 32>>>(qkv);

        flash_attn_kernel<<<dim3(SEQ / 128, NHEAD), 256>>>(qkv, qkv + DIM, qkv + 2 * DIM, ob, 3 * DIM);

        gemm_acc(ob, w + O_WO, h, SEQ, DIM, DIM, DIM, DIM, DIM);

        // ---- MoE (sparse top-2, fused act) ----
        rmsnorm_kernel<<<SEQ, 256>>>(h, ln2 + (size_t)l * DIM, xb);
        gate_topk<<<SEQ, 256>>>(xb, gate_w + (size_t)l * NEXP * DIM, topi, topw);
        zero_counts<<<1, 32>>>(cnt);
        gather_rows<<<SEQ, 256>>>(xb, xg, topi, pos, cnt);

        moe_gemm_act_kernel<<<dim3((2 * FFI) / 128, NEXP * 16), 256, GEMM_SMEM>>>(
            xg, w + O_GU, actb, cnt);
        moe_gemm_kernel<<<dim3(DIM / 128, NEXP * 16), 256, GEMM_SMEM>>>(
            actb, w + O_DN, yg, cnt, FFI, DIM);
        scatter_add<<<SEQ, 256>>>(h, yg, topi, pos, topw);

        // ---- shared expert (fused act) ----
        gemm_act_kernel<<<dim3((2 * SFI) / 128, SEQ / 128), 256, GEMM_SMEM>>>(
            xb, w + O_SH, gsb, DIM);
        gemm_acc(gsb, w + O_SD, h, SEQ, DIM, SFI, SFI, SFI, DIM);
    }

    // ---- head + fused loss ----
    rmsnorm_kernel<<<SEQ, 256>>>(h, final_ln, xb);
    cudaStreamWaitEvent(0, evLM, 0);
    lmhead_gemm_loss<<<dim3(NCB, SEQ / 128), 256, GEMM_SMEM>>>(xb, wbL, partb, DIM);
    zero_scalar<<<1, 32>>>(out);
    loss_reduce<<<SEQ, 256>>>(partb, xb, wbL, tgt, out);
}

// round 13
// speedup vs baseline: 25.2905x; 1.0559x over previous
#include <cuda_runtime.h>
#include <cuda_bf16.h>
#include <math.h>
#include <stdint.h>

// Model dims
#define SEQ    2048
#define DIM    1024
#define NHEAD  16
#define DH     64
#define NLAYER 2
#define NEXP   8
#define FFI    512
#define SFI    1024
#define VOCAB  32000
#define NCB    (VOCAB / 128)

#define BK 32
#define NSTAGE 4
#define BSTRIDE 40
#define STAGE_BYTES (128 * BSTRIDE * 2)
#define GEMM_SMEM (2 * NSTAGE * STAGE_BYTES)   // 81920

#define CONV_GRID 1184

#define QSCALE 0.1803368801111137f  // 0.125 * log2(e)

// flash-attn smem layout (bytes)
#define FA_Q     0
#define FA_QSZ   (128 * 72 * 2)         // 18432
#define FA_K     (FA_Q + FA_QSZ)
#define FA_KSZ   (128 * 72 * 2)         // per buffer
#define FA_V     (FA_K + 2 * FA_KSZ)
#define FA_VSZ   (64 * 136 * 2)         // 17408 per buffer
#define FA_SMEM  (FA_V + 2 * FA_VSZ)    // 90112

// layer weight scratch layout (bf16 elems)
#define WDD   ((size_t)DIM * DIM)
#define O_QKV 0
#define O_WO  (3 * WDD)
#define O_GU  (4 * WDD)
#define O_DN  (O_GU + (size_t)NEXP * 2 * FFI * DIM)
#define O_SH  (O_DN + (size_t)NEXP * FFI * DIM)
#define O_SD  (O_SH + (size_t)2 * SFI * DIM)
#define WL_TOTAL (O_SD + (size_t)SFI * DIM)

// ---------------- static scratch ----------------
__device__ float g_h[SEQ * DIM];
__device__ __nv_bfloat16 g_xb[SEQ * DIM];
__device__ float g_qkv[SEQ * 3 * DIM];
__device__ __nv_bfloat16 g_qbh[(size_t)NHEAD * SEQ * DH];   // rotated+scaled Q, per head
__device__ __nv_bfloat16 g_kbh[(size_t)NHEAD * SEQ * DH];   // rotated K, per head
__device__ __nv_bfloat16 g_vth[(size_t)NHEAD * DH * SEQ];   // V^T, per head
__device__ __nv_bfloat16 g_ob[SEQ * DIM];
__device__ float g_yg[(size_t)NEXP * SEQ * DIM];
__device__ __nv_bfloat16 g_actb[(size_t)NEXP * SEQ * FFI];
__device__ __nv_bfloat16 g_xg[(size_t)NEXP * SEQ * DIM];
__device__ __nv_bfloat16 g_gsb[SEQ * SFI];
__device__ __nv_bfloat16 g_wl0[WL_TOTAL];
__device__ __nv_bfloat16 g_wl1[WL_TOTAL];
__device__ __nv_bfloat16 g_wbL[(size_t)VOCAB * DIM];
__device__ float2 g_part[(size_t)SEQ * NCB];
__device__ int   g_cnt[NEXP];
__device__ int2  g_topi[SEQ];
__device__ int2  g_pos[SEQ];
__device__ float2 g_topw[SEQ];

// ---------------- helpers ----------------
__device__ __forceinline__ uint32_t cvt_bf16x2(float lo, float hi) {
    uint32_t r;
    asm("cvt.rn.bf16x2.f32 %0, %1, %2;" : "=r"(r) : "f"(hi), "f"(lo));
    return r;
}
__device__ __forceinline__ void ldsm4(uint32_t &r0, uint32_t &r1, uint32_t &r2, uint32_t &r3,
                                      uint32_t addr) {
    asm volatile("ldmatrix.sync.aligned.m8n8.x4.shared.b16 {%0,%1,%2,%3}, [%4];"
                 : "=r"(r0), "=r"(r1), "=r"(r2), "=r"(r3) : "r"(addr));
}
__device__ __forceinline__ void mma16816(float* c, const uint32_t* a, const uint32_t* b) {
    asm volatile(
        "mma.sync.aligned.m16n8k16.row.col.f32.bf16.bf16.f32 "
        "{%0,%1,%2,%3}, {%4,%5,%6,%7}, {%8,%9}, {%0,%1,%2,%3};"
        : "+f"(c[0]), "+f"(c[1]), "+f"(c[2]), "+f"(c[3])
        : "r"(a[0]), "r"(a[1]), "r"(a[2]), "r"(a[3]), "r"(b[0]), "r"(b[1]));
}
__device__ __forceinline__ void cp_async16(uint32_t dst, const void* src) {
    asm volatile("cp.async.cg.shared.global [%0], [%1], 16;" :: "r"(dst), "l"(src));
}
__device__ __forceinline__ void cp_commit() { asm volatile("cp.async.commit_group;"); }
template<int W> __device__ __forceinline__ void cp_wait() {
    asm volatile("cp.async.wait_group %0;" :: "n"(W));
}

// ---------------- 128x128 GEMM mainloop ----------------
__device__ __forceinline__ void gemm128_mainloop(
    const __nv_bfloat16* __restrict__ A, const __nv_bfloat16* __restrict__ B,
    int K, int lda, int ldb, float acc[2][8][4])
{
    extern __shared__ __align__(16) __nv_bfloat16 smem[];
    const int tid = threadIdx.x;
    const int lane = tid & 31;
    const int wid = tid >> 5;
    const int warp_m = wid & 3;
    const int warp_n = wid >> 2;
    const int g = lane >> 3, lr = lane & 7;

    const uint32_t As_base = (uint32_t)__cvta_generic_to_shared(smem);
    const uint32_t Bs_base = As_base + NSTAGE * STAGE_BYTES;
    const int ntiles = K >> 5;

    auto issue = [&](int t, int s) {
        const __nv_bfloat16* Ag = A + t * BK;
        const __nv_bfloat16* Bg = B + t * BK;
        const uint32_t a_s = As_base + s * STAGE_BYTES;
        const uint32_t b_s = Bs_base + s * STAGE_BYTES;
#pragma unroll
        for (int i = 0; i < 2; i++) {
            int id = i * 256 + tid;
            int r = id >> 2;
            int c = (id & 3) * 8;
            cp_async16(a_s + (r * BSTRIDE + c) * 2, Ag + (size_t)r * lda + c);
            cp_async16(b_s + (r * BSTRIDE + c) * 2, Bg + (size_t)r * ldb + c);
        }
    };

#pragma unroll
    for (int s = 0; s < NSTAGE - 1; s++) {
        if (s < ntiles) issue(s, s);
        cp_commit();
    }

#pragma unroll
    for (int mt = 0; mt < 2; mt++)
#pragma unroll
        for (int nt = 0; nt < 8; nt++)
#pragma unroll
            for (int i = 0; i < 4; i++) acc[mt][nt][i] = 0.f;

    for (int t = 0; t < ntiles; t++) {
        cp_wait<NSTAGE - 2>();
        __syncthreads();

        const int s = t & (NSTAGE - 1);
        const uint32_t a_base = As_base + s * STAGE_BYTES;
        const uint32_t b_base = Bs_base + s * STAGE_BYTES;

#pragma unroll
        for (int ks = 0; ks < 2; ks++) {
            uint32_t a[2][4];
#pragma unroll
            for (int mt = 0; mt < 2; mt++) {
                int row = warp_m * 32 + mt * 16 + (g & 1) * 8 + lr;
                int col = ks * 16 + (g >> 1) * 8;
                ldsm4(a[mt][0], a[mt][1], a[mt][2], a[mt][3],
                      a_base + (uint32_t)(row * BSTRIDE + col) * 2);
            }
            uint32_t b[8][2];
#pragma unroll
            for (int np = 0; np < 4; np++) {
                int row = warp_n * 64 + np * 16 + (g >> 1) * 8 + lr;
                int col = ks * 16 + (g & 1) * 8;
                uint32_t r0, r1, r2, r3;
                ldsm4(r0, r1, r2, r3, b_base + (uint32_t)(row * BSTRIDE + col) * 2);
                b[2 * np][0] = r0; b[2 * np][1] = r1;
                b[2 * np + 1][0] = r2; b[2 * np + 1][1] = r3;
            }
#pragma unroll
            for (int mt = 0; mt < 2; mt++)
#pragma unroll
                for (int nt = 0; nt < 8; nt++)
                    mma16816(acc[mt][nt], a[mt], b[nt]);
        }

        int nt2 = t + NSTAGE - 1;
        if (nt2 < ntiles) issue(nt2, nt2 & (NSTAGE - 1));
        cp_commit();
    }
}

template<bool ACC>
__device__ __forceinline__ void epilogue_store(float* __restrict__ C, int ldc,
                                               float acc[2][8][4])
{
    const int tid = threadIdx.x;
    const int lane = tid & 31;
    const int wid = tid >> 5;
    const int warp_m = wid & 3;
    const int warp_n = wid >> 2;
    const int r0c = lane >> 2;
    const int cc  = (lane & 3) * 2;
#pragma unroll
    for (int mt = 0; mt < 2; mt++) {
        int rbase = warp_m * 32 + mt * 16 + r0c;
#pragma unroll
        for (int nt = 0; nt < 8; nt++) {
            int col = warp_n * 64 + nt * 8 + cc;
            size_t i00 = (size_t)rbase * ldc + col;
            size_t i10 = (size_t)(rbase + 8) * ldc + col;
            if (ACC) {
                C[i00]     += acc[mt][nt][0]; C[i00 + 1] += acc[mt][nt][1];
                C[i10]     += acc[mt][nt][2]; C[i10 + 1] += acc[mt][nt][3];
            } else {
                C[i00]     = acc[mt][nt][0]; C[i00 + 1] = acc[mt][nt][1];
                C[i10]     = acc[mt][nt][2]; C[i10 + 1] = acc[mt][nt][3];
            }
        }
    }
}

__device__ __forceinline__ void epilogue_act(__nv_bfloat16* __restrict__ O, int ldo,
                                             float acc[2][8][4])
{
    const int tid = threadIdx.x;
    const int lane = tid & 31;
    const int wid = tid >> 5;
    const int warp_m = wid & 3;
    const int warp_n = wid >> 2;
    const int r0c = lane >> 2;
    const int cp0 = lane & 3;
#pragma unroll
    for (int mt = 0; mt < 2; mt++) {
        int rbase = warp_m * 32 + mt * 16 + r0c;
#pragma unroll
        for (int nt = 0; nt < 8; nt++) {
            int cp = warp_n * 32 + nt * 4 + cp0;
            float g0 = acc[mt][nt][0], u0 = acc[mt][nt][1];
            float g1 = acc[mt][nt][2], u1 = acc[mt][nt][3];
            float s0 = 1.f / (1.f + expf(-g0));
            float s1 = 1.f / (1.f + expf(-g1));
            O[(size_t)rbase * ldo + cp]       = __float2bfloat16(g0 * s0 * u0);
            O[(size_t)(rbase + 8) * ldo + cp] = __float2bfloat16(g1 * s1 * u1);
        }
    }
}

template<bool ACC>
__global__ void __launch_bounds__(256, 2) bf16_gemm_kernel(
    const __nv_bfloat16* __restrict__ A, const __nv_bfloat16* __restrict__ B,
    float* __restrict__ C, int K, int lda, int ldb, int ldc)
{
    A += (size_t)blockIdx.y * 128 * lda;
    B += (size_t)blockIdx.x * 128 * ldb;
    C += (size_t)blockIdx.y * 128 * ldc + blockIdx.x * 128;
    float acc[2][8][4];
    gemm128_mainloop(A, B, K, lda, ldb, acc);
    epilogue_store<ACC>(C, ldc, acc);
}

__global__ void __launch_bounds__(256, 2) gemm_act_kernel(
    const __nv_bfloat16* __restrict__ A, const __nv_bfloat16* __restrict__ B,
    __nv_bfloat16* __restrict__ O, int K)
{
    A += (size_t)blockIdx.y * 128 * K;
    B += (size_t)blockIdx.x * 128 * K;
    O += (size_t)blockIdx.y * 128 * SFI + blockIdx.x * 64;
    float acc[2][8][4];
    gemm128_mainloop(A, B, K, K, K, acc);
    epilogue_act(O, SFI, acc);
}

__global__ void __launch_bounds__(256, 2) moe_gemm_act_kernel(
    const __nv_bfloat16* __restrict__ A, const __nv_bfloat16* __restrict__ B,
    __nv_bfloat16* __restrict__ O, const int* __restrict__ cnt)
{
    const int e = blockIdx.y >> 4;
    const int rb = blockIdx.y & 15;
    if (rb * 128 >= cnt[e]) return;
    A += ((size_t)e * SEQ + rb * 128) * DIM;
    B += (size_t)e * (2 * FFI) * DIM + (size_t)blockIdx.x * 128 * DIM;
    O += ((size_t)e * SEQ + rb * 128) * FFI + blockIdx.x * 64;
    float acc[2][8][4];
    gemm128_mainloop(A, B, DIM, DIM, DIM, acc);
    epilogue_act(O, FFI, acc);
}

__global__ void __launch_bounds__(256, 2) moe_gemm_kernel(
    const __nv_bfloat16* __restrict__ A, const __nv_bfloat16* __restrict__ B,
    float* __restrict__ C, const int* __restrict__ cnt, int K, int N)
{
    const int e = blockIdx.y >> 4;
    const int rb = blockIdx.y & 15;
    if (rb * 128 >= cnt[e]) return;
    A += ((size_t)e * SEQ + rb * 128) * K;
    B += (size_t)e * N * K + (size_t)blockIdx.x * 128 * K;
    C += ((size_t)e * SEQ + rb * 128) * N + blockIdx.x * 128;
    float acc[2][8][4];
    gemm128_mainloop(A, B, K, K, K, acc);
    epilogue_store<false>(C, N, acc);
}

__global__ void __launch_bounds__(256, 2) lmhead_gemm_loss(
    const __nv_bfloat16* __restrict__ A, const __nv_bfloat16* __restrict__ B,
    float2* __restrict__ part, int K)
{
    const int bx = blockIdx.x;
    A += (size_t)blockIdx.y * 128 * K;
    B += (size_t)bx * 128 * K;
    float acc[2][8][4];
    gemm128_mainloop(A, B, K, K, K, acc);

    const int tid = threadIdx.x;
    const int lane = tid & 31;
    const int wid = tid >> 5;
    const int warp_m = wid & 3;
    const int warp_n = wid >> 2;

    __shared__ float sm_m[2][128], sm_s[2][128];

#pragma unroll
    for (int mt = 0; mt < 2; mt++) {
#pragma unroll
        for (int half = 0; half < 2; half++) {
            float m = -1e30f;
#pragma unroll
            for (int nt = 0; nt < 8; nt++)
                m = fmaxf(m, fmaxf(acc[mt][nt][2 * half], acc[mt][nt][2 * half + 1]));
            m = fmaxf(m, __shfl_xor_sync(0xffffffffu, m, 1));
            m = fmaxf(m, __shfl_xor_sync(0xffffffffu, m, 2));
            float s = 0.f;
#pragma unroll
            for (int nt = 0; nt < 8; nt++)
                s += expf(acc[mt][nt][2 * half] - m) + expf(acc[mt][nt][2 * half + 1] - m);
            s += __shfl_xor_sync(0xffffffffu, s, 1);
            s += __shfl_xor_sync(0xffffffffu, s, 2);
            if ((lane & 3) == 0) {
                int row_local = warp_m * 32 + mt * 16 + half * 8 + (lane >> 2);
                sm_m[warp_n][row_local] = m;
                sm_s[warp_n][row_local] = s;
            }
        }
    }
    __syncthreads();

    if (tid < 128) {
        float m1 = sm_m[0][tid], s1 = sm_s[0][tid];
        float m2 = sm_m[1][tid], s2 = sm_s[1][tid];
        float nm = fmaxf(m1, m2);
        float ns = s1 * expf(m1 - nm) + s2 * expf(m2 - nm);
        int row = blockIdx.y * 128 + tid;
        part[(size_t)row * NCB + bx] = make_float2(nm, ns);
    }
}

__global__ void loss_reduce(const float2* __restrict__ part,
                            const __nv_bfloat16* __restrict__ xb,
                            const __nv_bfloat16* __restrict__ wb,
                            const int* __restrict__ tgt, float* __restrict__ out)
{
    int row = blockIdx.x;
    int tid = threadIdx.x;

    float m = -1e30f, s = 0.f;
    for (int j = tid; j < NCB; j += 256) {
        float2 p = part[(size_t)row * NCB + j];
        float nm = fmaxf(m, p.x);
        s = s * expf(m - nm) + p.y * expf(p.x - nm);
        m = nm;
    }

    __shared__ float ms[256], ss[256], ds[256];
    ms[tid] = m; ss[tid] = s;
    __syncthreads();
    for (int st = 128; st > 0; st >>= 1) {
        if (tid < st) {
            float m1 = ms[tid], m2 = ms[tid + st];
            float nm = fmaxf(m1, m2);
            ss[tid] = ss[tid] * expf(m1 - nm) + ss[tid + st] * expf(m2 - nm);
            ms[tid] = nm;
        }
        __syncthreads();
    }

    int lab = tgt[row];
    int slab = (lab == -100) ? 0 : lab;
    const __nv_bfloat16* xr = xb + (size_t)row * DIM;
    const __nv_bfloat16* wr = wb + (size_t)slab * DIM;
    float d = 0.f;
    for (int i = tid; i < DIM; i += 256)
        d += __bfloat162float(xr[i]) * __bfloat162float(wr[i]);
    ds[tid] = d;
    __syncthreads();
    for (int st = 128; st > 0; st >>= 1) {
        if (tid < st) ds[tid] += ds[tid + st];
        __syncthreads();
    }

    if (tid == 0 && lab != -100) {
        float lse = ms[0] + logf(ss[0]);
        atomicAdd(out, lse - ds[0]);
    }
}

// ---------------- weight conversion (grid-stride) ----------------
__global__ void convert_w(const float* __restrict__ w, __nv_bfloat16* __restrict__ wb,
                          size_t n4)
{
    const float4* w4 = (const float4*)w;
    uint2* o2 = (uint2*)wb;
    size_t stride = (size_t)gridDim.x * 256;
    for (size_t i = (size_t)blockIdx.x * 256 + threadIdx.x; i < n4; i += stride * 4) {
        float4 v[4];
        bool ok[4];
#pragma unroll
        for (int k = 0; k < 4; k++) {
            size_t j = i + (size_t)k * stride;
            ok[k] = j < n4;
            if (ok[k]) v[k] = w4[j];
        }
#pragma unroll
        for (int k = 0; k < 4; k++) if (ok[k]) {
            uint2 pk;
            pk.x = cvt_bf16x2(v[k].x, v[k].y);
            pk.y = cvt_bf16x2(v[k].z, v[k].w);
            o2[i + (size_t)k * stride] = pk;
        }
    }
}

__global__ void convert_pair(const float* __restrict__ a, const float* __restrict__ b,
                             __nv_bfloat16* __restrict__ wb, size_t n4, int log2r2)
{
    uint2* o2 = (uint2*)wb;
    size_t stride = (size_t)gridDim.x * 256;
    for (size_t i = (size_t)blockIdx.x * 256 + threadIdx.x; i < n4; i += stride * 4) {
        float4 v[4];
        bool ok[4];
#pragma unroll
        for (int k = 0; k < 4; k++) {
            size_t j = i + (size_t)k * stride;
            ok[k] = j < n4;
            if (ok[k]) {
                int k4 = (int)(j & 255);
                size_t n = j >> 8;
                size_t e = n >> log2r2;
                int r = (int)(n & ((1u << log2r2) - 1));
                const float* src = ((r & 1) ? b : a)
                    + ((e << (log2r2 - 1)) + (r >> 1)) * (size_t)DIM + k4 * 4;
                v[k] = *(const float4*)src;
            }
        }
#pragma unroll
        for (int k = 0; k < 4; k++) if (ok[k]) {
            uint2 pk;
            pk.x = cvt_bf16x2(v[k].x, v[k].y);
            pk.y = cvt_bf16x2(v[k].z, v[k].w);
            o2[i + (size_t)k * stride] = pk;
        }
    }
}

// ---------------- rope -> bf16 per-head Q/K ----------------
__global__ void rope_bf16_kernel(const float* __restrict__ qkv,
                                 __nv_bfloat16* __restrict__ qb,
                                 __nv_bfloat16* __restrict__ kb)
{
    int s = blockIdx.x;
    int tid = threadIdx.x;          // 512 = 16 heads * 32 pairs
    int h = tid >> 5, i = tid & 31;
    float freq = powf(10000.f, -(float)(2 * i) / 64.f);
    float ang = (float)s * freq;
    float sn, cs;
    sincosf(ang, &sn, &cs);
    size_t src = (size_t)s * (3 * DIM) + h * DH + i;
    float q1 = qkv[src], q2 = qkv[src + 32];
    size_t dst = ((size_t)h * SEQ + s) * DH + i;
    qb[dst]      = __float2bfloat16((q1 * cs - q2 * sn) * QSCALE);
    qb[dst + 32] = __float2bfloat16((q2 * cs + q1 * sn) * QSCALE);
    float k1 = qkv[src + DIM], k2 = qkv[src + DIM + 32];
    kb[dst]      = __float2bfloat16(k1 * cs - k2 * sn);
    kb[dst + 32] = __float2bfloat16(k2 * cs + k1 * sn);
}

// V transpose: v fp32 [SEQ][3*DIM](offset 2*DIM) -> vt bf16 [DIM][SEQ]
__global__ void vtrans_kernel(const float* __restrict__ v, __nv_bfloat16* __restrict__ vt)
{
    __shared__ float tile[32][33];
    int s0 = blockIdx.x * 32, d0 = blockIdx.y * 32;
    int tx = threadIdx.x, ty = threadIdx.y;   // 32 x 8
#pragma unroll
    for (int i = 0; i < 4; i++) {
        int row = ty + i * 8;
        tile[row][tx] = v[(size_t)(s0 + row) * (3 * DIM) + 2 * DIM + d0 + tx];
    }
    __syncthreads();
#pragma unroll
    for (int i = 0; i < 4; i++) {
        int row = ty + i * 8;
        vt[(size_t)(d0 + row) * SEQ + s0 + tx] = __float2bfloat16(tile[tx][row]);
    }
}

// ---------------- flash attention, bf16 inputs + cp.async double-buffered KV ----
__global__ void __launch_bounds__(256, 1) flash_attn2_kernel(
    const __nv_bfloat16* __restrict__ qb, const __nv_bfloat16* __restrict__ kb,
    const __nv_bfloat16* __restrict__ vt, __nv_bfloat16* __restrict__ ob)
{
    extern __shared__ __align__(16) char fasm[];
    const int qblk = blockIdx.x;
    const int head = blockIdx.y;
    const int q0 = qblk * 128;

    const int tid = threadIdx.x;
    const int lane = tid & 31;
    const int wid = tid >> 5;
    const int g = lane >> 3, lr = lane & 7;
    const int r0 = wid * 16;

    const uint32_t smb = (uint32_t)__cvta_generic_to_shared(fasm);
    const uint32_t Qs = smb + FA_Q;
    const uint32_t Ks = smb + FA_K;
    const uint32_t Vs = smb + FA_V;

    const __nv_bfloat16* Qg = qb + ((size_t)head * SEQ + q0) * DH;
    const __nv_bfloat16* Kg = kb + (size_t)head * SEQ * DH;
    const __nv_bfloat16* Vg = vt + (size_t)head * DH * SEQ;

    // ---- load Q tile via cp.async (128 rows x 8 chunks) ----
#pragma unroll
    for (int i = 0; i < 4; i++) {
        int id = i * 256 + tid;
        int r = id >> 3;
        int c = id & 7;
        cp_async16(Qs + (uint32_t)(r * 144 + c * 16), Qg + (size_t)r * DH + c * 8);
    }
    cp_commit();

    auto issueKV = [&](int kblk, int buf) {
        const int kk0 = kblk * 128;
        const uint32_t kdst = Ks + buf * FA_KSZ;
        const uint32_t vdst = Vs + buf * FA_VSZ;
#pragma unroll
        for (int i = 0; i < 4; i++) {
            int id = i * 256 + tid;
            int r = id >> 3;
            int c = id & 7;
            cp_async16(kdst + (uint32_t)(r * 144 + c * 16),
                       Kg + (size_t)(kk0 + r) * DH + c * 8);
        }
#pragma unroll
        for (int i = 0; i < 4; i++) {
            int id = i * 256 + tid;
            int d = id >> 4;          // 0..63
            int c = id & 15;          // 16 chunks of 16B = 256B = 128 bf16
            cp_async16(vdst + (uint32_t)(d * 272 + c * 16),
                       Vg + (size_t)d * SEQ + kk0 + c * 8);
        }
    };

    issueKV(0, 0);
    cp_commit();

    // Q fragments (wait for both Q and first KV group: drain all)
    cp_wait<0>();
    __syncthreads();

    uint32_t qa[4][4];
#pragma unroll
    for (int kt = 0; kt < 4; kt++) {
        int row = r0 + (g & 1) * 8 + lr;
        int col = kt * 16 + (g >> 1) * 8;
        ldsm4(qa[kt][0], qa[kt][1], qa[kt][2], qa[kt][3],
              Qs + (uint32_t)(row * 72 + col) * 2);
    }

    float acc_o[8][4];
#pragma unroll
    for (int nt = 0; nt < 8; nt++)
#pragma unroll
        for (int i = 0; i < 4; i++) acc_o[nt][i] = 0.f;

    float mA = -1e30f, mB = -1e30f, lA = 0.f, lB = 0.f;
    const int rA = q0 + r0 + (lane >> 2);
    const int rB = rA + 8;

    for (int kblk = 0; kblk <= qblk; kblk++) {
        const int kk0 = kblk * 128;
        const int buf = kblk & 1;

        if (kblk > 0) {           // first iteration already drained above
            cp_wait<0>();
            __syncthreads();
        }
        if (kblk < qblk) {
            issueKV(kblk + 1, buf ^ 1);
            cp_commit();
        }

        const uint32_t kbase = Ks + buf * FA_KSZ;
        const uint32_t vbase = Vs + buf * FA_VSZ;

        float sacc[16][4];
#pragma unroll
        for (int nt = 0; nt < 16; nt++)
#pragma unroll
            for (int i = 0; i < 4; i++) sacc[nt][i] = 0.f;

#pragma unroll
        for (int kt = 0; kt < 4; kt++) {
#pragma unroll
            for (int np = 0; np < 8; np++) {
                int row = np * 16 + (g >> 1) * 8 + lr;
                int col = kt * 16 + (g & 1) * 8;
                uint32_t b0, b1, b2, b3;
                ldsm4(b0, b1, b2, b3, kbase + (uint32_t)(row * 72 + col) * 2);
                uint32_t bb0[2] = {b0, b1}, bb1[2] = {b2, b3};
                mma16816(sacc[2 * np],     qa[kt], bb0);
                mma16816(sacc[2 * np + 1], qa[kt], bb1);
            }
        }

        if (kblk == qblk) {
#pragma unroll
            for (int nt = 0; nt < 16; nt++) {
                int cb = kk0 + nt * 8 + 2 * (lane & 3);
                if (cb     > rA) sacc[nt][0] = -1e30f;
                if (cb + 1 > rA) sacc[nt][1] = -1e30f;
                if (cb     > rB) sacc[nt][2] = -1e30f;
                if (cb + 1 > rB) sacc[nt][3] = -1e30f;
            }
        }

        float cmA = -1e30f, cmB = -1e30f;
#pragma unroll
        for (int nt = 0; nt < 16; nt++) {
            cmA = fmaxf(cmA, fmaxf(sacc[nt][0], sacc[nt][1]));
            cmB = fmaxf(cmB, fmaxf(sacc[nt][2], sacc[nt][3]));
        }
        cmA = fmaxf(cmA, __shfl_xor_sync(0xffffffffu, cmA, 1));
        cmA = fmaxf(cmA, __shfl_xor_sync(0xffffffffu, cmA, 2));
        cmB = fmaxf(cmB, __shfl_xor_sync(0xffffffffu, cmB, 1));
        cmB = fmaxf(cmB, __shfl_xor_sync(0xffffffffu, cmB, 2));

        float nmA = fmaxf(mA, cmA), nmB = fmaxf(mB, cmB);
        float scA = exp2f(mA - nmA), scB = exp2f(mB - nmB);
        mA = nmA; mB = nmB;

        uint32_t pA[16], pB[16];
        float sA = 0.f, sB = 0.f;
#pragma unroll
        for (int nt = 0; nt < 16; nt++) {
            float p0 = exp2f(sacc[nt][0] - mA);
            float p1 = exp2f(sacc[nt][1] - mA);
            float p2 = exp2f(sacc[nt][2] - mB);
            float p3 = exp2f(sacc[nt][3] - mB);
            sA += p0 + p1; sB += p2 + p3;
            pA[nt] = cvt_bf16x2(p0, p1);
            pB[nt] = cvt_bf16x2(p2, p3);
        }
        lA = lA * scA + sA;
        lB = lB * scB + sB;
#pragma unroll
        for (int nt = 0; nt < 8; nt++) {
            acc_o[nt][0] *= scA; acc_o[nt][1] *= scA;
            acc_o[nt][2] *= scB; acc_o[nt][3] *= scB;
        }

#pragma unroll
        for (int kt2 = 0; kt2 < 8; kt2++) {
            uint32_t a[4] = { pA[2 * kt2], pB[2 * kt2], pA[2 * kt2 + 1], pB[2 * kt2 + 1] };
#pragma unroll
            for (int np2 = 0; np2 < 4; np2++) {
                int row = np2 * 16 + (g >> 1) * 8 + lr;
                int col = kt2 * 16 + (g & 1) * 8;
                uint32_t b0, b1, b2, b3;
                ldsm4(b0, b1, b2, b3, vbase + (uint32_t)(row * 136 + col) * 2);
                uint32_t bb0[2] = {b0, b1}, bb1[2] = {b2, b3};
                mma16816(acc_o[2 * np2],     a, bb0);
                mma16816(acc_o[2 * np2 + 1], a, bb1);
            }
        }
    }

    lA += __shfl_xor_sync(0xffffffffu, lA, 1);
    lA += __shfl_xor_sync(0xffffffffu, lA, 2);
    lB += __shfl_xor_sync(0xffffffffu, lB, 1);
    lB += __shfl_xor_sync(0xffffffffu, lB, 2);
    float iA = 1.f / lA, iB = 1.f / lB;

#pragma unroll
    for (int nt = 0; nt < 8; nt++) {
        int col = head * DH + nt * 8 + 2 * (lane & 3);
        uint32_t p0 = cvt_bf16x2(acc_o[nt][0] * iA, acc_o[nt][1] * iA);
        uint32_t p1 = cvt_bf16x2(acc_o[nt][2] * iB, acc_o[nt][3] * iB);
        *(uint32_t*)(ob + (size_t)rA * DIM + col) = p0;
        *(uint32_t*)(ob + (size_t)rB * DIM + col) = p1;
    }
}

// ---------------- small kernels ----------------
__global__ void embed_gather(const int* __restrict__ tok, const float* __restrict__ emb,
                             float* __restrict__ h)
{
    int s = blockIdx.x;
    int t = tok[s];
    const float* e = emb + (size_t)t * DIM;
    for (int d = threadIdx.x; d < DIM; d += blockDim.x)
        h[(size_t)s * DIM + d] = e[d];
}

__global__ void rmsnorm_kernel(const float* __restrict__ x, const float* __restrict__ w,
                               __nv_bfloat16* __restrict__ o)
{
    int row = blockIdx.x;
    const float* xr = x + (size_t)row * DIM;
    __shared__ float red[256];
    int tid = threadIdx.x;
    float s = 0.f;
    for (int d = tid; d < DIM; d += 256) { float v = xr[d]; s += v * v; }
    red[tid] = s; __syncthreads();
    for (int st = 128; st > 0; st >>= 1) {
        if (tid < st) red[tid] += red[tid + st];
        __syncthreads();
    }
    float rs = rsqrtf(red[0] / (float)DIM + 1e-6f);
    for (int d = tid; d < DIM; d += 256)
        o[(size_t)row * DIM + d] = __float2bfloat16(xr[d] * rs * w[d]);
}

__global__ void gate_topk(const __nv_bfloat16* __restrict__ x, const float* __restrict__ gw,
                          int2* __restrict__ topi, float2* __restrict__ topw)
{
    int t = blockIdx.x;
    int tid = threadIdx.x;
    int e = tid >> 5, lane = tid & 31;
    const __nv_bfloat16* xr = x + (size_t)t * DIM;
    const float* wr = gw + (size_t)e * DIM;
    float s = 0.f;
    for (int d = lane; d < DIM; d += 32) s += __bfloat162float(xr[d]) * wr[d];
    for (int o = 16; o; o >>= 1) s += __shfl_down_sync(0xffffffffu, s, o);
    __shared__ float lg[NEXP];
    if (lane == 0) lg[e] = s;
    __syncthreads();
    if (tid == 0) {
        float m = -1e30f;
        for (int i = 0; i < NEXP; i++) m = fmaxf(m, lg[i]);
        float p[NEXP]; float sum = 0.f;
        for (int i = 0; i < NEXP; i++) { p[i] = expf(lg[i] - m); sum += p[i]; }
        float inv = 1.f / sum;
        for (int i = 0; i < NEXP; i++) p[i] *= inv;
        int i0 = 0;
        for (int i = 1; i < NEXP; i++) if (p[i] > p[i0]) i0 = i;
        int i1 = -1;
        for (int i = 0; i < NEXP; i++) {
            if (i == i0) continue;
            if (i1 < 0 || p[i] > p[i1]) i1 = i;
        }
        topi[t] = make_int2(i0, i1);
        topw[t] = make_float2(p[i0], p[i1]);
    }
}

__global__ void zero_counts(int* cnt)
{
    if (threadIdx.x < NEXP) cnt[threadIdx.x] = 0;
}

__global__ void gather_rows(const __nv_bfloat16* __restrict__ xb, __nv_bfloat16* __restrict__ xg,
                            const int2* __restrict__ topi, int2* __restrict__ pos,
                            int* __restrict__ cnt)
{
    int t = blockIdx.x;
    __shared__ int sp[2];
    int2 ti = topi[t];
    if (threadIdx.x == 0) {
        sp[0] = atomicAdd(&cnt[ti.x], 1);
        sp[1] = atomicAdd(&cnt[ti.y], 1);
    }
    __syncthreads();
    const uint32_t* src = (const uint32_t*)(xb + (size_t)t * DIM);
    uint32_t* d0 = (uint32_t*)(xg + ((size_t)ti.x * SEQ + sp[0]) * DIM);
    uint32_t* d1 = (uint32_t*)(xg + ((size_t)ti.y * SEQ + sp[1]) * DIM);
    for (int i = threadIdx.x; i < DIM / 2; i += 256) {
        uint32_t v = src[i];
        d0[i] = v; d1[i] = v;
    }
    if (threadIdx.x == 0) pos[t] = make_int2(sp[0], sp[1]);
}

__global__ void scatter_add(float* __restrict__ h, const float* __restrict__ yg,
                            const int2* __restrict__ topi, const int2* __restrict__ pos,
                            const float2* __restrict__ topw)
{
    int t = blockIdx.x;
    int2 ti = topi[t];
    int2 ps = pos[t];
    float2 w = topw[t];
    const float* y0 = yg + ((size_t)ti.x * SEQ + ps.x) * DIM;
    const float* y1 = yg + ((size_t)ti.y * SEQ + ps.y) * DIM;
    float* hr = h + (size_t)t * DIM;
    for (int d = threadIdx.x; d < DIM; d += 256)
        hr[d] += w.x * y0[d] + w.y * y1[d];
}

__global__ void zero_scalar(float* p)
{
    if (threadIdx.x == 0 && blockIdx.x == 0) p[0] = 0.f;
}

// ---------------- host ----------------
static void gemm(const __nv_bfloat16* A, const __nv_bfloat16* B, float* C,
                 int M, int N, int K, int lda, int ldb, int ldc)
{
    bf16_gemm_kernel<false><<<dim3(N / 128, M / 128), 256, GEMM_SMEM>>>(A, B, C, K, lda, ldb, ldc);
}
static void gemm_acc(const __nv_bfloat16* A, const __nv_bfloat16* B, float* C,
                     int M, int N, int K, int lda, int ldb, int ldc)
{
    bf16_gemm_kernel<true><<<dim3(N / 128, M / 128), 256, GEMM_SMEM>>>(A, B, C, K, lda, ldb, ldc);
}
static void conv_w_s(cudaStream_t s, const float* w, __nv_bfloat16* wb, size_t nelem)
{
    convert_w<<<CONV_GRID, 256, 0, s>>>(w, wb, nelem / 4);
}

static void convert_layer(cudaStream_t s, int l,
                          const float* Wq, const float* Wk, const float* Wv, const float* Wo,
                          const float* gate_proj, const float* up_proj, const float* down_proj,
                          const float* sg, const float* su, const float* sd,
                          __nv_bfloat16* wl)
{
    const size_t DD = WDD;
    const size_t EID = (size_t)NEXP * FFI * DIM;
    const size_t SD = (size_t)SFI * DIM;
    conv_w_s(s, Wq + l * DD, wl + O_QKV,          DD);
    conv_w_s(s, Wk + l * DD, wl + O_QKV + DD,     DD);
    conv_w_s(s, Wv + l * DD, wl + O_QKV + 2 * DD, DD);
    conv_w_s(s, Wo + l * DD, wl + O_WO, DD);
    convert_pair<<<CONV_GRID, 256, 0, s>>>(gate_proj + l * EID, up_proj + l * EID,
                                           wl + O_GU, 2 * EID / 4, 10);
    conv_w_s(s, down_proj + l * EID, wl + O_DN, EID);
    convert_pair<<<CONV_GRID, 256, 0, s>>>(sg + l * SD, su + l * SD,
                                           wl + O_SH, 2 * SD / 4, 11);
    conv_w_s(s, sd + l * SD, wl + O_SD, SD);
}

extern "C" void kernel_launch(void* const* d_in, const int* in_sizes, int n_in,
                              void* d_out, int out_size)
{
    (void)in_sizes; (void)n_in; (void)out_size;
    const int*   src       = (const int*)d_in[0];
    const int*   tgt       = (const int*)d_in[1];
    const float* embed     = (const float*)d_in[2];
    const float* Wq        = (const float*)d_in[3];
    const float* Wk        = (const float*)d_in[4];
    const float* Wv        = (const float*)d_in[5];
    const float* Wo        = (const float*)d_in[6];
    const float* ln1       = (const float*)d_in[7];
    const float* ln2       = (const float*)d_in[8];
    const float* gate_w    = (const float*)d_in[9];
    const float* gate_proj = (const float*)d_in[10];
    const float* up_proj   = (const float*)d_in[11];
    const float* down_proj = (const float*)d_in[12];
    const float* sg        = (const float*)d_in[13];
    const float* su        = (const float*)d_in[14];
    const float* sd        = (const float*)d_in[15];
    const float* final_ln  = (const float*)d_in[16];
    const float* lm_head   = (const float*)d_in[17];
    float* out = (float*)d_out;

    static cudaStream_t sC = nullptr;
    static cudaEvent_t evFork = nullptr, evL[NLAYER], evLM = nullptr;
    if (!sC) {
        cudaStreamCreateWithFlags(&sC, cudaStreamNonBlocking);
        cudaEventCreateWithFlags(&evFork, cudaEventDisableTiming);
        for (int l = 0; l < NLAYER; l++)
            cudaEventCreateWithFlags(&evL[l], cudaEventDisableTiming);
        cudaEventCreateWithFlags(&evLM, cudaEventDisableTiming);

        cudaFuncSetAttribute(bf16_gemm_kernel<false>, cudaFuncAttributeMaxDynamicSharedMemorySize, GEMM_SMEM);
        cudaFuncSetAttribute(bf16_gemm_kernel<true>,  cudaFuncAttributeMaxDynamicSharedMemorySize, GEMM_SMEM);
        cudaFuncSetAttribute(moe_gemm_kernel,         cudaFuncAttributeMaxDynamicSharedMemorySize, GEMM_SMEM);
        cudaFuncSetAttribute(moe_gemm_act_kernel,     cudaFuncAttributeMaxDynamicSharedMemorySize, GEMM_SMEM);
        cudaFuncSetAttribute(gemm_act_kernel,         cudaFuncAttributeMaxDynamicSharedMemorySize, GEMM_SMEM);
        cudaFuncSetAttribute(lmhead_gemm_loss,        cudaFuncAttributeMaxDynamicSharedMemorySize, GEMM_SMEM);
        cudaFuncSetAttribute(flash_attn2_kernel,      cudaFuncAttributeMaxDynamicSharedMemorySize, FA_SMEM);
    }

    float *h, *qkv, *yg;
    __nv_bfloat16 *xb, *qbh, *kbh, *vth, *ob, *actb, *xg, *gsb, *wbL;
    __nv_bfloat16 *wl[NLAYER];
    float2 *partb;
    int *cnt; int2 *topi, *pos; float2 *topw;
    cudaGetSymbolAddress((void**)&h,     g_h);
    cudaGetSymbolAddress((void**)&xb,    g_xb);
    cudaGetSymbolAddress((void**)&qkv,   g_qkv);
    cudaGetSymbolAddress((void**)&qbh,   g_qbh);
    cudaGetSymbolAddress((void**)&kbh,   g_kbh);
    cudaGetSymbolAddress((void**)&vth,   g_vth);
    cudaGetSymbolAddress((void**)&ob,    g_ob);
    cudaGetSymbolAddress((void**)&yg,    g_yg);
    cudaGetSymbolAddress((void**)&actb,  g_actb);
    cudaGetSymbolAddress((void**)&xg,    g_xg);
    cudaGetSymbolAddress((void**)&gsb,   g_gsb);
    cudaGetSymbolAddress((void**)&wl[0], g_wl0);
    cudaGetSymbolAddress((void**)&wl[1], g_wl1);
    cudaGetSymbolAddress((void**)&wbL,   g_wbL);
    cudaGetSymbolAddress((void**)&partb, g_part);
    cudaGetSymbolAddress((void**)&cnt,   g_cnt);
    cudaGetSymbolAddress((void**)&topi,  g_topi);
    cudaGetSymbolAddress((void**)&pos,   g_pos);
    cudaGetSymbolAddress((void**)&topw,  g_topw);

    // ---- fork: all weight conversions on side stream ----
    cudaEventRecord(evFork, 0);
    cudaStreamWaitEvent(sC, evFork, 0);
    for (int l = 0; l < NLAYER; l++) {
        convert_layer(sC, l, Wq, Wk, Wv, Wo, gate_proj, up_proj, down_proj,
                      sg, su, sd, wl[l]);
        cudaEventRecord(evL[l], sC);
    }
    conv_w_s(sC, lm_head, wbL, (size_t)VOCAB * DIM);
    cudaEventRecord(evLM, sC);

    // ---- main stream compute ----
    embed_gather<<<SEQ, 256>>>(src, embed, h);

    for (int l = 0; l < NLAYER; l++) {
        __nv_bfloat16* w = wl[l];
        rmsnorm_kernel<<<SEQ, 256>>>(h, ln1 + (size_t)l * DIM, xb);
        cudaStreamWaitEvent(0, evL[l], 0);

        gemm(xb, w + O_QKV, qkv, SEQ, 3 * DIM, DIM, DIM, DIM, 3 * DIM);
        rope_bf16_kernel<<<SEQ, NHEAD * 32>>>(qkv, qbh, kbh);
        vtrans_kernel<<<dim3(SEQ / 32, DIM / 32), dim3(32, 8)>>>(qkv, vth);

        flash_attn2_kernel<<<dim3(SEQ / 128, NHEAD), 256, FA_SMEM>>>(qbh, kbh, vth, ob);

        gemm_acc(ob, w + O_WO, h, SEQ, DIM, DIM, DIM, DIM, DIM);

        // ---- MoE (sparse top-2, fused act) ----
        rmsnorm_kernel<<<SEQ, 256>>>(h, ln2 + (size_t)l * DIM, xb);
        gate_topk<<<SEQ, 256>>>(xb, gate_w + (size_t)l * NEXP * DIM, topi, topw);
        zero_counts<<<1, 32>>>(cnt);
        gather_rows<<<SEQ, 256>>>(xb, xg, topi, pos, cnt);

        moe_gemm_act_kernel<<<dim3((2 * FFI) / 128, NEXP * 16), 256, GEMM_SMEM>>>(
            xg, w + O_GU, actb, cnt);
        moe_gemm_kernel<<<dim3(DIM / 128, NEXP * 16), 256, GEMM_SMEM>>>(
            actb, w + O_DN, yg, cnt, FFI, DIM);
        scatter_add<<<SEQ, 256>>>(h, yg, topi, pos, topw);

        // ---- shared expert (fused act) ----
        gemm_act_kernel<<<dim3((2 * SFI) / 128, SEQ / 128), 256, GEMM_SMEM>>>(
            xb, w + O_SH, gsb, DIM);
        gemm_acc(gsb, w + O_SD, h, SEQ, DIM, SFI, SFI, SFI, DIM);
    }

    // ---- head + fused loss ----
    rmsnorm_kernel<<<SEQ, 256>>>(h, final_ln, xb);
    cudaStreamWaitEvent(0, evLM, 0);
    lmhead_gemm_loss<<<dim3(NCB, SEQ / 128), 256, GEMM_SMEM>>>(xb, wbL, partb, DIM);
    zero_scalar<<<1, 32>>>(out);
    loss_reduce<<<SEQ, 256>>>(partb, xb, wbL, tgt, out);
}

// round 14
// speedup vs baseline: 27.7677x; 1.0980x over previous
#include <cuda_runtime.h>
#include <cuda_bf16.h>
#include <math.h>
#include <stdint.h>

// Model dims
#define SEQ    2048
#define DIM    1024
#define NHEAD  16
#define DH     64
#define NLAYER 2
#define NEXP   8
#define FFI    512
#define SFI    1024
#define VOCAB  32000
#define NCB    (VOCAB / 128)

#define BK 64
#define NSTAGE 3
#define BSTRIDE 72
#define STAGE_BYTES (128 * BSTRIDE * 2)        // 18432
#define GEMM_SMEM (2 * NSTAGE * STAGE_BYTES)   // 110592

#define CONV_GRID 1184

#define QSCALE 0.1803368801111137f  // 0.125 * log2(e)

// flash-attn smem layout (bytes)
#define FA_Q     0
#define FA_QSZ   (128 * 72 * 2)
#define FA_K     (FA_Q + FA_QSZ)
#define FA_KSZ   (128 * 72 * 2)
#define FA_V     (FA_K + 2 * FA_KSZ)
#define FA_VSZ   (64 * 136 * 2)
#define FA_SMEM  (FA_V + 2 * FA_VSZ)    // 90112

// layer weight scratch layout (bf16 elems)
#define WDD   ((size_t)DIM * DIM)
#define O_QKV 0
#define O_WO  (3 * WDD)
#define O_GU  (4 * WDD)
#define O_DN  (O_GU + (size_t)NEXP * 2 * FFI * DIM)
#define O_SH  (O_DN + (size_t)NEXP * FFI * DIM)
#define O_SD  (O_SH + (size_t)2 * SFI * DIM)
#define WL_TOTAL (O_SD + (size_t)SFI * DIM)

// ---------------- static scratch ----------------
__device__ float g_h[SEQ * DIM];
__device__ __nv_bfloat16 g_xb[SEQ * DIM];
__device__ __nv_bfloat16 g_qkvb[SEQ * 3 * DIM];             // bf16 QKV
__device__ __nv_bfloat16 g_qbh[(size_t)NHEAD * SEQ * DH];
__device__ __nv_bfloat16 g_kbh[(size_t)NHEAD * SEQ * DH];
__device__ __nv_bfloat16 g_vth[(size_t)NHEAD * DH * SEQ];
__device__ __nv_bfloat16 g_ob[SEQ * DIM];
__device__ float g_yg[(size_t)NEXP * SEQ * DIM];
__device__ __nv_bfloat16 g_actb[(size_t)NEXP * SEQ * FFI];
__device__ __nv_bfloat16 g_xg[(size_t)NEXP * SEQ * DIM];
__device__ __nv_bfloat16 g_gsb[SEQ * SFI];
__device__ __nv_bfloat16 g_wl0[WL_TOTAL];
__device__ __nv_bfloat16 g_wl1[WL_TOTAL];
__device__ __nv_bfloat16 g_wbL[(size_t)VOCAB * DIM];
__device__ float2 g_part[(size_t)SEQ * NCB];
__device__ int   g_cnt[NEXP];
__device__ int2  g_topi[SEQ];
__device__ int2  g_pos[SEQ];
__device__ float2 g_topw[SEQ];

// ---------------- helpers ----------------
__device__ __forceinline__ uint32_t cvt_bf16x2(float lo, float hi) {
    uint32_t r;
    asm("cvt.rn.bf16x2.f32 %0, %1, %2;" : "=r"(r) : "f"(hi), "f"(lo));
    return r;
}
__device__ __forceinline__ void ldsm4(uint32_t &r0, uint32_t &r1, uint32_t &r2, uint32_t &r3,
                                      uint32_t addr) {
    asm volatile("ldmatrix.sync.aligned.m8n8.x4.shared.b16 {%0,%1,%2,%3}, [%4];"
                 : "=r"(r0), "=r"(r1), "=r"(r2), "=r"(r3) : "r"(addr));
}
__device__ __forceinline__ void mma16816(float* c, const uint32_t* a, const uint32_t* b) {
    asm volatile(
        "mma.sync.aligned.m16n8k16.row.col.f32.bf16.bf16.f32 "
        "{%0,%1,%2,%3}, {%4,%5,%6,%7}, {%8,%9}, {%0,%1,%2,%3};"
        : "+f"(c[0]), "+f"(c[1]), "+f"(c[2]), "+f"(c[3])
        : "r"(a[0]), "r"(a[1]), "r"(a[2]), "r"(a[3]), "r"(b[0]), "r"(b[1]));
}
__device__ __forceinline__ void cp_async16(uint32_t dst, const void* src) {
    asm volatile("cp.async.cg.shared.global [%0], [%1], 16;" :: "r"(dst), "l"(src));
}
__device__ __forceinline__ void cp_commit() { asm volatile("cp.async.commit_group;"); }
template<int W> __device__ __forceinline__ void cp_wait() {
    asm volatile("cp.async.wait_group %0;" :: "n"(W));
}

// ---------------- 128x128 GEMM mainloop, BK=64, 3-stage ----------------
__device__ __forceinline__ void gemm128_mainloop(
    const __nv_bfloat16* __restrict__ A, const __nv_bfloat16* __restrict__ B,
    int K, int lda, int ldb, float acc[2][8][4])
{
    extern __shared__ __align__(16) __nv_bfloat16 smem[];
    const int tid = threadIdx.x;
    const int lane = tid & 31;
    const int wid = tid >> 5;
    const int warp_m = wid & 3;
    const int warp_n = wid >> 2;
    const int g = lane >> 3, lr = lane & 7;

    const uint32_t As_base = (uint32_t)__cvta_generic_to_shared(smem);
    const uint32_t Bs_base = As_base + NSTAGE * STAGE_BYTES;
    const int ntiles = K >> 6;

    auto issue = [&](int t, int s) {
        const __nv_bfloat16* Ag = A + t * BK;
        const __nv_bfloat16* Bg = B + t * BK;
        const uint32_t a_s = As_base + s * STAGE_BYTES;
        const uint32_t b_s = Bs_base + s * STAGE_BYTES;
#pragma unroll
        for (int i = 0; i < 4; i++) {
            int id = i * 256 + tid;
            int r = id >> 3;
            int c = (id & 7) * 8;
            cp_async16(a_s + (r * BSTRIDE + c) * 2, Ag + (size_t)r * lda + c);
            cp_async16(b_s + (r * BSTRIDE + c) * 2, Bg + (size_t)r * ldb + c);
        }
    };

#pragma unroll
    for (int s = 0; s < NSTAGE - 1; s++) {
        if (s < ntiles) issue(s, s);
        cp_commit();
    }

#pragma unroll
    for (int mt = 0; mt < 2; mt++)
#pragma unroll
        for (int nt = 0; nt < 8; nt++)
#pragma unroll
            for (int i = 0; i < 4; i++) acc[mt][nt][i] = 0.f;

    int s = 0;
    for (int t = 0; t < ntiles; t++) {
        cp_wait<NSTAGE - 2>();
        __syncthreads();

        const uint32_t a_base = As_base + s * STAGE_BYTES;
        const uint32_t b_base = Bs_base + s * STAGE_BYTES;

#pragma unroll
        for (int ks = 0; ks < 4; ks++) {
            uint32_t a[2][4];
#pragma unroll
            for (int mt = 0; mt < 2; mt++) {
                int row = warp_m * 32 + mt * 16 + (g & 1) * 8 + lr;
                int col = ks * 16 + (g >> 1) * 8;
                ldsm4(a[mt][0], a[mt][1], a[mt][2], a[mt][3],
                      a_base + (uint32_t)(row * BSTRIDE + col) * 2);
            }
            uint32_t b[8][2];
#pragma unroll
            for (int np = 0; np < 4; np++) {
                int row = warp_n * 64 + np * 16 + (g >> 1) * 8 + lr;
                int col = ks * 16 + (g & 1) * 8;
                uint32_t r0, r1, r2, r3;
                ldsm4(r0, r1, r2, r3, b_base + (uint32_t)(row * BSTRIDE + col) * 2);
                b[2 * np][0] = r0; b[2 * np][1] = r1;
                b[2 * np + 1][0] = r2; b[2 * np + 1][1] = r3;
            }
#pragma unroll
            for (int mt = 0; mt < 2; mt++)
#pragma unroll
                for (int nt = 0; nt < 8; nt++)
                    mma16816(acc[mt][nt], a[mt], b[nt]);
        }

        int nt2 = t + NSTAGE - 1;
        if (nt2 < ntiles) {
            int s2 = nt2 % NSTAGE;
            issue(nt2, s2);
        }
        cp_commit();
        s = (s + 1 == NSTAGE) ? 0 : s + 1;
    }
}

template<bool ACC>
__device__ __forceinline__ void epilogue_store(float* __restrict__ C, int ldc,
                                               float acc[2][8][4])
{
    const int tid = threadIdx.x;
    const int lane = tid & 31;
    const int wid = tid >> 5;
    const int warp_m = wid & 3;
    const int warp_n = wid >> 2;
    const int r0c = lane >> 2;
    const int cc  = (lane & 3) * 2;
#pragma unroll
    for (int mt = 0; mt < 2; mt++) {
        int rbase = warp_m * 32 + mt * 16 + r0c;
#pragma unroll
        for (int nt = 0; nt < 8; nt++) {
            int col = warp_n * 64 + nt * 8 + cc;
            size_t i00 = (size_t)rbase * ldc + col;
            size_t i10 = (size_t)(rbase + 8) * ldc + col;
            if (ACC) {
                C[i00]     += acc[mt][nt][0]; C[i00 + 1] += acc[mt][nt][1];
                C[i10]     += acc[mt][nt][2]; C[i10 + 1] += acc[mt][nt][3];
            } else {
                C[i00]     = acc[mt][nt][0]; C[i00 + 1] = acc[mt][nt][1];
                C[i10]     = acc[mt][nt][2]; C[i10 + 1] = acc[mt][nt][3];
            }
        }
    }
}

// bf16 packed store epilogue
__device__ __forceinline__ void epilogue_store_bf16(__nv_bfloat16* __restrict__ C, int ldc,
                                                    float acc[2][8][4])
{
    const int tid = threadIdx.x;
    const int lane = tid & 31;
    const int wid = tid >> 5;
    const int warp_m = wid & 3;
    const int warp_n = wid >> 2;
    const int r0c = lane >> 2;
    const int cc  = (lane & 3) * 2;
#pragma unroll
    for (int mt = 0; mt < 2; mt++) {
        int rbase = warp_m * 32 + mt * 16 + r0c;
#pragma unroll
        for (int nt = 0; nt < 8; nt++) {
            int col = warp_n * 64 + nt * 8 + cc;
            *(uint32_t*)(C + (size_t)rbase * ldc + col) =
                cvt_bf16x2(acc[mt][nt][0], acc[mt][nt][1]);
            *(uint32_t*)(C + (size_t)(rbase + 8) * ldc + col) =
                cvt_bf16x2(acc[mt][nt][2], acc[mt][nt][3]);
        }
    }
}

__device__ __forceinline__ void epilogue_act(__nv_bfloat16* __restrict__ O, int ldo,
                                             float acc[2][8][4])
{
    const int tid = threadIdx.x;
    const int lane = tid & 31;
    const int wid = tid >> 5;
    const int warp_m = wid & 3;
    const int warp_n = wid >> 2;
    const int r0c = lane >> 2;
    const int cp0 = lane & 3;
#pragma unroll
    for (int mt = 0; mt < 2; mt++) {
        int rbase = warp_m * 32 + mt * 16 + r0c;
#pragma unroll
        for (int nt = 0; nt < 8; nt++) {
            int cp = warp_n * 32 + nt * 4 + cp0;
            float g0 = acc[mt][nt][0], u0 = acc[mt][nt][1];
            float g1 = acc[mt][nt][2], u1 = acc[mt][nt][3];
            float s0 = 1.f / (1.f + expf(-g0));
            float s1 = 1.f / (1.f + expf(-g1));
            O[(size_t)rbase * ldo + cp]       = __float2bfloat16(g0 * s0 * u0);
            O[(size_t)(rbase + 8) * ldo + cp] = __float2bfloat16(g1 * s1 * u1);
        }
    }
}

template<bool ACC>
__global__ void __launch_bounds__(256, 2) bf16_gemm_kernel(
    const __nv_bfloat16* __restrict__ A, const __nv_bfloat16* __restrict__ B,
    float* __restrict__ C, int K, int lda, int ldb, int ldc)
{
    A += (size_t)blockIdx.y * 128 * lda;
    B += (size_t)blockIdx.x * 128 * ldb;
    C += (size_t)blockIdx.y * 128 * ldc + blockIdx.x * 128;
    float acc[2][8][4];
    gemm128_mainloop(A, B, K, lda, ldb, acc);
    epilogue_store<ACC>(C, ldc, acc);
}

__global__ void __launch_bounds__(256, 2) bf16_gemm_bf16out(
    const __nv_bfloat16* __restrict__ A, const __nv_bfloat16* __restrict__ B,
    __nv_bfloat16* __restrict__ C, int K, int lda, int ldb, int ldc)
{
    A += (size_t)blockIdx.y * 128 * lda;
    B += (size_t)blockIdx.x * 128 * ldb;
    C += (size_t)blockIdx.y * 128 * ldc + blockIdx.x * 128;
    float acc[2][8][4];
    gemm128_mainloop(A, B, K, lda, ldb, acc);
    epilogue_store_bf16(C, ldc, acc);
}

__global__ void __launch_bounds__(256, 2) gemm_act_kernel(
    const __nv_bfloat16* __restrict__ A, const __nv_bfloat16* __restrict__ B,
    __nv_bfloat16* __restrict__ O, int K)
{
    A += (size_t)blockIdx.y * 128 * K;
    B += (size_t)blockIdx.x * 128 * K;
    O += (size_t)blockIdx.y * 128 * SFI + blockIdx.x * 64;
    float acc[2][8][4];
    gemm128_mainloop(A, B, K, K, K, acc);
    epilogue_act(O, SFI, acc);
}

__global__ void __launch_bounds__(256, 2) moe_gemm_act_kernel(
    const __nv_bfloat16* __restrict__ A, const __nv_bfloat16* __restrict__ B,
    __nv_bfloat16* __restrict__ O, const int* __restrict__ cnt)
{
    const int e = blockIdx.y >> 4;
    const int rb = blockIdx.y & 15;
    if (rb * 128 >= cnt[e]) return;
    A += ((size_t)e * SEQ + rb * 128) * DIM;
    B += (size_t)e * (2 * FFI) * DIM + (size_t)blockIdx.x * 128 * DIM;
    O += ((size_t)e * SEQ + rb * 128) * FFI + blockIdx.x * 64;
    float acc[2][8][4];
    gemm128_mainloop(A, B, DIM, DIM, DIM, acc);
    epilogue_act(O, FFI, acc);
}

__global__ void __launch_bounds__(256, 2) moe_gemm_kernel(
    const __nv_bfloat16* __restrict__ A, const __nv_bfloat16* __restrict__ B,
    float* __restrict__ C, const int* __restrict__ cnt, int K, int N)
{
    const int e = blockIdx.y >> 4;
    const int rb = blockIdx.y & 15;
    if (rb * 128 >= cnt[e]) return;
    A += ((size_t)e * SEQ + rb * 128) * K;
    B += (size_t)e * N * K + (size_t)blockIdx.x * 128 * K;
    C += ((size_t)e * SEQ + rb * 128) * N + blockIdx.x * 128;
    float acc[2][8][4];
    gemm128_mainloop(A, B, K, K, K, acc);
    epilogue_store<false>(C, N, acc);
}

__global__ void __launch_bounds__(256, 2) lmhead_gemm_loss(
    const __nv_bfloat16* __restrict__ A, const __nv_bfloat16* __restrict__ B,
    float2* __restrict__ part, int K)
{
    const int bx = blockIdx.x;
    A += (size_t)blockIdx.y * 128 * K;
    B += (size_t)bx * 128 * K;
    float acc[2][8][4];
    gemm128_mainloop(A, B, K, K, K, acc);

    const int tid = threadIdx.x;
    const int lane = tid & 31;
    const int wid = tid >> 5;
    const int warp_m = wid & 3;
    const int warp_n = wid >> 2;

    __shared__ float sm_m[2][128], sm_s[2][128];

#pragma unroll
    for (int mt = 0; mt < 2; mt++) {
#pragma unroll
        for (int half = 0; half < 2; half++) {
            float m = -1e30f;
#pragma unroll
            for (int nt = 0; nt < 8; nt++)
                m = fmaxf(m, fmaxf(acc[mt][nt][2 * half], acc[mt][nt][2 * half + 1]));
            m = fmaxf(m, __shfl_xor_sync(0xffffffffu, m, 1));
            m = fmaxf(m, __shfl_xor_sync(0xffffffffu, m, 2));
            float s = 0.f;
#pragma unroll
            for (int nt = 0; nt < 8; nt++)
                s += expf(acc[mt][nt][2 * half] - m) + expf(acc[mt][nt][2 * half + 1] - m);
            s += __shfl_xor_sync(0xffffffffu, s, 1);
            s += __shfl_xor_sync(0xffffffffu, s, 2);
            if ((lane & 3) == 0) {
                int row_local = warp_m * 32 + mt * 16 + half * 8 + (lane >> 2);
                sm_m[warp_n][row_local] = m;
                sm_s[warp_n][row_local] = s;
            }
        }
    }
    __syncthreads();

    if (tid < 128) {
        float m1 = sm_m[0][tid], s1 = sm_s[0][tid];
        float m2 = sm_m[1][tid], s2 = sm_s[1][tid];
        float nm = fmaxf(m1, m2);
        float ns = s1 * expf(m1 - nm) + s2 * expf(m2 - nm);
        int row = blockIdx.y * 128 + tid;
        part[(size_t)row * NCB + bx] = make_float2(nm, ns);
    }
}

__global__ void loss_reduce(const float2* __restrict__ part,
                            const __nv_bfloat16* __restrict__ xb,
                            const __nv_bfloat16* __restrict__ wb,
                            const int* __restrict__ tgt, float* __restrict__ out)
{
    int row = blockIdx.x;
    int tid = threadIdx.x;

    float m = -1e30f, s = 0.f;
    for (int j = tid; j < NCB; j += 256) {
        float2 p = part[(size_t)row * NCB + j];
        float nm = fmaxf(m, p.x);
        s = s * expf(m - nm) + p.y * expf(p.x - nm);
        m = nm;
    }

    __shared__ float ms[256], ss[256], ds[256];
    ms[tid] = m; ss[tid] = s;
    __syncthreads();
    for (int st = 128; st > 0; st >>= 1) {
        if (tid < st) {
            float m1 = ms[tid], m2 = ms[tid + st];
            float nm = fmaxf(m1, m2);
            ss[tid] = ss[tid] * expf(m1 - nm) + ss[tid + st] * expf(m2 - nm);
            ms[tid] = nm;
        }
        __syncthreads();
    }

    int lab = tgt[row];
    int slab = (lab == -100) ? 0 : lab;
    const __nv_bfloat16* xr = xb + (size_t)row * DIM;
    const __nv_bfloat16* wr = wb + (size_t)slab * DIM;
    float d = 0.f;
    for (int i = tid; i < DIM; i += 256)
        d += __bfloat162float(xr[i]) * __bfloat162float(wr[i]);
    ds[tid] = d;
    __syncthreads();
    for (int st = 128; st > 0; st >>= 1) {
        if (tid < st) ds[tid] += ds[tid + st];
        __syncthreads();
    }

    if (tid == 0 && lab != -100) {
        float lse = ms[0] + logf(ss[0]);
        atomicAdd(out, lse - ds[0]);
    }
}

// ---------------- weight conversion (grid-stride) ----------------
__global__ void convert_w(const float* __restrict__ w, __nv_bfloat16* __restrict__ wb,
                          size_t n4)
{
    const float4* w4 = (const float4*)w;
    uint2* o2 = (uint2*)wb;
    size_t stride = (size_t)gridDim.x * 256;
    for (size_t i = (size_t)blockIdx.x * 256 + threadIdx.x; i < n4; i += stride * 4) {
        float4 v[4];
        bool ok[4];
#pragma unroll
        for (int k = 0; k < 4; k++) {
            size_t j = i + (size_t)k * stride;
            ok[k] = j < n4;
            if (ok[k]) v[k] = w4[j];
        }
#pragma unroll
        for (int k = 0; k < 4; k++) if (ok[k]) {
            uint2 pk;
            pk.x = cvt_bf16x2(v[k].x, v[k].y);
            pk.y = cvt_bf16x2(v[k].z, v[k].w);
            o2[i + (size_t)k * stride] = pk;
        }
    }
}

__global__ void convert_pair(const float* __restrict__ a, const float* __restrict__ b,
                             __nv_bfloat16* __restrict__ wb, size_t n4, int log2r2)
{
    uint2* o2 = (uint2*)wb;
    size_t stride = (size_t)gridDim.x * 256;
    for (size_t i = (size_t)blockIdx.x * 256 + threadIdx.x; i < n4; i += stride * 4) {
        float4 v[4];
        bool ok[4];
#pragma unroll
        for (int k = 0; k < 4; k++) {
            size_t j = i + (size_t)k * stride;
            ok[k] = j < n4;
            if (ok[k]) {
                int k4 = (int)(j & 255);
                size_t n = j >> 8;
                size_t e = n >> log2r2;
                int r = (int)(n & ((1u << log2r2) - 1));
                const float* src = ((r & 1) ? b : a)
                    + ((e << (log2r2 - 1)) + (r >> 1)) * (size_t)DIM + k4 * 4;
                v[k] = *(const float4*)src;
            }
        }
#pragma unroll
        for (int k = 0; k < 4; k++) if (ok[k]) {
            uint2 pk;
            pk.x = cvt_bf16x2(v[k].x, v[k].y);
            pk.y = cvt_bf16x2(v[k].z, v[k].w);
            o2[i + (size_t)k * stride] = pk;
        }
    }
}

// ---------------- rope (bf16 in) -> bf16 per-head Q/K ----------------
__global__ void rope_bf16_kernel(const __nv_bfloat16* __restrict__ qkv,
                                 __nv_bfloat16* __restrict__ qb,
                                 __nv_bfloat16* __restrict__ kb)
{
    int s = blockIdx.x;
    int tid = threadIdx.x;
    int h = tid >> 5, i = tid & 31;
    float freq = powf(10000.f, -(float)(2 * i) / 64.f);
    float ang = (float)s * freq;
    float sn, cs;
    sincosf(ang, &sn, &cs);
    size_t src = (size_t)s * (3 * DIM) + h * DH + i;
    float q1 = __bfloat162float(qkv[src]), q2 = __bfloat162float(qkv[src + 32]);
    size_t dst = ((size_t)h * SEQ + s) * DH + i;
    qb[dst]      = __float2bfloat16((q1 * cs - q2 * sn) * QSCALE);
    qb[dst + 32] = __float2bfloat16((q2 * cs + q1 * sn) * QSCALE);
    float k1 = __bfloat162float(qkv[src + DIM]), k2 = __bfloat162float(qkv[src + DIM + 32]);
    kb[dst]      = __float2bfloat16(k1 * cs - k2 * sn);
    kb[dst + 32] = __float2bfloat16(k2 * cs + k1 * sn);
}

// V transpose: bf16 [SEQ][3*DIM](offset 2*DIM) -> vt bf16 [DIM][SEQ]
__global__ void vtrans_kernel(const __nv_bfloat16* __restrict__ v,
                              __nv_bfloat16* __restrict__ vt)
{
    __shared__ __nv_bfloat16 tile[32][34];
    int s0 = blockIdx.x * 32, d0 = blockIdx.y * 32;
    int tx = threadIdx.x, ty = threadIdx.y;   // 32 x 8
#pragma unroll
    for (int i = 0; i < 4; i++) {
        int row = ty + i * 8;
        tile[row][tx] = v[(size_t)(s0 + row) * (3 * DIM) + 2 * DIM + d0 + tx];
    }
    __syncthreads();
#pragma unroll
    for (int i = 0; i < 4; i++) {
        int row = ty + i * 8;
        vt[(size_t)(d0 + row) * SEQ + s0 + tx] = tile[tx][row];
    }
}

// ---------------- flash attention (unchanged from R13) ----------------
__global__ void __launch_bounds__(256, 1) flash_attn2_kernel(
    const __nv_bfloat16* __restrict__ qb, const __nv_bfloat16* __restrict__ kb,
    const __nv_bfloat16* __restrict__ vt, __nv_bfloat16* __restrict__ ob)
{
    extern __shared__ __align__(16) char fasm[];
    const int qblk = blockIdx.x;
    const int head = blockIdx.y;
    const int q0 = qblk * 128;

    const int tid = threadIdx.x;
    const int lane = tid & 31;
    const int wid = tid >> 5;
    const int g = lane >> 3, lr = lane & 7;
    const int r0 = wid * 16;

    const uint32_t smb = (uint32_t)__cvta_generic_to_shared(fasm);
    const uint32_t Qs = smb + FA_Q;
    const uint32_t Ks = smb + FA_K;
    const uint32_t Vs = smb + FA_V;

    const __nv_bfloat16* Qg = qb + ((size_t)head * SEQ + q0) * DH;
    const __nv_bfloat16* Kg = kb + (size_t)head * SEQ * DH;
    const __nv_bfloat16* Vg = vt + (size_t)head * DH * SEQ;

#pragma unroll
    for (int i = 0; i < 4; i++) {
        int id = i * 256 + tid;
        int r = id >> 3;
        int c = id & 7;
        cp_async16(Qs + (uint32_t)(r * 144 + c * 16), Qg + (size_t)r * DH + c * 8);
    }
    cp_commit();

    auto issueKV = [&](int kblk, int buf) {
        const int kk0 = kblk * 128;
        const uint32_t kdst = Ks + buf * FA_KSZ;
        const uint32_t vdst = Vs + buf * FA_VSZ;
#pragma unroll
        for (int i = 0; i < 4; i++) {
            int id = i * 256 + tid;
            int r = id >> 3;
            int c = id & 7;
            cp_async16(kdst + (uint32_t)(r * 144 + c * 16),
                       Kg + (size_t)(kk0 + r) * DH + c * 8);
        }
#pragma unroll
        for (int i = 0; i < 4; i++) {
            int id = i * 256 + tid;
            int d = id >> 4;
            int c = id & 15;
            cp_async16(vdst + (uint32_t)(d * 272 + c * 16),
                       Vg + (size_t)d * SEQ + kk0 + c * 8);
        }
    };

    issueKV(0, 0);
    cp_commit();
    cp_wait<0>();
    __syncthreads();

    uint32_t qa[4][4];
#pragma unroll
    for (int kt = 0; kt < 4; kt++) {
        int row = r0 + (g & 1) * 8 + lr;
        int col = kt * 16 + (g >> 1) * 8;
        ldsm4(qa[kt][0], qa[kt][1], qa[kt][2], qa[kt][3],
              Qs + (uint32_t)(row * 72 + col) * 2);
    }

    float acc_o[8][4];
#pragma unroll
    for (int nt = 0; nt < 8; nt++)
#pragma unroll
        for (int i = 0; i < 4; i++) acc_o[nt][i] = 0.f;

    float mA = -1e30f, mB = -1e30f, lA = 0.f, lB = 0.f;
    const int rA = q0 + r0 + (lane >> 2);
    const int rB = rA + 8;

    for (int kblk = 0; kblk <= qblk; kblk++) {
        const int kk0 = kblk * 128;
        const int buf = kblk & 1;

        if (kblk > 0) {
            cp_wait<0>();
            __syncthreads();
        }
        if (kblk < qblk) {
            issueKV(kblk + 1, buf ^ 1);
            cp_commit();
        }

        const uint32_t kbase = Ks + buf * FA_KSZ;
        const uint32_t vbase = Vs + buf * FA_VSZ;

        float sacc[16][4];
#pragma unroll
        for (int nt = 0; nt < 16; nt++)
#pragma unroll
            for (int i = 0; i < 4; i++) sacc[nt][i] = 0.f;

#pragma unroll
        for (int kt = 0; kt < 4; kt++) {
#pragma unroll
            for (int np = 0; np < 8; np++) {
                int row = np * 16 + (g >> 1) * 8 + lr;
                int col = kt * 16 + (g & 1) * 8;
                uint32_t b0, b1, b2, b3;
                ldsm4(b0, b1, b2, b3, kbase + (uint32_t)(row * 72 + col) * 2);
                uint32_t bb0[2] = {b0, b1}, bb1[2] = {b2, b3};
                mma16816(sacc[2 * np],     qa[kt], bb0);
                mma16816(sacc[2 * np + 1], qa[kt], bb1);
            }
        }

        if (kblk == qblk) {
#pragma unroll
            for (int nt = 0; nt < 16; nt++) {
                int cb = kk0 + nt * 8 + 2 * (lane & 3);
                if (cb     > rA) sacc[nt][0] = -1e30f;
                if (cb + 1 > rA) sacc[nt][1] = -1e30f;
                if (cb     > rB) sacc[nt][2] = -1e30f;
                if (cb + 1 > rB) sacc[nt][3] = -1e30f;
            }
        }

        float cmA = -1e30f, cmB = -1e30f;
#pragma unroll
        for (int nt = 0; nt < 16; nt++) {
            cmA = fmaxf(cmA, fmaxf(sacc[nt][0], sacc[nt][1]));
            cmB = fmaxf(cmB, fmaxf(sacc[nt][2], sacc[nt][3]));
        }
        cmA = fmaxf(cmA, __shfl_xor_sync(0xffffffffu, cmA, 1));
        cmA = fmaxf(cmA, __shfl_xor_sync(0xffffffffu, cmA, 2));
        cmB = fmaxf(cmB, __shfl_xor_sync(0xffffffffu, cmB, 1));
        cmB = fmaxf(cmB, __shfl_xor_sync(0xffffffffu, cmB, 2));

        float nmA = fmaxf(mA, cmA), nmB = fmaxf(mB, cmB);
        float scA = exp2f(mA - nmA), scB = exp2f(mB - nmB);
        mA = nmA; mB = nmB;

        uint32_t pA[16], pB[16];
        float sA = 0.f, sB = 0.f;
#pragma unroll
        for (int nt = 0; nt < 16; nt++) {
            float p0 = exp2f(sacc[nt][0] - mA);
            float p1 = exp2f(sacc[nt][1] - mA);
            float p2 = exp2f(sacc[nt][2] - mB);
            float p3 = exp2f(sacc[nt][3] - mB);
            sA += p0 + p1; sB += p2 + p3;
            pA[nt] = cvt_bf16x2(p0, p1);
            pB[nt] = cvt_bf16x2(p2, p3);
        }
        lA = lA * scA + sA;
        lB = lB * scB + sB;
#pragma unroll
        for (int nt = 0; nt < 8; nt++) {
            acc_o[nt][0] *= scA; acc_o[nt][1] *= scA;
            acc_o[nt][2] *= scB; acc_o[nt][3] *= scB;
        }

#pragma unroll
        for (int kt2 = 0; kt2 < 8; kt2++) {
            uint32_t a[4] = { pA[2 * kt2], pB[2 * kt2], pA[2 * kt2 + 1], pB[2 * kt2 + 1] };
#pragma unroll
            for (int np2 = 0; np2 < 4; np2++) {
                int row = np2 * 16 + (g >> 1) * 8 + lr;
                int col = kt2 * 16 + (g & 1) * 8;
                uint32_t b0, b1, b2, b3;
                ldsm4(b0, b1, b2, b3, vbase + (uint32_t)(row * 136 + col) * 2);
                uint32_t bb0[2] = {b0, b1}, bb1[2] = {b2, b3};
                mma16816(acc_o[2 * np2],     a, bb0);
                mma16816(acc_o[2 * np2 + 1], a, bb1);
            }
        }
    }

    lA += __shfl_xor_sync(0xffffffffu, lA, 1);
    lA += __shfl_xor_sync(0xffffffffu, lA, 2);
    lB += __shfl_xor_sync(0xffffffffu, lB, 1);
    lB += __shfl_xor_sync(0xffffffffu, lB, 2);
    float iA = 1.f / lA, iB = 1.f / lB;

#pragma unroll
    for (int nt = 0; nt < 8; nt++) {
        int col = head * DH + nt * 8 + 2 * (lane & 3);
        uint32_t p0 = cvt_bf16x2(acc_o[nt][0] * iA, acc_o[nt][1] * iA);
        uint32_t p1 = cvt_bf16x2(acc_o[nt][2] * iB, acc_o[nt][3] * iB);
        *(uint32_t*)(ob + (size_t)rA * DIM + col) = p0;
        *(uint32_t*)(ob + (size_t)rB * DIM + col) = p1;
    }
}

// ---------------- small kernels ----------------
__global__ void embed_gather(const int* __restrict__ tok, const float* __restrict__ emb,
                             float* __restrict__ h)
{
    int s = blockIdx.x;
    int t = tok[s];
    const float* e = emb + (size_t)t * DIM;
    for (int d = threadIdx.x; d < DIM; d += blockDim.x)
        h[(size_t)s * DIM + d] = e[d];
}

__global__ void rmsnorm_kernel(const float* __restrict__ x, const float* __restrict__ w,
                               __nv_bfloat16* __restrict__ o)
{
    int row = blockIdx.x;
    const float* xr = x + (size_t)row * DIM;
    __shared__ float red[256];
    int tid = threadIdx.x;
    float s = 0.f;
    for (int d = tid; d < DIM; d += 256) { float v = xr[d]; s += v * v; }
    red[tid] = s; __syncthreads();
    for (int st = 128; st > 0; st >>= 1) {
        if (tid < st) red[tid] += red[tid + st];
        __syncthreads();
    }
    float rs = rsqrtf(red[0] / (float)DIM + 1e-6f);
    for (int d = tid; d < DIM; d += 256)
        o[(size_t)row * DIM + d] = __float2bfloat16(xr[d] * rs * w[d]);
}

__global__ void gate_topk(const __nv_bfloat16* __restrict__ x, const float* __restrict__ gw,
                          int2* __restrict__ topi, float2* __restrict__ topw)
{
    int t = blockIdx.x;
    int tid = threadIdx.x;
    int e = tid >> 5, lane = tid & 31;
    const __nv_bfloat16* xr = x + (size_t)t * DIM;
    const float* wr = gw + (size_t)e * DIM;
    float s = 0.f;
    for (int d = lane; d < DIM; d += 32) s += __bfloat162float(xr[d]) * wr[d];
    for (int o = 16; o; o >>= 1) s += __shfl_down_sync(0xffffffffu, s, o);
    __shared__ float lg[NEXP];
    if (lane == 0) lg[e] = s;
    __syncthreads();
    if (tid == 0) {
        float m = -1e30f;
        for (int i = 0; i < NEXP; i++) m = fmaxf(m, lg[i]);
        float p[NEXP]; float sum = 0.f;
        for (int i = 0; i < NEXP; i++) { p[i] = expf(lg[i] - m); sum += p[i]; }
        float inv = 1.f / sum;
        for (int i = 0; i < NEXP; i++) p[i] *= inv;
        int i0 = 0;
        for (int i = 1; i < NEXP; i++) if (p[i] > p[i0]) i0 = i;
        int i1 = -1;
        for (int i = 0; i < NEXP; i++) {
            if (i == i0) continue;
            if (i1 < 0 || p[i] > p[i1]) i1 = i;
        }
        topi[t] = make_int2(i0, i1);
        topw[t] = make_float2(p[i0], p[i1]);
    }
}

__global__ void zero_counts(int* cnt)
{
    if (threadIdx.x < NEXP) cnt[threadIdx.x] = 0;
}

__global__ void gather_rows(const __nv_bfloat16* __restrict__ xb, __nv_bfloat16* __restrict__ xg,
                            const int2* __restrict__ topi, int2* __restrict__ pos,
                            int* __restrict__ cnt)
{
    int t = blockIdx.x;
    __shared__ int sp[2];
    int2 ti = topi[t];
    if (threadIdx.x == 0) {
        sp[0] = atomicAdd(&cnt[ti.x], 1);
        sp[1] = atomicAdd(&cnt[ti.y], 1);
    }
    __syncthreads();
    const uint32_t* src = (const uint32_t*)(xb + (size_t)t * DIM);
    uint32_t* d0 = (uint32_t*)(xg + ((size_t)ti.x * SEQ + sp[0]) * DIM);
    uint32_t* d1 = (uint32_t*)(xg + ((size_t)ti.y * SEQ + sp[1]) * DIM);
    for (int i = threadIdx.x; i < DIM / 2; i += 256) {
        uint32_t v = src[i];
        d0[i] = v; d1[i] = v;
    }
    if (threadIdx.x == 0) pos[t] = make_int2(sp[0], sp[1]);
}

__global__ void scatter_add(float* __restrict__ h, const float* __restrict__ yg,
                            const int2* __restrict__ topi, const int2* __restrict__ pos,
                            const float2* __restrict__ topw)
{
    int t = blockIdx.x;
    int2 ti = topi[t];
    int2 ps = pos[t];
    float2 w = topw[t];
    const float* y0 = yg + ((size_t)ti.x * SEQ + ps.x) * DIM;
    const float* y1 = yg + ((size_t)ti.y * SEQ + ps.y) * DIM;
    float* hr = h + (size_t)t * DIM;
    for (int d = threadIdx.x; d < DIM; d += 256)
        hr[d] += w.x * y0[d] + w.y * y1[d];
}

__global__ void zero_scalar(float* p)
{
    if (threadIdx.x == 0 && blockIdx.x == 0) p[0] = 0.f;
}

// ---------------- host ----------------
static void gemm_acc(const __nv_bfloat16* A, const __nv_bfloat16* B, float* C,
                     int M, int N, int K, int lda, int ldb, int ldc)
{
    bf16_gemm_kernel<true><<<dim3(N / 128, M / 128), 256, GEMM_SMEM>>>(A, B, C, K, lda, ldb, ldc);
}
static void conv_w_s(cudaStream_t s, const float* w, __nv_bfloat16* wb, size_t nelem)
{
    convert_w<<<CONV_GRID, 256, 0, s>>>(w, wb, nelem / 4);
}

static void convert_layer(cudaStream_t s, int l,
                          const float* Wq, const float* Wk, const float* Wv, const float* Wo,
                          const float* gate_proj, const float* up_proj, const float* down_proj,
                          const float* sg, const float* su, const float* sd,
                          __nv_bfloat16* wl)
{
    const size_t DD = WDD;
    const size_t EID = (size_t)NEXP * FFI * DIM;
    const size_t SD = (size_t)SFI * DIM;
    conv_w_s(s, Wq + l * DD, wl + O_QKV,          DD);
    conv_w_s(s, Wk + l * DD, wl + O_QKV + DD,     DD);
    conv_w_s(s, Wv + l * DD, wl + O_QKV + 2 * DD, DD);
    conv_w_s(s, Wo + l * DD, wl + O_WO, DD);
    convert_pair<<<CONV_GRID, 256, 0, s>>>(gate_proj + l * EID, up_proj + l * EID,
                                           wl + O_GU, 2 * EID / 4, 10);
    conv_w_s(s, down_proj + l * EID, wl + O_DN, EID);
    convert_pair<<<CONV_GRID, 256, 0, s>>>(sg + l * SD, su + l * SD,
                                           wl + O_SH, 2 * SD / 4, 11);
    conv_w_s(s, sd + l * SD, wl + O_SD, SD);
}

extern "C" void kernel_launch(void* const* d_in, const int* in_sizes, int n_in,
                              void* d_out, int out_size)
{
    (void)in_sizes; (void)n_in; (void)out_size;
    const int*   src       = (const int*)d_in[0];
    const int*   tgt       = (const int*)d_in[1];
    const float* embed     = (const float*)d_in[2];
    const float* Wq        = (const float*)d_in[3];
    const float* Wk        = (const float*)d_in[4];
    const float* Wv        = (const float*)d_in[5];
    const float* Wo        = (const float*)d_in[6];
    const float* ln1       = (const float*)d_in[7];
    const float* ln2       = (const float*)d_in[8];
    const float* gate_w    = (const float*)d_in[9];
    const float* gate_proj = (const float*)d_in[10];
    const float* up_proj   = (const float*)d_in[11];
    const float* down_proj = (const float*)d_in[12];
    const float* sg        = (const float*)d_in[13];
    const float* su        = (const float*)d_in[14];
    const float* sd        = (const float*)d_in[15];
    const float* final_ln  = (const float*)d_in[16];
    const float* lm_head   = (const float*)d_in[17];
    float* out = (float*)d_out;

    static cudaStream_t sC = nullptr;
    static cudaEvent_t evFork = nullptr, evL[NLAYER], evLM = nullptr;
    if (!sC) {
        cudaStreamCreateWithFlags(&sC, cudaStreamNonBlocking);
        cudaEventCreateWithFlags(&evFork, cudaEventDisableTiming);
        for (int l = 0; l < NLAYER; l++)
            cudaEventCreateWithFlags(&evL[l], cudaEventDisableTiming);
        cudaEventCreateWithFlags(&evLM, cudaEventDisableTiming);

        cudaFuncSetAttribute(bf16_gemm_kernel<false>, cudaFuncAttributeMaxDynamicSharedMemorySize, GEMM_SMEM);
        cudaFuncSetAttribute(bf16_gemm_kernel<true>,  cudaFuncAttributeMaxDynamicSharedMemorySize, GEMM_SMEM);
        cudaFuncSetAttribute(bf16_gemm_bf16out,       cudaFuncAttributeMaxDynamicSharedMemorySize, GEMM_SMEM);
        cudaFuncSetAttribute(moe_gemm_kernel,         cudaFuncAttributeMaxDynamicSharedMemorySize, GEMM_SMEM);
        cudaFuncSetAttribute(moe_gemm_act_kernel,     cudaFuncAttributeMaxDynamicSharedMemorySize, GEMM_SMEM);
        cudaFuncSetAttribute(gemm_act_kernel,         cudaFuncAttributeMaxDynamicSharedMemorySize, GEMM_SMEM);
        cudaFuncSetAttribute(lmhead_gemm_loss,        cudaFuncAttributeMaxDynamicSharedMemorySize, GEMM_SMEM);
        cudaFuncSetAttribute(flash_attn2_kernel,      cudaFuncAttributeMaxDynamicSharedMemorySize, FA_SMEM);
    }

    float *h, *yg;
    __nv_bfloat16 *xb, *qkvb, *qbh, *kbh, *vth, *ob, *actb, *xg, *gsb, *wbL;
    __nv_bfloat16 *wl[NLAYER];
    float2 *partb;
    int *cnt; int2 *topi, *pos; float2 *topw;
    cudaGetSymbolAddress((void**)&h,     g_h);
    cudaGetSymbolAddress((void**)&xb,    g_xb);
    cudaGetSymbolAddress((void**)&qkvb,  g_qkvb);
    cudaGetSymbolAddress((void**)&qbh,   g_qbh);
    cudaGetSymbolAddress((void**)&kbh,   g_kbh);
    cudaGetSymbolAddress((void**)&vth,   g_vth);
    cudaGetSymbolAddress((void**)&ob,    g_ob);
    cudaGetSymbolAddress((void**)&yg,    g_yg);
    cudaGetSymbolAddress((void**)&actb,  g_actb);
    cudaGetSymbolAddress((void**)&xg,    g_xg);
    cudaGetSymbolAddress((void**)&gsb,   g_gsb);
    cudaGetSymbolAddress((void**)&wl[0], g_wl0);
    cudaGetSymbolAddress((void**)&wl[1], g_wl1);
    cudaGetSymbolAddress((void**)&wbL,   g_wbL);
    cudaGetSymbolAddress((void**)&partb, g_part);
    cudaGetSymbolAddress((void**)&cnt,   g_cnt);
    cudaGetSymbolAddress((void**)&topi,  g_topi);
    cudaGetSymbolAddress((void**)&pos,   g_pos);
    cudaGetSymbolAddress((void**)&topw,  g_topw);

    // ---- fork: all weight conversions on side stream ----
    cudaEventRecord(evFork, 0);
    cudaStreamWaitEvent(sC, evFork, 0);
    for (int l = 0; l < NLAYER; l++) {
        convert_layer(sC, l, Wq, Wk, Wv, Wo, gate_proj, up_proj, down_proj,
                      sg, su, sd, wl[l]);
        cudaEventRecord(evL[l], sC);
    }
    conv_w_s(sC, lm_head, wbL, (size_t)VOCAB * DIM);
    cudaEventRecord(evLM, sC);

    // ---- main stream compute ----
    embed_gather<<<SEQ, 256>>>(src, embed, h);

    for (int l = 0; l < NLAYER; l++) {
        __nv_bfloat16* w = wl[l];
        rmsnorm_kernel<<<SEQ, 256>>>(h, ln1 + (size_t)l * DIM, xb);
        cudaStreamWaitEvent(0, evL[l], 0);

        bf16_gemm_bf16out<<<dim3((3 * DIM) / 128, SEQ / 128), 256, GEMM_SMEM>>>(
            xb, w + O_QKV, qkvb, DIM, DIM, DIM, 3 * DIM);
        rope_bf16_kernel<<<SEQ, NHEAD * 32>>>(qkvb, qbh, kbh);
        vtrans_kernel<<<dim3(SEQ / 32, DIM / 32), dim3(32, 8)>>>(qkvb, vth);

        flash_attn2_kernel<<<dim3(SEQ / 128, NHEAD), 256, FA_SMEM>>>(qbh, kbh, vth, ob);

        gemm_acc(ob, w + O_WO, h, SEQ, DIM, DIM, DIM, DIM, DIM);

        // ---- MoE (sparse top-2, fused act) ----
        rmsnorm_kernel<<<SEQ, 256>>>(h, ln2 + (size_t)l * DIM, xb);
        gate_topk<<<SEQ, 256>>>(xb, gate_w + (size_t)l * NEXP * DIM, topi, topw);
        zero_counts<<<1, 32>>>(cnt);
        gather_rows<<<SEQ, 256>>>(xb, xg, topi, pos, cnt);

        moe_gemm_act_kernel<<<dim3((2 * FFI) / 128, NEXP * 16), 256, GEMM_SMEM>>>(
            xg, w + O_GU, actb, cnt);
        moe_gemm_kernel<<<dim3(DIM / 128, NEXP * 16), 256, GEMM_SMEM>>>(
            actb, w + O_DN, yg, cnt, FFI, DIM);
        scatter_add<<<SEQ, 256>>>(h, yg, topi, pos, topw);

        // ---- shared expert (fused act) ----
        gemm_act_kernel<<<dim3((2 * SFI) / 128, SEQ / 128), 256, GEMM_SMEM>>>(
            xb, w + O_SH, gsb, DIM);
        gemm_acc(gsb, w + O_SD, h, SEQ, DIM, SFI, SFI, SFI, DIM);
    }

    // ---- head + fused loss ----
    rmsnorm_kernel<<<SEQ, 256>>>(h, final_ln, xb);
    cudaStreamWaitEvent(0, evLM, 0);
    lmhead_gemm_loss<<<dim3(NCB, SEQ / 128), 256, GEMM_SMEM>>>(xb, wbL, partb, DIM);
    zero_scalar<<<1, 32>>>(out);
    loss_reduce<<<SEQ, 256>>>(partb, xb, wbL, tgt, out);
}